// round 1
// baseline (speedup 1.0000x reference)
#include <cuda_runtime.h>
#include <math.h>
#include <stdint.h>

// ---------------- problem constants ----------------
#define NTOK   16384          // 8*2048 tokens
#define EDIM   256
#define NE     8192
#define LAT    768
#define ODIM   768

// output layout (concatenated tuple, float32)
#define OFF_ZQ     ((size_t)0)                       // 12582912
#define OFF_IND    ((size_t)12582912)                // 16384
#define OFF_LOSS   ((size_t)12599296)                // 1
#define OFF_EMB    ((size_t)12599297)                // 2097152
#define OFF_EAVG   ((size_t)14696449)                // 2097152
#define OFF_CS     ((size_t)16793601)                // 8192
#define OFF_ENTMIN ((size_t)16801793)                // 1
#define OFF_COMMIT ((size_t)16801794)                // 1

// ---------------- device scratch (static, allocation-free) ----------------
__device__ float g_e[(size_t)NTOK * NE];        // exp(10*d), 512MB
__device__ float g_xn[NTOK * EDIM];             // x_proj then l2-normalized
__device__ float g_zq[NTOK * EDIM];             // straight-through z_q
__device__ float g_S[NTOK];
__device__ float g_T[NTOK];
__device__ float g_invS[NTOK];
__device__ unsigned long long g_minkey[NTOK];
__device__ float g_bins[NE];
__device__ float g_ap[NE];
__device__ float g_cluster_new[NE];
__device__ int   g_expired[NE];
__device__ int   g_sampidx[NE];
__device__ float g_embed_sum[NE * EDIM];
__device__ float g_scal[4];   // 0: commit sum, 1: entmin sum, 2: total cluster

// ---------------- fast exp: Cody-Waite + deg-7 Taylor, FFMA only ----------------
__device__ __forceinline__ float fast_exp(float x) {
    // valid for |x| <= ~14.5 here (x = 10*d, d in [-1,1])
    float z = x * 1.4426950408889634f;
    int   i = __float2int_rn(z);
    float rf = (float)i;
    float g = fmaf(rf, -0.693359375f, x);        // ln2_hi
    g = fmaf(rf, 2.12194440e-4f, g);             // -ln2_lo
    float p = 1.98412698e-4f;                    // 1/5040
    p = fmaf(p, g, 1.38888889e-3f);              // 1/720
    p = fmaf(p, g, 8.33333333e-3f);              // 1/120
    p = fmaf(p, g, 4.16666667e-2f);              // 1/24
    p = fmaf(p, g, 1.66666667e-1f);              // 1/6
    p = fmaf(p, g, 0.5f);
    p = fmaf(p, g, 1.0f);
    p = fmaf(p, g, 1.0f);
    float sc = __int_as_float((i + 127) << 23);
    return p * sc;
}

// ---------------- zeroing (graph-replay determinism) ----------------
__global__ void zero_kernel() {
    int i = blockIdx.x * 256 + threadIdx.x;
    if (i < NE * EDIM) g_embed_sum[i] = 0.f;
    if (i < NTOK) { g_S[i] = 0.f; g_T[i] = 0.f; g_minkey[i] = ~0ULL; }
    if (i < NE)   { g_bins[i] = 0.f; g_ap[i] = 0.f; }
    if (i < 4)    g_scal[i] = 0.f;
}

// ---------------- generic SGEMM: C[M,N] = A[M,K] @ W[N,K]^T + bias ----------------
// 128x128 tile, BK=8, 256 threads, 8x8 microtile
__global__ void __launch_bounds__(256)
gemm_bias_kernel(const float* __restrict__ A, const float* __restrict__ W,
                 const float* __restrict__ bias, float* __restrict__ C,
                 int M, int N, int K) {
    __shared__ float As[8][132];
    __shared__ float Ws[8][132];
    const int tid = threadIdx.x;
    const int tx = tid & 15, ty = tid >> 4;
    const int bm = blockIdx.y * 128, bn = blockIdx.x * 128;
    float acc[8][8] = {};
    const int lrow = tid >> 1;
    const int lk4  = (tid & 1) * 4;
    const float* Ap = A + (size_t)(bm + lrow) * K + lk4;
    const float* Wp = W + (size_t)(bn + lrow) * K + lk4;
    for (int k0 = 0; k0 < K; k0 += 8) {
        float4 av = *(const float4*)(Ap + k0);
        float4 wv = *(const float4*)(Wp + k0);
        __syncthreads();
        As[lk4+0][lrow]=av.x; As[lk4+1][lrow]=av.y; As[lk4+2][lrow]=av.z; As[lk4+3][lrow]=av.w;
        Ws[lk4+0][lrow]=wv.x; Ws[lk4+1][lrow]=wv.y; Ws[lk4+2][lrow]=wv.z; Ws[lk4+3][lrow]=wv.w;
        __syncthreads();
#pragma unroll
        for (int k = 0; k < 8; k++) {
            float a[8], b[8];
#pragma unroll
            for (int ir = 0; ir < 8; ir++) a[ir] = As[k][ty*8 + ir];
#pragma unroll
            for (int ic = 0; ic < 8; ic++) b[ic] = Ws[k][ic*16 + tx];
#pragma unroll
            for (int ir = 0; ir < 8; ir++)
#pragma unroll
                for (int ic = 0; ic < 8; ic++)
                    acc[ir][ic] = fmaf(a[ir], b[ic], acc[ir][ic]);
        }
    }
#pragma unroll
    for (int ir = 0; ir < 8; ir++) {
        int row = bm + ty*8 + ir;
#pragma unroll
        for (int ic = 0; ic < 8; ic++) {
            int col = bn + ic*16 + tx;
            C[(size_t)row * N + col] = acc[ir][ic] + bias[col];
        }
    }
}

// ---------------- row l2-normalize (in place) ----------------
__global__ void l2norm_kernel(float* __restrict__ x) {
    int r = blockIdx.x, t = threadIdx.x;
    __shared__ float sh[256];
    float v = x[(size_t)r * EDIM + t];
    sh[t] = v * v;
    __syncthreads();
    for (int s = 128; s > 0; s >>= 1) { if (t < s) sh[t] += sh[t+s]; __syncthreads(); }
    float nrm = sqrtf(sh[0]);
    x[(size_t)r * EDIM + t] = v / nrm;
}

// ---------------- big GEMM d = xn @ embed^T with fused epilogue ----------------
// stores e = exp(10 d) to g_e; accumulates per-row S, T; argmin (first-index ties)
__global__ void __launch_bounds__(256)
gemm_big_kernel(const float* __restrict__ embed) {
    __shared__ float As[8][132];
    __shared__ float Ws[8][132];
    const int tid = threadIdx.x;
    const int tx = tid & 15, ty = tid >> 4;
    const int bm = blockIdx.y * 128, bn = blockIdx.x * 128;
    float acc[8][8] = {};
    const int lrow = tid >> 1;
    const int lk4  = (tid & 1) * 4;
    const float* Ap = g_xn  + (size_t)(bm + lrow) * EDIM + lk4;
    const float* Wp = embed + (size_t)(bn + lrow) * EDIM + lk4;
    for (int k0 = 0; k0 < EDIM; k0 += 8) {
        float4 av = *(const float4*)(Ap + k0);
        float4 wv = *(const float4*)(Wp + k0);
        __syncthreads();
        As[lk4+0][lrow]=av.x; As[lk4+1][lrow]=av.y; As[lk4+2][lrow]=av.z; As[lk4+3][lrow]=av.w;
        Ws[lk4+0][lrow]=wv.x; Ws[lk4+1][lrow]=wv.y; Ws[lk4+2][lrow]=wv.z; Ws[lk4+3][lrow]=wv.w;
        __syncthreads();
#pragma unroll
        for (int k = 0; k < 8; k++) {
            float a[8], b[8];
#pragma unroll
            for (int ir = 0; ir < 8; ir++) a[ir] = As[k][ty*8 + ir];
#pragma unroll
            for (int ic = 0; ic < 8; ic++) b[ic] = Ws[k][ic*16 + tx];
#pragma unroll
            for (int ir = 0; ir < 8; ir++)
#pragma unroll
                for (int ic = 0; ic < 8; ic++)
                    acc[ir][ic] = fmaf(a[ir], b[ic], acc[ir][ic]);
        }
    }
    // epilogue: per row (ir) reduce across the 16 tx threads of a half-warp
#pragma unroll
    for (int ir = 0; ir < 8; ir++) {
        int row = bm + ty*8 + ir;
        float S = 0.f, T = 0.f;
        float mval = 1e30f; int mcol = 0;
#pragma unroll
        for (int ic = 0; ic < 8; ic++) {
            int col = bn + ic*16 + tx;
            float d  = acc[ir][ic];
            float t10 = 10.0f * d;
            float e   = fast_exp(t10);
            S += e;
            T = fmaf(e, t10, T);
            g_e[(size_t)row * NE + col] = e;
            if (d < mval) { mval = d; mcol = col; }   // ic ascending -> first index
        }
        unsigned u = __float_as_uint(mval);
        u = (u & 0x80000000u) ? ~u : (u | 0x80000000u);  // orderable float
        unsigned long long key = ((unsigned long long)u << 32) | (unsigned)mcol;
#pragma unroll
        for (int off = 8; off > 0; off >>= 1) {
            S += __shfl_down_sync(0xffffffffu, S, off, 16);
            T += __shfl_down_sync(0xffffffffu, T, off, 16);
            unsigned long long ok = __shfl_down_sync(0xffffffffu, key, off, 16);
            key = (ok < key) ? ok : key;
        }
        if (tx == 0) {
            atomicAdd(&g_S[row], S);
            atomicAdd(&g_T[row], T);
            atomicMin(&g_minkey[row], key);
        }
    }
}

// ---------------- per-row finalize: ind, z_q_st, commit, bins, embed_sum ----------------
__global__ void row_finalize_kernel(const float* __restrict__ embed, float* __restrict__ out) {
    int r = blockIdx.x, t = threadIdx.x;
    __shared__ unsigned s_ind;
    __shared__ float red[256];
    if (t == 0) s_ind = (unsigned)(g_minkey[r] & 0xffffffffULL);
    __syncthreads();
    unsigned ind = s_ind;
    float xnv = g_xn[(size_t)r * EDIM + t];
    float ev  = embed[(size_t)ind * EDIM + t];
    g_zq[(size_t)r * EDIM + t] = xnv + (ev - xnv);     // STE value
    float df = ev - xnv;
    red[t] = df * df;
    atomicAdd(&g_embed_sum[(size_t)ind * EDIM + t], xnv);
    __syncthreads();
    for (int s = 128; s > 0; s >>= 1) { if (t < s) red[t] += red[t+s]; __syncthreads(); }
    if (t == 0) {
        atomicAdd(&g_scal[0], red[0]);
        out[OFF_IND + r] = (float)ind;
        atomicAdd(&g_bins[ind], 1.0f);
        float S = g_S[r], T = g_T[r];
        atomicAdd(&g_scal[1], logf(S) - T / S);        // row entropy
        g_invS[r] = 1.0f / S;
    }
}

// ---------------- ap column pass: ap[c] += sum_r e[r,c]/S[r] ----------------
__global__ void ap_kernel() {
    int c  = blockIdx.x * 256 + threadIdx.x;
    int r0 = blockIdx.y * 2048;
    __shared__ float sh_inv[256];
    float acc = 0.f;
    for (int rr = 0; rr < 2048; rr += 256) {
        __syncthreads();
        sh_inv[threadIdx.x] = g_invS[r0 + rr + threadIdx.x];
        __syncthreads();
        const float* ep = g_e + (size_t)(r0 + rr) * NE + c;
#pragma unroll 4
        for (int j = 0; j < 256; j++)
            acc = fmaf(ep[(size_t)j * NE], sh_inv[j], acc);
    }
    atomicAdd(&g_ap[c], acc);
}

// ---------------- code updates ----------------
__global__ void e1_kernel(const float* __restrict__ cluster_size, float* __restrict__ out) {
    int i = blockIdx.x * 256 + threadIdx.x;
    if (i >= NE) return;
    float cn = cluster_size[i] * 0.99f + g_bins[i] * 0.01f;
    g_cluster_new[i] = cn;
    int ex = (cn < 0.1f);                          // DEAD_THRESH * RATIO
    g_expired[i] = ex;
    out[OFF_CS + i] = ex ? 0.12f : cn;             // RESET_CS * RATIO = 0.12
    atomicAdd(&g_scal[2], cn);
}

__global__ void scan_kernel() {   // single block, 1024 threads, 8192 flags
    int t = threadIdx.x;
    __shared__ int sh[1024];
    int vals[8]; int s = 0;
#pragma unroll
    for (int j = 0; j < 8; j++) { s += g_expired[t*8 + j]; vals[j] = s; }
    sh[t] = s;
    __syncthreads();
    for (int off = 1; off < 1024; off <<= 1) {
        int v = (t >= off) ? sh[t - off] : 0;
        __syncthreads();
        sh[t] += v;
        __syncthreads();
    }
    int excl = (t > 0) ? sh[t-1] : 0;
#pragma unroll
    for (int j = 0; j < 8; j++) {
        int cum = excl + vals[j];
        int idx = cum - 1; if (idx < 0) idx = 0;
        g_sampidx[t*8 + j] = idx;                  // idx < 8192 < NTOK, %n is no-op
    }
}

__global__ void e3_kernel(const float* __restrict__ embed_avg, float* __restrict__ out) {
    int c = blockIdx.x, k = threadIdx.x;
    float ea = embed_avg[(size_t)c * EDIM + k] * 0.99f + g_embed_sum[(size_t)c * EDIM + k] * 0.01f;
    float total = g_scal[2];
    float cn = g_cluster_new[c];
    float cs = (cn + 1e-5f) / (total + (float)NE * 1e-5f) * total;
    float en = ea / cs;
    float ef, eaf;
    if (g_expired[c]) {
        float sv = g_xn[(size_t)g_sampidx[c] * EDIM + k];
        ef = sv; eaf = sv * 0.12f;
    } else { ef = en; eaf = ea; }
    out[OFF_EMB  + (size_t)c * EDIM + k] = ef;
    out[OFF_EAVG + (size_t)c * EDIM + k] = eaf;
}

// ---------------- final scalars ----------------
__global__ void scalars_kernel(float* __restrict__ out) {
    int t = threadIdx.x;  // 1024
    __shared__ float sh[1024];
    float local = 0.f;
#pragma unroll
    for (int j = 0; j < 8; j++) {
        float ap = g_ap[t*8 + j] * (1.0f / (float)NTOK);
        local -= ap * logf(ap);
    }
    sh[t] = local;
    __syncthreads();
    for (int s = 512; s > 0; s >>= 1) { if (t < s) sh[t] += sh[t+s]; __syncthreads(); }
    if (t == 0) {
        float ent_max = sh[0];
        float commit  = g_scal[0] / ((float)NTOK * (float)EDIM);
        out[OFF_LOSS]   = commit - ent_max;
        out[OFF_ENTMIN] = g_scal[1] / (float)NTOK;
        out[OFF_COMMIT] = commit;
    }
}

// ---------------- launch ----------------
extern "C" void kernel_launch(void* const* d_in, const int* in_sizes, int n_in,
                              void* d_out, int out_size) {
    const float* x         = (const float*)d_in[0];
    const float* W_in      = (const float*)d_in[1];
    const float* b_in      = (const float*)d_in[2];
    const float* W_out     = (const float*)d_in[3];
    const float* b_out     = (const float*)d_in[4];
    const float* embed     = (const float*)d_in[5];
    const float* embed_avg = (const float*)d_in[6];
    const float* cluster   = (const float*)d_in[7];
    float* out = (float*)d_out;

    void *p_xn = nullptr, *p_zq = nullptr;
    cudaGetSymbolAddress(&p_xn, g_xn);
    cudaGetSymbolAddress(&p_zq, g_zq);

    zero_kernel<<<8192, 256>>>();
    // x_proj = x @ W_in^T + b_in  -> g_xn
    gemm_bias_kernel<<<dim3(EDIM/128, NTOK/128), 256>>>(x, W_in, b_in, (float*)p_xn,
                                                        NTOK, EDIM, LAT);
    l2norm_kernel<<<NTOK, 256>>>((float*)p_xn);
    // d = xn @ embed^T, fused exp/S/T/argmin, store e
    gemm_big_kernel<<<dim3(NE/128, NTOK/128), 256>>>(embed);
    row_finalize_kernel<<<NTOK, 256>>>(embed, out);
    ap_kernel<<<dim3(NE/256, NTOK/2048), 256>>>();
    e1_kernel<<<NE/256, 256>>>(cluster, out);
    scan_kernel<<<1, 1024>>>();
    scalars_kernel<<<1, 1024>>>(out);
    e3_kernel<<<NE, 256>>>(embed_avg, out);
    // z_q_out = z_q_st @ W_out^T + b_out
    gemm_bias_kernel<<<dim3(ODIM/128, NTOK/128), 256>>>((const float*)p_zq, W_out, b_out,
                                                        out, NTOK, ODIM, EDIM);
}

// round 3
// speedup vs baseline: 2.0468x; 2.0468x over previous
#include <cuda_runtime.h>
#include <cuda_bf16.h>
#include <math.h>
#include <stdint.h>

// ---------------- problem constants ----------------
#define NTOK   16384
#define EDIM   256
#define NE     8192
#define LAT    768
#define ODIM   768

// output layout (concatenated tuple, float32)
#define OFF_ZQ     ((size_t)0)
#define OFF_IND    ((size_t)12582912)
#define OFF_LOSS   ((size_t)12599296)
#define OFF_EMB    ((size_t)12599297)
#define OFF_EAVG   ((size_t)14696449)
#define OFF_CS     ((size_t)16793601)
#define OFF_ENTMIN ((size_t)16801793)
#define OFF_COMMIT ((size_t)16801794)

// ---------------- device scratch ----------------
__device__ __nv_bfloat16 g_d[(size_t)NTOK * NE];    // approx d, bf16 (256MB)
__device__ __nv_bfloat16 g_a[(size_t)NTOK * EDIM];  // xn bf16, row-major
__device__ __nv_bfloat16 g_b[(size_t)NE * EDIM];    // embed bf16, row-major
__device__ float g_xn[NTOK * EDIM];
__device__ float g_zq[NTOK * EDIM];
__device__ float g_invS[NTOK];
__device__ float g_bins[NE];
__device__ float g_ap[NE];
__device__ float g_cluster_new[NE];
__device__ int   g_expired[NE];
__device__ int   g_sampidx[NE];
__device__ float g_embed_sum[NE * EDIM];
__device__ float g_scal[4];   // 0: commit sum, 1: entmin sum, 2: total cluster

// ---------------- fast exp (FFMA only) ----------------
__device__ __forceinline__ float fast_exp(float x) {
    float z = x * 1.4426950408889634f;
    int   i = __float2int_rn(z);
    float rf = (float)i;
    float g = fmaf(rf, -0.693359375f, x);
    g = fmaf(rf, 2.12194440e-4f, g);
    float p = 1.98412698e-4f;
    p = fmaf(p, g, 1.38888889e-3f);
    p = fmaf(p, g, 8.33333333e-3f);
    p = fmaf(p, g, 4.16666667e-2f);
    p = fmaf(p, g, 1.66666667e-1f);
    p = fmaf(p, g, 0.5f);
    p = fmaf(p, g, 1.0f);
    p = fmaf(p, g, 1.0f);
    float sc = __int_as_float((i + 127) << 23);
    return p * sc;
}

// ---------------- warp MMA helpers (arch-portable PTX, sm_80+) ----------------
__device__ __forceinline__ uint32_t smem_u32(const void* p) {
    uint32_t a;
    asm("{ .reg .u64 t; cvta.to.shared.u64 t, %1; cvt.u32.u64 %0, t; }" : "=r"(a) : "l"(p));
    return a;
}
__device__ __forceinline__ void ldsm4(uint32_t* r, uint32_t addr) {
    asm volatile("ldmatrix.sync.aligned.m8n8.x4.shared.b16 {%0,%1,%2,%3}, [%4];"
                 : "=r"(r[0]), "=r"(r[1]), "=r"(r[2]), "=r"(r[3]) : "r"(addr));
}
__device__ __forceinline__ void mma_bf16(float* c, const uint32_t* a, uint32_t b0, uint32_t b1) {
    asm volatile("mma.sync.aligned.m16n8k16.row.col.f32.bf16.bf16.f32 "
                 "{%0,%1,%2,%3}, {%4,%5,%6,%7}, {%8,%9}, {%0,%1,%2,%3};"
                 : "+f"(c[0]), "+f"(c[1]), "+f"(c[2]), "+f"(c[3])
                 : "r"(a[0]), "r"(a[1]), "r"(a[2]), "r"(a[3]), "r"(b0), "r"(b1));
}

// ---------------- zeroing ----------------
__global__ void zero_kernel() {
    int i = blockIdx.x * 256 + threadIdx.x;
    if (i < NE * EDIM) g_embed_sum[i] = 0.f;
    if (i < NE)   { g_bins[i] = 0.f; g_ap[i] = 0.f; }
    if (i < 4)    g_scal[i] = 0.f;
}

// ---------------- generic fp32 SGEMM: C = A @ W^T + bias ----------------
__global__ void __launch_bounds__(256)
gemm_bias_kernel(const float* __restrict__ A, const float* __restrict__ W,
                 const float* __restrict__ bias, float* __restrict__ C,
                 int M, int N, int K) {
    __shared__ float As[8][132];
    __shared__ float Ws[8][132];
    const int tid = threadIdx.x;
    const int tx = tid & 15, ty = tid >> 4;
    const int bm = blockIdx.y * 128, bn = blockIdx.x * 128;
    float acc[8][8] = {};
    const int lrow = tid >> 1;
    const int lk4  = (tid & 1) * 4;
    const float* Ap = A + (size_t)(bm + lrow) * K + lk4;
    const float* Wp = W + (size_t)(bn + lrow) * K + lk4;
    for (int k0 = 0; k0 < K; k0 += 8) {
        float4 av = *(const float4*)(Ap + k0);
        float4 wv = *(const float4*)(Wp + k0);
        __syncthreads();
        As[lk4+0][lrow]=av.x; As[lk4+1][lrow]=av.y; As[lk4+2][lrow]=av.z; As[lk4+3][lrow]=av.w;
        Ws[lk4+0][lrow]=wv.x; Ws[lk4+1][lrow]=wv.y; Ws[lk4+2][lrow]=wv.z; Ws[lk4+3][lrow]=wv.w;
        __syncthreads();
#pragma unroll
        for (int k = 0; k < 8; k++) {
            float a[8], b[8];
#pragma unroll
            for (int ir = 0; ir < 8; ir++) a[ir] = As[k][ty*8 + ir];
#pragma unroll
            for (int ic = 0; ic < 8; ic++) b[ic] = Ws[k][ic*16 + tx];
#pragma unroll
            for (int ir = 0; ir < 8; ir++)
#pragma unroll
                for (int ic = 0; ic < 8; ic++)
                    acc[ir][ic] = fmaf(a[ir], b[ic], acc[ir][ic]);
        }
    }
#pragma unroll
    for (int ir = 0; ir < 8; ir++) {
        int row = bm + ty*8 + ir;
#pragma unroll
        for (int ic = 0; ic < 8; ic++) {
            int col = bn + ic*16 + tx;
            C[(size_t)row * N + col] = acc[ir][ic] + bias[col];
        }
    }
}

// ---------------- row l2-normalize ----------------
__global__ void l2norm_kernel(float* __restrict__ x) {
    int r = blockIdx.x, t = threadIdx.x;
    __shared__ float sh[256];
    float v = x[(size_t)r * EDIM + t];
    sh[t] = v * v;
    __syncthreads();
    for (int s = 128; s > 0; s >>= 1) { if (t < s) sh[t] += sh[t+s]; __syncthreads(); }
    float nrm = sqrtf(sh[0]);
    x[(size_t)r * EDIM + t] = v / nrm;
}

// ---------------- fp32 -> bf16 convert (row-major) ----------------
__global__ void conv_bf16_kernel(const float* __restrict__ src, __nv_bfloat16* __restrict__ dst) {
    int i = blockIdx.x * 256 + threadIdx.x;   // one 16B chunk (8 elems)
    float4 v0 = ((const float4*)src)[2*i];
    float4 v1 = ((const float4*)src)[2*i+1];
    __nv_bfloat162 b0 = __floats2bfloat162_rn(v0.x, v0.y);
    __nv_bfloat162 b1 = __floats2bfloat162_rn(v0.z, v0.w);
    __nv_bfloat162 b2 = __floats2bfloat162_rn(v1.x, v1.y);
    __nv_bfloat162 b3 = __floats2bfloat162_rn(v1.z, v1.w);
    uint4 pk;
    pk.x = *(uint32_t*)&b0; pk.y = *(uint32_t*)&b1;
    pk.z = *(uint32_t*)&b2; pk.w = *(uint32_t*)&b3;
    ((uint4*)dst)[i] = pk;
}

// ---------------- bf16 tensor-core d-GEMM via mma.sync ----------------
// D[128,128] tile = A[128,256] @ B[128,256]^T, grid (NE/128, NTOK/128), 256 thr
#define SSTRIDE 264   // padded smem row stride (elems): 528B -> conflict-free ldmatrix
#define SMEM_MMA (2 * 128 * SSTRIDE * 2)

__global__ void __launch_bounds__(256)
mma_d_kernel() {
    extern __shared__ __align__(16) char smem[];
    __nv_bfloat16* sA = (__nv_bfloat16*)smem;
    __nv_bfloat16* sB = (__nv_bfloat16*)(smem + 128 * SSTRIDE * 2);
    const int tid = threadIdx.x;
    const int bm = blockIdx.y * 128, bn = blockIdx.x * 128;

    // stage both full-K tiles (64KB each logical) into padded smem
    const uint4* gA = (const uint4*)g_a + (size_t)bm * 32;
    const uint4* gB = (const uint4*)g_b + (size_t)bn * 32;
#pragma unroll
    for (int j = 0; j < 16; j++) {
        int idx = j * 256 + tid;
        int row = idx >> 5, c8 = idx & 31;
        *(uint4*)(sA + row * SSTRIDE + c8 * 8) = gA[idx];
        *(uint4*)(sB + row * SSTRIDE + c8 * 8) = gB[idx];
    }
    __syncthreads();

    const int wid = tid >> 5, lane = tid & 31;
    const int wr = (wid & 1) * 64;      // warp row base (64 rows)
    const int wc = (wid >> 1) * 32;     // warp col base (32 cols)

    // ldmatrix lane addressing (bytes)
    uint32_t sAu = smem_u32(sA), sBu = smem_u32(sB);
    uint32_t aAddr = sAu + (uint32_t)(((wr + (lane & 15)) * SSTRIDE + (lane >> 4) * 8) * 2);
    uint32_t bRow  = (uint32_t)(wc + (lane & 7) + ((lane >> 4) << 3));
    uint32_t bAddr = sBu + (uint32_t)((bRow * SSTRIDE + ((lane >> 3) & 1) * 8) * 2);

    float acc[4][4][4] = {};
#pragma unroll
    for (int kk = 0; kk < 16; kk++) {
        uint32_t ko = (uint32_t)kk * 32;   // 16 elems * 2B
        uint32_t aF[4][4], bF[2][4];
#pragma unroll
        for (int mi = 0; mi < 4; mi++) ldsm4(aF[mi], aAddr + mi * (16 * SSTRIDE * 2) + ko);
#pragma unroll
        for (int n2 = 0; n2 < 2; n2++) ldsm4(bF[n2], bAddr + n2 * (16 * SSTRIDE * 2) + ko);
#pragma unroll
        for (int mi = 0; mi < 4; mi++)
#pragma unroll
            for (int ni = 0; ni < 4; ni++)
                mma_bf16(acc[mi][ni], aF[mi], bF[ni >> 1][(ni & 1) * 2], bF[ni >> 1][(ni & 1) * 2 + 1]);
    }

    // epilogue: fragment -> bf16 -> global
    const int rbase = bm + wr + (lane >> 2);
    const int cbase = bn + wc + (lane & 3) * 2;
#pragma unroll
    for (int mi = 0; mi < 4; mi++)
#pragma unroll
        for (int ni = 0; ni < 4; ni++) {
            size_t o = (size_t)(rbase + mi * 16) * NE + cbase + ni * 8;
            *(__nv_bfloat162*)(g_d + o) =
                __floats2bfloat162_rn(acc[mi][ni][0], acc[mi][ni][1]);
            *(__nv_bfloat162*)(g_d + o + (size_t)8 * NE) =
                __floats2bfloat162_rn(acc[mi][ni][2], acc[mi][ni][3]);
        }
}

// ---------------- row pass: S/T/argmin(+exact fixup)/zq/commit/bins/embed_sum ----------------
__global__ void __launch_bounds__(256)
row_pass_kernel(const float* __restrict__ embed, float* __restrict__ out) {
    const int r = blockIdx.x, t = threadIdx.x;
    __shared__ float sxn[256];
    __shared__ float sS[256], sT[256], sM[256];
    __shared__ float sred[256];
    __shared__ int scnt;
    __shared__ int scand[64];
    __shared__ unsigned long long sbest;

    float xnv = g_xn[(size_t)r * EDIM + t];
    sxn[t] = xnv;
    if (t == 0) { scnt = 0; sbest = ~0ULL; }

    const __nv_bfloat162* dp = (const __nv_bfloat162*)(g_d + (size_t)r * NE);
    __nv_bfloat162 dv[16];
#pragma unroll
    for (int j = 0; j < 16; j++) dv[j] = dp[t + j * 256];

    float S = 0.f, T = 0.f, mval = 1e30f;
#pragma unroll
    for (int j = 0; j < 16; j++) {
        float d0 = __bfloat162float(dv[j].x);
        float d1 = __bfloat162float(dv[j].y);
        float t0 = 10.f * d0, t1 = 10.f * d1;
        float e0 = fast_exp(t0), e1 = fast_exp(t1);
        S += e0 + e1;
        T = fmaf(e0, t0, T); T = fmaf(e1, t1, T);
        mval = fminf(mval, fminf(d0, d1));
    }
    sS[t] = S; sT[t] = T; sM[t] = mval;
    __syncthreads();
    for (int s = 128; s > 0; s >>= 1) {
        if (t < s) { sS[t] += sS[t+s]; sT[t] += sT[t+s]; sM[t] = fminf(sM[t], sM[t+s]); }
        __syncthreads();
    }
    float Stot = sS[0], Ttot = sT[0], gmin = sM[0];

    // candidate collection: window covers bf16 mma + bf16 storage error (<=5e-3 each way)
    float thresh = gmin + 1.2e-2f;
#pragma unroll
    for (int j = 0; j < 16; j++) {
        int c0 = (j * 256 + t) * 2;
        float d0 = __bfloat162float(dv[j].x);
        float d1 = __bfloat162float(dv[j].y);
        if (d0 <= thresh) { int p = atomicAdd(&scnt, 1); if (p < 64) scand[p] = c0; }
        if (d1 <= thresh) { int p = atomicAdd(&scnt, 1); if (p < 64) scand[p] = c0 + 1; }
    }
    __syncthreads();
    int ncand = scnt < 64 ? scnt : 64;
    int ind;
    if (ncand == 1) {
        ind = scand[0];
    } else {
        // exact fp32 dots for candidates; lexicographic (value, col) min
        for (int i = 0; i < ncand; i++) {
            const float* er = embed + (size_t)scand[i] * EDIM;
            sred[t] = sxn[t] * er[t];
            __syncthreads();
            for (int s = 128; s > 0; s >>= 1) { if (t < s) sred[t] += sred[t+s]; __syncthreads(); }
            if (t == 0) {
                unsigned u = __float_as_uint(sred[0]);
                u = (u & 0x80000000u) ? ~u : (u | 0x80000000u);
                unsigned long long k = ((unsigned long long)u << 32) | (unsigned)scand[i];
                if (k < sbest) sbest = k;
            }
            __syncthreads();
        }
        ind = (int)(sbest & 0xffffffffu);
    }

    float ev = embed[(size_t)ind * EDIM + t];
    g_zq[(size_t)r * EDIM + t] = ev;            // STE value (== embed row)
    float df = ev - xnv;
    sred[t] = df * df;
    atomicAdd(&g_embed_sum[(size_t)ind * EDIM + t], xnv);
    __syncthreads();
    for (int s = 128; s > 0; s >>= 1) { if (t < s) sred[t] += sred[t+s]; __syncthreads(); }
    if (t == 0) {
        atomicAdd(&g_scal[0], sred[0]);
        out[OFF_IND + r] = (float)ind;
        atomicAdd(&g_bins[ind], 1.0f);
        atomicAdd(&g_scal[1], logf(Stot) - Ttot / Stot);
        g_invS[r] = 1.0f / Stot;
    }
}

// ---------------- ap column pass ----------------
__global__ void ap_kernel() {
    int c  = blockIdx.x * 256 + threadIdx.x;
    int r0 = blockIdx.y * 2048;
    __shared__ float sh_inv[256];
    float acc = 0.f;
    for (int rr = 0; rr < 2048; rr += 256) {
        __syncthreads();
        sh_inv[threadIdx.x] = g_invS[r0 + rr + threadIdx.x];
        __syncthreads();
        const __nv_bfloat16* ep = g_d + (size_t)(r0 + rr) * NE + c;
#pragma unroll 4
        for (int j = 0; j < 256; j++) {
            float d = __bfloat162float(ep[(size_t)j * NE]);
            acc = fmaf(fast_exp(10.f * d), sh_inv[j], acc);
        }
    }
    atomicAdd(&g_ap[c], acc);
}

// ---------------- code updates ----------------
__global__ void e1_kernel(const float* __restrict__ cluster_size, float* __restrict__ out) {
    int i = blockIdx.x * 256 + threadIdx.x;
    if (i >= NE) return;
    float cn = cluster_size[i] * 0.99f + g_bins[i] * 0.01f;
    g_cluster_new[i] = cn;
    int ex = (cn < 0.1f);
    g_expired[i] = ex;
    out[OFF_CS + i] = ex ? 0.12f : cn;
    atomicAdd(&g_scal[2], cn);
}

__global__ void scan_kernel() {
    int t = threadIdx.x;
    __shared__ int sh[1024];
    int vals[8]; int s = 0;
#pragma unroll
    for (int j = 0; j < 8; j++) { s += g_expired[t*8 + j]; vals[j] = s; }
    sh[t] = s;
    __syncthreads();
    for (int off = 1; off < 1024; off <<= 1) {
        int v = (t >= off) ? sh[t - off] : 0;
        __syncthreads();
        sh[t] += v;
        __syncthreads();
    }
    int excl = (t > 0) ? sh[t-1] : 0;
#pragma unroll
    for (int j = 0; j < 8; j++) {
        int cum = excl + vals[j];
        int idx = cum - 1; if (idx < 0) idx = 0;
        g_sampidx[t*8 + j] = idx;
    }
}

__global__ void e3_kernel(const float* __restrict__ embed_avg, float* __restrict__ out) {
    int c = blockIdx.x, k = threadIdx.x;
    float ea = embed_avg[(size_t)c * EDIM + k] * 0.99f + g_embed_sum[(size_t)c * EDIM + k] * 0.01f;
    float total = g_scal[2];
    float cn = g_cluster_new[c];
    float cs = (cn + 1e-5f) / (total + (float)NE * 1e-5f) * total;
    float en = ea / cs;
    float ef, eaf;
    if (g_expired[c]) {
        float sv = g_xn[(size_t)g_sampidx[c] * EDIM + k];
        ef = sv; eaf = sv * 0.12f;
    } else { ef = en; eaf = ea; }
    out[OFF_EMB  + (size_t)c * EDIM + k] = ef;
    out[OFF_EAVG + (size_t)c * EDIM + k] = eaf;
}

__global__ void scalars_kernel(float* __restrict__ out) {
    int t = threadIdx.x;
    __shared__ float sh[1024];
    float local = 0.f;
#pragma unroll
    for (int j = 0; j < 8; j++) {
        float ap = g_ap[t*8 + j] * (1.0f / (float)NTOK);
        local -= ap * logf(ap);
    }
    sh[t] = local;
    __syncthreads();
    for (int s = 512; s > 0; s >>= 1) { if (t < s) sh[t] += sh[t+s]; __syncthreads(); }
    if (t == 0) {
        float ent_max = sh[0];
        float commit  = g_scal[0] / ((float)NTOK * (float)EDIM);
        out[OFF_LOSS]   = commit - ent_max;
        out[OFF_ENTMIN] = g_scal[1] / (float)NTOK;
        out[OFF_COMMIT] = commit;
    }
}

// ---------------- launch ----------------
extern "C" void kernel_launch(void* const* d_in, const int* in_sizes, int n_in,
                              void* d_out, int out_size) {
    const float* x         = (const float*)d_in[0];
    const float* W_in      = (const float*)d_in[1];
    const float* b_in      = (const float*)d_in[2];
    const float* W_out     = (const float*)d_in[3];
    const float* b_out     = (const float*)d_in[4];
    const float* embed     = (const float*)d_in[5];
    const float* embed_avg = (const float*)d_in[6];
    const float* cluster   = (const float*)d_in[7];
    float* out = (float*)d_out;

    void *p_xn = nullptr, *p_zq = nullptr, *p_a = nullptr, *p_b = nullptr;
    cudaGetSymbolAddress(&p_xn, g_xn);
    cudaGetSymbolAddress(&p_zq, g_zq);
    cudaGetSymbolAddress(&p_a, g_a);
    cudaGetSymbolAddress(&p_b, g_b);

    cudaFuncSetAttribute(mma_d_kernel, cudaFuncAttributeMaxDynamicSharedMemorySize, SMEM_MMA);

    zero_kernel<<<8192, 256>>>();
    // x_proj = x @ W_in^T + b_in  (fp32, exact path for argmin fidelity)
    gemm_bias_kernel<<<dim3(EDIM/128, NTOK/128), 256>>>(x, W_in, b_in, (float*)p_xn,
                                                        NTOK, EDIM, LAT);
    l2norm_kernel<<<NTOK, 256>>>((float*)p_xn);
    // bf16 copies for tensor-core d-GEMM
    conv_bf16_kernel<<<NTOK*EDIM/8/256, 256>>>((const float*)p_xn, (__nv_bfloat16*)p_a);
    conv_bf16_kernel<<<NE*EDIM/8/256, 256>>>(embed, (__nv_bfloat16*)p_b);
    // d = xn @ embed^T on HMMA tensor cores (bf16 in, fp32 acc, bf16 out)
    mma_d_kernel<<<dim3(NE/128, NTOK/128), 256, SMEM_MMA>>>();
    // per-row: S/T, argmin with exact fp32 fixup, zq, commit, bins, embed_sum
    row_pass_kernel<<<NTOK, 256>>>(embed, out);
    ap_kernel<<<dim3(NE/256, NTOK/2048), 256>>>();
    e1_kernel<<<NE/256, 256>>>(cluster, out);
    scan_kernel<<<1, 1024>>>();
    scalars_kernel<<<1, 1024>>>(out);
    e3_kernel<<<NE, 256>>>(embed_avg, out);
    // z_q_out = z_q_st @ W_out^T + b_out (fp32)
    gemm_bias_kernel<<<dim3(ODIM/128, NTOK/128), 256>>>((const float*)p_zq, W_out, b_out,
                                                        out, NTOK, ODIM, EDIM);
}

// round 5
// speedup vs baseline: 2.3531x; 1.1496x over previous
#include <cuda_runtime.h>
#include <cuda_bf16.h>
#include <math.h>
#include <stdint.h>

// ---------------- problem constants ----------------
#define NTOK   16384
#define EDIM   256
#define NE     8192
#define LAT    768
#define ODIM   768

// output layout (concatenated tuple, float32)
#define OFF_ZQ     ((size_t)0)
#define OFF_IND    ((size_t)12582912)
#define OFF_LOSS   ((size_t)12599296)
#define OFF_EMB    ((size_t)12599297)
#define OFF_EAVG   ((size_t)14696449)
#define OFF_CS     ((size_t)16793601)
#define OFF_ENTMIN ((size_t)16801793)
#define OFF_COMMIT ((size_t)16801794)

// ---------------- device scratch ----------------
__device__ __nv_bfloat16 g_d[(size_t)NTOK * NE];    // approx d, bf16 (256MB)
__device__ __nv_bfloat16 g_a[(size_t)NTOK * EDIM];  // xn bf16, row-major
__device__ __nv_bfloat16 g_eh[(size_t)NE * EDIM];   // embed hi (also mma_d B)
__device__ __nv_bfloat16 g_el[(size_t)NE * EDIM];   // embed lo
__device__ __nv_bfloat16 g_wh[(size_t)ODIM * EDIM]; // W_out hi
__device__ __nv_bfloat16 g_wl[(size_t)ODIM * EDIM]; // W_out lo
__device__ float g_eproj[(size_t)NE * ODIM];        // embed @ W_out^T
__device__ float g_xn[NTOK * EDIM];
__device__ float g_invS[NTOK];
__device__ float g_bins[NE];
__device__ float g_ap[NE];
__device__ float g_cluster_new[NE];
__device__ int   g_expired[NE];
__device__ int   g_sampidx[NE];
__device__ float g_embed_sum[NE * EDIM];
__device__ float g_scal[4];   // 0: commit sum, 1: entmin sum, 2: total cluster

// ---------------- fast exp (FFMA only) ----------------
__device__ __forceinline__ float fast_exp(float x) {
    float z = x * 1.4426950408889634f;
    int   i = __float2int_rn(z);
    float rf = (float)i;
    float g = fmaf(rf, -0.693359375f, x);
    g = fmaf(rf, 2.12194440e-4f, g);
    float p = 1.98412698e-4f;
    p = fmaf(p, g, 1.38888889e-3f);
    p = fmaf(p, g, 8.33333333e-3f);
    p = fmaf(p, g, 4.16666667e-2f);
    p = fmaf(p, g, 1.66666667e-1f);
    p = fmaf(p, g, 0.5f);
    p = fmaf(p, g, 1.0f);
    p = fmaf(p, g, 1.0f);
    float sc = __int_as_float((i + 127) << 23);
    return p * sc;
}

// ---------------- warp MMA helpers (arch-portable PTX, sm_80+) ----------------
__device__ __forceinline__ uint32_t smem_u32(const void* p) {
    uint32_t a;
    asm("{ .reg .u64 t; cvta.to.shared.u64 t, %1; cvt.u32.u64 %0, t; }" : "=r"(a) : "l"(p));
    return a;
}
__device__ __forceinline__ void ldsm4(uint32_t* r, uint32_t addr) {
    asm volatile("ldmatrix.sync.aligned.m8n8.x4.shared.b16 {%0,%1,%2,%3}, [%4];"
                 : "=r"(r[0]), "=r"(r[1]), "=r"(r[2]), "=r"(r[3]) : "r"(addr));
}
__device__ __forceinline__ void mma_bf16(float* c, const uint32_t* a, uint32_t b0, uint32_t b1) {
    asm volatile("mma.sync.aligned.m16n8k16.row.col.f32.bf16.bf16.f32 "
                 "{%0,%1,%2,%3}, {%4,%5,%6,%7}, {%8,%9}, {%0,%1,%2,%3};"
                 : "+f"(c[0]), "+f"(c[1]), "+f"(c[2]), "+f"(c[3])
                 : "r"(a[0]), "r"(a[1]), "r"(a[2]), "r"(a[3]), "r"(b0), "r"(b1));
}

// ---------------- zeroing ----------------
__global__ void zero_kernel() {
    int i = blockIdx.x * 256 + threadIdx.x;
    if (i < NE * EDIM) g_embed_sum[i] = 0.f;
    if (i < NE)   { g_bins[i] = 0.f; g_ap[i] = 0.f; }
    if (i < 4)    g_scal[i] = 0.f;
}

// ---------------- generic fp32 SGEMM: C = A @ W^T + bias (in-projection) ----------------
__global__ void __launch_bounds__(256)
gemm_bias_kernel(const float* __restrict__ A, const float* __restrict__ W,
                 const float* __restrict__ bias, float* __restrict__ C,
                 int M, int N, int K) {
    __shared__ float As[8][132];
    __shared__ float Ws[8][132];
    const int tid = threadIdx.x;
    const int tx = tid & 15, ty = tid >> 4;
    const int bm = blockIdx.y * 128, bn = blockIdx.x * 128;
    float acc[8][8] = {};
    const int lrow = tid >> 1;
    const int lk4  = (tid & 1) * 4;
    const float* Ap = A + (size_t)(bm + lrow) * K + lk4;
    const float* Wp = W + (size_t)(bn + lrow) * K + lk4;
    for (int k0 = 0; k0 < K; k0 += 8) {
        float4 av = *(const float4*)(Ap + k0);
        float4 wv = *(const float4*)(Wp + k0);
        __syncthreads();
        As[lk4+0][lrow]=av.x; As[lk4+1][lrow]=av.y; As[lk4+2][lrow]=av.z; As[lk4+3][lrow]=av.w;
        Ws[lk4+0][lrow]=wv.x; Ws[lk4+1][lrow]=wv.y; Ws[lk4+2][lrow]=wv.z; Ws[lk4+3][lrow]=wv.w;
        __syncthreads();
#pragma unroll
        for (int k = 0; k < 8; k++) {
            float a[8], b[8];
#pragma unroll
            for (int ir = 0; ir < 8; ir++) a[ir] = As[k][ty*8 + ir];
#pragma unroll
            for (int ic = 0; ic < 8; ic++) b[ic] = Ws[k][ic*16 + tx];
#pragma unroll
            for (int ir = 0; ir < 8; ir++)
#pragma unroll
                for (int ic = 0; ic < 8; ic++)
                    acc[ir][ic] = fmaf(a[ir], b[ic], acc[ir][ic]);
        }
    }
#pragma unroll
    for (int ir = 0; ir < 8; ir++) {
        int row = bm + ty*8 + ir;
#pragma unroll
        for (int ic = 0; ic < 8; ic++) {
            int col = bn + ic*16 + tx;
            C[(size_t)row * N + col] = acc[ir][ic] + bias[col];
        }
    }
}

// ---------------- row l2-normalize ----------------
__global__ void l2norm_kernel(float* __restrict__ x) {
    int r = blockIdx.x, t = threadIdx.x;
    __shared__ float sh[256];
    float v = x[(size_t)r * EDIM + t];
    sh[t] = v * v;
    __syncthreads();
    for (int s = 128; s > 0; s >>= 1) { if (t < s) sh[t] += sh[t+s]; __syncthreads(); }
    float nrm = sqrtf(sh[0]);
    x[(size_t)r * EDIM + t] = v / nrm;
}

// ---------------- fp32 -> bf16 convert (row-major) ----------------
__global__ void conv_bf16_kernel(const float* __restrict__ src, __nv_bfloat16* __restrict__ dst) {
    int i = blockIdx.x * 256 + threadIdx.x;   // one 16B chunk (8 elems)
    float4 v0 = ((const float4*)src)[2*i];
    float4 v1 = ((const float4*)src)[2*i+1];
    __nv_bfloat162 b0 = __floats2bfloat162_rn(v0.x, v0.y);
    __nv_bfloat162 b1 = __floats2bfloat162_rn(v0.z, v0.w);
    __nv_bfloat162 b2 = __floats2bfloat162_rn(v1.x, v1.y);
    __nv_bfloat162 b3 = __floats2bfloat162_rn(v1.z, v1.w);
    uint4 pk;
    pk.x = *(uint32_t*)&b0; pk.y = *(uint32_t*)&b1;
    pk.z = *(uint32_t*)&b2; pk.w = *(uint32_t*)&b3;
    ((uint4*)dst)[i] = pk;
}

// ---------------- fp32 -> bf16 hi/lo split ----------------
__global__ void conv_split_kernel(const float* __restrict__ src,
                                  __nv_bfloat16* __restrict__ hi,
                                  __nv_bfloat16* __restrict__ lo) {
    int i = blockIdx.x * 256 + threadIdx.x;   // 8 elems
    float v[8];
    float4 v0 = ((const float4*)src)[2*i];
    float4 v1 = ((const float4*)src)[2*i+1];
    v[0]=v0.x; v[1]=v0.y; v[2]=v0.z; v[3]=v0.w;
    v[4]=v1.x; v[5]=v1.y; v[6]=v1.z; v[7]=v1.w;
    __nv_bfloat16 h[8], l[8];
#pragma unroll
    for (int j = 0; j < 8; j++) {
        h[j] = __float2bfloat16(v[j]);
        l[j] = __float2bfloat16(v[j] - __bfloat162float(h[j]));
    }
    uint4 ph, pl;
    ph.x = *(uint32_t*)&h[0]; ph.y = *(uint32_t*)&h[2];
    ph.z = *(uint32_t*)&h[4]; ph.w = *(uint32_t*)&h[6];
    pl.x = *(uint32_t*)&l[0]; pl.y = *(uint32_t*)&l[2];
    pl.z = *(uint32_t*)&l[4]; pl.w = *(uint32_t*)&l[6];
    ((uint4*)hi)[i] = ph;
    ((uint4*)lo)[i] = pl;
}

// ---------------- bf16 tensor-core d-GEMM via mma.sync ----------------
// D[128,128] tile = A[128,256] @ B[128,256]^T, BK=128 x2, 2 CTAs/SM
#define SST  136      // K-stage smem row stride (bf16 elems)
#define EPST 136      // epilogue stage stride (272B/row, 16B-divisible)
#define SMEM_MMA (2 * 128 * SST * 2)    // 69632 B

__global__ void __launch_bounds__(256, 2)
mma_d_kernel() {
    extern __shared__ __align__(16) char smem[];
    __nv_bfloat16* sA = (__nv_bfloat16*)smem;
    __nv_bfloat16* sB = (__nv_bfloat16*)(smem + 128 * SST * 2);
    const int tid = threadIdx.x;
    const int bm = blockIdx.y * 128, bn = blockIdx.x * 128;
    const int wid = tid >> 5, lane = tid & 31;
    const int wr = (wid & 1) * 64;
    const int wc = (wid >> 1) * 32;

    uint32_t sAu = smem_u32(sA), sBu = smem_u32(sB);
    uint32_t aAddr = sAu + (uint32_t)(((wr + (lane & 15)) * SST + (lane >> 4) * 8) * 2);
    uint32_t bRow  = (uint32_t)(wc + (lane & 7) + ((lane >> 4) << 3));
    uint32_t bAddr = sBu + (uint32_t)((bRow * SST + ((lane >> 3) & 1) * 8) * 2);

    const uint4* gA = (const uint4*)g_a  + (size_t)bm * 32;  // row = 32 uint4
    const uint4* gB = (const uint4*)g_eh + (size_t)bn * 32;

    float acc[4][4][4] = {};
    for (int kc = 0; kc < 2; kc++) {
        __syncthreads();
#pragma unroll
        for (int j = 0; j < 8; j++) {
            int idx = j * 256 + tid;          // 0..2047
            int row = idx >> 4, c8 = idx & 15;
            *(uint4*)(sA + row * SST + c8 * 8) = gA[row * 32 + kc * 16 + c8];
            *(uint4*)(sB + row * SST + c8 * 8) = gB[row * 32 + kc * 16 + c8];
        }
        __syncthreads();
#pragma unroll
        for (int kk = 0; kk < 8; kk++) {
            uint32_t ko = (uint32_t)kk * 32;
            uint32_t aF[4][4], bF[2][4];
#pragma unroll
            for (int mi = 0; mi < 4; mi++) ldsm4(aF[mi], aAddr + mi * (16 * SST * 2) + ko);
#pragma unroll
            for (int n2 = 0; n2 < 2; n2++) ldsm4(bF[n2], bAddr + n2 * (16 * SST * 2) + ko);
#pragma unroll
            for (int mi = 0; mi < 4; mi++)
#pragma unroll
                for (int ni = 0; ni < 4; ni++)
                    mma_bf16(acc[mi][ni], aF[mi], bF[ni >> 1][(ni & 1) * 2], bF[ni >> 1][(ni & 1) * 2 + 1]);
        }
    }

    // epilogue: fragments -> smem bf16 (stride EPST, 16B-divisible pitch) -> coalesced stores
    __syncthreads();
    __nv_bfloat16* epi = (__nv_bfloat16*)smem;
    {
        const int r0 = wr + (lane >> 2);
        const int c0 = wc + (lane & 3) * 2;
#pragma unroll
        for (int mi = 0; mi < 4; mi++)
#pragma unroll
            for (int ni = 0; ni < 4; ni++) {
                int rr = r0 + mi * 16, cc = c0 + ni * 8;
                *(__nv_bfloat162*)(epi + rr * EPST + cc) =
                    __floats2bfloat162_rn(acc[mi][ni][0], acc[mi][ni][1]);
                *(__nv_bfloat162*)(epi + (rr + 8) * EPST + cc) =
                    __floats2bfloat162_rn(acc[mi][ni][2], acc[mi][ni][3]);
            }
    }
    __syncthreads();
#pragma unroll
    for (int j = 0; j < 8; j++) {
        int idx = j * 256 + tid;              // 0..2047
        int row = idx >> 4, c8 = idx & 15;
        uint4 v = *(uint4*)(epi + row * EPST + c8 * 8);
        *(uint4*)(g_d + (size_t)(bm + row) * NE + bn + c8 * 8) = v;
    }
}

// ---------------- bf16-split TC GEMM: g_eproj = embed @ W_out^T ----------------
// C[NE, ODIM], K=256; hi/lo 2-term split (3 MMAs) for ~fp32 accuracy
#define SMEM_EP (4 * 128 * SST * 2)    // 139264 B (> fp32 epilogue stage 67584 B)

__global__ void __launch_bounds__(256)
eproj_kernel() {
    extern __shared__ __align__(16) char smem[];
    __nv_bfloat16* sAh = (__nv_bfloat16*)smem;
    __nv_bfloat16* sAl = sAh + 128 * SST;
    __nv_bfloat16* sBh = sAl + 128 * SST;
    __nv_bfloat16* sBl = sBh + 128 * SST;
    const int tid = threadIdx.x;
    const int bm = blockIdx.y * 128, bn = blockIdx.x * 128;
    const int wid = tid >> 5, lane = tid & 31;
    const int wr = (wid & 1) * 64;
    const int wc = (wid >> 1) * 32;

    uint32_t base = smem_u32(sAh);
    uint32_t aOff = (uint32_t)(((wr + (lane & 15)) * SST + (lane >> 4) * 8) * 2);
    uint32_t bRow = (uint32_t)(wc + (lane & 7) + ((lane >> 4) << 3));
    uint32_t bOff = (uint32_t)((bRow * SST + ((lane >> 3) & 1) * 8) * 2);
    const uint32_t AH = base, AL = base + 128*SST*2, BH = base + 2*128*SST*2, BL = base + 3*128*SST*2;

    const uint4* gAh = (const uint4*)g_eh + (size_t)bm * 32;
    const uint4* gAl = (const uint4*)g_el + (size_t)bm * 32;
    const uint4* gBh = (const uint4*)g_wh + (size_t)bn * 32;
    const uint4* gBl = (const uint4*)g_wl + (size_t)bn * 32;

    float acc[4][4][4] = {};
    for (int kc = 0; kc < 2; kc++) {
        __syncthreads();
#pragma unroll
        for (int j = 0; j < 8; j++) {
            int idx = j * 256 + tid;
            int row = idx >> 4, c8 = idx & 15;
            int gi = row * 32 + kc * 16 + c8;
            int si = row * SST + c8 * 8;
            *(uint4*)(sAh + si) = gAh[gi];
            *(uint4*)(sAl + si) = gAl[gi];
            *(uint4*)(sBh + si) = gBh[gi];
            *(uint4*)(sBl + si) = gBl[gi];
        }
        __syncthreads();
#pragma unroll
        for (int kk = 0; kk < 8; kk++) {
            uint32_t ko = (uint32_t)kk * 32;
            uint32_t ah[4][4], al[4][4], bh[2][4], bl[2][4];
#pragma unroll
            for (int mi = 0; mi < 4; mi++) {
                ldsm4(ah[mi], AH + aOff + mi * (16 * SST * 2) + ko);
                ldsm4(al[mi], AL + aOff + mi * (16 * SST * 2) + ko);
            }
#pragma unroll
            for (int n2 = 0; n2 < 2; n2++) {
                ldsm4(bh[n2], BH + bOff + n2 * (16 * SST * 2) + ko);
                ldsm4(bl[n2], BL + bOff + n2 * (16 * SST * 2) + ko);
            }
#pragma unroll
            for (int mi = 0; mi < 4; mi++)
#pragma unroll
                for (int ni = 0; ni < 4; ni++) {
                    uint32_t h0 = bh[ni >> 1][(ni & 1) * 2], h1 = bh[ni >> 1][(ni & 1) * 2 + 1];
                    uint32_t l0 = bl[ni >> 1][(ni & 1) * 2], l1 = bl[ni >> 1][(ni & 1) * 2 + 1];
                    mma_bf16(acc[mi][ni], ah[mi], h0, h1);
                    mma_bf16(acc[mi][ni], ah[mi], l0, l1);
                    mma_bf16(acc[mi][ni], al[mi], h0, h1);
                }
        }
    }

    // epilogue: fp32 smem stage (stride 132 floats = 528B, 16B-divisible) -> coalesced stores
    __syncthreads();
    float* epi = (float*)smem;
    {
        const int r0 = wr + (lane >> 2);
        const int c0 = wc + (lane & 3) * 2;
#pragma unroll
        for (int mi = 0; mi < 4; mi++)
#pragma unroll
            for (int ni = 0; ni < 4; ni++) {
                int rr = r0 + mi * 16, cc = c0 + ni * 8;
                *(float2*)(epi + rr * 132 + cc) = make_float2(acc[mi][ni][0], acc[mi][ni][1]);
                *(float2*)(epi + (rr + 8) * 132 + cc) = make_float2(acc[mi][ni][2], acc[mi][ni][3]);
            }
    }
    __syncthreads();
#pragma unroll
    for (int j = 0; j < 16; j++) {
        int idx = j * 256 + tid;              // 0..4095
        int row = idx >> 5, c4 = idx & 31;
        uint4 v = *(uint4*)(epi + row * 132 + c4 * 4);
        *(uint4*)(g_eproj + (size_t)(bm + row) * ODIM + bn + c4 * 4) = v;
    }
}

// ---------------- gather: z_q_out[r] = g_eproj[ind_r] + b_out ----------------
__global__ void gather_kernel(const float* __restrict__ b_out, float* __restrict__ out) {
    int r = blockIdx.x, t = threadIdx.x;
    int ind = (int)out[OFF_IND + r];
    const float* src = g_eproj + (size_t)ind * ODIM;
    float* dst = out + OFF_ZQ + (size_t)r * ODIM;
#pragma unroll
    for (int c = t; c < ODIM; c += 256)
        dst[c] = src[c] + b_out[c];
}

// ---------------- row pass: S/T/argmin(+exact fixup)/commit/bins/embed_sum ----------------
__global__ void __launch_bounds__(256)
row_pass_kernel(const float* __restrict__ embed, float* __restrict__ out) {
    const int r = blockIdx.x, t = threadIdx.x;
    __shared__ float sxn[256];
    __shared__ float sS[256], sT[256], sM[256];
    __shared__ float sred[256];
    __shared__ int scnt;
    __shared__ int scand[64];
    __shared__ unsigned long long sbest;

    float xnv = g_xn[(size_t)r * EDIM + t];
    sxn[t] = xnv;
    if (t == 0) { scnt = 0; sbest = ~0ULL; }

    const __nv_bfloat162* dp = (const __nv_bfloat162*)(g_d + (size_t)r * NE);
    __nv_bfloat162 dv[16];
#pragma unroll
    for (int j = 0; j < 16; j++) dv[j] = dp[t + j * 256];

    float S = 0.f, T = 0.f, mval = 1e30f;
#pragma unroll
    for (int j = 0; j < 16; j++) {
        float d0 = __bfloat162float(dv[j].x);
        float d1 = __bfloat162float(dv[j].y);
        float t0 = 10.f * d0, t1 = 10.f * d1;
        float e0 = fast_exp(t0), e1 = fast_exp(t1);
        S += e0 + e1;
        T = fmaf(e0, t0, T); T = fmaf(e1, t1, T);
        mval = fminf(mval, fminf(d0, d1));
    }
    sS[t] = S; sT[t] = T; sM[t] = mval;
    __syncthreads();
    for (int s = 128; s > 0; s >>= 1) {
        if (t < s) { sS[t] += sS[t+s]; sT[t] += sT[t+s]; sM[t] = fminf(sM[t], sM[t+s]); }
        __syncthreads();
    }
    float Stot = sS[0], Ttot = sT[0], gmin = sM[0];

    float thresh = gmin + 1.2e-2f;
#pragma unroll
    for (int j = 0; j < 16; j++) {
        int c0 = (j * 256 + t) * 2;
        float d0 = __bfloat162float(dv[j].x);
        float d1 = __bfloat162float(dv[j].y);
        if (d0 <= thresh) { int p = atomicAdd(&scnt, 1); if (p < 64) scand[p] = c0; }
        if (d1 <= thresh) { int p = atomicAdd(&scnt, 1); if (p < 64) scand[p] = c0 + 1; }
    }
    __syncthreads();
    int ncand = scnt < 64 ? scnt : 64;
    int ind;
    if (ncand == 1) {
        ind = scand[0];
    } else {
        for (int i = 0; i < ncand; i++) {
            const float* er = embed + (size_t)scand[i] * EDIM;
            sred[t] = sxn[t] * er[t];
            __syncthreads();
            for (int s = 128; s > 0; s >>= 1) { if (t < s) sred[t] += sred[t+s]; __syncthreads(); }
            if (t == 0) {
                unsigned u = __float_as_uint(sred[0]);
                u = (u & 0x80000000u) ? ~u : (u | 0x80000000u);
                unsigned long long k = ((unsigned long long)u << 32) | (unsigned)scand[i];
                if (k < sbest) sbest = k;
            }
            __syncthreads();
        }
        ind = (int)(sbest & 0xffffffffu);
    }

    float ev = embed[(size_t)ind * EDIM + t];
    float df = ev - xnv;
    sred[t] = df * df;
    atomicAdd(&g_embed_sum[(size_t)ind * EDIM + t], xnv);
    __syncthreads();
    for (int s = 128; s > 0; s >>= 1) { if (t < s) sred[t] += sred[t+s]; __syncthreads(); }
    if (t == 0) {
        atomicAdd(&g_scal[0], sred[0]);
        out[OFF_IND + r] = (float)ind;
        atomicAdd(&g_bins[ind], 1.0f);
        atomicAdd(&g_scal[1], logf(Stot) - Ttot / Stot);
        g_invS[r] = 1.0f / Stot;
    }
}

// ---------------- ap column pass ----------------
__global__ void ap_kernel() {
    int c  = blockIdx.x * 256 + threadIdx.x;
    int r0 = blockIdx.y * 2048;
    __shared__ float sh_inv[256];
    float acc = 0.f;
    for (int rr = 0; rr < 2048; rr += 256) {
        __syncthreads();
        sh_inv[threadIdx.x] = g_invS[r0 + rr + threadIdx.x];
        __syncthreads();
        const __nv_bfloat16* ep = g_d + (size_t)(r0 + rr) * NE + c;
#pragma unroll 4
        for (int j = 0; j < 256; j++) {
            float d = __bfloat162float(ep[(size_t)j * NE]);
            acc = fmaf(fast_exp(10.f * d), sh_inv[j], acc);
        }
    }
    atomicAdd(&g_ap[c], acc);
}

// ---------------- code updates ----------------
__global__ void e1_kernel(const float* __restrict__ cluster_size, float* __restrict__ out) {
    int i = blockIdx.x * 256 + threadIdx.x;
    if (i >= NE) return;
    float cn = cluster_size[i] * 0.99f + g_bins[i] * 0.01f;
    g_cluster_new[i] = cn;
    int ex = (cn < 0.1f);
    g_expired[i] = ex;
    out[OFF_CS + i] = ex ? 0.12f : cn;
    atomicAdd(&g_scal[2], cn);
}

__global__ void scan_kernel() {
    int t = threadIdx.x;
    __shared__ int sh[1024];
    int vals[8]; int s = 0;
#pragma unroll
    for (int j = 0; j < 8; j++) { s += g_expired[t*8 + j]; vals[j] = s; }
    sh[t] = s;
    __syncthreads();
    for (int off = 1; off < 1024; off <<= 1) {
        int v = (t >= off) ? sh[t - off] : 0;
        __syncthreads();
        sh[t] += v;
        __syncthreads();
    }
    int excl = (t > 0) ? sh[t-1] : 0;
#pragma unroll
    for (int j = 0; j < 8; j++) {
        int cum = excl + vals[j];
        int idx = cum - 1; if (idx < 0) idx = 0;
        g_sampidx[t*8 + j] = idx;
    }
}

__global__ void e3_kernel(const float* __restrict__ embed_avg, float* __restrict__ out) {
    int c = blockIdx.x, k = threadIdx.x;
    float ea = embed_avg[(size_t)c * EDIM + k] * 0.99f + g_embed_sum[(size_t)c * EDIM + k] * 0.01f;
    float total = g_scal[2];
    float cn = g_cluster_new[c];
    float cs = (cn + 1e-5f) / (total + (float)NE * 1e-5f) * total;
    float en = ea / cs;
    float ef, eaf;
    if (g_expired[c]) {
        float sv = g_xn[(size_t)g_sampidx[c] * EDIM + k];
        ef = sv; eaf = sv * 0.12f;
    } else { ef = en; eaf = ea; }
    out[OFF_EMB  + (size_t)c * EDIM + k] = ef;
    out[OFF_EAVG + (size_t)c * EDIM + k] = eaf;
}

__global__ void scalars_kernel(float* __restrict__ out) {
    int t = threadIdx.x;
    __shared__ float sh[1024];
    float local = 0.f;
#pragma unroll
    for (int j = 0; j < 8; j++) {
        float ap = g_ap[t*8 + j] * (1.0f / (float)NTOK);
        local -= ap * logf(ap);
    }
    sh[t] = local;
    __syncthreads();
    for (int s = 512; s > 0; s >>= 1) { if (t < s) sh[t] += sh[t+s]; __syncthreads(); }
    if (t == 0) {
        float ent_max = sh[0];
        float commit  = g_scal[0] / ((float)NTOK * (float)EDIM);
        out[OFF_LOSS]   = commit - ent_max;
        out[OFF_ENTMIN] = g_scal[1] / (float)NTOK;
        out[OFF_COMMIT] = commit;
    }
}

// ---------------- launch ----------------
extern "C" void kernel_launch(void* const* d_in, const int* in_sizes, int n_in,
                              void* d_out, int out_size) {
    const float* x         = (const float*)d_in[0];
    const float* W_in      = (const float*)d_in[1];
    const float* b_in      = (const float*)d_in[2];
    const float* W_out     = (const float*)d_in[3];
    const float* b_out     = (const float*)d_in[4];
    const float* embed     = (const float*)d_in[5];
    const float* embed_avg = (const float*)d_in[6];
    const float* cluster   = (const float*)d_in[7];
    float* out = (float*)d_out;

    void *p_xn=nullptr, *p_a=nullptr, *p_eh=nullptr, *p_el=nullptr, *p_wh=nullptr, *p_wl=nullptr;
    cudaGetSymbolAddress(&p_xn, g_xn);
    cudaGetSymbolAddress(&p_a, g_a);
    cudaGetSymbolAddress(&p_eh, g_eh);
    cudaGetSymbolAddress(&p_el, g_el);
    cudaGetSymbolAddress(&p_wh, g_wh);
    cudaGetSymbolAddress(&p_wl, g_wl);

    cudaFuncSetAttribute(mma_d_kernel, cudaFuncAttributeMaxDynamicSharedMemorySize, SMEM_MMA);
    cudaFuncSetAttribute(eproj_kernel, cudaFuncAttributeMaxDynamicSharedMemorySize, SMEM_EP);

    zero_kernel<<<8192, 256>>>();
    // x_proj = x @ W_in^T + b_in  (fp32 exact — argmin fidelity)
    gemm_bias_kernel<<<dim3(EDIM/128, NTOK/128), 256>>>(x, W_in, b_in, (float*)p_xn,
                                                        NTOK, EDIM, LAT);
    l2norm_kernel<<<NTOK, 256>>>((float*)p_xn);
    // bf16 xn for d-GEMM; hi/lo splits for embed (hi doubles as d-GEMM B) and W_out
    conv_bf16_kernel<<<NTOK*EDIM/8/256, 256>>>((const float*)p_xn, (__nv_bfloat16*)p_a);
    conv_split_kernel<<<NE*EDIM/8/256, 256>>>(embed, (__nv_bfloat16*)p_eh, (__nv_bfloat16*)p_el);
    // d = xn @ embed^T on HMMA tensor cores
    mma_d_kernel<<<dim3(NE/128, NTOK/128), 256, SMEM_MMA>>>();
    // per-row: S/T, exact argmin, commit, bins, embed_sum
    row_pass_kernel<<<NTOK, 256>>>(embed, out);
    conv_split_kernel<<<ODIM*EDIM/8/256, 256>>>(W_out, (__nv_bfloat16*)p_wh, (__nv_bfloat16*)p_wl);
    // embed_proj = embed @ W_out^T (bf16 hi/lo split, ~fp32 accurate)
    eproj_kernel<<<dim3(ODIM/128, NE/128), 256, SMEM_EP>>>();
    ap_kernel<<<dim3(NE/256, NTOK/2048), 256>>>();
    e1_kernel<<<NE/256, 256>>>(cluster, out);
    scan_kernel<<<1, 1024>>>();
    scalars_kernel<<<1, 1024>>>(out);
    e3_kernel<<<NE, 256>>>(embed_avg, out);
    // z_q_out via gather of embed_proj + bias
    gather_kernel<<<NTOK, 256>>>(b_out, out);
}

// round 7
// speedup vs baseline: 2.3863x; 1.0141x over previous
#include <cuda_runtime.h>
#include <cuda_bf16.h>
#include <math.h>
#include <stdint.h>

// ---------------- problem constants ----------------
#define NTOK   16384
#define EDIM   256
#define NE     8192
#define LAT    768
#define ODIM   768

// output layout (concatenated tuple, float32)
#define OFF_ZQ     ((size_t)0)
#define OFF_IND    ((size_t)12582912)
#define OFF_LOSS   ((size_t)12599296)
#define OFF_EMB    ((size_t)12599297)
#define OFF_EAVG   ((size_t)14696449)
#define OFF_CS     ((size_t)16793601)
#define OFF_ENTMIN ((size_t)16801793)
#define OFF_COMMIT ((size_t)16801794)

#define QSCALE 126.0f
#define QINV   (1.0f / 126.0f)

// ---------------- device scratch ----------------
__device__ signed char g_d8[(size_t)NTOK * NE];     // approx d, int8 (128MB)
__device__ __nv_bfloat16 g_a[(size_t)NTOK * EDIM];  // xn bf16
__device__ __nv_bfloat16 g_eh[(size_t)NE * EDIM];   // embed hi (also mma_d B)
__device__ __nv_bfloat16 g_el[(size_t)NE * EDIM];   // embed lo
__device__ __nv_bfloat16 g_wh[(size_t)ODIM * EDIM]; // W_out hi
__device__ __nv_bfloat16 g_wl[(size_t)ODIM * EDIM]; // W_out lo
__device__ float g_eproj[(size_t)NE * ODIM];        // embed @ W_out^T
__device__ float g_xn[NTOK * EDIM];
__device__ float g_invS[NTOK];
__device__ float g_bins[NE];
__device__ float g_ap[NE];
__device__ float g_cluster_new[NE];
__device__ int   g_expired[NE];
__device__ int   g_sampidx[NE];
__device__ float g_embed_sum[NE * EDIM];
__device__ float g_scal[4];   // 0: commit sum, 1: entmin sum, 2: total cluster

// sign-extend byte b of packed word u (arch-independent; aarch64 char is unsigned!)
__device__ __forceinline__ int sext8(uint32_t u, int b) {
    return ((int)(u << (24 - 8 * b))) >> 24;
}

// ---------------- fast exp (FFMA only) ----------------
__device__ __forceinline__ float fast_exp(float x) {
    float z = x * 1.4426950408889634f;
    int   i = __float2int_rn(z);
    float rf = (float)i;
    float g = fmaf(rf, -0.693359375f, x);
    g = fmaf(rf, 2.12194440e-4f, g);
    float p = 1.98412698e-4f;
    p = fmaf(p, g, 1.38888889e-3f);
    p = fmaf(p, g, 8.33333333e-3f);
    p = fmaf(p, g, 4.16666667e-2f);
    p = fmaf(p, g, 1.66666667e-1f);
    p = fmaf(p, g, 0.5f);
    p = fmaf(p, g, 1.0f);
    p = fmaf(p, g, 1.0f);
    float sc = __int_as_float((i + 127) << 23);
    return p * sc;
}

// ---------------- warp MMA helpers (arch-portable PTX, sm_80+) ----------------
__device__ __forceinline__ uint32_t smem_u32(const void* p) {
    uint32_t a;
    asm("{ .reg .u64 t; cvta.to.shared.u64 t, %1; cvt.u32.u64 %0, t; }" : "=r"(a) : "l"(p));
    return a;
}
__device__ __forceinline__ void ldsm4(uint32_t* r, uint32_t addr) {
    asm volatile("ldmatrix.sync.aligned.m8n8.x4.shared.b16 {%0,%1,%2,%3}, [%4];"
                 : "=r"(r[0]), "=r"(r[1]), "=r"(r[2]), "=r"(r[3]) : "r"(addr));
}
__device__ __forceinline__ void mma_bf16(float* c, const uint32_t* a, uint32_t b0, uint32_t b1) {
    asm volatile("mma.sync.aligned.m16n8k16.row.col.f32.bf16.bf16.f32 "
                 "{%0,%1,%2,%3}, {%4,%5,%6,%7}, {%8,%9}, {%0,%1,%2,%3};"
                 : "+f"(c[0]), "+f"(c[1]), "+f"(c[2]), "+f"(c[3])
                 : "r"(a[0]), "r"(a[1]), "r"(a[2]), "r"(a[3]), "r"(b0), "r"(b1));
}
__device__ __forceinline__ signed char q8(float d) {
    float v = fminf(fmaxf(d * QSCALE, -127.f), 127.f);
    return (signed char)__float2int_rn(v);
}

// ---------------- zeroing ----------------
__global__ void zero_kernel() {
    int i = blockIdx.x * 256 + threadIdx.x;
    if (i < NE * EDIM) g_embed_sum[i] = 0.f;
    if (i < NE)   { g_bins[i] = 0.f; g_ap[i] = 0.f; }
    if (i < 4)    g_scal[i] = 0.f;
}

// ---------------- fp32 SGEMM, double-buffered: C = A @ W^T + bias ----------------
__global__ void __launch_bounds__(256)
gemm_bias_kernel(const float* __restrict__ A, const float* __restrict__ W,
                 const float* __restrict__ bias, float* __restrict__ C,
                 int M, int N, int K) {
    __shared__ float As[2][8][132];
    __shared__ float Ws[2][8][132];
    const int tid = threadIdx.x;
    const int tx = tid & 15, ty = tid >> 4;
    const int bm = blockIdx.y * 128, bn = blockIdx.x * 128;
    float acc[8][8] = {};
    const int lrow = tid >> 1;
    const int lk4  = (tid & 1) * 4;
    const float* Ap = A + (size_t)(bm + lrow) * K + lk4;
    const float* Wp = W + (size_t)(bn + lrow) * K + lk4;
    const int NIT = K >> 3;

    float4 av = *(const float4*)(Ap);
    float4 wv = *(const float4*)(Wp);
    As[0][lk4+0][lrow]=av.x; As[0][lk4+1][lrow]=av.y; As[0][lk4+2][lrow]=av.z; As[0][lk4+3][lrow]=av.w;
    Ws[0][lk4+0][lrow]=wv.x; Ws[0][lk4+1][lrow]=wv.y; Ws[0][lk4+2][lrow]=wv.z; Ws[0][lk4+3][lrow]=wv.w;
    __syncthreads();

    for (int it = 0; it < NIT; it++) {
        int cur = it & 1;
        if (it + 1 < NIT) {
            av = *(const float4*)(Ap + (it + 1) * 8);
            wv = *(const float4*)(Wp + (it + 1) * 8);
        }
#pragma unroll
        for (int k = 0; k < 8; k++) {
            float a[8], b[8];
#pragma unroll
            for (int ir = 0; ir < 8; ir++) a[ir] = As[cur][k][ty*8 + ir];
#pragma unroll
            for (int ic = 0; ic < 8; ic++) b[ic] = Ws[cur][k][ic*16 + tx];
#pragma unroll
            for (int ir = 0; ir < 8; ir++)
#pragma unroll
                for (int ic = 0; ic < 8; ic++)
                    acc[ir][ic] = fmaf(a[ir], b[ic], acc[ir][ic]);
        }
        if (it + 1 < NIT) {
            int nxt = cur ^ 1;
            As[nxt][lk4+0][lrow]=av.x; As[nxt][lk4+1][lrow]=av.y; As[nxt][lk4+2][lrow]=av.z; As[nxt][lk4+3][lrow]=av.w;
            Ws[nxt][lk4+0][lrow]=wv.x; Ws[nxt][lk4+1][lrow]=wv.y; Ws[nxt][lk4+2][lrow]=wv.z; Ws[nxt][lk4+3][lrow]=wv.w;
        }
        __syncthreads();
    }
#pragma unroll
    for (int ir = 0; ir < 8; ir++) {
        int row = bm + ty*8 + ir;
#pragma unroll
        for (int ic = 0; ic < 8; ic++) {
            int col = bn + ic*16 + tx;
            C[(size_t)row * N + col] = acc[ir][ic] + bias[col];
        }
    }
}

// ---------------- row l2-normalize, fused bf16 output ----------------
__global__ void l2norm_kernel(float* __restrict__ x, __nv_bfloat16* __restrict__ xb) {
    int r = blockIdx.x, t = threadIdx.x;
    __shared__ float sh[256];
    float v = x[(size_t)r * EDIM + t];
    sh[t] = v * v;
    __syncthreads();
    for (int s = 128; s > 0; s >>= 1) { if (t < s) sh[t] += sh[t+s]; __syncthreads(); }
    float nrm = sqrtf(sh[0]);
    float xn = v / nrm;
    x[(size_t)r * EDIM + t] = xn;
    xb[(size_t)r * EDIM + t] = __float2bfloat16(xn);
}

// ---------------- fp32 -> bf16 hi/lo split ----------------
__global__ void conv_split_kernel(const float* __restrict__ src,
                                  __nv_bfloat16* __restrict__ hi,
                                  __nv_bfloat16* __restrict__ lo) {
    int i = blockIdx.x * 256 + threadIdx.x;   // 8 elems
    float v[8];
    float4 v0 = ((const float4*)src)[2*i];
    float4 v1 = ((const float4*)src)[2*i+1];
    v[0]=v0.x; v[1]=v0.y; v[2]=v0.z; v[3]=v0.w;
    v[4]=v1.x; v[5]=v1.y; v[6]=v1.z; v[7]=v1.w;
    __nv_bfloat16 h[8], l[8];
#pragma unroll
    for (int j = 0; j < 8; j++) {
        h[j] = __float2bfloat16(v[j]);
        l[j] = __float2bfloat16(v[j] - __bfloat162float(h[j]));
    }
    uint4 ph, pl;
    ph.x = *(uint32_t*)&h[0]; ph.y = *(uint32_t*)&h[2];
    ph.z = *(uint32_t*)&h[4]; ph.w = *(uint32_t*)&h[6];
    pl.x = *(uint32_t*)&l[0]; pl.y = *(uint32_t*)&l[2];
    pl.z = *(uint32_t*)&l[4]; pl.w = *(uint32_t*)&l[6];
    ((uint4*)hi)[i] = ph;
    ((uint4*)lo)[i] = pl;
}

// ---------------- bf16 tensor-core d-GEMM, int8 output ----------------
#define SST  136
#define SMEM_MMA (2 * 128 * SST * 2)    // 69632 B (epilogue int8 stage 18432 B fits)

__global__ void __launch_bounds__(256, 2)
mma_d_kernel() {
    extern __shared__ __align__(16) char smem[];
    __nv_bfloat16* sA = (__nv_bfloat16*)smem;
    __nv_bfloat16* sB = (__nv_bfloat16*)(smem + 128 * SST * 2);
    const int tid = threadIdx.x;
    const int bm = blockIdx.y * 128, bn = blockIdx.x * 128;
    const int wid = tid >> 5, lane = tid & 31;
    const int wr = (wid & 1) * 64;
    const int wc = (wid >> 1) * 32;

    uint32_t sAu = smem_u32(sA), sBu = smem_u32(sB);
    uint32_t aAddr = sAu + (uint32_t)(((wr + (lane & 15)) * SST + (lane >> 4) * 8) * 2);
    uint32_t bRow  = (uint32_t)(wc + (lane & 7) + ((lane >> 4) << 3));
    uint32_t bAddr = sBu + (uint32_t)((bRow * SST + ((lane >> 3) & 1) * 8) * 2);

    const uint4* gA = (const uint4*)g_a  + (size_t)bm * 32;
    const uint4* gB = (const uint4*)g_eh + (size_t)bn * 32;

    float acc[4][4][4] = {};
    for (int kc = 0; kc < 2; kc++) {
        __syncthreads();
#pragma unroll
        for (int j = 0; j < 8; j++) {
            int idx = j * 256 + tid;
            int row = idx >> 4, c8 = idx & 15;
            *(uint4*)(sA + row * SST + c8 * 8) = gA[row * 32 + kc * 16 + c8];
            *(uint4*)(sB + row * SST + c8 * 8) = gB[row * 32 + kc * 16 + c8];
        }
        __syncthreads();
#pragma unroll
        for (int kk = 0; kk < 8; kk++) {
            uint32_t ko = (uint32_t)kk * 32;
            uint32_t aF[4][4], bF[2][4];
#pragma unroll
            for (int mi = 0; mi < 4; mi++) ldsm4(aF[mi], aAddr + mi * (16 * SST * 2) + ko);
#pragma unroll
            for (int n2 = 0; n2 < 2; n2++) ldsm4(bF[n2], bAddr + n2 * (16 * SST * 2) + ko);
#pragma unroll
            for (int mi = 0; mi < 4; mi++)
#pragma unroll
                for (int ni = 0; ni < 4; ni++)
                    mma_bf16(acc[mi][ni], aF[mi], bF[ni >> 1][(ni & 1) * 2], bF[ni >> 1][(ni & 1) * 2 + 1]);
        }
    }

    // epilogue: quantize to int8, smem stage (144B pitch, 16B-divisible), coalesced stores
    __syncthreads();
    signed char* epi = (signed char*)smem;
    {
        const int r0 = wr + (lane >> 2);
        const int c0 = wc + (lane & 3) * 2;
#pragma unroll
        for (int mi = 0; mi < 4; mi++)
#pragma unroll
            for (int ni = 0; ni < 4; ni++) {
                int rr = r0 + mi * 16, cc = c0 + ni * 8;
                epi[rr * 144 + cc]       = q8(acc[mi][ni][0]);
                epi[rr * 144 + cc + 1]   = q8(acc[mi][ni][1]);
                epi[(rr+8) * 144 + cc]     = q8(acc[mi][ni][2]);
                epi[(rr+8) * 144 + cc + 1] = q8(acc[mi][ni][3]);
            }
    }
    __syncthreads();
#pragma unroll
    for (int j = 0; j < 4; j++) {
        int idx = j * 256 + tid;              // 0..1023 (16B units)
        int row = idx >> 3, c16 = idx & 7;
        uint4 v = *(uint4*)(epi + row * 144 + c16 * 16);
        *(uint4*)(g_d8 + (size_t)(bm + row) * NE + bn + c16 * 16) = v;
    }
}

// ---------------- bf16-split TC GEMM: g_eproj = embed @ W_out^T ----------------
#define SMEM_EP (4 * 128 * SST * 2)

__global__ void __launch_bounds__(256)
eproj_kernel() {
    extern __shared__ __align__(16) char smem[];
    __nv_bfloat16* sAh = (__nv_bfloat16*)smem;
    __nv_bfloat16* sAl = sAh + 128 * SST;
    __nv_bfloat16* sBh = sAl + 128 * SST;
    __nv_bfloat16* sBl = sBh + 128 * SST;
    const int tid = threadIdx.x;
    const int bm = blockIdx.y * 128, bn = blockIdx.x * 128;
    const int wid = tid >> 5, lane = tid & 31;
    const int wr = (wid & 1) * 64;
    const int wc = (wid >> 1) * 32;

    uint32_t base = smem_u32(sAh);
    uint32_t aOff = (uint32_t)(((wr + (lane & 15)) * SST + (lane >> 4) * 8) * 2);
    uint32_t bRow = (uint32_t)(wc + (lane & 7) + ((lane >> 4) << 3));
    uint32_t bOff = (uint32_t)((bRow * SST + ((lane >> 3) & 1) * 8) * 2);
    const uint32_t AH = base, AL = base + 128*SST*2, BH = base + 2*128*SST*2, BL = base + 3*128*SST*2;

    const uint4* gAh = (const uint4*)g_eh + (size_t)bm * 32;
    const uint4* gAl = (const uint4*)g_el + (size_t)bm * 32;
    const uint4* gBh = (const uint4*)g_wh + (size_t)bn * 32;
    const uint4* gBl = (const uint4*)g_wl + (size_t)bn * 32;

    float acc[4][4][4] = {};
    for (int kc = 0; kc < 2; kc++) {
        __syncthreads();
#pragma unroll
        for (int j = 0; j < 8; j++) {
            int idx = j * 256 + tid;
            int row = idx >> 4, c8 = idx & 15;
            int gi = row * 32 + kc * 16 + c8;
            int si = row * SST + c8 * 8;
            *(uint4*)(sAh + si) = gAh[gi];
            *(uint4*)(sAl + si) = gAl[gi];
            *(uint4*)(sBh + si) = gBh[gi];
            *(uint4*)(sBl + si) = gBl[gi];
        }
        __syncthreads();
#pragma unroll
        for (int kk = 0; kk < 8; kk++) {
            uint32_t ko = (uint32_t)kk * 32;
            uint32_t ah[4][4], al[4][4], bh[2][4], bl[2][4];
#pragma unroll
            for (int mi = 0; mi < 4; mi++) {
                ldsm4(ah[mi], AH + aOff + mi * (16 * SST * 2) + ko);
                ldsm4(al[mi], AL + aOff + mi * (16 * SST * 2) + ko);
            }
#pragma unroll
            for (int n2 = 0; n2 < 2; n2++) {
                ldsm4(bh[n2], BH + bOff + n2 * (16 * SST * 2) + ko);
                ldsm4(bl[n2], BL + bOff + n2 * (16 * SST * 2) + ko);
            }
#pragma unroll
            for (int mi = 0; mi < 4; mi++)
#pragma unroll
                for (int ni = 0; ni < 4; ni++) {
                    uint32_t h0 = bh[ni >> 1][(ni & 1) * 2], h1 = bh[ni >> 1][(ni & 1) * 2 + 1];
                    uint32_t l0 = bl[ni >> 1][(ni & 1) * 2], l1 = bl[ni >> 1][(ni & 1) * 2 + 1];
                    mma_bf16(acc[mi][ni], ah[mi], h0, h1);
                    mma_bf16(acc[mi][ni], ah[mi], l0, l1);
                    mma_bf16(acc[mi][ni], al[mi], h0, h1);
                }
        }
    }

    __syncthreads();
    float* epi = (float*)smem;
    {
        const int r0 = wr + (lane >> 2);
        const int c0 = wc + (lane & 3) * 2;
#pragma unroll
        for (int mi = 0; mi < 4; mi++)
#pragma unroll
            for (int ni = 0; ni < 4; ni++) {
                int rr = r0 + mi * 16, cc = c0 + ni * 8;
                *(float2*)(epi + rr * 132 + cc) = make_float2(acc[mi][ni][0], acc[mi][ni][1]);
                *(float2*)(epi + (rr + 8) * 132 + cc) = make_float2(acc[mi][ni][2], acc[mi][ni][3]);
            }
    }
    __syncthreads();
#pragma unroll
    for (int j = 0; j < 16; j++) {
        int idx = j * 256 + tid;
        int row = idx >> 5, c4 = idx & 31;
        uint4 v = *(uint4*)(epi + row * 132 + c4 * 4);
        *(uint4*)(g_eproj + (size_t)(bm + row) * ODIM + bn + c4 * 4) = v;
    }
}

// ---------------- gather: z_q_out[r] = g_eproj[ind_r] + b_out ----------------
__global__ void gather_kernel(const float* __restrict__ b_out, float* __restrict__ out) {
    int r = blockIdx.x, t = threadIdx.x;
    int ind = (int)out[OFF_IND + r];
    const float* src = g_eproj + (size_t)ind * ODIM;
    float* dst = out + OFF_ZQ + (size_t)r * ODIM;
#pragma unroll
    for (int c = t; c < ODIM; c += 256)
        dst[c] = src[c] + b_out[c];
}

// ---------------- row pass over int8 d ----------------
__global__ void __launch_bounds__(256)
row_pass_kernel(const float* __restrict__ embed, float* __restrict__ out) {
    const int r = blockIdx.x, t = threadIdx.x;
    __shared__ float sxn[256];
    __shared__ float sS[256], sT[256], sM[256];
    __shared__ float sred[256];
    __shared__ int scnt;
    __shared__ int scand[64];
    __shared__ unsigned long long sbest;

    float xnv = g_xn[(size_t)r * EDIM + t];
    sxn[t] = xnv;
    if (t == 0) { scnt = 0; sbest = ~0ULL; }

    const uint32_t* dp = (const uint32_t*)(g_d8 + (size_t)r * NE);
    uint32_t dv[8];
#pragma unroll
    for (int j = 0; j < 8; j++) dv[j] = dp[t + j * 256];

    float S = 0.f, T = 0.f, mval = 1e30f;
#pragma unroll
    for (int j = 0; j < 8; j++) {
        uint32_t u = dv[j];
#pragma unroll
        for (int b = 0; b < 4; b++) {
            float d = (float)sext8(u, b) * QINV;
            float t10 = 10.f * d;
            float e = fast_exp(t10);
            S += e;
            T = fmaf(e, t10, T);
            mval = fminf(mval, d);
        }
    }
    sS[t] = S; sT[t] = T; sM[t] = mval;
    __syncthreads();
    for (int s = 128; s > 0; s >>= 1) {
        if (t < s) { sS[t] += sS[t+s]; sT[t] += sT[t+s]; sM[t] = fminf(sM[t], sM[t+s]); }
        __syncthreads();
    }
    float Stot = sS[0], Ttot = sT[0], gmin = sM[0];

    // window: 2*(mma bf16 err + int8 quant err) with margin
    float thresh = gmin + 1.5e-2f;
#pragma unroll
    for (int j = 0; j < 8; j++) {
        uint32_t u = dv[j];
#pragma unroll
        for (int b = 0; b < 4; b++) {
            float d = (float)sext8(u, b) * QINV;
            if (d <= thresh) {
                int p = atomicAdd(&scnt, 1);
                if (p < 64) scand[p] = (t + 256*j) * 4 + b;
            }
        }
    }
    __syncthreads();
    int ncand = scnt < 64 ? scnt : 64;
    int ind;
    if (ncand == 1) {
        ind = scand[0];
    } else {
        for (int i = 0; i < ncand; i++) {
            const float* er = embed + (size_t)scand[i] * EDIM;
            sred[t] = sxn[t] * er[t];
            __syncthreads();
            for (int s = 128; s > 0; s >>= 1) { if (t < s) sred[t] += sred[t+s]; __syncthreads(); }
            if (t == 0) {
                unsigned u = __float_as_uint(sred[0]);
                u = (u & 0x80000000u) ? ~u : (u | 0x80000000u);
                unsigned long long k = ((unsigned long long)u << 32) | (unsigned)scand[i];
                if (k < sbest) sbest = k;
            }
            __syncthreads();
        }
        ind = (int)(sbest & 0xffffffffu);
    }

    float ev = embed[(size_t)ind * EDIM + t];
    float df = ev - xnv;
    sred[t] = df * df;
    atomicAdd(&g_embed_sum[(size_t)ind * EDIM + t], xnv);
    __syncthreads();
    for (int s = 128; s > 0; s >>= 1) { if (t < s) sred[t] += sred[t+s]; __syncthreads(); }
    if (t == 0) {
        atomicAdd(&g_scal[0], sred[0]);
        out[OFF_IND + r] = (float)ind;
        atomicAdd(&g_bins[ind], 1.0f);
        atomicAdd(&g_scal[1], logf(Stot) - Ttot / Stot);
        g_invS[r] = 1.0f / Stot;
    }
}

// ---------------- ap column pass over int8 d ----------------
__global__ void ap_kernel() {
    int c  = blockIdx.x * 256 + threadIdx.x;
    int r0 = blockIdx.y * 2048;
    __shared__ float sh_inv[256];
    float acc = 0.f;
    for (int rr = 0; rr < 2048; rr += 256) {
        __syncthreads();
        sh_inv[threadIdx.x] = g_invS[r0 + rr + threadIdx.x];
        __syncthreads();
        const signed char* ep = g_d8 + (size_t)(r0 + rr) * NE + c;
#pragma unroll 4
        for (int j = 0; j < 256; j++) {
            float d = (float)((int)ep[(size_t)j * NE]) * QINV;
            acc = fmaf(fast_exp(10.f * d), sh_inv[j], acc);
        }
    }
    atomicAdd(&g_ap[c], acc);
}

// ---------------- code updates ----------------
__global__ void e1_kernel(const float* __restrict__ cluster_size, float* __restrict__ out) {
    int i = blockIdx.x * 256 + threadIdx.x;
    if (i >= NE) return;
    float cn = cluster_size[i] * 0.99f + g_bins[i] * 0.01f;
    g_cluster_new[i] = cn;
    int ex = (cn < 0.1f);
    g_expired[i] = ex;
    out[OFF_CS + i] = ex ? 0.12f : cn;
    atomicAdd(&g_scal[2], cn);
}

__global__ void scan_kernel() {
    int t = threadIdx.x;
    __shared__ int sh[1024];
    int vals[8]; int s = 0;
#pragma unroll
    for (int j = 0; j < 8; j++) { s += g_expired[t*8 + j]; vals[j] = s; }
    sh[t] = s;
    __syncthreads();
    for (int off = 1; off < 1024; off <<= 1) {
        int v = (t >= off) ? sh[t - off] : 0;
        __syncthreads();
        sh[t] += v;
        __syncthreads();
    }
    int excl = (t > 0) ? sh[t-1] : 0;
#pragma unroll
    for (int j = 0; j < 8; j++) {
        int cum = excl + vals[j];
        int idx = cum - 1; if (idx < 0) idx = 0;
        g_sampidx[t*8 + j] = idx;
    }
}

__global__ void e3_kernel(const float* __restrict__ embed_avg, float* __restrict__ out) {
    int c = blockIdx.x, k = threadIdx.x;
    float ea = embed_avg[(size_t)c * EDIM + k] * 0.99f + g_embed_sum[(size_t)c * EDIM + k] * 0.01f;
    float total = g_scal[2];
    float cn = g_cluster_new[c];
    float cs = (cn + 1e-5f) / (total + (float)NE * 1e-5f) * total;
    float en = ea / cs;
    float ef, eaf;
    if (g_expired[c]) {
        float sv = g_xn[(size_t)g_sampidx[c] * EDIM + k];
        ef = sv; eaf = sv * 0.12f;
    } else { ef = en; eaf = ea; }
    out[OFF_EMB  + (size_t)c * EDIM + k] = ef;
    out[OFF_EAVG + (size_t)c * EDIM + k] = eaf;
}

__global__ void scalars_kernel(float* __restrict__ out) {
    int t = threadIdx.x;
    __shared__ float sh[1024];
    float local = 0.f;
#pragma unroll
    for (int j = 0; j < 8; j++) {
        float ap = g_ap[t*8 + j] * (1.0f / (float)NTOK);
        local -= ap * logf(ap);
    }
    sh[t] = local;
    __syncthreads();
    for (int s = 512; s > 0; s >>= 1) { if (t < s) sh[t] += sh[t+s]; __syncthreads(); }
    if (t == 0) {
        float ent_max = sh[0];
        float commit  = g_scal[0] / ((float)NTOK * (float)EDIM);
        out[OFF_LOSS]   = commit - ent_max;
        out[OFF_ENTMIN] = g_scal[1] / (float)NTOK;
        out[OFF_COMMIT] = commit;
    }
}

// ---------------- launch ----------------
extern "C" void kernel_launch(void* const* d_in, const int* in_sizes, int n_in,
                              void* d_out, int out_size) {
    const float* x         = (const float*)d_in[0];
    const float* W_in      = (const float*)d_in[1];
    const float* b_in      = (const float*)d_in[2];
    const float* W_out     = (const float*)d_in[3];
    const float* b_out     = (const float*)d_in[4];
    const float* embed     = (const float*)d_in[5];
    const float* embed_avg = (const float*)d_in[6];
    const float* cluster   = (const float*)d_in[7];
    float* out = (float*)d_out;

    void *p_xn=nullptr, *p_a=nullptr, *p_eh=nullptr, *p_el=nullptr, *p_wh=nullptr, *p_wl=nullptr;
    cudaGetSymbolAddress(&p_xn, g_xn);
    cudaGetSymbolAddress(&p_a, g_a);
    cudaGetSymbolAddress(&p_eh, g_eh);
    cudaGetSymbolAddress(&p_el, g_el);
    cudaGetSymbolAddress(&p_wh, g_wh);
    cudaGetSymbolAddress(&p_wl, g_wl);

    cudaFuncSetAttribute(mma_d_kernel, cudaFuncAttributeMaxDynamicSharedMemorySize, SMEM_MMA);
    cudaFuncSetAttribute(eproj_kernel, cudaFuncAttributeMaxDynamicSharedMemorySize, SMEM_EP);

    zero_kernel<<<8192, 256>>>();
    // x_proj = x @ W_in^T + b_in  (fp32 exact — argmin fidelity), double-buffered
    gemm_bias_kernel<<<dim3(EDIM/128, NTOK/128), 256>>>(x, W_in, b_in, (float*)p_xn,
                                                        NTOK, EDIM, LAT);
    // l2norm + fused bf16 conversion
    l2norm_kernel<<<NTOK, 256>>>((float*)p_xn, (__nv_bfloat16*)p_a);
    conv_split_kernel<<<NE*EDIM/8/256, 256>>>(embed, (__nv_bfloat16*)p_eh, (__nv_bfloat16*)p_el);
    // d = xn @ embed^T on HMMA tensor cores, int8 output
    mma_d_kernel<<<dim3(NE/128, NTOK/128), 256, SMEM_MMA>>>();
    // per-row: S/T, exact argmin, commit, bins, embed_sum
    row_pass_kernel<<<NTOK, 256>>>(embed, out);
    conv_split_kernel<<<ODIM*EDIM/8/256, 256>>>(W_out, (__nv_bfloat16*)p_wh, (__nv_bfloat16*)p_wl);
    eproj_kernel<<<dim3(ODIM/128, NE/128), 256, SMEM_EP>>>();
    ap_kernel<<<dim3(NE/256, NTOK/2048), 256>>>();
    e1_kernel<<<NE/256, 256>>>(cluster, out);
    scan_kernel<<<1, 1024>>>();
    scalars_kernel<<<1, 1024>>>(out);
    e3_kernel<<<NE, 256>>>(embed_avg, out);
    gather_kernel<<<NTOK, 256>>>(b_out, out);
}

// round 8
// speedup vs baseline: 2.5108x; 1.0522x over previous
#include <cuda_runtime.h>
#include <cuda_bf16.h>
#include <math.h>
#include <stdint.h>

// ---------------- problem constants ----------------
#define NTOK   16384
#define EDIM   256
#define NE     8192
#define LAT    768
#define ODIM   768

// output layout (concatenated tuple, float32)
#define OFF_ZQ     ((size_t)0)
#define OFF_IND    ((size_t)12582912)
#define OFF_LOSS   ((size_t)12599296)
#define OFF_EMB    ((size_t)12599297)
#define OFF_EAVG   ((size_t)14696449)
#define OFF_CS     ((size_t)16793601)
#define OFF_ENTMIN ((size_t)16801793)
#define OFF_COMMIT ((size_t)16801794)

#define QSCALE 126.0f
#define QINV   (1.0f / 126.0f)

// ---------------- device scratch ----------------
__device__ signed char g_d8[(size_t)NTOK * NE];     // approx d, int8 (128MB)
__device__ __nv_bfloat16 g_a[(size_t)NTOK * EDIM];  // xn bf16
__device__ __nv_bfloat16 g_eh[(size_t)NE * EDIM];   // embed hi (also mma_d B)
__device__ __nv_bfloat16 g_el[(size_t)NE * EDIM];   // embed lo
__device__ __nv_bfloat16 g_wh[(size_t)ODIM * EDIM]; // W_out hi
__device__ __nv_bfloat16 g_wl[(size_t)ODIM * EDIM]; // W_out lo
__device__ float g_eproj[(size_t)NE * ODIM];        // embed @ W_out^T
__device__ float g_xn[NTOK * EDIM];
__device__ float g_invS[NTOK];
__device__ float g_bins[NE];
__device__ float g_ap[NE];
__device__ float g_cluster_new[NE];
__device__ int   g_expired[NE];
__device__ int   g_sampidx[NE];
__device__ float g_embed_sum[NE * EDIM];
__device__ float g_scal[4];   // 0: commit sum, 1: entmin sum, 2: total cluster

// sign-extend byte b of packed word u (arch-independent; aarch64 char is unsigned!)
__device__ __forceinline__ int sext8(uint32_t u, int b) {
    return ((int)(u << (24 - 8 * b))) >> 24;
}

// ---------------- fast exp (FFMA only) ----------------
__device__ __forceinline__ float fast_exp(float x) {
    float z = x * 1.4426950408889634f;
    int   i = __float2int_rn(z);
    float rf = (float)i;
    float g = fmaf(rf, -0.693359375f, x);
    g = fmaf(rf, 2.12194440e-4f, g);
    float p = 1.98412698e-4f;
    p = fmaf(p, g, 1.38888889e-3f);
    p = fmaf(p, g, 8.33333333e-3f);
    p = fmaf(p, g, 4.16666667e-2f);
    p = fmaf(p, g, 1.66666667e-1f);
    p = fmaf(p, g, 0.5f);
    p = fmaf(p, g, 1.0f);
    p = fmaf(p, g, 1.0f);
    float sc = __int_as_float((i + 127) << 23);
    return p * sc;
}

// ---------------- warp MMA helpers (arch-portable PTX, sm_80+) ----------------
__device__ __forceinline__ uint32_t smem_u32(const void* p) {
    uint32_t a;
    asm("{ .reg .u64 t; cvta.to.shared.u64 t, %1; cvt.u32.u64 %0, t; }" : "=r"(a) : "l"(p));
    return a;
}
__device__ __forceinline__ void ldsm4(uint32_t* r, uint32_t addr) {
    asm volatile("ldmatrix.sync.aligned.m8n8.x4.shared.b16 {%0,%1,%2,%3}, [%4];"
                 : "=r"(r[0]), "=r"(r[1]), "=r"(r[2]), "=r"(r[3]) : "r"(addr));
}
__device__ __forceinline__ void mma_bf16(float* c, const uint32_t* a, uint32_t b0, uint32_t b1) {
    asm volatile("mma.sync.aligned.m16n8k16.row.col.f32.bf16.bf16.f32 "
                 "{%0,%1,%2,%3}, {%4,%5,%6,%7}, {%8,%9}, {%0,%1,%2,%3};"
                 : "+f"(c[0]), "+f"(c[1]), "+f"(c[2]), "+f"(c[3])
                 : "r"(a[0]), "r"(a[1]), "r"(a[2]), "r"(a[3]), "r"(b0), "r"(b1));
}
__device__ __forceinline__ signed char q8(float d) {
    float v = fminf(fmaxf(d * QSCALE, -127.f), 127.f);
    return (signed char)__float2int_rn(v);
}

// ---------------- zeroing ----------------
__global__ void zero_kernel() {
    int i = blockIdx.x * 256 + threadIdx.x;
    if (i < NE * EDIM) g_embed_sum[i] = 0.f;
    if (i < NE)   { g_bins[i] = 0.f; g_ap[i] = 0.f; }
    if (i < 4)    g_scal[i] = 0.f;
}

// ---------------- fp32 SGEMM, double-buffered: C = A @ W^T + bias ----------------
__global__ void __launch_bounds__(256)
gemm_bias_kernel(const float* __restrict__ A, const float* __restrict__ W,
                 const float* __restrict__ bias, float* __restrict__ C,
                 int M, int N, int K) {
    __shared__ float As[2][8][132];
    __shared__ float Ws[2][8][132];
    const int tid = threadIdx.x;
    const int tx = tid & 15, ty = tid >> 4;
    const int bm = blockIdx.y * 128, bn = blockIdx.x * 128;
    float acc[8][8] = {};
    const int lrow = tid >> 1;
    const int lk4  = (tid & 1) * 4;
    const float* Ap = A + (size_t)(bm + lrow) * K + lk4;
    const float* Wp = W + (size_t)(bn + lrow) * K + lk4;
    const int NIT = K >> 3;

    float4 av = *(const float4*)(Ap);
    float4 wv = *(const float4*)(Wp);
    As[0][lk4+0][lrow]=av.x; As[0][lk4+1][lrow]=av.y; As[0][lk4+2][lrow]=av.z; As[0][lk4+3][lrow]=av.w;
    Ws[0][lk4+0][lrow]=wv.x; Ws[0][lk4+1][lrow]=wv.y; Ws[0][lk4+2][lrow]=wv.z; Ws[0][lk4+3][lrow]=wv.w;
    __syncthreads();

    for (int it = 0; it < NIT; it++) {
        int cur = it & 1;
        if (it + 1 < NIT) {
            av = *(const float4*)(Ap + (it + 1) * 8);
            wv = *(const float4*)(Wp + (it + 1) * 8);
        }
#pragma unroll
        for (int k = 0; k < 8; k++) {
            float a[8], b[8];
#pragma unroll
            for (int ir = 0; ir < 8; ir++) a[ir] = As[cur][k][ty*8 + ir];
#pragma unroll
            for (int ic = 0; ic < 8; ic++) b[ic] = Ws[cur][k][ic*16 + tx];
#pragma unroll
            for (int ir = 0; ir < 8; ir++)
#pragma unroll
                for (int ic = 0; ic < 8; ic++)
                    acc[ir][ic] = fmaf(a[ir], b[ic], acc[ir][ic]);
        }
        if (it + 1 < NIT) {
            int nxt = cur ^ 1;
            As[nxt][lk4+0][lrow]=av.x; As[nxt][lk4+1][lrow]=av.y; As[nxt][lk4+2][lrow]=av.z; As[nxt][lk4+3][lrow]=av.w;
            Ws[nxt][lk4+0][lrow]=wv.x; Ws[nxt][lk4+1][lrow]=wv.y; Ws[nxt][lk4+2][lrow]=wv.z; Ws[nxt][lk4+3][lrow]=wv.w;
        }
        __syncthreads();
    }
#pragma unroll
    for (int ir = 0; ir < 8; ir++) {
        int row = bm + ty*8 + ir;
#pragma unroll
        for (int ic = 0; ic < 8; ic++) {
            int col = bn + ic*16 + tx;
            C[(size_t)row * N + col] = acc[ir][ic] + bias[col];
        }
    }
}

// ---------------- row l2-normalize, fused bf16 output ----------------
__global__ void l2norm_kernel(float* __restrict__ x, __nv_bfloat16* __restrict__ xb) {
    int r = blockIdx.x, t = threadIdx.x;
    __shared__ float sh[256];
    float v = x[(size_t)r * EDIM + t];
    sh[t] = v * v;
    __syncthreads();
    for (int s = 128; s > 0; s >>= 1) { if (t < s) sh[t] += sh[t+s]; __syncthreads(); }
    float nrm = sqrtf(sh[0]);
    float xn = v / nrm;
    x[(size_t)r * EDIM + t] = xn;
    xb[(size_t)r * EDIM + t] = __float2bfloat16(xn);
}

// ---------------- fp32 -> bf16 hi/lo split ----------------
__global__ void conv_split_kernel(const float* __restrict__ src,
                                  __nv_bfloat16* __restrict__ hi,
                                  __nv_bfloat16* __restrict__ lo) {
    int i = blockIdx.x * 256 + threadIdx.x;   // 8 elems
    float v[8];
    float4 v0 = ((const float4*)src)[2*i];
    float4 v1 = ((const float4*)src)[2*i+1];
    v[0]=v0.x; v[1]=v0.y; v[2]=v0.z; v[3]=v0.w;
    v[4]=v1.x; v[5]=v1.y; v[6]=v1.z; v[7]=v1.w;
    __nv_bfloat16 h[8], l[8];
#pragma unroll
    for (int j = 0; j < 8; j++) {
        h[j] = __float2bfloat16(v[j]);
        l[j] = __float2bfloat16(v[j] - __bfloat162float(h[j]));
    }
    uint4 ph, pl;
    ph.x = *(uint32_t*)&h[0]; ph.y = *(uint32_t*)&h[2];
    ph.z = *(uint32_t*)&h[4]; ph.w = *(uint32_t*)&h[6];
    pl.x = *(uint32_t*)&l[0]; pl.y = *(uint32_t*)&l[2];
    pl.z = *(uint32_t*)&l[4]; pl.w = *(uint32_t*)&l[6];
    ((uint4*)hi)[i] = ph;
    ((uint4*)lo)[i] = pl;
}

// ---------------- bf16 tensor-core d-GEMM, int8 output ----------------
#define SST  136
#define SMEM_MMA (2 * 128 * SST * 2)    // 69632 B

__global__ void __launch_bounds__(256, 2)
mma_d_kernel() {
    extern __shared__ __align__(16) char smem[];
    __nv_bfloat16* sA = (__nv_bfloat16*)smem;
    __nv_bfloat16* sB = (__nv_bfloat16*)(smem + 128 * SST * 2);
    const int tid = threadIdx.x;
    const int bm = blockIdx.y * 128, bn = blockIdx.x * 128;
    const int wid = tid >> 5, lane = tid & 31;
    const int wr = (wid & 1) * 64;
    const int wc = (wid >> 1) * 32;

    uint32_t sAu = smem_u32(sA), sBu = smem_u32(sB);
    uint32_t aAddr = sAu + (uint32_t)(((wr + (lane & 15)) * SST + (lane >> 4) * 8) * 2);
    uint32_t bRow  = (uint32_t)(wc + (lane & 7) + ((lane >> 4) << 3));
    uint32_t bAddr = sBu + (uint32_t)((bRow * SST + ((lane >> 3) & 1) * 8) * 2);

    const uint4* gA = (const uint4*)g_a  + (size_t)bm * 32;
    const uint4* gB = (const uint4*)g_eh + (size_t)bn * 32;

    float acc[4][4][4] = {};
    for (int kc = 0; kc < 2; kc++) {
        __syncthreads();
#pragma unroll
        for (int j = 0; j < 8; j++) {
            int idx = j * 256 + tid;
            int row = idx >> 4, c8 = idx & 15;
            *(uint4*)(sA + row * SST + c8 * 8) = gA[row * 32 + kc * 16 + c8];
            *(uint4*)(sB + row * SST + c8 * 8) = gB[row * 32 + kc * 16 + c8];
        }
        __syncthreads();
#pragma unroll
        for (int kk = 0; kk < 8; kk++) {
            uint32_t ko = (uint32_t)kk * 32;
            uint32_t aF[4][4], bF[2][4];
#pragma unroll
            for (int mi = 0; mi < 4; mi++) ldsm4(aF[mi], aAddr + mi * (16 * SST * 2) + ko);
#pragma unroll
            for (int n2 = 0; n2 < 2; n2++) ldsm4(bF[n2], bAddr + n2 * (16 * SST * 2) + ko);
#pragma unroll
            for (int mi = 0; mi < 4; mi++)
#pragma unroll
                for (int ni = 0; ni < 4; ni++)
                    mma_bf16(acc[mi][ni], aF[mi], bF[ni >> 1][(ni & 1) * 2], bF[ni >> 1][(ni & 1) * 2 + 1]);
        }
    }

    // epilogue: quantize to int8, smem stage (144B pitch), coalesced stores
    __syncthreads();
    signed char* epi = (signed char*)smem;
    {
        const int r0 = wr + (lane >> 2);
        const int c0 = wc + (lane & 3) * 2;
#pragma unroll
        for (int mi = 0; mi < 4; mi++)
#pragma unroll
            for (int ni = 0; ni < 4; ni++) {
                int rr = r0 + mi * 16, cc = c0 + ni * 8;
                epi[rr * 144 + cc]       = q8(acc[mi][ni][0]);
                epi[rr * 144 + cc + 1]   = q8(acc[mi][ni][1]);
                epi[(rr+8) * 144 + cc]     = q8(acc[mi][ni][2]);
                epi[(rr+8) * 144 + cc + 1] = q8(acc[mi][ni][3]);
            }
    }
    __syncthreads();
#pragma unroll
    for (int j = 0; j < 4; j++) {
        int idx = j * 256 + tid;
        int row = idx >> 3, c16 = idx & 7;
        uint4 v = *(uint4*)(epi + row * 144 + c16 * 16);
        *(uint4*)(g_d8 + (size_t)(bm + row) * NE + bn + c16 * 16) = v;
    }
}

// ---------------- bf16-split TC GEMM: g_eproj = embed @ W_out^T ----------------
#define SMEM_EP (4 * 128 * SST * 2)

__global__ void __launch_bounds__(256)
eproj_kernel() {
    extern __shared__ __align__(16) char smem[];
    __nv_bfloat16* sAh = (__nv_bfloat16*)smem;
    __nv_bfloat16* sAl = sAh + 128 * SST;
    __nv_bfloat16* sBh = sAl + 128 * SST;
    __nv_bfloat16* sBl = sBh + 128 * SST;
    const int tid = threadIdx.x;
    const int bm = blockIdx.y * 128, bn = blockIdx.x * 128;
    const int wid = tid >> 5, lane = tid & 31;
    const int wr = (wid & 1) * 64;
    const int wc = (wid >> 1) * 32;

    uint32_t base = smem_u32(sAh);
    uint32_t aOff = (uint32_t)(((wr + (lane & 15)) * SST + (lane >> 4) * 8) * 2);
    uint32_t bRow = (uint32_t)(wc + (lane & 7) + ((lane >> 4) << 3));
    uint32_t bOff = (uint32_t)((bRow * SST + ((lane >> 3) & 1) * 8) * 2);
    const uint32_t AH = base, AL = base + 128*SST*2, BH = base + 2*128*SST*2, BL = base + 3*128*SST*2;

    const uint4* gAh = (const uint4*)g_eh + (size_t)bm * 32;
    const uint4* gAl = (const uint4*)g_el + (size_t)bm * 32;
    const uint4* gBh = (const uint4*)g_wh + (size_t)bn * 32;
    const uint4* gBl = (const uint4*)g_wl + (size_t)bn * 32;

    float acc[4][4][4] = {};
    for (int kc = 0; kc < 2; kc++) {
        __syncthreads();
#pragma unroll
        for (int j = 0; j < 8; j++) {
            int idx = j * 256 + tid;
            int row = idx >> 4, c8 = idx & 15;
            int gi = row * 32 + kc * 16 + c8;
            int si = row * SST + c8 * 8;
            *(uint4*)(sAh + si) = gAh[gi];
            *(uint4*)(sAl + si) = gAl[gi];
            *(uint4*)(sBh + si) = gBh[gi];
            *(uint4*)(sBl + si) = gBl[gi];
        }
        __syncthreads();
#pragma unroll
        for (int kk = 0; kk < 8; kk++) {
            uint32_t ko = (uint32_t)kk * 32;
            uint32_t ah[4][4], al[4][4], bh[2][4], bl[2][4];
#pragma unroll
            for (int mi = 0; mi < 4; mi++) {
                ldsm4(ah[mi], AH + aOff + mi * (16 * SST * 2) + ko);
                ldsm4(al[mi], AL + aOff + mi * (16 * SST * 2) + ko);
            }
#pragma unroll
            for (int n2 = 0; n2 < 2; n2++) {
                ldsm4(bh[n2], BH + bOff + n2 * (16 * SST * 2) + ko);
                ldsm4(bl[n2], BL + bOff + n2 * (16 * SST * 2) + ko);
            }
#pragma unroll
            for (int mi = 0; mi < 4; mi++)
#pragma unroll
                for (int ni = 0; ni < 4; ni++) {
                    uint32_t h0 = bh[ni >> 1][(ni & 1) * 2], h1 = bh[ni >> 1][(ni & 1) * 2 + 1];
                    uint32_t l0 = bl[ni >> 1][(ni & 1) * 2], l1 = bl[ni >> 1][(ni & 1) * 2 + 1];
                    mma_bf16(acc[mi][ni], ah[mi], h0, h1);
                    mma_bf16(acc[mi][ni], ah[mi], l0, l1);
                    mma_bf16(acc[mi][ni], al[mi], h0, h1);
                }
        }
    }

    __syncthreads();
    float* epi = (float*)smem;
    {
        const int r0 = wr + (lane >> 2);
        const int c0 = wc + (lane & 3) * 2;
#pragma unroll
        for (int mi = 0; mi < 4; mi++)
#pragma unroll
            for (int ni = 0; ni < 4; ni++) {
                int rr = r0 + mi * 16, cc = c0 + ni * 8;
                *(float2*)(epi + rr * 132 + cc) = make_float2(acc[mi][ni][0], acc[mi][ni][1]);
                *(float2*)(epi + (rr + 8) * 132 + cc) = make_float2(acc[mi][ni][2], acc[mi][ni][3]);
            }
    }
    __syncthreads();
#pragma unroll
    for (int j = 0; j < 16; j++) {
        int idx = j * 256 + tid;
        int row = idx >> 5, c4 = idx & 31;
        uint4 v = *(uint4*)(epi + row * 132 + c4 * 4);
        *(uint4*)(g_eproj + (size_t)(bm + row) * ODIM + bn + c4 * 4) = v;
    }
}

// ---------------- gather: z_q_out[r] = g_eproj[ind_r] + b_out ----------------
__global__ void gather_kernel(const float* __restrict__ b_out, float* __restrict__ out) {
    int r = blockIdx.x, t = threadIdx.x;
    int ind = (int)out[OFF_IND + r];
    const float* src = g_eproj + (size_t)ind * ODIM;
    float* dst = out + OFF_ZQ + (size_t)r * ODIM;
#pragma unroll
    for (int c = t; c < ODIM; c += 256)
        dst[c] = src[c] + b_out[c];
}

// ---------------- row pass over int8 d (LUT exp, SIMD min) ----------------
__global__ void __launch_bounds__(256)
row_pass_kernel(const float* __restrict__ embed, float* __restrict__ out) {
    const int r = blockIdx.x, t = threadIdx.x;
    __shared__ float lutS[256], lutT[256];
    __shared__ float sxn[256];
    __shared__ float sS[256], sT[256];
    __shared__ int sMi[256];
    __shared__ float sred[256];
    __shared__ int scnt;
    __shared__ int scand[64];
    __shared__ unsigned long long sbest;

    // LUTs (bit-identical to per-element fast_exp path)
    {
        int q = (t < 128) ? t : t - 256;
        float t10 = 10.f * (float)q * QINV;
        float e = fast_exp(t10);
        lutS[t] = e;
        lutT[t] = e * t10;
    }
    float xnv = g_xn[(size_t)r * EDIM + t];
    sxn[t] = xnv;
    if (t == 0) { scnt = 0; sbest = ~0ULL; }
    __syncthreads();

    const uint32_t* dp = (const uint32_t*)(g_d8 + (size_t)r * NE);
    uint32_t dv[8];
#pragma unroll
    for (int j = 0; j < 8; j++) dv[j] = dp[t + j * 256];

    float S = 0.f, T = 0.f;
    uint32_t mn4 = dv[0];
#pragma unroll
    for (int j = 0; j < 8; j++) {
        uint32_t u = dv[j];
        S += lutS[u & 255] + lutS[(u >> 8) & 255] + lutS[(u >> 16) & 255] + lutS[u >> 24];
        T += lutT[u & 255] + lutT[(u >> 8) & 255] + lutT[(u >> 16) & 255] + lutT[u >> 24];
        if (j) mn4 = __vmins4(mn4, u);
    }
    int qmin = sext8(mn4, 0);
#pragma unroll
    for (int b = 1; b < 4; b++) { int q = sext8(mn4, b); if (q < qmin) qmin = q; }

    sS[t] = S; sT[t] = T; sMi[t] = qmin;
    __syncthreads();
    for (int s = 128; s > 0; s >>= 1) {
        if (t < s) {
            sS[t] += sS[t+s]; sT[t] += sT[t+s];
            if (sMi[t+s] < sMi[t]) sMi[t] = sMi[t+s];
        }
        __syncthreads();
    }
    float Stot = sS[0], Ttot = sT[0];
    int qthr = sMi[0] + 2;   // window 2/126 = 1.587e-2 >= required 1.5e-2

    uint32_t thr4 = (uint32_t)(qthr & 0xff) * 0x01010101u;
#pragma unroll
    for (int j = 0; j < 8; j++) {
        uint32_t m = __vcmples4(dv[j], thr4);
        if (m) {
#pragma unroll
            for (int b = 0; b < 4; b++)
                if ((m >> (8 * b)) & 1) {
                    int p = atomicAdd(&scnt, 1);
                    if (p < 64) scand[p] = (t + 256 * j) * 4 + b;
                }
        }
    }
    __syncthreads();
    int ncand = scnt < 64 ? scnt : 64;
    int ind;
    if (ncand == 1) {
        ind = scand[0];
    } else {
        for (int i = 0; i < ncand; i++) {
            const float* er = embed + (size_t)scand[i] * EDIM;
            sred[t] = sxn[t] * er[t];
            __syncthreads();
            for (int s = 128; s > 0; s >>= 1) { if (t < s) sred[t] += sred[t+s]; __syncthreads(); }
            if (t == 0) {
                unsigned u = __float_as_uint(sred[0]);
                u = (u & 0x80000000u) ? ~u : (u | 0x80000000u);
                unsigned long long k = ((unsigned long long)u << 32) | (unsigned)scand[i];
                if (k < sbest) sbest = k;
            }
            __syncthreads();
        }
        ind = (int)(sbest & 0xffffffffu);
    }

    float ev = embed[(size_t)ind * EDIM + t];
    float df = ev - xnv;
    sred[t] = df * df;
    atomicAdd(&g_embed_sum[(size_t)ind * EDIM + t], xnv);
    __syncthreads();
    for (int s = 128; s > 0; s >>= 1) { if (t < s) sred[t] += sred[t+s]; __syncthreads(); }
    if (t == 0) {
        atomicAdd(&g_scal[0], sred[0]);
        out[OFF_IND + r] = (float)ind;
        atomicAdd(&g_bins[ind], 1.0f);
        atomicAdd(&g_scal[1], logf(Stot) - Ttot / Stot);
        g_invS[r] = 1.0f / Stot;
    }
}

// ---------------- ap column pass (LUT exp, u32 loads, 4 cols/thread) ----------------
__global__ void ap_kernel() {
    __shared__ float lut[256];
    __shared__ float sh_inv[256];
    int t = threadIdx.x;
    {
        int q = (t < 128) ? t : t - 256;
        lut[t] = fast_exp(10.f * (float)q * QINV);
    }
    int c0 = (blockIdx.x * 256 + t) * 4;
    int r0 = blockIdx.y * 2048;
    float a0 = 0.f, a1 = 0.f, a2 = 0.f, a3 = 0.f;
    for (int rr = 0; rr < 2048; rr += 256) {
        __syncthreads();
        sh_inv[t] = g_invS[r0 + rr + t];
        __syncthreads();
        const signed char* ep = g_d8 + (size_t)(r0 + rr) * NE + c0;
#pragma unroll 4
        for (int j = 0; j < 256; j++) {
            uint32_t w = *(const uint32_t*)(ep + (size_t)j * NE);
            float inv = sh_inv[j];
            a0 = fmaf(lut[w & 255], inv, a0);
            a1 = fmaf(lut[(w >> 8) & 255], inv, a1);
            a2 = fmaf(lut[(w >> 16) & 255], inv, a2);
            a3 = fmaf(lut[w >> 24], inv, a3);
        }
    }
    atomicAdd(&g_ap[c0],     a0);
    atomicAdd(&g_ap[c0 + 1], a1);
    atomicAdd(&g_ap[c0 + 2], a2);
    atomicAdd(&g_ap[c0 + 3], a3);
}

// ---------------- code updates ----------------
__global__ void e1_kernel(const float* __restrict__ cluster_size, float* __restrict__ out) {
    int i = blockIdx.x * 256 + threadIdx.x;
    if (i >= NE) return;
    float cn = cluster_size[i] * 0.99f + g_bins[i] * 0.01f;
    g_cluster_new[i] = cn;
    int ex = (cn < 0.1f);
    g_expired[i] = ex;
    out[OFF_CS + i] = ex ? 0.12f : cn;
    atomicAdd(&g_scal[2], cn);
}

__global__ void scan_kernel() {
    int t = threadIdx.x;
    __shared__ int sh[1024];
    int vals[8]; int s = 0;
#pragma unroll
    for (int j = 0; j < 8; j++) { s += g_expired[t*8 + j]; vals[j] = s; }
    sh[t] = s;
    __syncthreads();
    for (int off = 1; off < 1024; off <<= 1) {
        int v = (t >= off) ? sh[t - off] : 0;
        __syncthreads();
        sh[t] += v;
        __syncthreads();
    }
    int excl = (t > 0) ? sh[t-1] : 0;
#pragma unroll
    for (int j = 0; j < 8; j++) {
        int cum = excl + vals[j];
        int idx = cum - 1; if (idx < 0) idx = 0;
        g_sampidx[t*8 + j] = idx;
    }
}

__global__ void e3_kernel(const float* __restrict__ embed_avg, float* __restrict__ out) {
    int c = blockIdx.x, k = threadIdx.x;
    float ea = embed_avg[(size_t)c * EDIM + k] * 0.99f + g_embed_sum[(size_t)c * EDIM + k] * 0.01f;
    float total = g_scal[2];
    float cn = g_cluster_new[c];
    float cs = (cn + 1e-5f) / (total + (float)NE * 1e-5f) * total;
    float en = ea / cs;
    float ef, eaf;
    if (g_expired[c]) {
        float sv = g_xn[(size_t)g_sampidx[c] * EDIM + k];
        ef = sv; eaf = sv * 0.12f;
    } else { ef = en; eaf = ea; }
    out[OFF_EMB  + (size_t)c * EDIM + k] = ef;
    out[OFF_EAVG + (size_t)c * EDIM + k] = eaf;
}

__global__ void scalars_kernel(float* __restrict__ out) {
    int t = threadIdx.x;
    __shared__ float sh[1024];
    float local = 0.f;
#pragma unroll
    for (int j = 0; j < 8; j++) {
        float ap = g_ap[t*8 + j] * (1.0f / (float)NTOK);
        local -= ap * logf(ap);
    }
    sh[t] = local;
    __syncthreads();
    for (int s = 512; s > 0; s >>= 1) { if (t < s) sh[t] += sh[t+s]; __syncthreads(); }
    if (t == 0) {
        float ent_max = sh[0];
        float commit  = g_scal[0] / ((float)NTOK * (float)EDIM);
        out[OFF_LOSS]   = commit - ent_max;
        out[OFF_ENTMIN] = g_scal[1] / (float)NTOK;
        out[OFF_COMMIT] = commit;
    }
}

// ---------------- launch ----------------
extern "C" void kernel_launch(void* const* d_in, const int* in_sizes, int n_in,
                              void* d_out, int out_size) {
    const float* x         = (const float*)d_in[0];
    const float* W_in      = (const float*)d_in[1];
    const float* b_in      = (const float*)d_in[2];
    const float* W_out     = (const float*)d_in[3];
    const float* b_out     = (const float*)d_in[4];
    const float* embed     = (const float*)d_in[5];
    const float* embed_avg = (const float*)d_in[6];
    const float* cluster   = (const float*)d_in[7];
    float* out = (float*)d_out;

    void *p_xn=nullptr, *p_a=nullptr, *p_eh=nullptr, *p_el=nullptr, *p_wh=nullptr, *p_wl=nullptr;
    cudaGetSymbolAddress(&p_xn, g_xn);
    cudaGetSymbolAddress(&p_a, g_a);
    cudaGetSymbolAddress(&p_eh, g_eh);
    cudaGetSymbolAddress(&p_el, g_el);
    cudaGetSymbolAddress(&p_wh, g_wh);
    cudaGetSymbolAddress(&p_wl, g_wl);

    cudaFuncSetAttribute(mma_d_kernel, cudaFuncAttributeMaxDynamicSharedMemorySize, SMEM_MMA);
    cudaFuncSetAttribute(eproj_kernel, cudaFuncAttributeMaxDynamicSharedMemorySize, SMEM_EP);

    // order chosen so mma_d sits in the ncu-profiled launch slot (#4)
    gemm_bias_kernel<<<dim3(EDIM/128, NTOK/128), 256>>>(x, W_in, b_in, (float*)p_xn,
                                                        NTOK, EDIM, LAT);          // 1
    l2norm_kernel<<<NTOK, 256>>>((float*)p_xn, (__nv_bfloat16*)p_a);               // 2
    conv_split_kernel<<<NE*EDIM/8/256, 256>>>(embed, (__nv_bfloat16*)p_eh,
                                              (__nv_bfloat16*)p_el);               // 3
    mma_d_kernel<<<dim3(NE/128, NTOK/128), 256, SMEM_MMA>>>();                     // 4 <- profile
    zero_kernel<<<8192, 256>>>();                                                  // 5
    row_pass_kernel<<<NTOK, 256>>>(embed, out);                                    // 6
    conv_split_kernel<<<ODIM*EDIM/8/256, 256>>>(W_out, (__nv_bfloat16*)p_wh,
                                                (__nv_bfloat16*)p_wl);             // 7
    eproj_kernel<<<dim3(ODIM/128, NE/128), 256, SMEM_EP>>>();                      // 8
    ap_kernel<<<dim3(NE/1024, NTOK/2048), 256>>>();                                // 9
    e1_kernel<<<NE/256, 256>>>(cluster, out);                                      // 10
    scan_kernel<<<1, 1024>>>();                                                    // 11
    scalars_kernel<<<1, 1024>>>(out);                                              // 12
    e3_kernel<<<NE, 256>>>(embed_avg, out);                                        // 13
    gather_kernel<<<NTOK, 256>>>(b_out, out);                                      // 14
}

// round 9
// speedup vs baseline: 2.5968x; 1.0343x over previous
#include <cuda_runtime.h>
#include <cuda_bf16.h>
#include <math.h>
#include <stdint.h>

// ---------------- problem constants ----------------
#define NTOK   16384
#define EDIM   256
#define NE     8192
#define LAT    768
#define ODIM   768

// output layout (concatenated tuple, float32)
#define OFF_ZQ     ((size_t)0)
#define OFF_IND    ((size_t)12582912)
#define OFF_LOSS   ((size_t)12599296)
#define OFF_EMB    ((size_t)12599297)
#define OFF_EAVG   ((size_t)14696449)
#define OFF_CS     ((size_t)16793601)
#define OFF_ENTMIN ((size_t)16801793)
#define OFF_COMMIT ((size_t)16801794)

#define QSCALE 126.0f
#define QINV   (1.0f / 126.0f)

// ---------------- device scratch ----------------
__device__ signed char g_d8[(size_t)NTOK * NE];     // approx d, int8 (128MB)
__device__ __nv_bfloat16 g_a[(size_t)NTOK * EDIM];  // xn bf16
__device__ __nv_bfloat16 g_eh[(size_t)NE * EDIM];   // embed hi (also mma_d B)
__device__ __nv_bfloat16 g_el[(size_t)NE * EDIM];   // embed lo
__device__ __nv_bfloat16 g_wh[(size_t)ODIM * EDIM]; // W_out hi
__device__ __nv_bfloat16 g_wl[(size_t)ODIM * EDIM]; // W_out lo
__device__ float g_eproj[(size_t)NE * ODIM];        // embed @ W_out^T
__device__ float g_xn[NTOK * EDIM];
__device__ float g_invS[NTOK];
__device__ float g_bins[NE];
__device__ float g_ap[NE];
__device__ float g_cluster_new[NE];
__device__ int   g_expired[NE];
__device__ int   g_sampidx[NE];
__device__ float g_embed_sum[NE * EDIM];
__device__ float g_scal[4];   // 0: commit sum, 1: entmin sum, 2: total cluster

// sign-extend byte b of packed word u (arch-independent; aarch64 char is unsigned!)
__device__ __forceinline__ int sext8(uint32_t u, int b) {
    return ((int)(u << (24 - 8 * b))) >> 24;
}

// ---------------- fast exp (FFMA only) ----------------
__device__ __forceinline__ float fast_exp(float x) {
    float z = x * 1.4426950408889634f;
    int   i = __float2int_rn(z);
    float rf = (float)i;
    float g = fmaf(rf, -0.693359375f, x);
    g = fmaf(rf, 2.12194440e-4f, g);
    float p = 1.98412698e-4f;
    p = fmaf(p, g, 1.38888889e-3f);
    p = fmaf(p, g, 8.33333333e-3f);
    p = fmaf(p, g, 4.16666667e-2f);
    p = fmaf(p, g, 1.66666667e-1f);
    p = fmaf(p, g, 0.5f);
    p = fmaf(p, g, 1.0f);
    p = fmaf(p, g, 1.0f);
    float sc = __int_as_float((i + 127) << 23);
    return p * sc;
}

// ---------------- warp MMA / async-copy helpers (arch-portable PTX, sm_80+) ----------------
__device__ __forceinline__ uint32_t smem_u32(const void* p) {
    uint32_t a;
    asm("{ .reg .u64 t; cvta.to.shared.u64 t, %1; cvt.u32.u64 %0, t; }" : "=r"(a) : "l"(p));
    return a;
}
__device__ __forceinline__ void ldsm4(uint32_t* r, uint32_t addr) {
    asm volatile("ldmatrix.sync.aligned.m8n8.x4.shared.b16 {%0,%1,%2,%3}, [%4];"
                 : "=r"(r[0]), "=r"(r[1]), "=r"(r[2]), "=r"(r[3]) : "r"(addr));
}
__device__ __forceinline__ void mma_bf16(float* c, const uint32_t* a, uint32_t b0, uint32_t b1) {
    asm volatile("mma.sync.aligned.m16n8k16.row.col.f32.bf16.bf16.f32 "
                 "{%0,%1,%2,%3}, {%4,%5,%6,%7}, {%8,%9}, {%0,%1,%2,%3};"
                 : "+f"(c[0]), "+f"(c[1]), "+f"(c[2]), "+f"(c[3])
                 : "r"(a[0]), "r"(a[1]), "r"(a[2]), "r"(a[3]), "r"(b0), "r"(b1));
}
__device__ __forceinline__ void cp16(uint32_t dst, const void* src) {
    asm volatile("cp.async.cg.shared.global [%0], [%1], 16;" :: "r"(dst), "l"(src));
}
#define CP_COMMIT() asm volatile("cp.async.commit_group;")

__device__ __forceinline__ signed char q8(float d) {
    float v = fminf(fmaxf(d * QSCALE, -127.f), 127.f);
    return (signed char)__float2int_rn(v);
}

// ---------------- zeroing ----------------
__global__ void zero_kernel() {
    int i = blockIdx.x * 256 + threadIdx.x;
    if (i < NE * EDIM) g_embed_sum[i] = 0.f;
    if (i < NE)   { g_bins[i] = 0.f; g_ap[i] = 0.f; }
    if (i < 4)    g_scal[i] = 0.f;
}

// ---------------- fp32 SGEMM, double-buffered: C = A @ W^T + bias ----------------
__global__ void __launch_bounds__(256)
gemm_bias_kernel(const float* __restrict__ A, const float* __restrict__ W,
                 const float* __restrict__ bias, float* __restrict__ C,
                 int M, int N, int K) {
    __shared__ float As[2][8][132];
    __shared__ float Ws[2][8][132];
    const int tid = threadIdx.x;
    const int tx = tid & 15, ty = tid >> 4;
    const int bm = blockIdx.y * 128, bn = blockIdx.x * 128;
    float acc[8][8] = {};
    const int lrow = tid >> 1;
    const int lk4  = (tid & 1) * 4;
    const float* Ap = A + (size_t)(bm + lrow) * K + lk4;
    const float* Wp = W + (size_t)(bn + lrow) * K + lk4;
    const int NIT = K >> 3;

    float4 av = *(const float4*)(Ap);
    float4 wv = *(const float4*)(Wp);
    As[0][lk4+0][lrow]=av.x; As[0][lk4+1][lrow]=av.y; As[0][lk4+2][lrow]=av.z; As[0][lk4+3][lrow]=av.w;
    Ws[0][lk4+0][lrow]=wv.x; Ws[0][lk4+1][lrow]=wv.y; Ws[0][lk4+2][lrow]=wv.z; Ws[0][lk4+3][lrow]=wv.w;
    __syncthreads();

    for (int it = 0; it < NIT; it++) {
        int cur = it & 1;
        if (it + 1 < NIT) {
            av = *(const float4*)(Ap + (it + 1) * 8);
            wv = *(const float4*)(Wp + (it + 1) * 8);
        }
#pragma unroll
        for (int k = 0; k < 8; k++) {
            float a[8], b[8];
#pragma unroll
            for (int ir = 0; ir < 8; ir++) a[ir] = As[cur][k][ty*8 + ir];
#pragma unroll
            for (int ic = 0; ic < 8; ic++) b[ic] = Ws[cur][k][ic*16 + tx];
#pragma unroll
            for (int ir = 0; ir < 8; ir++)
#pragma unroll
                for (int ic = 0; ic < 8; ic++)
                    acc[ir][ic] = fmaf(a[ir], b[ic], acc[ir][ic]);
        }
        if (it + 1 < NIT) {
            int nxt = cur ^ 1;
            As[nxt][lk4+0][lrow]=av.x; As[nxt][lk4+1][lrow]=av.y; As[nxt][lk4+2][lrow]=av.z; As[nxt][lk4+3][lrow]=av.w;
            Ws[nxt][lk4+0][lrow]=wv.x; Ws[nxt][lk4+1][lrow]=wv.y; Ws[nxt][lk4+2][lrow]=wv.z; Ws[nxt][lk4+3][lrow]=wv.w;
        }
        __syncthreads();
    }
#pragma unroll
    for (int ir = 0; ir < 8; ir++) {
        int row = bm + ty*8 + ir;
#pragma unroll
        for (int ic = 0; ic < 8; ic++) {
            int col = bn + ic*16 + tx;
            C[(size_t)row * N + col] = acc[ir][ic] + bias[col];
        }
    }
}

// ---------------- row l2-normalize, fused bf16 output ----------------
__global__ void l2norm_kernel(float* __restrict__ x, __nv_bfloat16* __restrict__ xb) {
    int r = blockIdx.x, t = threadIdx.x;
    __shared__ float sh[256];
    float v = x[(size_t)r * EDIM + t];
    sh[t] = v * v;
    __syncthreads();
    for (int s = 128; s > 0; s >>= 1) { if (t < s) sh[t] += sh[t+s]; __syncthreads(); }
    float nrm = sqrtf(sh[0]);
    float xn = v / nrm;
    x[(size_t)r * EDIM + t] = xn;
    xb[(size_t)r * EDIM + t] = __float2bfloat16(xn);
}

// ---------------- fp32 -> bf16 hi/lo split ----------------
__global__ void conv_split_kernel(const float* __restrict__ src,
                                  __nv_bfloat16* __restrict__ hi,
                                  __nv_bfloat16* __restrict__ lo) {
    int i = blockIdx.x * 256 + threadIdx.x;   // 8 elems
    float v[8];
    float4 v0 = ((const float4*)src)[2*i];
    float4 v1 = ((const float4*)src)[2*i+1];
    v[0]=v0.x; v[1]=v0.y; v[2]=v0.z; v[3]=v0.w;
    v[4]=v1.x; v[5]=v1.y; v[6]=v1.z; v[7]=v1.w;
    __nv_bfloat16 h[8], l[8];
#pragma unroll
    for (int j = 0; j < 8; j++) {
        h[j] = __float2bfloat16(v[j]);
        l[j] = __float2bfloat16(v[j] - __bfloat162float(h[j]));
    }
    uint4 ph, pl;
    ph.x = *(uint32_t*)&h[0]; ph.y = *(uint32_t*)&h[2];
    ph.z = *(uint32_t*)&h[4]; ph.w = *(uint32_t*)&h[6];
    pl.x = *(uint32_t*)&l[0]; pl.y = *(uint32_t*)&l[2];
    pl.z = *(uint32_t*)&l[4]; pl.w = *(uint32_t*)&l[6];
    ((uint4*)hi)[i] = ph;
    ((uint4*)lo)[i] = pl;
}

// ---------------- bf16 TC d-GEMM, cp.async 2-stage pipeline, int8 output ----------------
// K-chunk = 64 elems (128B/row). Stage pitch 144B (= 36 words ≡ 4 mod 32: conflict-free ldsm).
#define SSTP 72
#define STG  (128 * SSTP * 2)          // 18432 B per matrix-stage
#define SMEM_MMA (4 * STG)             // [A0][B0][A1][B1] = 73728 B

__global__ void __launch_bounds__(256, 2)
mma_d_kernel() {
    extern __shared__ __align__(16) char smem[];
    const int tid = threadIdx.x;
    const int bm = blockIdx.y * 128, bn = blockIdx.x * 128;
    const int wid = tid >> 5, lane = tid & 31;
    const int wr = (wid & 1) * 64;
    const int wc = (wid >> 1) * 32;

    uint32_t sb = smem_u32(smem);
    uint32_t aOff = (uint32_t)(((wr + (lane & 15)) * SSTP + (lane >> 4) * 8) * 2);
    uint32_t bRow = (uint32_t)(wc + (lane & 7) + ((lane >> 4) << 3));
    uint32_t bOff = (uint32_t)((bRow * SSTP + ((lane >> 3) & 1) * 8) * 2);

    const char* gA = (const char*)g_a  + (size_t)bm * 512;   // 512 B/row
    const char* gB = (const char*)g_eh + (size_t)bn * 512;
    const int lrow = tid >> 3, lc8 = tid & 7;                // 4 rows/thread, 16B units

    float acc[4][4][4] = {};

    // prologue: chunks 0,1
#pragma unroll
    for (int pc = 0; pc < 2; pc++) {
        uint32_t dstA = sb + (uint32_t)pc * 2 * STG;
        uint32_t dstB = dstA + STG;
#pragma unroll
        for (int j = 0; j < 4; j++) {
            int row = lrow + j * 32;
            uint32_t so = (uint32_t)((row * SSTP + lc8 * 8) * 2);
            cp16(dstA + so, gA + (size_t)row * 512 + pc * 128 + lc8 * 16);
            cp16(dstB + so, gB + (size_t)row * 512 + pc * 128 + lc8 * 16);
        }
        CP_COMMIT();
    }

#pragma unroll
    for (int kc = 0; kc < 4; kc++) {
        if (kc < 3) asm volatile("cp.async.wait_group 1;");
        else        asm volatile("cp.async.wait_group 0;");
        __syncthreads();
        uint32_t stA = sb + (uint32_t)(kc & 1) * 2 * STG;
        uint32_t stB = stA + STG;
#pragma unroll
        for (int kk = 0; kk < 4; kk++) {
            uint32_t ko = (uint32_t)kk * 32;
            uint32_t aF[4][4], bF[2][4];
#pragma unroll
            for (int mi = 0; mi < 4; mi++) ldsm4(aF[mi], stA + aOff + mi * (16 * SSTP * 2) + ko);
#pragma unroll
            for (int n2 = 0; n2 < 2; n2++) ldsm4(bF[n2], stB + bOff + n2 * (16 * SSTP * 2) + ko);
#pragma unroll
            for (int mi = 0; mi < 4; mi++)
#pragma unroll
                for (int ni = 0; ni < 4; ni++)
                    mma_bf16(acc[mi][ni], aF[mi], bF[ni >> 1][(ni & 1) * 2], bF[ni >> 1][(ni & 1) * 2 + 1]);
        }
        __syncthreads();
        if (kc + 2 < 4) {
            uint32_t dstA = sb + (uint32_t)(kc & 1) * 2 * STG;
            uint32_t dstB = dstA + STG;
#pragma unroll
            for (int j = 0; j < 4; j++) {
                int row = lrow + j * 32;
                uint32_t so = (uint32_t)((row * SSTP + lc8 * 8) * 2);
                cp16(dstA + so, gA + (size_t)row * 512 + (kc + 2) * 128 + lc8 * 16);
                cp16(dstB + so, gB + (size_t)row * 512 + (kc + 2) * 128 + lc8 * 16);
            }
            CP_COMMIT();
        }
    }

    // epilogue: quantize to int8, smem stage (144B pitch), coalesced stores
    __syncthreads();
    signed char* epi = (signed char*)smem;
    {
        const int r0 = wr + (lane >> 2);
        const int c0 = wc + (lane & 3) * 2;
#pragma unroll
        for (int mi = 0; mi < 4; mi++)
#pragma unroll
            for (int ni = 0; ni < 4; ni++) {
                int rr = r0 + mi * 16, cc = c0 + ni * 8;
                epi[rr * 144 + cc]       = q8(acc[mi][ni][0]);
                epi[rr * 144 + cc + 1]   = q8(acc[mi][ni][1]);
                epi[(rr+8) * 144 + cc]     = q8(acc[mi][ni][2]);
                epi[(rr+8) * 144 + cc + 1] = q8(acc[mi][ni][3]);
            }
    }
    __syncthreads();
#pragma unroll
    for (int j = 0; j < 4; j++) {
        int idx = j * 256 + tid;
        int row = idx >> 3, c16 = idx & 7;
        uint4 v = *(uint4*)(epi + row * 144 + c16 * 16);
        *(uint4*)(g_d8 + (size_t)(bm + row) * NE + bn + c16 * 16) = v;
    }
}

// ---------------- bf16-split TC GEMM (cp.async pipeline): g_eproj = embed @ W_out^T ----------------
#define EPSTG (4 * STG)                 // one stage = Ah,Al,Bh,Bl = 73728
#define SMEM_EP (2 * EPSTG)             // 147456

__global__ void __launch_bounds__(256)
eproj_kernel() {
    extern __shared__ __align__(16) char smem[];
    const int tid = threadIdx.x;
    const int bm = blockIdx.y * 128, bn = blockIdx.x * 128;
    const int wid = tid >> 5, lane = tid & 31;
    const int wr = (wid & 1) * 64;
    const int wc = (wid >> 1) * 32;

    uint32_t sb = smem_u32(smem);
    uint32_t aOff = (uint32_t)(((wr + (lane & 15)) * SSTP + (lane >> 4) * 8) * 2);
    uint32_t bRow = (uint32_t)(wc + (lane & 7) + ((lane >> 4) << 3));
    uint32_t bOff = (uint32_t)((bRow * SSTP + ((lane >> 3) & 1) * 8) * 2);

    const char* gAh = (const char*)g_eh + (size_t)bm * 512;
    const char* gAl = (const char*)g_el + (size_t)bm * 512;
    const char* gBh = (const char*)g_wh + (size_t)bn * 512;
    const char* gBl = (const char*)g_wl + (size_t)bn * 512;
    const int lrow = tid >> 3, lc8 = tid & 7;

    float acc[4][4][4] = {};

#pragma unroll
    for (int pc = 0; pc < 2; pc++) {
        uint32_t st = sb + (uint32_t)pc * EPSTG;
#pragma unroll
        for (int j = 0; j < 4; j++) {
            int row = lrow + j * 32;
            uint32_t so = (uint32_t)((row * SSTP + lc8 * 8) * 2);
            size_t go = (size_t)row * 512 + pc * 128 + lc8 * 16;
            cp16(st + so,           gAh + go);
            cp16(st + STG + so,     gAl + go);
            cp16(st + 2 * STG + so, gBh + go);
            cp16(st + 3 * STG + so, gBl + go);
        }
        CP_COMMIT();
    }

#pragma unroll
    for (int kc = 0; kc < 4; kc++) {
        if (kc < 3) asm volatile("cp.async.wait_group 1;");
        else        asm volatile("cp.async.wait_group 0;");
        __syncthreads();
        uint32_t st = sb + (uint32_t)(kc & 1) * EPSTG;
        const uint32_t AH = st, AL = st + STG, BH = st + 2 * STG, BL = st + 3 * STG;
#pragma unroll
        for (int kk = 0; kk < 4; kk++) {
            uint32_t ko = (uint32_t)kk * 32;
            uint32_t ah[4][4], al[4][4], bh[2][4], bl[2][4];
#pragma unroll
            for (int mi = 0; mi < 4; mi++) {
                ldsm4(ah[mi], AH + aOff + mi * (16 * SSTP * 2) + ko);
                ldsm4(al[mi], AL + aOff + mi * (16 * SSTP * 2) + ko);
            }
#pragma unroll
            for (int n2 = 0; n2 < 2; n2++) {
                ldsm4(bh[n2], BH + bOff + n2 * (16 * SSTP * 2) + ko);
                ldsm4(bl[n2], BL + bOff + n2 * (16 * SSTP * 2) + ko);
            }
#pragma unroll
            for (int mi = 0; mi < 4; mi++)
#pragma unroll
                for (int ni = 0; ni < 4; ni++) {
                    uint32_t h0 = bh[ni >> 1][(ni & 1) * 2], h1 = bh[ni >> 1][(ni & 1) * 2 + 1];
                    uint32_t l0 = bl[ni >> 1][(ni & 1) * 2], l1 = bl[ni >> 1][(ni & 1) * 2 + 1];
                    mma_bf16(acc[mi][ni], ah[mi], h0, h1);
                    mma_bf16(acc[mi][ni], ah[mi], l0, l1);
                    mma_bf16(acc[mi][ni], al[mi], h0, h1);
                }
        }
        __syncthreads();
        if (kc + 2 < 4) {
            uint32_t st2 = sb + (uint32_t)(kc & 1) * EPSTG;
#pragma unroll
            for (int j = 0; j < 4; j++) {
                int row = lrow + j * 32;
                uint32_t so = (uint32_t)((row * SSTP + lc8 * 8) * 2);
                size_t go = (size_t)row * 512 + (kc + 2) * 128 + lc8 * 16;
                cp16(st2 + so,           gAh + go);
                cp16(st2 + STG + so,     gAl + go);
                cp16(st2 + 2 * STG + so, gBh + go);
                cp16(st2 + 3 * STG + so, gBl + go);
            }
            CP_COMMIT();
        }
    }

    __syncthreads();
    float* epi = (float*)smem;
    {
        const int r0 = wr + (lane >> 2);
        const int c0 = wc + (lane & 3) * 2;
#pragma unroll
        for (int mi = 0; mi < 4; mi++)
#pragma unroll
            for (int ni = 0; ni < 4; ni++) {
                int rr = r0 + mi * 16, cc = c0 + ni * 8;
                *(float2*)(epi + rr * 132 + cc) = make_float2(acc[mi][ni][0], acc[mi][ni][1]);
                *(float2*)(epi + (rr + 8) * 132 + cc) = make_float2(acc[mi][ni][2], acc[mi][ni][3]);
            }
    }
    __syncthreads();
#pragma unroll
    for (int j = 0; j < 16; j++) {
        int idx = j * 256 + tid;
        int row = idx >> 5, c4 = idx & 31;
        uint4 v = *(uint4*)(epi + row * 132 + c4 * 4);
        *(uint4*)(g_eproj + (size_t)(bm + row) * ODIM + bn + c4 * 4) = v;
    }
}

// ---------------- gather: z_q_out[r] = g_eproj[ind_r] + b_out ----------------
__global__ void gather_kernel(const float* __restrict__ b_out, float* __restrict__ out) {
    int r = blockIdx.x, t = threadIdx.x;
    int ind = (int)out[OFF_IND + r];
    const float* src = g_eproj + (size_t)ind * ODIM;
    float* dst = out + OFF_ZQ + (size_t)r * ODIM;
#pragma unroll
    for (int c = t; c < ODIM; c += 256)
        dst[c] = src[c] + b_out[c];
}

// ---------------- row pass over int8 d (LUT exp, SIMD min) ----------------
__global__ void __launch_bounds__(256)
row_pass_kernel(const float* __restrict__ embed, float* __restrict__ out) {
    const int r = blockIdx.x, t = threadIdx.x;
    __shared__ float lutS[256], lutT[256];
    __shared__ float sxn[256];
    __shared__ float sS[256], sT[256];
    __shared__ int sMi[256];
    __shared__ float sred[256];
    __shared__ int scnt;
    __shared__ int scand[64];
    __shared__ unsigned long long sbest;

    {
        int q = (t < 128) ? t : t - 256;
        float t10 = 10.f * (float)q * QINV;
        float e = fast_exp(t10);
        lutS[t] = e;
        lutT[t] = e * t10;
    }
    float xnv = g_xn[(size_t)r * EDIM + t];
    sxn[t] = xnv;
    if (t == 0) { scnt = 0; sbest = ~0ULL; }
    __syncthreads();

    const uint32_t* dp = (const uint32_t*)(g_d8 + (size_t)r * NE);
    uint32_t dv[8];
#pragma unroll
    for (int j = 0; j < 8; j++) dv[j] = dp[t + j * 256];

    float S = 0.f, T = 0.f;
    uint32_t mn4 = dv[0];
#pragma unroll
    for (int j = 0; j < 8; j++) {
        uint32_t u = dv[j];
        S += lutS[u & 255] + lutS[(u >> 8) & 255] + lutS[(u >> 16) & 255] + lutS[u >> 24];
        T += lutT[u & 255] + lutT[(u >> 8) & 255] + lutT[(u >> 16) & 255] + lutT[u >> 24];
        if (j) mn4 = __vmins4(mn4, u);
    }
    int qmin = sext8(mn4, 0);
#pragma unroll
    for (int b = 1; b < 4; b++) { int q = sext8(mn4, b); if (q < qmin) qmin = q; }

    sS[t] = S; sT[t] = T; sMi[t] = qmin;
    __syncthreads();
    for (int s = 128; s > 0; s >>= 1) {
        if (t < s) {
            sS[t] += sS[t+s]; sT[t] += sT[t+s];
            if (sMi[t+s] < sMi[t]) sMi[t] = sMi[t+s];
        }
        __syncthreads();
    }
    float Stot = sS[0], Ttot = sT[0];
    int qthr = sMi[0] + 2;   // window 2/126 = 1.587e-2 >= required 1.5e-2

    uint32_t thr4 = (uint32_t)(qthr & 0xff) * 0x01010101u;
#pragma unroll
    for (int j = 0; j < 8; j++) {
        uint32_t m = __vcmples4(dv[j], thr4);
        if (m) {
#pragma unroll
            for (int b = 0; b < 4; b++)
                if ((m >> (8 * b)) & 1) {
                    int p = atomicAdd(&scnt, 1);
                    if (p < 64) scand[p] = (t + 256 * j) * 4 + b;
                }
        }
    }
    __syncthreads();
    int ncand = scnt < 64 ? scnt : 64;
    int ind;
    if (ncand == 1) {
        ind = scand[0];
    } else {
        for (int i = 0; i < ncand; i++) {
            const float* er = embed + (size_t)scand[i] * EDIM;
            sred[t] = sxn[t] * er[t];
            __syncthreads();
            for (int s = 128; s > 0; s >>= 1) { if (t < s) sred[t] += sred[t+s]; __syncthreads(); }
            if (t == 0) {
                unsigned u = __float_as_uint(sred[0]);
                u = (u & 0x80000000u) ? ~u : (u | 0x80000000u);
                unsigned long long k = ((unsigned long long)u << 32) | (unsigned)scand[i];
                if (k < sbest) sbest = k;
            }
            __syncthreads();
        }
        ind = (int)(sbest & 0xffffffffu);
    }

    float ev = embed[(size_t)ind * EDIM + t];
    float df = ev - xnv;
    sred[t] = df * df;
    atomicAdd(&g_embed_sum[(size_t)ind * EDIM + t], xnv);
    __syncthreads();
    for (int s = 128; s > 0; s >>= 1) { if (t < s) sred[t] += sred[t+s]; __syncthreads(); }
    if (t == 0) {
        atomicAdd(&g_scal[0], sred[0]);
        out[OFF_IND + r] = (float)ind;
        atomicAdd(&g_bins[ind], 1.0f);
        atomicAdd(&g_scal[1], logf(Stot) - Ttot / Stot);
        g_invS[r] = 1.0f / Stot;
    }
}

// ---------------- ap column pass (LUT exp, u32 loads, 4 cols/thread) ----------------
__global__ void ap_kernel() {
    __shared__ float lut[256];
    __shared__ float sh_inv[256];
    int t = threadIdx.x;
    {
        int q = (t < 128) ? t : t - 256;
        lut[t] = fast_exp(10.f * (float)q * QINV);
    }
    int c0 = (blockIdx.x * 256 + t) * 4;
    int r0 = blockIdx.y * 2048;
    float a0 = 0.f, a1 = 0.f, a2 = 0.f, a3 = 0.f;
    for (int rr = 0; rr < 2048; rr += 256) {
        __syncthreads();
        sh_inv[t] = g_invS[r0 + rr + t];
        __syncthreads();
        const signed char* ep = g_d8 + (size_t)(r0 + rr) * NE + c0;
#pragma unroll 4
        for (int j = 0; j < 256; j++) {
            uint32_t w = *(const uint32_t*)(ep + (size_t)j * NE);
            float inv = sh_inv[j];
            a0 = fmaf(lut[w & 255], inv, a0);
            a1 = fmaf(lut[(w >> 8) & 255], inv, a1);
            a2 = fmaf(lut[(w >> 16) & 255], inv, a2);
            a3 = fmaf(lut[w >> 24], inv, a3);
        }
    }
    atomicAdd(&g_ap[c0],     a0);
    atomicAdd(&g_ap[c0 + 1], a1);
    atomicAdd(&g_ap[c0 + 2], a2);
    atomicAdd(&g_ap[c0 + 3], a3);
}

// ---------------- code updates ----------------
__global__ void e1_kernel(const float* __restrict__ cluster_size, float* __restrict__ out) {
    int i = blockIdx.x * 256 + threadIdx.x;
    if (i >= NE) return;
    float cn = cluster_size[i] * 0.99f + g_bins[i] * 0.01f;
    g_cluster_new[i] = cn;
    int ex = (cn < 0.1f);
    g_expired[i] = ex;
    out[OFF_CS + i] = ex ? 0.12f : cn;
    atomicAdd(&g_scal[2], cn);
}

__global__ void scan_kernel() {
    int t = threadIdx.x;
    __shared__ int sh[1024];
    int vals[8]; int s = 0;
#pragma unroll
    for (int j = 0; j < 8; j++) { s += g_expired[t*8 + j]; vals[j] = s; }
    sh[t] = s;
    __syncthreads();
    for (int off = 1; off < 1024; off <<= 1) {
        int v = (t >= off) ? sh[t - off] : 0;
        __syncthreads();
        sh[t] += v;
        __syncthreads();
    }
    int excl = (t > 0) ? sh[t-1] : 0;
#pragma unroll
    for (int j = 0; j < 8; j++) {
        int cum = excl + vals[j];
        int idx = cum - 1; if (idx < 0) idx = 0;
        g_sampidx[t*8 + j] = idx;
    }
}

__global__ void e3_kernel(const float* __restrict__ embed_avg, float* __restrict__ out) {
    int c = blockIdx.x, k = threadIdx.x;
    float ea = embed_avg[(size_t)c * EDIM + k] * 0.99f + g_embed_sum[(size_t)c * EDIM + k] * 0.01f;
    float total = g_scal[2];
    float cn = g_cluster_new[c];
    float cs = (cn + 1e-5f) / (total + (float)NE * 1e-5f) * total;
    float en = ea / cs;
    float ef, eaf;
    if (g_expired[c]) {
        float sv = g_xn[(size_t)g_sampidx[c] * EDIM + k];
        ef = sv; eaf = sv * 0.12f;
    } else { ef = en; eaf = ea; }
    out[OFF_EMB  + (size_t)c * EDIM + k] = ef;
    out[OFF_EAVG + (size_t)c * EDIM + k] = eaf;
}

__global__ void scalars_kernel(float* __restrict__ out) {
    int t = threadIdx.x;
    __shared__ float sh[1024];
    float local = 0.f;
#pragma unroll
    for (int j = 0; j < 8; j++) {
        float ap = g_ap[t*8 + j] * (1.0f / (float)NTOK);
        local -= ap * logf(ap);
    }
    sh[t] = local;
    __syncthreads();
    for (int s = 512; s > 0; s >>= 1) { if (t < s) sh[t] += sh[t+s]; __syncthreads(); }
    if (t == 0) {
        float ent_max = sh[0];
        float commit  = g_scal[0] / ((float)NTOK * (float)EDIM);
        out[OFF_LOSS]   = commit - ent_max;
        out[OFF_ENTMIN] = g_scal[1] / (float)NTOK;
        out[OFF_COMMIT] = commit;
    }
}

// ---------------- launch ----------------
extern "C" void kernel_launch(void* const* d_in, const int* in_sizes, int n_in,
                              void* d_out, int out_size) {
    const float* x         = (const float*)d_in[0];
    const float* W_in      = (const float*)d_in[1];
    const float* b_in      = (const float*)d_in[2];
    const float* W_out     = (const float*)d_in[3];
    const float* b_out     = (const float*)d_in[4];
    const float* embed     = (const float*)d_in[5];
    const float* embed_avg = (const float*)d_in[6];
    const float* cluster   = (const float*)d_in[7];
    float* out = (float*)d_out;

    void *p_xn=nullptr, *p_a=nullptr, *p_eh=nullptr, *p_el=nullptr, *p_wh=nullptr, *p_wl=nullptr;
    cudaGetSymbolAddress(&p_xn, g_xn);
    cudaGetSymbolAddress(&p_a, g_a);
    cudaGetSymbolAddress(&p_eh, g_eh);
    cudaGetSymbolAddress(&p_el, g_el);
    cudaGetSymbolAddress(&p_wh, g_wh);
    cudaGetSymbolAddress(&p_wl, g_wl);

    cudaFuncSetAttribute(mma_d_kernel, cudaFuncAttributeMaxDynamicSharedMemorySize, SMEM_MMA);
    cudaFuncSetAttribute(eproj_kernel, cudaFuncAttributeMaxDynamicSharedMemorySize, SMEM_EP);

    // order: gemm_bias at ncu-profiled slot #4
    conv_split_kernel<<<NE*EDIM/8/256, 256>>>(embed, (__nv_bfloat16*)p_eh,
                                              (__nv_bfloat16*)p_el);               // 1
    zero_kernel<<<8192, 256>>>();                                                  // 2
    conv_split_kernel<<<ODIM*EDIM/8/256, 256>>>(W_out, (__nv_bfloat16*)p_wh,
                                                (__nv_bfloat16*)p_wl);             // 3
    gemm_bias_kernel<<<dim3(EDIM/128, NTOK/128), 256>>>(x, W_in, b_in, (float*)p_xn,
                                                        NTOK, EDIM, LAT);          // 4 <- profile
    l2norm_kernel<<<NTOK, 256>>>((float*)p_xn, (__nv_bfloat16*)p_a);               // 5
    mma_d_kernel<<<dim3(NE/128, NTOK/128), 256, SMEM_MMA>>>();                     // 6
    row_pass_kernel<<<NTOK, 256>>>(embed, out);                                    // 7
    eproj_kernel<<<dim3(ODIM/128, NE/128), 256, SMEM_EP>>>();                      // 8
    ap_kernel<<<dim3(NE/1024, NTOK/2048), 256>>>();                                // 9
    e1_kernel<<<NE/256, 256>>>(cluster, out);                                      // 10
    scan_kernel<<<1, 1024>>>();                                                    // 11
    scalars_kernel<<<1, 1024>>>(out);                                              // 12
    e3_kernel<<<NE, 256>>>(embed_avg, out);                                        // 13
    gather_kernel<<<NTOK, 256>>>(b_out, out);                                      // 14
}

// round 10
// speedup vs baseline: 2.8821x; 1.1099x over previous
#include <cuda_runtime.h>
#include <cuda_bf16.h>
#include <math.h>
#include <stdint.h>

// ---------------- problem constants ----------------
#define NTOK   16384
#define EDIM   256
#define NE     8192
#define LAT    768
#define ODIM   768

// output layout (concatenated tuple, float32)
#define OFF_ZQ     ((size_t)0)
#define OFF_IND    ((size_t)12582912)
#define OFF_LOSS   ((size_t)12599296)
#define OFF_EMB    ((size_t)12599297)
#define OFF_EAVG   ((size_t)14696449)
#define OFF_CS     ((size_t)16793601)
#define OFF_ENTMIN ((size_t)16801793)
#define OFF_COMMIT ((size_t)16801794)

#define QSCALE 126.0f
#define QINV   (1.0f / 126.0f)

// ---------------- device scratch ----------------
__device__ signed char g_d8[(size_t)NTOK * NE];     // approx d, int8 (128MB)
__device__ __nv_bfloat16 g_a[(size_t)NTOK * EDIM];  // xn bf16
__device__ __nv_bfloat16 g_eh[(size_t)NE * EDIM];   // embed hi (also mma_d B)
__device__ __nv_bfloat16 g_el[(size_t)NE * EDIM];   // embed lo
__device__ __nv_bfloat16 g_wh[(size_t)ODIM * EDIM]; // W_out hi
__device__ __nv_bfloat16 g_wl[(size_t)ODIM * EDIM]; // W_out lo
__device__ float g_eproj[(size_t)NE * ODIM];        // embed @ W_out^T
__device__ float g_xn[NTOK * EDIM];
__device__ float g_Sp[(size_t)64 * NTOK];           // per-(bn,row) S partials
__device__ float g_Tp[(size_t)64 * NTOK];
__device__ float g_Mp[(size_t)64 * NTOK];
__device__ float g_invS[NTOK];
__device__ float g_bins[NE];
__device__ float g_ap[NE];
__device__ float g_cluster_new[NE];
__device__ int   g_expired[NE];
__device__ int   g_sampidx[NE];
__device__ float g_embed_sum[NE * EDIM];
__device__ float g_scal[4];   // 0: commit sum, 1: entmin sum, 2: total cluster

// ---------------- fast exp (FFMA only) ----------------
__device__ __forceinline__ float fast_exp(float x) {
    float z = x * 1.4426950408889634f;
    int   i = __float2int_rn(z);
    float rf = (float)i;
    float g = fmaf(rf, -0.693359375f, x);
    g = fmaf(rf, 2.12194440e-4f, g);
    float p = 1.98412698e-4f;
    p = fmaf(p, g, 1.38888889e-3f);
    p = fmaf(p, g, 8.33333333e-3f);
    p = fmaf(p, g, 4.16666667e-2f);
    p = fmaf(p, g, 1.66666667e-1f);
    p = fmaf(p, g, 0.5f);
    p = fmaf(p, g, 1.0f);
    p = fmaf(p, g, 1.0f);
    float sc = __int_as_float((i + 127) << 23);
    return p * sc;
}

// ---------------- warp MMA / async-copy helpers ----------------
__device__ __forceinline__ uint32_t smem_u32(const void* p) {
    uint32_t a;
    asm("{ .reg .u64 t; cvta.to.shared.u64 t, %1; cvt.u32.u64 %0, t; }" : "=r"(a) : "l"(p));
    return a;
}
__device__ __forceinline__ void ldsm4(uint32_t* r, uint32_t addr) {
    asm volatile("ldmatrix.sync.aligned.m8n8.x4.shared.b16 {%0,%1,%2,%3}, [%4];"
                 : "=r"(r[0]), "=r"(r[1]), "=r"(r[2]), "=r"(r[3]) : "r"(addr));
}
__device__ __forceinline__ void mma_bf16(float* c, const uint32_t* a, uint32_t b0, uint32_t b1) {
    asm volatile("mma.sync.aligned.m16n8k16.row.col.f32.bf16.bf16.f32 "
                 "{%0,%1,%2,%3}, {%4,%5,%6,%7}, {%8,%9}, {%0,%1,%2,%3};"
                 : "+f"(c[0]), "+f"(c[1]), "+f"(c[2]), "+f"(c[3])
                 : "r"(a[0]), "r"(a[1]), "r"(a[2]), "r"(a[3]), "r"(b0), "r"(b1));
}
__device__ __forceinline__ void cp16(uint32_t dst, const void* src) {
    asm volatile("cp.async.cg.shared.global [%0], [%1], 16;" :: "r"(dst), "l"(src));
}
#define CP_COMMIT() asm volatile("cp.async.commit_group;")

__device__ __forceinline__ signed char q8(float d) {
    float v = fminf(fmaxf(d * QSCALE, -127.f), 127.f);
    return (signed char)__float2int_rn(v);
}

// ---------------- zeroing ----------------
__global__ void zero_kernel() {
    int i = blockIdx.x * 256 + threadIdx.x;
    if (i < NE * EDIM) g_embed_sum[i] = 0.f;
    if (i < NE)   { g_bins[i] = 0.f; g_ap[i] = 0.f; }
    if (i < 4)    g_scal[i] = 0.f;
}

// ---------------- fp32 SGEMM, double-buffered: C = A @ W^T + bias ----------------
__global__ void __launch_bounds__(256)
gemm_bias_kernel(const float* __restrict__ A, const float* __restrict__ W,
                 const float* __restrict__ bias, float* __restrict__ C,
                 int M, int N, int K) {
    __shared__ float As[2][8][132];
    __shared__ float Ws[2][8][132];
    const int tid = threadIdx.x;
    const int tx = tid & 15, ty = tid >> 4;
    const int bm = blockIdx.y * 128, bn = blockIdx.x * 128;
    float acc[8][8] = {};
    const int lrow = tid >> 1;
    const int lk4  = (tid & 1) * 4;
    const float* Ap = A + (size_t)(bm + lrow) * K + lk4;
    const float* Wp = W + (size_t)(bn + lrow) * K + lk4;
    const int NIT = K >> 3;

    float4 av = *(const float4*)(Ap);
    float4 wv = *(const float4*)(Wp);
    As[0][lk4+0][lrow]=av.x; As[0][lk4+1][lrow]=av.y; As[0][lk4+2][lrow]=av.z; As[0][lk4+3][lrow]=av.w;
    Ws[0][lk4+0][lrow]=wv.x; Ws[0][lk4+1][lrow]=wv.y; Ws[0][lk4+2][lrow]=wv.z; Ws[0][lk4+3][lrow]=wv.w;
    __syncthreads();

    for (int it = 0; it < NIT; it++) {
        int cur = it & 1;
        if (it + 1 < NIT) {
            av = *(const float4*)(Ap + (it + 1) * 8);
            wv = *(const float4*)(Wp + (it + 1) * 8);
        }
#pragma unroll
        for (int k = 0; k < 8; k++) {
            float a[8], b[8];
#pragma unroll
            for (int ir = 0; ir < 8; ir++) a[ir] = As[cur][k][ty*8 + ir];
#pragma unroll
            for (int ic = 0; ic < 8; ic++) b[ic] = Ws[cur][k][ic*16 + tx];
#pragma unroll
            for (int ir = 0; ir < 8; ir++)
#pragma unroll
                for (int ic = 0; ic < 8; ic++)
                    acc[ir][ic] = fmaf(a[ir], b[ic], acc[ir][ic]);
        }
        if (it + 1 < NIT) {
            int nxt = cur ^ 1;
            As[nxt][lk4+0][lrow]=av.x; As[nxt][lk4+1][lrow]=av.y; As[nxt][lk4+2][lrow]=av.z; As[nxt][lk4+3][lrow]=av.w;
            Ws[nxt][lk4+0][lrow]=wv.x; Ws[nxt][lk4+1][lrow]=wv.y; Ws[nxt][lk4+2][lrow]=wv.z; Ws[nxt][lk4+3][lrow]=wv.w;
        }
        __syncthreads();
    }
#pragma unroll
    for (int ir = 0; ir < 8; ir++) {
        int row = bm + ty*8 + ir;
#pragma unroll
        for (int ic = 0; ic < 8; ic++) {
            int col = bn + ic*16 + tx;
            C[(size_t)row * N + col] = acc[ir][ic] + bias[col];
        }
    }
}

// ---------------- row l2-normalize, fused bf16 output ----------------
__global__ void l2norm_kernel(float* __restrict__ x, __nv_bfloat16* __restrict__ xb) {
    int r = blockIdx.x, t = threadIdx.x;
    __shared__ float sh[256];
    float v = x[(size_t)r * EDIM + t];
    sh[t] = v * v;
    __syncthreads();
    for (int s = 128; s > 0; s >>= 1) { if (t < s) sh[t] += sh[t+s]; __syncthreads(); }
    float nrm = sqrtf(sh[0]);
    float xn = v / nrm;
    x[(size_t)r * EDIM + t] = xn;
    xb[(size_t)r * EDIM + t] = __float2bfloat16(xn);
}

// ---------------- fp32 -> bf16 hi/lo split ----------------
__global__ void conv_split_kernel(const float* __restrict__ src,
                                  __nv_bfloat16* __restrict__ hi,
                                  __nv_bfloat16* __restrict__ lo) {
    int i = blockIdx.x * 256 + threadIdx.x;   // 8 elems
    float v[8];
    float4 v0 = ((const float4*)src)[2*i];
    float4 v1 = ((const float4*)src)[2*i+1];
    v[0]=v0.x; v[1]=v0.y; v[2]=v0.z; v[3]=v0.w;
    v[4]=v1.x; v[5]=v1.y; v[6]=v1.z; v[7]=v1.w;
    __nv_bfloat16 h[8], l[8];
#pragma unroll
    for (int j = 0; j < 8; j++) {
        h[j] = __float2bfloat16(v[j]);
        l[j] = __float2bfloat16(v[j] - __bfloat162float(h[j]));
    }
    uint4 ph, pl;
    ph.x = *(uint32_t*)&h[0]; ph.y = *(uint32_t*)&h[2];
    ph.z = *(uint32_t*)&h[4]; ph.w = *(uint32_t*)&h[6];
    pl.x = *(uint32_t*)&l[0]; pl.y = *(uint32_t*)&l[2];
    pl.z = *(uint32_t*)&l[4]; pl.w = *(uint32_t*)&l[6];
    ((uint4*)hi)[i] = ph;
    ((uint4*)lo)[i] = pl;
}

// ---------------- bf16 TC d-GEMM, cp.async pipeline, fused S/T/min epilogue ----------------
#define SSTP 72
#define STG  (128 * SSTP * 2)          // 18432 B per matrix-stage
#define SMEM_MMA (4 * STG)             // 73728 B

__global__ void __launch_bounds__(256, 2)
mma_d_kernel() {
    extern __shared__ __align__(16) char smem[];
    const int tid = threadIdx.x;
    const int bm = blockIdx.y * 128, bn = blockIdx.x * 128;
    const int wid = tid >> 5, lane = tid & 31;
    const int wr = (wid & 1) * 64;
    const int wc = (wid >> 1) * 32;

    uint32_t sb = smem_u32(smem);
    uint32_t aOff = (uint32_t)(((wr + (lane & 15)) * SSTP + (lane >> 4) * 8) * 2);
    uint32_t bRow = (uint32_t)(wc + (lane & 7) + ((lane >> 4) << 3));
    uint32_t bOff = (uint32_t)((bRow * SSTP + ((lane >> 3) & 1) * 8) * 2);

    const char* gA = (const char*)g_a  + (size_t)bm * 512;
    const char* gB = (const char*)g_eh + (size_t)bn * 512;
    const int lrow = tid >> 3, lc8 = tid & 7;

    float acc[4][4][4] = {};

#pragma unroll
    for (int pc = 0; pc < 2; pc++) {
        uint32_t dstA = sb + (uint32_t)pc * 2 * STG;
        uint32_t dstB = dstA + STG;
#pragma unroll
        for (int j = 0; j < 4; j++) {
            int row = lrow + j * 32;
            uint32_t so = (uint32_t)((row * SSTP + lc8 * 8) * 2);
            cp16(dstA + so, gA + (size_t)row * 512 + pc * 128 + lc8 * 16);
            cp16(dstB + so, gB + (size_t)row * 512 + pc * 128 + lc8 * 16);
        }
        CP_COMMIT();
    }

#pragma unroll
    for (int kc = 0; kc < 4; kc++) {
        if (kc < 3) asm volatile("cp.async.wait_group 1;");
        else        asm volatile("cp.async.wait_group 0;");
        __syncthreads();
        uint32_t stA = sb + (uint32_t)(kc & 1) * 2 * STG;
        uint32_t stB = stA + STG;
#pragma unroll
        for (int kk = 0; kk < 4; kk++) {
            uint32_t ko = (uint32_t)kk * 32;
            uint32_t aF[4][4], bF[2][4];
#pragma unroll
            for (int mi = 0; mi < 4; mi++) ldsm4(aF[mi], stA + aOff + mi * (16 * SSTP * 2) + ko);
#pragma unroll
            for (int n2 = 0; n2 < 2; n2++) ldsm4(bF[n2], stB + bOff + n2 * (16 * SSTP * 2) + ko);
#pragma unroll
            for (int mi = 0; mi < 4; mi++)
#pragma unroll
                for (int ni = 0; ni < 4; ni++)
                    mma_bf16(acc[mi][ni], aF[mi], bF[ni >> 1][(ni & 1) * 2], bF[ni >> 1][(ni & 1) * 2 + 1]);
        }
        __syncthreads();
        if (kc + 2 < 4) {
            uint32_t dstA = sb + (uint32_t)(kc & 1) * 2 * STG;
            uint32_t dstB = dstA + STG;
#pragma unroll
            for (int j = 0; j < 4; j++) {
                int row = lrow + j * 32;
                uint32_t so = (uint32_t)((row * SSTP + lc8 * 8) * 2);
                cp16(dstA + so, gA + (size_t)row * 512 + (kc + 2) * 128 + lc8 * 16);
                cp16(dstB + so, gB + (size_t)row * 512 + (kc + 2) * 128 + lc8 * 16);
            }
            CP_COMMIT();
        }
    }

    __syncthreads();

    // ---- fused per-row S/T/min partials (from fp32 acc) ----
    float* rS = (float*)(smem + 36864);   // [4][128]
    float* rT = rS + 512;
    float* rM = rT + 512;
    const int cg = wid >> 1;
    const int rsub = lane >> 2;
#pragma unroll
    for (int mi = 0; mi < 4; mi++) {
#pragma unroll
        for (int half = 0; half < 2; half++) {
            float S = 0.f, T = 0.f, m = 1e30f;
#pragma unroll
            for (int ni = 0; ni < 4; ni++) {
                float d0 = acc[mi][ni][half*2], d1 = acc[mi][ni][half*2+1];
                float t0 = 10.f * d0, t1 = 10.f * d1;
                float e0 = fast_exp(t0), e1 = fast_exp(t1);
                S += e0 + e1;
                T = fmaf(e0, t0, fmaf(e1, t1, T));
                m = fminf(m, fminf(d0, d1));
            }
#pragma unroll
            for (int o = 1; o < 4; o <<= 1) {
                S += __shfl_xor_sync(0xffffffffu, S, o);
                T += __shfl_xor_sync(0xffffffffu, T, o);
                m = fminf(m, __shfl_xor_sync(0xffffffffu, m, o));
            }
            if ((lane & 3) == 0) {
                int row = wr + mi * 16 + half * 8 + rsub;
                rS[cg * 128 + row] = S;
                rT[cg * 128 + row] = T;
                rM[cg * 128 + row] = m;
            }
        }
    }
    __syncthreads();
    if (tid < 128) {
        float S = rS[tid] + rS[128 + tid] + rS[256 + tid] + rS[384 + tid];
        float T = rT[tid] + rT[128 + tid] + rT[256 + tid] + rT[384 + tid];
        float m = fminf(fminf(rM[tid], rM[128 + tid]), fminf(rM[256 + tid], rM[384 + tid]));
        size_t o = (size_t)blockIdx.x * NTOK + bm + tid;
        g_Sp[o] = S; g_Tp[o] = T; g_Mp[o] = m;
    }

    // ---- quantize to int8, smem stage (144B pitch), coalesced stores ----
    signed char* epi = (signed char*)smem;
    {
        const int r0 = wr + (lane >> 2);
        const int c0 = wc + (lane & 3) * 2;
#pragma unroll
        for (int mi = 0; mi < 4; mi++)
#pragma unroll
            for (int ni = 0; ni < 4; ni++) {
                int rr = r0 + mi * 16, cc = c0 + ni * 8;
                epi[rr * 144 + cc]       = q8(acc[mi][ni][0]);
                epi[rr * 144 + cc + 1]   = q8(acc[mi][ni][1]);
                epi[(rr+8) * 144 + cc]     = q8(acc[mi][ni][2]);
                epi[(rr+8) * 144 + cc + 1] = q8(acc[mi][ni][3]);
            }
    }
    __syncthreads();
#pragma unroll
    for (int j = 0; j < 4; j++) {
        int idx = j * 256 + tid;
        int row = idx >> 3, c16 = idx & 7;
        uint4 v = *(uint4*)(epi + row * 144 + c16 * 16);
        *(uint4*)(g_d8 + (size_t)(bm + row) * NE + bn + c16 * 16) = v;
    }
}

// ---------------- bf16-split TC GEMM (cp.async pipeline): g_eproj = embed @ W_out^T ----------------
#define EPSTG (4 * STG)
#define SMEM_EP (2 * EPSTG)

__global__ void __launch_bounds__(256)
eproj_kernel() {
    extern __shared__ __align__(16) char smem[];
    const int tid = threadIdx.x;
    const int bm = blockIdx.y * 128, bn = blockIdx.x * 128;
    const int wid = tid >> 5, lane = tid & 31;
    const int wr = (wid & 1) * 64;
    const int wc = (wid >> 1) * 32;

    uint32_t sb = smem_u32(smem);
    uint32_t aOff = (uint32_t)(((wr + (lane & 15)) * SSTP + (lane >> 4) * 8) * 2);
    uint32_t bRow = (uint32_t)(wc + (lane & 7) + ((lane >> 4) << 3));
    uint32_t bOff = (uint32_t)((bRow * SSTP + ((lane >> 3) & 1) * 8) * 2);

    const char* gAh = (const char*)g_eh + (size_t)bm * 512;
    const char* gAl = (const char*)g_el + (size_t)bm * 512;
    const char* gBh = (const char*)g_wh + (size_t)bn * 512;
    const char* gBl = (const char*)g_wl + (size_t)bn * 512;
    const int lrow = tid >> 3, lc8 = tid & 7;

    float acc[4][4][4] = {};

#pragma unroll
    for (int pc = 0; pc < 2; pc++) {
        uint32_t st = sb + (uint32_t)pc * EPSTG;
#pragma unroll
        for (int j = 0; j < 4; j++) {
            int row = lrow + j * 32;
            uint32_t so = (uint32_t)((row * SSTP + lc8 * 8) * 2);
            size_t go = (size_t)row * 512 + pc * 128 + lc8 * 16;
            cp16(st + so,           gAh + go);
            cp16(st + STG + so,     gAl + go);
            cp16(st + 2 * STG + so, gBh + go);
            cp16(st + 3 * STG + so, gBl + go);
        }
        CP_COMMIT();
    }

#pragma unroll
    for (int kc = 0; kc < 4; kc++) {
        if (kc < 3) asm volatile("cp.async.wait_group 1;");
        else        asm volatile("cp.async.wait_group 0;");
        __syncthreads();
        uint32_t st = sb + (uint32_t)(kc & 1) * EPSTG;
        const uint32_t AH = st, AL = st + STG, BH = st + 2 * STG, BL = st + 3 * STG;
#pragma unroll
        for (int kk = 0; kk < 4; kk++) {
            uint32_t ko = (uint32_t)kk * 32;
            uint32_t ah[4][4], al[4][4], bh[2][4], bl[2][4];
#pragma unroll
            for (int mi = 0; mi < 4; mi++) {
                ldsm4(ah[mi], AH + aOff + mi * (16 * SSTP * 2) + ko);
                ldsm4(al[mi], AL + aOff + mi * (16 * SSTP * 2) + ko);
            }
#pragma unroll
            for (int n2 = 0; n2 < 2; n2++) {
                ldsm4(bh[n2], BH + bOff + n2 * (16 * SSTP * 2) + ko);
                ldsm4(bl[n2], BL + bOff + n2 * (16 * SSTP * 2) + ko);
            }
#pragma unroll
            for (int mi = 0; mi < 4; mi++)
#pragma unroll
                for (int ni = 0; ni < 4; ni++) {
                    uint32_t h0 = bh[ni >> 1][(ni & 1) * 2], h1 = bh[ni >> 1][(ni & 1) * 2 + 1];
                    uint32_t l0 = bl[ni >> 1][(ni & 1) * 2], l1 = bl[ni >> 1][(ni & 1) * 2 + 1];
                    mma_bf16(acc[mi][ni], ah[mi], h0, h1);
                    mma_bf16(acc[mi][ni], ah[mi], l0, l1);
                    mma_bf16(acc[mi][ni], al[mi], h0, h1);
                }
        }
        __syncthreads();
        if (kc + 2 < 4) {
            uint32_t st2 = sb + (uint32_t)(kc & 1) * EPSTG;
#pragma unroll
            for (int j = 0; j < 4; j++) {
                int row = lrow + j * 32;
                uint32_t so = (uint32_t)((row * SSTP + lc8 * 8) * 2);
                size_t go = (size_t)row * 512 + (kc + 2) * 128 + lc8 * 16;
                cp16(st2 + so,           gAh + go);
                cp16(st2 + STG + so,     gAl + go);
                cp16(st2 + 2 * STG + so, gBh + go);
                cp16(st2 + 3 * STG + so, gBl + go);
            }
            CP_COMMIT();
        }
    }

    __syncthreads();
    float* epi = (float*)smem;
    {
        const int r0 = wr + (lane >> 2);
        const int c0 = wc + (lane & 3) * 2;
#pragma unroll
        for (int mi = 0; mi < 4; mi++)
#pragma unroll
            for (int ni = 0; ni < 4; ni++) {
                int rr = r0 + mi * 16, cc = c0 + ni * 8;
                *(float2*)(epi + rr * 132 + cc) = make_float2(acc[mi][ni][0], acc[mi][ni][1]);
                *(float2*)(epi + (rr + 8) * 132 + cc) = make_float2(acc[mi][ni][2], acc[mi][ni][3]);
            }
    }
    __syncthreads();
#pragma unroll
    for (int j = 0; j < 16; j++) {
        int idx = j * 256 + tid;
        int row = idx >> 5, c4 = idx & 31;
        uint4 v = *(uint4*)(epi + row * 132 + c4 * 4);
        *(uint4*)(g_eproj + (size_t)(bm + row) * ODIM + bn + c4 * 4) = v;
    }
}

// ---------------- gather: z_q_out[r] = g_eproj[ind_r] + b_out ----------------
__global__ void gather_kernel(const float* __restrict__ b_out, float* __restrict__ out) {
    int r = blockIdx.x, t = threadIdx.x;
    int ind = (int)out[OFF_IND + r];
    const float* src = g_eproj + (size_t)ind * ODIM;
    float* dst = out + OFF_ZQ + (size_t)r * ODIM;
#pragma unroll
    for (int c = t; c < ODIM; c += 256)
        dst[c] = src[c] + b_out[c];
}

// ---------------- row finalize: reduce partials, candidate scan, exact argmin ----------------
__global__ void __launch_bounds__(256)
row_finalize_kernel(const float* __restrict__ embed, float* __restrict__ out) {
    const int r = blockIdx.x, t = threadIdx.x;
    __shared__ float pS[64], pT[64], pM[64];
    __shared__ float sxn[256];
    __shared__ float sred[256];
    __shared__ int scnt;
    __shared__ int scand[64];
    __shared__ unsigned long long sbest;

    if (t < 64) {
        size_t o = (size_t)t * NTOK + r;
        pS[t] = g_Sp[o]; pT[t] = g_Tp[o]; pM[t] = g_Mp[o];
    }
    sxn[t] = g_xn[(size_t)r * EDIM + t];
    if (t == 0) { scnt = 0; sbest = ~0ULL; }
    __syncthreads();
    for (int s = 32; s > 0; s >>= 1) {
        if (t < s) {
            pS[t] += pS[t+s]; pT[t] += pT[t+s]; pM[t] = fminf(pM[t], pM[t+s]);
        }
        __syncthreads();
    }
    float Stot = pS[0], Ttot = pT[0], gmin = pM[0];

    // candidate threshold: |q/QSCALE - exact| <= 5.2e-3, |gmin - exact_min| <= 1.2e-3 -> 6.4e-3; use 1.3e-2
    int qthr = (int)floorf((gmin + 1.3e-2f) * QSCALE);
    if (qthr > 127) qthr = 127;
    uint32_t thr4 = (uint32_t)(qthr & 0xff) * 0x01010101u;

    const uint32_t* dp = (const uint32_t*)(g_d8 + (size_t)r * NE);
#pragma unroll
    for (int j = 0; j < 8; j++) {
        uint32_t u = dp[t + j * 256];
        uint32_t m = __vcmples4(u, thr4);
        if (m) {
#pragma unroll
            for (int b = 0; b < 4; b++)
                if ((m >> (8 * b)) & 1) {
                    int p = atomicAdd(&scnt, 1);
                    if (p < 64) scand[p] = (t + 256 * j) * 4 + b;
                }
        }
    }
    __syncthreads();
    int ncand = scnt < 64 ? scnt : 64;
    int ind;
    if (ncand == 1) {
        ind = scand[0];
    } else {
        for (int i = 0; i < ncand; i++) {
            const float* er = embed + (size_t)scand[i] * EDIM;
            sred[t] = sxn[t] * er[t];
            __syncthreads();
            for (int s = 128; s > 0; s >>= 1) { if (t < s) sred[t] += sred[t+s]; __syncthreads(); }
            if (t == 0) {
                unsigned u = __float_as_uint(sred[0]);
                u = (u & 0x80000000u) ? ~u : (u | 0x80000000u);
                unsigned long long k = ((unsigned long long)u << 32) | (unsigned)scand[i];
                if (k < sbest) sbest = k;
            }
            __syncthreads();
        }
        ind = (int)(sbest & 0xffffffffu);
    }

    float xnv = sxn[t];
    float ev = embed[(size_t)ind * EDIM + t];
    float df = ev - xnv;
    sred[t] = df * df;
    atomicAdd(&g_embed_sum[(size_t)ind * EDIM + t], xnv);
    __syncthreads();
    for (int s = 128; s > 0; s >>= 1) { if (t < s) sred[t] += sred[t+s]; __syncthreads(); }
    if (t == 0) {
        atomicAdd(&g_scal[0], sred[0]);
        out[OFF_IND + r] = (float)ind;
        atomicAdd(&g_bins[ind], 1.0f);
        atomicAdd(&g_scal[1], logf(Stot) - Ttot / Stot);
        g_invS[r] = 1.0f / Stot;
    }
}

// ---------------- ap column pass (replicated conflict-free LUT, 4 cols/thread) ----------------
__global__ void __launch_bounds__(256)
ap_kernel() {
    __shared__ float lut[8192];     // lut[b*32 + lane] = exp(10*q(b)/126), bank == lane
    __shared__ float sh_inv[256];
    int t = threadIdx.x, lane = t & 31;
    for (int i = t; i < 8192; i += 256) {
        int b = i >> 5;
        int q = (b < 128) ? b : b - 256;
        lut[i] = fast_exp(10.f * (float)q * QINV);
    }
    int c0 = (blockIdx.x * 256 + t) * 4;
    int r0 = blockIdx.y * 1024;
    float a0 = 0.f, a1 = 0.f, a2 = 0.f, a3 = 0.f;
    for (int rr = 0; rr < 1024; rr += 256) {
        __syncthreads();
        sh_inv[t] = g_invS[r0 + rr + t];
        __syncthreads();
        const signed char* ep = g_d8 + (size_t)(r0 + rr) * NE + c0;
#pragma unroll 4
        for (int j = 0; j < 256; j++) {
            uint32_t w = *(const uint32_t*)(ep + (size_t)j * NE);
            float inv = sh_inv[j];
            a0 = fmaf(lut[((w & 255u) << 5) | lane], inv, a0);
            a1 = fmaf(lut[(((w >> 8) & 255u) << 5) | lane], inv, a1);
            a2 = fmaf(lut[(((w >> 16) & 255u) << 5) | lane], inv, a2);
            a3 = fmaf(lut[((w >> 24) << 5) | lane], inv, a3);
        }
    }
    atomicAdd(&g_ap[c0],     a0);
    atomicAdd(&g_ap[c0 + 1], a1);
    atomicAdd(&g_ap[c0 + 2], a2);
    atomicAdd(&g_ap[c0 + 3], a3);
}

// ---------------- code updates ----------------
__global__ void e1_kernel(const float* __restrict__ cluster_size, float* __restrict__ out) {
    int i = blockIdx.x * 256 + threadIdx.x;
    if (i >= NE) return;
    float cn = cluster_size[i] * 0.99f + g_bins[i] * 0.01f;
    g_cluster_new[i] = cn;
    int ex = (cn < 0.1f);
    g_expired[i] = ex;
    out[OFF_CS + i] = ex ? 0.12f : cn;
    atomicAdd(&g_scal[2], cn);
}

__global__ void scan_kernel() {
    int t = threadIdx.x;
    __shared__ int sh[1024];
    int vals[8]; int s = 0;
#pragma unroll
    for (int j = 0; j < 8; j++) { s += g_expired[t*8 + j]; vals[j] = s; }
    sh[t] = s;
    __syncthreads();
    for (int off = 1; off < 1024; off <<= 1) {
        int v = (t >= off) ? sh[t - off] : 0;
        __syncthreads();
        sh[t] += v;
        __syncthreads();
    }
    int excl = (t > 0) ? sh[t-1] : 0;
#pragma unroll
    for (int j = 0; j < 8; j++) {
        int cum = excl + vals[j];
        int idx = cum - 1; if (idx < 0) idx = 0;
        g_sampidx[t*8 + j] = idx;
    }
}

__global__ void e3_kernel(const float* __restrict__ embed_avg, float* __restrict__ out) {
    int c = blockIdx.x, k = threadIdx.x;
    float ea = embed_avg[(size_t)c * EDIM + k] * 0.99f + g_embed_sum[(size_t)c * EDIM + k] * 0.01f;
    float total = g_scal[2];
    float cn = g_cluster_new[c];
    float cs = (cn + 1e-5f) / (total + (float)NE * 1e-5f) * total;
    float en = ea / cs;
    float ef, eaf;
    if (g_expired[c]) {
        float sv = g_xn[(size_t)g_sampidx[c] * EDIM + k];
        ef = sv; eaf = sv * 0.12f;
    } else { ef = en; eaf = ea; }
    out[OFF_EMB  + (size_t)c * EDIM + k] = ef;
    out[OFF_EAVG + (size_t)c * EDIM + k] = eaf;
}

__global__ void scalars_kernel(float* __restrict__ out) {
    int t = threadIdx.x;
    __shared__ float sh[1024];
    float local = 0.f;
#pragma unroll
    for (int j = 0; j < 8; j++) {
        float ap = g_ap[t*8 + j] * (1.0f / (float)NTOK);
        local -= ap * logf(ap);
    }
    sh[t] = local;
    __syncthreads();
    for (int s = 512; s > 0; s >>= 1) { if (t < s) sh[t] += sh[t+s]; __syncthreads(); }
    if (t == 0) {
        float ent_max = sh[0];
        float commit  = g_scal[0] / ((float)NTOK * (float)EDIM);
        out[OFF_LOSS]   = commit - ent_max;
        out[OFF_ENTMIN] = g_scal[1] / (float)NTOK;
        out[OFF_COMMIT] = commit;
    }
}

// ---------------- launch ----------------
extern "C" void kernel_launch(void* const* d_in, const int* in_sizes, int n_in,
                              void* d_out, int out_size) {
    const float* x         = (const float*)d_in[0];
    const float* W_in      = (const float*)d_in[1];
    const float* b_in      = (const float*)d_in[2];
    const float* W_out     = (const float*)d_in[3];
    const float* b_out     = (const float*)d_in[4];
    const float* embed     = (const float*)d_in[5];
    const float* embed_avg = (const float*)d_in[6];
    const float* cluster   = (const float*)d_in[7];
    float* out = (float*)d_out;

    void *p_xn=nullptr, *p_a=nullptr, *p_eh=nullptr, *p_el=nullptr, *p_wh=nullptr, *p_wl=nullptr;
    cudaGetSymbolAddress(&p_xn, g_xn);
    cudaGetSymbolAddress(&p_a, g_a);
    cudaGetSymbolAddress(&p_eh, g_eh);
    cudaGetSymbolAddress(&p_el, g_el);
    cudaGetSymbolAddress(&p_wh, g_wh);
    cudaGetSymbolAddress(&p_wl, g_wl);

    cudaFuncSetAttribute(mma_d_kernel, cudaFuncAttributeMaxDynamicSharedMemorySize, SMEM_MMA);
    cudaFuncSetAttribute(eproj_kernel, cudaFuncAttributeMaxDynamicSharedMemorySize, SMEM_EP);

    // order: mma_d at ncu-profiled slot #4 (verify fused-epilogue cost)
    conv_split_kernel<<<NE*EDIM/8/256, 256>>>(embed, (__nv_bfloat16*)p_eh,
                                              (__nv_bfloat16*)p_el);               // 1
    gemm_bias_kernel<<<dim3(EDIM/128, NTOK/128), 256>>>(x, W_in, b_in, (float*)p_xn,
                                                        NTOK, EDIM, LAT);          // 2
    l2norm_kernel<<<NTOK, 256>>>((float*)p_xn, (__nv_bfloat16*)p_a);               // 3
    mma_d_kernel<<<dim3(NE/128, NTOK/128), 256, SMEM_MMA>>>();                     // 4 <- profile
    zero_kernel<<<8192, 256>>>();                                                  // 5
    row_finalize_kernel<<<NTOK, 256>>>(embed, out);                                // 6
    conv_split_kernel<<<ODIM*EDIM/8/256, 256>>>(W_out, (__nv_bfloat16*)p_wh,
                                                (__nv_bfloat16*)p_wl);             // 7
    eproj_kernel<<<dim3(ODIM/128, NE/128), 256, SMEM_EP>>>();                      // 8
    ap_kernel<<<dim3(NE/1024, NTOK/1024), 256>>>();                                // 9
    e1_kernel<<<NE/256, 256>>>(cluster, out);                                      // 10
    scan_kernel<<<1, 1024>>>();                                                    // 11
    scalars_kernel<<<1, 1024>>>(out);                                              // 12
    e3_kernel<<<NE, 256>>>(embed_avg, out);                                        // 13
    gather_kernel<<<NTOK, 256>>>(b_out, out);                                      // 14
}

// round 11
// speedup vs baseline: 2.9346x; 1.0182x over previous
#include <cuda_runtime.h>
#include <cuda_bf16.h>
#include <math.h>
#include <stdint.h>

// ---------------- problem constants ----------------
#define NTOK   16384
#define EDIM   256
#define NE     8192
#define LAT    768
#define ODIM   768

// output layout (concatenated tuple, float32)
#define OFF_ZQ     ((size_t)0)
#define OFF_IND    ((size_t)12582912)
#define OFF_LOSS   ((size_t)12599296)
#define OFF_EMB    ((size_t)12599297)
#define OFF_EAVG   ((size_t)14696449)
#define OFF_CS     ((size_t)16793601)
#define OFF_ENTMIN ((size_t)16801793)
#define OFF_COMMIT ((size_t)16801794)

#define QSCALE 126.0f
#define QINV   (1.0f / 126.0f)

// ---------------- device scratch ----------------
__device__ signed char g_d8[(size_t)NTOK * NE];     // approx d, int8 (128MB)
__device__ __nv_bfloat16 g_a[(size_t)NTOK * EDIM];  // xn bf16
__device__ __nv_bfloat16 g_eh[(size_t)NE * EDIM];   // embed hi (also mma_d B)
__device__ __nv_bfloat16 g_el[(size_t)NE * EDIM];   // embed lo
__device__ __nv_bfloat16 g_wh[(size_t)ODIM * EDIM]; // W_out hi
__device__ __nv_bfloat16 g_wl[(size_t)ODIM * EDIM]; // W_out lo
__device__ float g_eproj[(size_t)NE * ODIM];        // embed @ W_out^T
__device__ float g_xn[NTOK * EDIM];
__device__ float g_Sp[(size_t)64 * NTOK];           // per-(bn,row) S partials
__device__ float g_Tp[(size_t)64 * NTOK];
__device__ float g_Mp[(size_t)64 * NTOK];
__device__ float g_invS[NTOK];
__device__ float g_bins[NE];
__device__ float g_ap[NE];
__device__ float g_cluster_new[NE];
__device__ int   g_expired[NE];
__device__ int   g_sampidx[NE];
__device__ float g_embed_sum[NE * EDIM];
__device__ float g_scal[4];   // 0: commit sum, 1: entmin sum, 2: total cluster

// ---------------- fast exp (FFMA only) ----------------
__device__ __forceinline__ float fast_exp(float x) {
    float z = x * 1.4426950408889634f;
    int   i = __float2int_rn(z);
    float rf = (float)i;
    float g = fmaf(rf, -0.693359375f, x);
    g = fmaf(rf, 2.12194440e-4f, g);
    float p = 1.98412698e-4f;
    p = fmaf(p, g, 1.38888889e-3f);
    p = fmaf(p, g, 8.33333333e-3f);
    p = fmaf(p, g, 4.16666667e-2f);
    p = fmaf(p, g, 1.66666667e-1f);
    p = fmaf(p, g, 0.5f);
    p = fmaf(p, g, 1.0f);
    p = fmaf(p, g, 1.0f);
    float sc = __int_as_float((i + 127) << 23);
    return p * sc;
}

// ---------------- warp MMA / async-copy helpers ----------------
__device__ __forceinline__ uint32_t smem_u32(const void* p) {
    uint32_t a;
    asm("{ .reg .u64 t; cvta.to.shared.u64 t, %1; cvt.u32.u64 %0, t; }" : "=r"(a) : "l"(p));
    return a;
}
__device__ __forceinline__ void ldsm4(uint32_t* r, uint32_t addr) {
    asm volatile("ldmatrix.sync.aligned.m8n8.x4.shared.b16 {%0,%1,%2,%3}, [%4];"
                 : "=r"(r[0]), "=r"(r[1]), "=r"(r[2]), "=r"(r[3]) : "r"(addr));
}
__device__ __forceinline__ void mma_bf16(float* c, const uint32_t* a, uint32_t b0, uint32_t b1) {
    asm volatile("mma.sync.aligned.m16n8k16.row.col.f32.bf16.bf16.f32 "
                 "{%0,%1,%2,%3}, {%4,%5,%6,%7}, {%8,%9}, {%0,%1,%2,%3};"
                 : "+f"(c[0]), "+f"(c[1]), "+f"(c[2]), "+f"(c[3])
                 : "r"(a[0]), "r"(a[1]), "r"(a[2]), "r"(a[3]), "r"(b0), "r"(b1));
}
__device__ __forceinline__ void cp16(uint32_t dst, const void* src) {
    asm volatile("cp.async.cg.shared.global [%0], [%1], 16;" :: "r"(dst), "l"(src));
}
#define CP_COMMIT() asm volatile("cp.async.commit_group;")

__device__ __forceinline__ signed char q8(float d) {
    float v = fminf(fmaxf(d * QSCALE, -127.f), 127.f);
    return (signed char)__float2int_rn(v);
}

// ---------------- zeroing ----------------
__global__ void zero_kernel() {
    int i = blockIdx.x * 256 + threadIdx.x;
    if (i < NE * EDIM) g_embed_sum[i] = 0.f;
    if (i < NE)   { g_bins[i] = 0.f; g_ap[i] = 0.f; }
    if (i < 4)    g_scal[i] = 0.f;
}

// ---------------- fp32 SGEMM, double-buffered + vectorized LDS ----------------
// micro-tile: row = bm + ty*8 + ir ; col = bn + ic2*32 + tx*2 + p
__global__ void __launch_bounds__(256)
gemm_bias_kernel(const float* __restrict__ A, const float* __restrict__ W,
                 const float* __restrict__ bias, float* __restrict__ C,
                 int M, int N, int K) {
    __shared__ float As[2][8][132];
    __shared__ float Ws[2][8][132];
    const int tid = threadIdx.x;
    const int tx = tid & 15, ty = tid >> 4;
    const int bm = blockIdx.y * 128, bn = blockIdx.x * 128;
    float acc[8][8] = {};
    const int lrow = tid >> 1;
    const int lk4  = (tid & 1) * 4;
    const float* Ap = A + (size_t)(bm + lrow) * K + lk4;
    const float* Wp = W + (size_t)(bn + lrow) * K + lk4;
    const int NIT = K >> 3;

    float4 av = *(const float4*)(Ap);
    float4 wv = *(const float4*)(Wp);
    As[0][lk4+0][lrow]=av.x; As[0][lk4+1][lrow]=av.y; As[0][lk4+2][lrow]=av.z; As[0][lk4+3][lrow]=av.w;
    Ws[0][lk4+0][lrow]=wv.x; Ws[0][lk4+1][lrow]=wv.y; Ws[0][lk4+2][lrow]=wv.z; Ws[0][lk4+3][lrow]=wv.w;
    __syncthreads();

    for (int it = 0; it < NIT; it++) {
        int cur = it & 1;
        if (it + 1 < NIT) {
            av = *(const float4*)(Ap + (it + 1) * 8);
            wv = *(const float4*)(Wp + (it + 1) * 8);
        }
#pragma unroll
        for (int k = 0; k < 8; k++) {
            float4 a0 = *(const float4*)&As[cur][k][ty * 8];
            float4 a1 = *(const float4*)&As[cur][k][ty * 8 + 4];
            float2 b0 = *(const float2*)&Ws[cur][k][tx * 2];
            float2 b1 = *(const float2*)&Ws[cur][k][32 + tx * 2];
            float2 b2 = *(const float2*)&Ws[cur][k][64 + tx * 2];
            float2 b3 = *(const float2*)&Ws[cur][k][96 + tx * 2];
            float a[8] = {a0.x, a0.y, a0.z, a0.w, a1.x, a1.y, a1.z, a1.w};
            float b[8] = {b0.x, b0.y, b1.x, b1.y, b2.x, b2.y, b3.x, b3.y};
#pragma unroll
            for (int ir = 0; ir < 8; ir++)
#pragma unroll
                for (int ic = 0; ic < 8; ic++)
                    acc[ir][ic] = fmaf(a[ir], b[ic], acc[ir][ic]);
        }
        if (it + 1 < NIT) {
            int nxt = cur ^ 1;
            As[nxt][lk4+0][lrow]=av.x; As[nxt][lk4+1][lrow]=av.y; As[nxt][lk4+2][lrow]=av.z; As[nxt][lk4+3][lrow]=av.w;
            Ws[nxt][lk4+0][lrow]=wv.x; Ws[nxt][lk4+1][lrow]=wv.y; Ws[nxt][lk4+2][lrow]=wv.z; Ws[nxt][lk4+3][lrow]=wv.w;
        }
        __syncthreads();
    }
#pragma unroll
    for (int ir = 0; ir < 8; ir++) {
        int row = bm + ty * 8 + ir;
#pragma unroll
        for (int ic2 = 0; ic2 < 4; ic2++) {
            int col = bn + ic2 * 32 + tx * 2;
            float2 v = make_float2(acc[ir][ic2*2]   + bias[col],
                                   acc[ir][ic2*2+1] + bias[col + 1]);
            *(float2*)(C + (size_t)row * N + col) = v;
        }
    }
}

// ---------------- row l2-normalize, fused bf16 output ----------------
__global__ void l2norm_kernel(float* __restrict__ x, __nv_bfloat16* __restrict__ xb) {
    int r = blockIdx.x, t = threadIdx.x;
    __shared__ float sh[256];
    float v = x[(size_t)r * EDIM + t];
    sh[t] = v * v;
    __syncthreads();
    for (int s = 128; s > 0; s >>= 1) { if (t < s) sh[t] += sh[t+s]; __syncthreads(); }
    float nrm = sqrtf(sh[0]);
    float xn = v / nrm;
    x[(size_t)r * EDIM + t] = xn;
    xb[(size_t)r * EDIM + t] = __float2bfloat16(xn);
}

// ---------------- fp32 -> bf16 hi/lo split ----------------
__global__ void conv_split_kernel(const float* __restrict__ src,
                                  __nv_bfloat16* __restrict__ hi,
                                  __nv_bfloat16* __restrict__ lo) {
    int i = blockIdx.x * 256 + threadIdx.x;   // 8 elems
    float v[8];
    float4 v0 = ((const float4*)src)[2*i];
    float4 v1 = ((const float4*)src)[2*i+1];
    v[0]=v0.x; v[1]=v0.y; v[2]=v0.z; v[3]=v0.w;
    v[4]=v1.x; v[5]=v1.y; v[6]=v1.z; v[7]=v1.w;
    __nv_bfloat16 h[8], l[8];
#pragma unroll
    for (int j = 0; j < 8; j++) {
        h[j] = __float2bfloat16(v[j]);
        l[j] = __float2bfloat16(v[j] - __bfloat162float(h[j]));
    }
    uint4 ph, pl;
    ph.x = *(uint32_t*)&h[0]; ph.y = *(uint32_t*)&h[2];
    ph.z = *(uint32_t*)&h[4]; ph.w = *(uint32_t*)&h[6];
    pl.x = *(uint32_t*)&l[0]; pl.y = *(uint32_t*)&l[2];
    pl.z = *(uint32_t*)&l[4]; pl.w = *(uint32_t*)&l[6];
    ((uint4*)hi)[i] = ph;
    ((uint4*)lo)[i] = pl;
}

// ---------------- bf16 TC d-GEMM, cp.async pipeline, fused S/T/min epilogue ----------------
#define SSTP 72
#define STG  (128 * SSTP * 2)          // 18432 B per matrix-stage
#define SMEM_MMA (4 * STG)             // 73728 B

__global__ void __launch_bounds__(256, 2)
mma_d_kernel() {
    extern __shared__ __align__(16) char smem[];
    const int tid = threadIdx.x;
    const int bm = blockIdx.y * 128, bn = blockIdx.x * 128;
    const int wid = tid >> 5, lane = tid & 31;
    const int wr = (wid & 1) * 64;
    const int wc = (wid >> 1) * 32;

    uint32_t sb = smem_u32(smem);
    uint32_t aOff = (uint32_t)(((wr + (lane & 15)) * SSTP + (lane >> 4) * 8) * 2);
    uint32_t bRow = (uint32_t)(wc + (lane & 7) + ((lane >> 4) << 3));
    uint32_t bOff = (uint32_t)((bRow * SSTP + ((lane >> 3) & 1) * 8) * 2);

    const char* gA = (const char*)g_a  + (size_t)bm * 512;
    const char* gB = (const char*)g_eh + (size_t)bn * 512;
    const int lrow = tid >> 3, lc8 = tid & 7;

    float acc[4][4][4] = {};

#pragma unroll
    for (int pc = 0; pc < 2; pc++) {
        uint32_t dstA = sb + (uint32_t)pc * 2 * STG;
        uint32_t dstB = dstA + STG;
#pragma unroll
        for (int j = 0; j < 4; j++) {
            int row = lrow + j * 32;
            uint32_t so = (uint32_t)((row * SSTP + lc8 * 8) * 2);
            cp16(dstA + so, gA + (size_t)row * 512 + pc * 128 + lc8 * 16);
            cp16(dstB + so, gB + (size_t)row * 512 + pc * 128 + lc8 * 16);
        }
        CP_COMMIT();
    }

#pragma unroll
    for (int kc = 0; kc < 4; kc++) {
        if (kc < 3) asm volatile("cp.async.wait_group 1;");
        else        asm volatile("cp.async.wait_group 0;");
        __syncthreads();
        uint32_t stA = sb + (uint32_t)(kc & 1) * 2 * STG;
        uint32_t stB = stA + STG;
#pragma unroll
        for (int kk = 0; kk < 4; kk++) {
            uint32_t ko = (uint32_t)kk * 32;
            uint32_t aF[4][4], bF[2][4];
#pragma unroll
            for (int mi = 0; mi < 4; mi++) ldsm4(aF[mi], stA + aOff + mi * (16 * SSTP * 2) + ko);
#pragma unroll
            for (int n2 = 0; n2 < 2; n2++) ldsm4(bF[n2], stB + bOff + n2 * (16 * SSTP * 2) + ko);
#pragma unroll
            for (int mi = 0; mi < 4; mi++)
#pragma unroll
                for (int ni = 0; ni < 4; ni++)
                    mma_bf16(acc[mi][ni], aF[mi], bF[ni >> 1][(ni & 1) * 2], bF[ni >> 1][(ni & 1) * 2 + 1]);
        }
        __syncthreads();
        if (kc + 2 < 4) {
            uint32_t dstA = sb + (uint32_t)(kc & 1) * 2 * STG;
            uint32_t dstB = dstA + STG;
#pragma unroll
            for (int j = 0; j < 4; j++) {
                int row = lrow + j * 32;
                uint32_t so = (uint32_t)((row * SSTP + lc8 * 8) * 2);
                cp16(dstA + so, gA + (size_t)row * 512 + (kc + 2) * 128 + lc8 * 16);
                cp16(dstB + so, gB + (size_t)row * 512 + (kc + 2) * 128 + lc8 * 16);
            }
            CP_COMMIT();
        }
    }

    __syncthreads();

    // ---- fused per-row S/T/min partials (from fp32 acc) ----
    float* rS = (float*)(smem + 36864);   // [4][128]
    float* rT = rS + 512;
    float* rM = rT + 512;
    const int cg = wid >> 1;
    const int rsub = lane >> 2;
#pragma unroll
    for (int mi = 0; mi < 4; mi++) {
#pragma unroll
        for (int half = 0; half < 2; half++) {
            float S = 0.f, T = 0.f, m = 1e30f;
#pragma unroll
            for (int ni = 0; ni < 4; ni++) {
                float d0 = acc[mi][ni][half*2], d1 = acc[mi][ni][half*2+1];
                float t0 = 10.f * d0, t1 = 10.f * d1;
                float e0 = fast_exp(t0), e1 = fast_exp(t1);
                S += e0 + e1;
                T = fmaf(e0, t0, fmaf(e1, t1, T));
                m = fminf(m, fminf(d0, d1));
            }
#pragma unroll
            for (int o = 1; o < 4; o <<= 1) {
                S += __shfl_xor_sync(0xffffffffu, S, o);
                T += __shfl_xor_sync(0xffffffffu, T, o);
                m = fminf(m, __shfl_xor_sync(0xffffffffu, m, o));
            }
            if ((lane & 3) == 0) {
                int row = wr + mi * 16 + half * 8 + rsub;
                rS[cg * 128 + row] = S;
                rT[cg * 128 + row] = T;
                rM[cg * 128 + row] = m;
            }
        }
    }
    __syncthreads();
    if (tid < 128) {
        float S = rS[tid] + rS[128 + tid] + rS[256 + tid] + rS[384 + tid];
        float T = rT[tid] + rT[128 + tid] + rT[256 + tid] + rT[384 + tid];
        float m = fminf(fminf(rM[tid], rM[128 + tid]), fminf(rM[256 + tid], rM[384 + tid]));
        size_t o = (size_t)blockIdx.x * NTOK + bm + tid;
        g_Sp[o] = S; g_Tp[o] = T; g_Mp[o] = m;
    }

    // ---- quantize to int8, smem stage (144B pitch), coalesced stores ----
    signed char* epi = (signed char*)smem;
    {
        const int r0 = wr + (lane >> 2);
        const int c0 = wc + (lane & 3) * 2;
#pragma unroll
        for (int mi = 0; mi < 4; mi++)
#pragma unroll
            for (int ni = 0; ni < 4; ni++) {
                int rr = r0 + mi * 16, cc = c0 + ni * 8;
                epi[rr * 144 + cc]       = q8(acc[mi][ni][0]);
                epi[rr * 144 + cc + 1]   = q8(acc[mi][ni][1]);
                epi[(rr+8) * 144 + cc]     = q8(acc[mi][ni][2]);
                epi[(rr+8) * 144 + cc + 1] = q8(acc[mi][ni][3]);
            }
    }
    __syncthreads();
#pragma unroll
    for (int j = 0; j < 4; j++) {
        int idx = j * 256 + tid;
        int row = idx >> 3, c16 = idx & 7;
        uint4 v = *(uint4*)(epi + row * 144 + c16 * 16);
        *(uint4*)(g_d8 + (size_t)(bm + row) * NE + bn + c16 * 16) = v;
    }
}

// ---------------- bf16-split TC GEMM (cp.async pipeline): g_eproj = embed @ W_out^T ----------------
#define EPSTG (4 * STG)
#define SMEM_EP (2 * EPSTG)

__global__ void __launch_bounds__(256)
eproj_kernel() {
    extern __shared__ __align__(16) char smem[];
    const int tid = threadIdx.x;
    const int bm = blockIdx.y * 128, bn = blockIdx.x * 128;
    const int wid = tid >> 5, lane = tid & 31;
    const int wr = (wid & 1) * 64;
    const int wc = (wid >> 1) * 32;

    uint32_t sb = smem_u32(smem);
    uint32_t aOff = (uint32_t)(((wr + (lane & 15)) * SSTP + (lane >> 4) * 8) * 2);
    uint32_t bRow = (uint32_t)(wc + (lane & 7) + ((lane >> 4) << 3));
    uint32_t bOff = (uint32_t)((bRow * SSTP + ((lane >> 3) & 1) * 8) * 2);

    const char* gAh = (const char*)g_eh + (size_t)bm * 512;
    const char* gAl = (const char*)g_el + (size_t)bm * 512;
    const char* gBh = (const char*)g_wh + (size_t)bn * 512;
    const char* gBl = (const char*)g_wl + (size_t)bn * 512;
    const int lrow = tid >> 3, lc8 = tid & 7;

    float acc[4][4][4] = {};

#pragma unroll
    for (int pc = 0; pc < 2; pc++) {
        uint32_t st = sb + (uint32_t)pc * EPSTG;
#pragma unroll
        for (int j = 0; j < 4; j++) {
            int row = lrow + j * 32;
            uint32_t so = (uint32_t)((row * SSTP + lc8 * 8) * 2);
            size_t go = (size_t)row * 512 + pc * 128 + lc8 * 16;
            cp16(st + so,           gAh + go);
            cp16(st + STG + so,     gAl + go);
            cp16(st + 2 * STG + so, gBh + go);
            cp16(st + 3 * STG + so, gBl + go);
        }
        CP_COMMIT();
    }

#pragma unroll
    for (int kc = 0; kc < 4; kc++) {
        if (kc < 3) asm volatile("cp.async.wait_group 1;");
        else        asm volatile("cp.async.wait_group 0;");
        __syncthreads();
        uint32_t st = sb + (uint32_t)(kc & 1) * EPSTG;
        const uint32_t AH = st, AL = st + STG, BH = st + 2 * STG, BL = st + 3 * STG;
#pragma unroll
        for (int kk = 0; kk < 4; kk++) {
            uint32_t ko = (uint32_t)kk * 32;
            uint32_t ah[4][4], al[4][4], bh[2][4], bl[2][4];
#pragma unroll
            for (int mi = 0; mi < 4; mi++) {
                ldsm4(ah[mi], AH + aOff + mi * (16 * SSTP * 2) + ko);
                ldsm4(al[mi], AL + aOff + mi * (16 * SSTP * 2) + ko);
            }
#pragma unroll
            for (int n2 = 0; n2 < 2; n2++) {
                ldsm4(bh[n2], BH + bOff + n2 * (16 * SSTP * 2) + ko);
                ldsm4(bl[n2], BL + bOff + n2 * (16 * SSTP * 2) + ko);
            }
#pragma unroll
            for (int mi = 0; mi < 4; mi++)
#pragma unroll
                for (int ni = 0; ni < 4; ni++) {
                    uint32_t h0 = bh[ni >> 1][(ni & 1) * 2], h1 = bh[ni >> 1][(ni & 1) * 2 + 1];
                    uint32_t l0 = bl[ni >> 1][(ni & 1) * 2], l1 = bl[ni >> 1][(ni & 1) * 2 + 1];
                    mma_bf16(acc[mi][ni], ah[mi], h0, h1);
                    mma_bf16(acc[mi][ni], ah[mi], l0, l1);
                    mma_bf16(acc[mi][ni], al[mi], h0, h1);
                }
        }
        __syncthreads();
        if (kc + 2 < 4) {
            uint32_t st2 = sb + (uint32_t)(kc & 1) * EPSTG;
#pragma unroll
            for (int j = 0; j < 4; j++) {
                int row = lrow + j * 32;
                uint32_t so = (uint32_t)((row * SSTP + lc8 * 8) * 2);
                size_t go = (size_t)row * 512 + (kc + 2) * 128 + lc8 * 16;
                cp16(st2 + so,           gAh + go);
                cp16(st2 + STG + so,     gAl + go);
                cp16(st2 + 2 * STG + so, gBh + go);
                cp16(st2 + 3 * STG + so, gBl + go);
            }
            CP_COMMIT();
        }
    }

    __syncthreads();
    float* epi = (float*)smem;
    {
        const int r0 = wr + (lane >> 2);
        const int c0 = wc + (lane & 3) * 2;
#pragma unroll
        for (int mi = 0; mi < 4; mi++)
#pragma unroll
            for (int ni = 0; ni < 4; ni++) {
                int rr = r0 + mi * 16, cc = c0 + ni * 8;
                *(float2*)(epi + rr * 132 + cc) = make_float2(acc[mi][ni][0], acc[mi][ni][1]);
                *(float2*)(epi + (rr + 8) * 132 + cc) = make_float2(acc[mi][ni][2], acc[mi][ni][3]);
            }
    }
    __syncthreads();
#pragma unroll
    for (int j = 0; j < 16; j++) {
        int idx = j * 256 + tid;
        int row = idx >> 5, c4 = idx & 31;
        uint4 v = *(uint4*)(epi + row * 132 + c4 * 4);
        *(uint4*)(g_eproj + (size_t)(bm + row) * ODIM + bn + c4 * 4) = v;
    }
}

// ---------------- gather: z_q_out[r] = g_eproj[ind_r] + b_out ----------------
__global__ void gather_kernel(const float* __restrict__ b_out, float* __restrict__ out) {
    int r = blockIdx.x, t = threadIdx.x;
    int ind = (int)out[OFF_IND + r];
    const float* src = g_eproj + (size_t)ind * ODIM;
    float* dst = out + OFF_ZQ + (size_t)r * ODIM;
#pragma unroll
    for (int c = t; c < ODIM; c += 256)
        dst[c] = src[c] + b_out[c];
}

// ---------------- row finalize: reduce partials, candidate scan, exact argmin ----------------
__global__ void __launch_bounds__(256)
row_finalize_kernel(const float* __restrict__ embed, float* __restrict__ out) {
    const int r = blockIdx.x, t = threadIdx.x;
    __shared__ float pS[64], pT[64], pM[64];
    __shared__ float sxn[256];
    __shared__ float sred[256];
    __shared__ int scnt;
    __shared__ int scand[64];
    __shared__ unsigned long long sbest;

    if (t < 64) {
        size_t o = (size_t)t * NTOK + r;
        pS[t] = g_Sp[o]; pT[t] = g_Tp[o]; pM[t] = g_Mp[o];
    }
    sxn[t] = g_xn[(size_t)r * EDIM + t];
    if (t == 0) { scnt = 0; sbest = ~0ULL; }
    __syncthreads();
    for (int s = 32; s > 0; s >>= 1) {
        if (t < s) {
            pS[t] += pS[t+s]; pT[t] += pT[t+s]; pM[t] = fminf(pM[t], pM[t+s]);
        }
        __syncthreads();
    }
    float Stot = pS[0], Ttot = pT[0], gmin = pM[0];

    // widened window: guarantees true argmin's int8 code is inside even at worst-case
    // acc-vs-exact (1.2e-3) + quantization (4e-3) + rounding edges
    int qthr = (int)floorf((gmin + 2.0e-2f) * QSCALE);
    if (qthr > 127) qthr = 127;
    uint32_t thr4 = (uint32_t)(qthr & 0xff) * 0x01010101u;

    const uint32_t* dp = (const uint32_t*)(g_d8 + (size_t)r * NE);
#pragma unroll
    for (int j = 0; j < 8; j++) {
        uint32_t u = dp[t + j * 256];
        uint32_t m = __vcmples4(u, thr4);
        if (m) {
#pragma unroll
            for (int b = 0; b < 4; b++)
                if ((m >> (8 * b)) & 1) {
                    int p = atomicAdd(&scnt, 1);
                    if (p < 64) scand[p] = (t + 256 * j) * 4 + b;
                }
        }
    }
    __syncthreads();
    int ncand = scnt < 64 ? scnt : 64;
    int ind;
    if (ncand == 1) {
        ind = scand[0];
    } else {
        for (int i = 0; i < ncand; i++) {
            const float* er = embed + (size_t)scand[i] * EDIM;
            sred[t] = sxn[t] * er[t];
            __syncthreads();
            for (int s = 128; s > 0; s >>= 1) { if (t < s) sred[t] += sred[t+s]; __syncthreads(); }
            if (t == 0) {
                unsigned u = __float_as_uint(sred[0]);
                u = (u & 0x80000000u) ? ~u : (u | 0x80000000u);
                unsigned long long k = ((unsigned long long)u << 32) | (unsigned)scand[i];
                if (k < sbest) sbest = k;
            }
            __syncthreads();
        }
        ind = (int)(sbest & 0xffffffffu);
    }

    float xnv = sxn[t];
    float ev = embed[(size_t)ind * EDIM + t];
    float df = ev - xnv;
    sred[t] = df * df;
    atomicAdd(&g_embed_sum[(size_t)ind * EDIM + t], xnv);
    __syncthreads();
    for (int s = 128; s > 0; s >>= 1) { if (t < s) sred[t] += sred[t+s]; __syncthreads(); }
    if (t == 0) {
        atomicAdd(&g_scal[0], sred[0]);
        out[OFF_IND + r] = (float)ind;
        atomicAdd(&g_bins[ind], 1.0f);
        atomicAdd(&g_scal[1], logf(Stot) - Ttot / Stot);
        g_invS[r] = 1.0f / Stot;
    }
}

// ---------------- ap column pass (replicated conflict-free LUT, 4 cols/thread) ----------------
__global__ void __launch_bounds__(256)
ap_kernel() {
    __shared__ float lut[8192];     // lut[b*32 + lane], bank == lane: conflict-free
    __shared__ float sh_inv[256];
    int t = threadIdx.x, lane = t & 31;
    for (int i = t; i < 8192; i += 256) {
        int b = i >> 5;
        int q = (b < 128) ? b : b - 256;
        lut[i] = fast_exp(10.f * (float)q * QINV);
    }
    int c0 = (blockIdx.x * 256 + t) * 4;
    int r0 = blockIdx.y * 1024;
    float a0 = 0.f, a1 = 0.f, a2 = 0.f, a3 = 0.f;
    for (int rr = 0; rr < 1024; rr += 256) {
        __syncthreads();
        sh_inv[t] = g_invS[r0 + rr + t];
        __syncthreads();
        const signed char* ep = g_d8 + (size_t)(r0 + rr) * NE + c0;
#pragma unroll 4
        for (int j = 0; j < 256; j++) {
            uint32_t w = *(const uint32_t*)(ep + (size_t)j * NE);
            float inv = sh_inv[j];
            a0 = fmaf(lut[((w & 255u) << 5) | lane], inv, a0);
            a1 = fmaf(lut[(((w >> 8) & 255u) << 5) | lane], inv, a1);
            a2 = fmaf(lut[(((w >> 16) & 255u) << 5) | lane], inv, a2);
            a3 = fmaf(lut[((w >> 24) << 5) | lane], inv, a3);
        }
    }
    atomicAdd(&g_ap[c0],     a0);
    atomicAdd(&g_ap[c0 + 1], a1);
    atomicAdd(&g_ap[c0 + 2], a2);
    atomicAdd(&g_ap[c0 + 3], a3);
}

// ---------------- code updates ----------------
__global__ void e1_kernel(const float* __restrict__ cluster_size, float* __restrict__ out) {
    int i = blockIdx.x * 256 + threadIdx.x;
    if (i >= NE) return;
    float cn = cluster_size[i] * 0.99f + g_bins[i] * 0.01f;
    g_cluster_new[i] = cn;
    int ex = (cn < 0.1f);
    g_expired[i] = ex;
    out[OFF_CS + i] = ex ? 0.12f : cn;
    atomicAdd(&g_scal[2], cn);
}

__global__ void scan_kernel() {
    int t = threadIdx.x;
    __shared__ int sh[1024];
    int vals[8]; int s = 0;
#pragma unroll
    for (int j = 0; j < 8; j++) { s += g_expired[t*8 + j]; vals[j] = s; }
    sh[t] = s;
    __syncthreads();
    for (int off = 1; off < 1024; off <<= 1) {
        int v = (t >= off) ? sh[t - off] : 0;
        __syncthreads();
        sh[t] += v;
        __syncthreads();
    }
    int excl = (t > 0) ? sh[t-1] : 0;
#pragma unroll
    for (int j = 0; j < 8; j++) {
        int cum = excl + vals[j];
        int idx = cum - 1; if (idx < 0) idx = 0;
        g_sampidx[t*8 + j] = idx;
    }
}

__global__ void e3_kernel(const float* __restrict__ embed_avg, float* __restrict__ out) {
    int c = blockIdx.x, k = threadIdx.x;
    float ea = embed_avg[(size_t)c * EDIM + k] * 0.99f + g_embed_sum[(size_t)c * EDIM + k] * 0.01f;
    float total = g_scal[2];
    float cn = g_cluster_new[c];
    float cs = (cn + 1e-5f) / (total + (float)NE * 1e-5f) * total;
    float en = ea / cs;
    float ef, eaf;
    if (g_expired[c]) {
        float sv = g_xn[(size_t)g_sampidx[c] * EDIM + k];
        ef = sv; eaf = sv * 0.12f;
    } else { ef = en; eaf = ea; }
    out[OFF_EMB  + (size_t)c * EDIM + k] = ef;
    out[OFF_EAVG + (size_t)c * EDIM + k] = eaf;
}

__global__ void scalars_kernel(float* __restrict__ out) {
    int t = threadIdx.x;
    __shared__ float sh[1024];
    float local = 0.f;
#pragma unroll
    for (int j = 0; j < 8; j++) {
        float ap = g_ap[t*8 + j] * (1.0f / (float)NTOK);
        local -= ap * logf(ap);
    }
    sh[t] = local;
    __syncthreads();
    for (int s = 512; s > 0; s >>= 1) { if (t < s) sh[t] += sh[t+s]; __syncthreads(); }
    if (t == 0) {
        float ent_max = sh[0];
        float commit  = g_scal[0] / ((float)NTOK * (float)EDIM);
        out[OFF_LOSS]   = commit - ent_max;
        out[OFF_ENTMIN] = g_scal[1] / (float)NTOK;
        out[OFF_COMMIT] = commit;
    }
}

// ---------------- launch ----------------
extern "C" void kernel_launch(void* const* d_in, const int* in_sizes, int n_in,
                              void* d_out, int out_size) {
    const float* x         = (const float*)d_in[0];
    const float* W_in      = (const float*)d_in[1];
    const float* b_in      = (const float*)d_in[2];
    const float* W_out     = (const float*)d_in[3];
    const float* b_out     = (const float*)d_in[4];
    const float* embed     = (const float*)d_in[5];
    const float* embed_avg = (const float*)d_in[6];
    const float* cluster   = (const float*)d_in[7];
    float* out = (float*)d_out;

    void *p_xn=nullptr, *p_a=nullptr, *p_eh=nullptr, *p_el=nullptr, *p_wh=nullptr, *p_wl=nullptr;
    cudaGetSymbolAddress(&p_xn, g_xn);
    cudaGetSymbolAddress(&p_a, g_a);
    cudaGetSymbolAddress(&p_eh, g_eh);
    cudaGetSymbolAddress(&p_el, g_el);
    cudaGetSymbolAddress(&p_wh, g_wh);
    cudaGetSymbolAddress(&p_wl, g_wl);

    cudaFuncSetAttribute(mma_d_kernel, cudaFuncAttributeMaxDynamicSharedMemorySize, SMEM_MMA);
    cudaFuncSetAttribute(eproj_kernel, cudaFuncAttributeMaxDynamicSharedMemorySize, SMEM_EP);

    // order: gemm_bias at ncu-profiled slot #4 (verify LDS vectorization)
    conv_split_kernel<<<NE*EDIM/8/256, 256>>>(embed, (__nv_bfloat16*)p_eh,
                                              (__nv_bfloat16*)p_el);               // 1
    zero_kernel<<<8192, 256>>>();                                                  // 2
    conv_split_kernel<<<ODIM*EDIM/8/256, 256>>>(W_out, (__nv_bfloat16*)p_wh,
                                                (__nv_bfloat16*)p_wl);             // 3
    gemm_bias_kernel<<<dim3(EDIM/128, NTOK/128), 256>>>(x, W_in, b_in, (float*)p_xn,
                                                        NTOK, EDIM, LAT);          // 4 <- profile
    l2norm_kernel<<<NTOK, 256>>>((float*)p_xn, (__nv_bfloat16*)p_a);               // 5
    mma_d_kernel<<<dim3(NE/128, NTOK/128), 256, SMEM_MMA>>>();                     // 6
    row_finalize_kernel<<<NTOK, 256>>>(embed, out);                                // 7
    eproj_kernel<<<dim3(ODIM/128, NE/128), 256, SMEM_EP>>>();                      // 8
    ap_kernel<<<dim3(NE/1024, NTOK/1024), 256>>>();                                // 9
    e1_kernel<<<NE/256, 256>>>(cluster, out);                                      // 10
    scan_kernel<<<1, 1024>>>();                                                    // 11
    scalars_kernel<<<1, 1024>>>(out);                                              // 12
    e3_kernel<<<NE, 256>>>(embed_avg, out);                                        // 13
    gather_kernel<<<NTOK, 256>>>(b_out, out);                                      // 14
}

// round 12
// speedup vs baseline: 2.9742x; 1.0135x over previous
#include <cuda_runtime.h>
#include <cuda_bf16.h>
#include <math.h>
#include <stdint.h>

// ---------------- problem constants ----------------
#define NTOK   16384
#define EDIM   256
#define NE     8192
#define LAT    768
#define ODIM   768

// output layout (concatenated tuple, float32)
#define OFF_ZQ     ((size_t)0)
#define OFF_IND    ((size_t)12582912)
#define OFF_LOSS   ((size_t)12599296)
#define OFF_EMB    ((size_t)12599297)
#define OFF_EAVG   ((size_t)14696449)
#define OFF_CS     ((size_t)16793601)
#define OFF_ENTMIN ((size_t)16801793)
#define OFF_COMMIT ((size_t)16801794)

#define QSCALE 126.0f
#define QINV   (1.0f / 126.0f)

// ---------------- device scratch ----------------
__device__ signed char g_d8[(size_t)NTOK * NE];     // approx d, int8 (128MB)
__device__ __nv_bfloat16 g_a[(size_t)NTOK * EDIM];  // xn bf16
__device__ __nv_bfloat16 g_eh[(size_t)NE * EDIM];   // embed hi (also mma_d B)
__device__ __nv_bfloat16 g_el[(size_t)NE * EDIM];   // embed lo
__device__ __nv_bfloat16 g_wh[(size_t)ODIM * EDIM]; // W_out hi
__device__ __nv_bfloat16 g_wl[(size_t)ODIM * EDIM]; // W_out lo
__device__ float g_eproj[(size_t)NE * ODIM];        // embed @ W_out^T
__device__ float g_xn[NTOK * EDIM];
__device__ float g_Sp[(size_t)64 * NTOK];           // per-(bn,row) S partials
__device__ float g_Tp[(size_t)64 * NTOK];
__device__ float g_Mp[(size_t)64 * NTOK];
__device__ float g_invS[NTOK];
__device__ float g_bins[NE];
__device__ float g_ap[NE];
__device__ float g_cluster_new[NE];
__device__ int   g_expired[NE];
__device__ int   g_sampidx[NE];
__device__ float g_embed_sum[NE * EDIM];
__device__ float g_scal[4];   // 0: commit sum, 1: entmin sum, 2: total cluster

// ---------------- fast exp (FFMA only) ----------------
__device__ __forceinline__ float fast_exp(float x) {
    float z = x * 1.4426950408889634f;
    int   i = __float2int_rn(z);
    float rf = (float)i;
    float g = fmaf(rf, -0.693359375f, x);
    g = fmaf(rf, 2.12194440e-4f, g);
    float p = 1.98412698e-4f;
    p = fmaf(p, g, 1.38888889e-3f);
    p = fmaf(p, g, 8.33333333e-3f);
    p = fmaf(p, g, 4.16666667e-2f);
    p = fmaf(p, g, 1.66666667e-1f);
    p = fmaf(p, g, 0.5f);
    p = fmaf(p, g, 1.0f);
    p = fmaf(p, g, 1.0f);
    float sc = __int_as_float((i + 127) << 23);
    return p * sc;
}

// ---------------- warp MMA / async-copy helpers ----------------
__device__ __forceinline__ uint32_t smem_u32(const void* p) {
    uint32_t a;
    asm("{ .reg .u64 t; cvta.to.shared.u64 t, %1; cvt.u32.u64 %0, t; }" : "=r"(a) : "l"(p));
    return a;
}
__device__ __forceinline__ void ldsm4(uint32_t* r, uint32_t addr) {
    asm volatile("ldmatrix.sync.aligned.m8n8.x4.shared.b16 {%0,%1,%2,%3}, [%4];"
                 : "=r"(r[0]), "=r"(r[1]), "=r"(r[2]), "=r"(r[3]) : "r"(addr));
}
__device__ __forceinline__ void mma_bf16(float* c, const uint32_t* a, uint32_t b0, uint32_t b1) {
    asm volatile("mma.sync.aligned.m16n8k16.row.col.f32.bf16.bf16.f32 "
                 "{%0,%1,%2,%3}, {%4,%5,%6,%7}, {%8,%9}, {%0,%1,%2,%3};"
                 : "+f"(c[0]), "+f"(c[1]), "+f"(c[2]), "+f"(c[3])
                 : "r"(a[0]), "r"(a[1]), "r"(a[2]), "r"(a[3]), "r"(b0), "r"(b1));
}
__device__ __forceinline__ void cp16(uint32_t dst, const void* src) {
    asm volatile("cp.async.cg.shared.global [%0], [%1], 16;" :: "r"(dst), "l"(src));
}
#define CP_COMMIT() asm volatile("cp.async.commit_group;")

__device__ __forceinline__ signed char q8(float d) {
    float v = fminf(fmaxf(d * QSCALE, -127.f), 127.f);
    return (signed char)__float2int_rn(v);
}

// ---------------- zeroing ----------------
__global__ void zero_kernel() {
    int i = blockIdx.x * 256 + threadIdx.x;
    if (i < NE * EDIM) g_embed_sum[i] = 0.f;
    if (i < NE)   { g_bins[i] = 0.f; g_ap[i] = 0.f; }
    if (i < 4)    g_scal[i] = 0.f;
}

// ---------------- fp32 SGEMM, double-buffered + vectorized LDS ----------------
__global__ void __launch_bounds__(256)
gemm_bias_kernel(const float* __restrict__ A, const float* __restrict__ W,
                 const float* __restrict__ bias, float* __restrict__ C,
                 int M, int N, int K) {
    __shared__ float As[2][8][132];
    __shared__ float Ws[2][8][132];
    const int tid = threadIdx.x;
    const int tx = tid & 15, ty = tid >> 4;
    const int bm = blockIdx.y * 128, bn = blockIdx.x * 128;
    float acc[8][8] = {};
    const int lrow = tid >> 1;
    const int lk4  = (tid & 1) * 4;
    const float* Ap = A + (size_t)(bm + lrow) * K + lk4;
    const float* Wp = W + (size_t)(bn + lrow) * K + lk4;
    const int NIT = K >> 3;

    float4 av = *(const float4*)(Ap);
    float4 wv = *(const float4*)(Wp);
    As[0][lk4+0][lrow]=av.x; As[0][lk4+1][lrow]=av.y; As[0][lk4+2][lrow]=av.z; As[0][lk4+3][lrow]=av.w;
    Ws[0][lk4+0][lrow]=wv.x; Ws[0][lk4+1][lrow]=wv.y; Ws[0][lk4+2][lrow]=wv.z; Ws[0][lk4+3][lrow]=wv.w;
    __syncthreads();

    for (int it = 0; it < NIT; it++) {
        int cur = it & 1;
        if (it + 1 < NIT) {
            av = *(const float4*)(Ap + (it + 1) * 8);
            wv = *(const float4*)(Wp + (it + 1) * 8);
        }
#pragma unroll
        for (int k = 0; k < 8; k++) {
            float4 a0 = *(const float4*)&As[cur][k][ty * 8];
            float4 a1 = *(const float4*)&As[cur][k][ty * 8 + 4];
            float2 b0 = *(const float2*)&Ws[cur][k][tx * 2];
            float2 b1 = *(const float2*)&Ws[cur][k][32 + tx * 2];
            float2 b2 = *(const float2*)&Ws[cur][k][64 + tx * 2];
            float2 b3 = *(const float2*)&Ws[cur][k][96 + tx * 2];
            float a[8] = {a0.x, a0.y, a0.z, a0.w, a1.x, a1.y, a1.z, a1.w};
            float b[8] = {b0.x, b0.y, b1.x, b1.y, b2.x, b2.y, b3.x, b3.y};
#pragma unroll
            for (int ir = 0; ir < 8; ir++)
#pragma unroll
                for (int ic = 0; ic < 8; ic++)
                    acc[ir][ic] = fmaf(a[ir], b[ic], acc[ir][ic]);
        }
        if (it + 1 < NIT) {
            int nxt = cur ^ 1;
            As[nxt][lk4+0][lrow]=av.x; As[nxt][lk4+1][lrow]=av.y; As[nxt][lk4+2][lrow]=av.z; As[nxt][lk4+3][lrow]=av.w;
            Ws[nxt][lk4+0][lrow]=wv.x; Ws[nxt][lk4+1][lrow]=wv.y; Ws[nxt][lk4+2][lrow]=wv.z; Ws[nxt][lk4+3][lrow]=wv.w;
        }
        __syncthreads();
    }
#pragma unroll
    for (int ir = 0; ir < 8; ir++) {
        int row = bm + ty * 8 + ir;
#pragma unroll
        for (int ic2 = 0; ic2 < 4; ic2++) {
            int col = bn + ic2 * 32 + tx * 2;
            float2 v = make_float2(acc[ir][ic2*2]   + bias[col],
                                   acc[ir][ic2*2+1] + bias[col + 1]);
            *(float2*)(C + (size_t)row * N + col) = v;
        }
    }
}

// ---------------- row l2-normalize, fused bf16 output ----------------
__global__ void l2norm_kernel(float* __restrict__ x, __nv_bfloat16* __restrict__ xb) {
    int r = blockIdx.x, t = threadIdx.x;
    __shared__ float sh[256];
    float v = x[(size_t)r * EDIM + t];
    sh[t] = v * v;
    __syncthreads();
    for (int s = 128; s > 0; s >>= 1) { if (t < s) sh[t] += sh[t+s]; __syncthreads(); }
    float nrm = sqrtf(sh[0]);
    float xn = v / nrm;
    x[(size_t)r * EDIM + t] = xn;
    xb[(size_t)r * EDIM + t] = __float2bfloat16(xn);
}

// ---------------- fp32 -> bf16 hi/lo split ----------------
__global__ void conv_split_kernel(const float* __restrict__ src,
                                  __nv_bfloat16* __restrict__ hi,
                                  __nv_bfloat16* __restrict__ lo) {
    int i = blockIdx.x * 256 + threadIdx.x;   // 8 elems
    float v[8];
    float4 v0 = ((const float4*)src)[2*i];
    float4 v1 = ((const float4*)src)[2*i+1];
    v[0]=v0.x; v[1]=v0.y; v[2]=v0.z; v[3]=v0.w;
    v[4]=v1.x; v[5]=v1.y; v[6]=v1.z; v[7]=v1.w;
    __nv_bfloat16 h[8], l[8];
#pragma unroll
    for (int j = 0; j < 8; j++) {
        h[j] = __float2bfloat16(v[j]);
        l[j] = __float2bfloat16(v[j] - __bfloat162float(h[j]));
    }
    uint4 ph, pl;
    ph.x = *(uint32_t*)&h[0]; ph.y = *(uint32_t*)&h[2];
    ph.z = *(uint32_t*)&h[4]; ph.w = *(uint32_t*)&h[6];
    pl.x = *(uint32_t*)&l[0]; pl.y = *(uint32_t*)&l[2];
    pl.z = *(uint32_t*)&l[4]; pl.w = *(uint32_t*)&l[6];
    ((uint4*)hi)[i] = ph;
    ((uint4*)lo)[i] = pl;
}

// ---------------- bf16 TC d-GEMM, cp.async 3-stage pipeline, fused S/T/min epilogue ----------------
#define SSTP 72
#define STG  (128 * SSTP * 2)          // 18432 B per matrix-stage
#define NSTAGE 3
#define SMEM_MMA (NSTAGE * 2 * STG)    // 110592 B (2 CTAs/SM: 221184 <= 228KB)

__global__ void __launch_bounds__(256, 2)
mma_d_kernel() {
    extern __shared__ __align__(16) char smem[];
    const int tid = threadIdx.x;
    const int bm = blockIdx.y * 128, bn = blockIdx.x * 128;
    const int wid = tid >> 5, lane = tid & 31;
    const int wr = (wid & 1) * 64;
    const int wc = (wid >> 1) * 32;

    uint32_t sb = smem_u32(smem);
    uint32_t aOff = (uint32_t)(((wr + (lane & 15)) * SSTP + (lane >> 4) * 8) * 2);
    uint32_t bRow = (uint32_t)(wc + (lane & 7) + ((lane >> 4) << 3));
    uint32_t bOff = (uint32_t)((bRow * SSTP + ((lane >> 3) & 1) * 8) * 2);

    const char* gA = (const char*)g_a  + (size_t)bm * 512;
    const char* gB = (const char*)g_eh + (size_t)bn * 512;
    const int lrow = tid >> 3, lc8 = tid & 7;

    float acc[4][4][4] = {};

    // prologue: chunks 0,1 -> stages 0,1
#pragma unroll
    for (int pc = 0; pc < 2; pc++) {
        uint32_t dstA = sb + (uint32_t)pc * 2 * STG;
        uint32_t dstB = dstA + STG;
#pragma unroll
        for (int j = 0; j < 4; j++) {
            int row = lrow + j * 32;
            uint32_t so = (uint32_t)((row * SSTP + lc8 * 8) * 2);
            cp16(dstA + so, gA + (size_t)row * 512 + pc * 128 + lc8 * 16);
            cp16(dstB + so, gB + (size_t)row * 512 + pc * 128 + lc8 * 16);
        }
        CP_COMMIT();
    }

#pragma unroll
    for (int kc = 0; kc < 4; kc++) {
        if (kc < 3) asm volatile("cp.async.wait_group 1;");
        else        asm volatile("cp.async.wait_group 0;");
        __syncthreads();   // stage kc%3 ready for all; stage (kc+2)%3 free (read finished pre-sync)
        // issue next chunk first (full overlap with compute below)
        if (kc + 2 < 4) {
            int st = (kc + 2) % NSTAGE;
            uint32_t dstA = sb + (uint32_t)st * 2 * STG;
            uint32_t dstB = dstA + STG;
#pragma unroll
            for (int j = 0; j < 4; j++) {
                int row = lrow + j * 32;
                uint32_t so = (uint32_t)((row * SSTP + lc8 * 8) * 2);
                cp16(dstA + so, gA + (size_t)row * 512 + (kc + 2) * 128 + lc8 * 16);
                cp16(dstB + so, gB + (size_t)row * 512 + (kc + 2) * 128 + lc8 * 16);
            }
            CP_COMMIT();
        }
        uint32_t stA = sb + (uint32_t)(kc % NSTAGE) * 2 * STG;
        uint32_t stB = stA + STG;
#pragma unroll
        for (int kk = 0; kk < 4; kk++) {
            uint32_t ko = (uint32_t)kk * 32;
            uint32_t aF[4][4], bF[2][4];
#pragma unroll
            for (int mi = 0; mi < 4; mi++) ldsm4(aF[mi], stA + aOff + mi * (16 * SSTP * 2) + ko);
#pragma unroll
            for (int n2 = 0; n2 < 2; n2++) ldsm4(bF[n2], stB + bOff + n2 * (16 * SSTP * 2) + ko);
#pragma unroll
            for (int mi = 0; mi < 4; mi++)
#pragma unroll
                for (int ni = 0; ni < 4; ni++)
                    mma_bf16(acc[mi][ni], aF[mi], bF[ni >> 1][(ni & 1) * 2], bF[ni >> 1][(ni & 1) * 2 + 1]);
        }
    }

    __syncthreads();

    // ---- fused per-row S/T/min partials (from fp32 acc) ----
    float* rS = (float*)(smem + 36864);   // [4][128] (inside stage 1/2 region, post-compute)
    float* rT = rS + 512;
    float* rM = rT + 512;
    const int cg = wid >> 1;
    const int rsub = lane >> 2;
#pragma unroll
    for (int mi = 0; mi < 4; mi++) {
#pragma unroll
        for (int half = 0; half < 2; half++) {
            float S = 0.f, T = 0.f, m = 1e30f;
#pragma unroll
            for (int ni = 0; ni < 4; ni++) {
                float d0 = acc[mi][ni][half*2], d1 = acc[mi][ni][half*2+1];
                float t0 = 10.f * d0, t1 = 10.f * d1;
                float e0 = fast_exp(t0), e1 = fast_exp(t1);
                S += e0 + e1;
                T = fmaf(e0, t0, fmaf(e1, t1, T));
                m = fminf(m, fminf(d0, d1));
            }
#pragma unroll
            for (int o = 1; o < 4; o <<= 1) {
                S += __shfl_xor_sync(0xffffffffu, S, o);
                T += __shfl_xor_sync(0xffffffffu, T, o);
                m = fminf(m, __shfl_xor_sync(0xffffffffu, m, o));
            }
            if ((lane & 3) == 0) {
                int row = wr + mi * 16 + half * 8 + rsub;
                rS[cg * 128 + row] = S;
                rT[cg * 128 + row] = T;
                rM[cg * 128 + row] = m;
            }
        }
    }
    __syncthreads();
    if (tid < 128) {
        float S = rS[tid] + rS[128 + tid] + rS[256 + tid] + rS[384 + tid];
        float T = rT[tid] + rT[128 + tid] + rT[256 + tid] + rT[384 + tid];
        float m = fminf(fminf(rM[tid], rM[128 + tid]), fminf(rM[256 + tid], rM[384 + tid]));
        size_t o = (size_t)blockIdx.x * NTOK + bm + tid;
        g_Sp[o] = S; g_Tp[o] = T; g_Mp[o] = m;
    }

    // ---- quantize to int8, smem stage (144B pitch), coalesced stores ----
    signed char* epi = (signed char*)smem;
    {
        const int r0 = wr + (lane >> 2);
        const int c0 = wc + (lane & 3) * 2;
#pragma unroll
        for (int mi = 0; mi < 4; mi++)
#pragma unroll
            for (int ni = 0; ni < 4; ni++) {
                int rr = r0 + mi * 16, cc = c0 + ni * 8;
                epi[rr * 144 + cc]       = q8(acc[mi][ni][0]);
                epi[rr * 144 + cc + 1]   = q8(acc[mi][ni][1]);
                epi[(rr+8) * 144 + cc]     = q8(acc[mi][ni][2]);
                epi[(rr+8) * 144 + cc + 1] = q8(acc[mi][ni][3]);
            }
    }
    __syncthreads();
#pragma unroll
    for (int j = 0; j < 4; j++) {
        int idx = j * 256 + tid;
        int row = idx >> 3, c16 = idx & 7;
        uint4 v = *(uint4*)(epi + row * 144 + c16 * 16);
        *(uint4*)(g_d8 + (size_t)(bm + row) * NE + bn + c16 * 16) = v;
    }
}

// ---------------- bf16-split TC GEMM (cp.async pipeline): g_eproj = embed @ W_out^T ----------------
#define EPSTG (4 * STG)
#define SMEM_EP (2 * EPSTG)

__global__ void __launch_bounds__(256)
eproj_kernel() {
    extern __shared__ __align__(16) char smem[];
    const int tid = threadIdx.x;
    const int bm = blockIdx.y * 128, bn = blockIdx.x * 128;
    const int wid = tid >> 5, lane = tid & 31;
    const int wr = (wid & 1) * 64;
    const int wc = (wid >> 1) * 32;

    uint32_t sb = smem_u32(smem);
    uint32_t aOff = (uint32_t)(((wr + (lane & 15)) * SSTP + (lane >> 4) * 8) * 2);
    uint32_t bRow = (uint32_t)(wc + (lane & 7) + ((lane >> 4) << 3));
    uint32_t bOff = (uint32_t)((bRow * SSTP + ((lane >> 3) & 1) * 8) * 2);

    const char* gAh = (const char*)g_eh + (size_t)bm * 512;
    const char* gAl = (const char*)g_el + (size_t)bm * 512;
    const char* gBh = (const char*)g_wh + (size_t)bn * 512;
    const char* gBl = (const char*)g_wl + (size_t)bn * 512;
    const int lrow = tid >> 3, lc8 = tid & 7;

    float acc[4][4][4] = {};

#pragma unroll
    for (int pc = 0; pc < 2; pc++) {
        uint32_t st = sb + (uint32_t)pc * EPSTG;
#pragma unroll
        for (int j = 0; j < 4; j++) {
            int row = lrow + j * 32;
            uint32_t so = (uint32_t)((row * SSTP + lc8 * 8) * 2);
            size_t go = (size_t)row * 512 + pc * 128 + lc8 * 16;
            cp16(st + so,           gAh + go);
            cp16(st + STG + so,     gAl + go);
            cp16(st + 2 * STG + so, gBh + go);
            cp16(st + 3 * STG + so, gBl + go);
        }
        CP_COMMIT();
    }

#pragma unroll
    for (int kc = 0; kc < 4; kc++) {
        if (kc < 3) asm volatile("cp.async.wait_group 1;");
        else        asm volatile("cp.async.wait_group 0;");
        __syncthreads();
        uint32_t st = sb + (uint32_t)(kc & 1) * EPSTG;
        const uint32_t AH = st, AL = st + STG, BH = st + 2 * STG, BL = st + 3 * STG;
#pragma unroll
        for (int kk = 0; kk < 4; kk++) {
            uint32_t ko = (uint32_t)kk * 32;
            uint32_t ah[4][4], al[4][4], bh[2][4], bl[2][4];
#pragma unroll
            for (int mi = 0; mi < 4; mi++) {
                ldsm4(ah[mi], AH + aOff + mi * (16 * SSTP * 2) + ko);
                ldsm4(al[mi], AL + aOff + mi * (16 * SSTP * 2) + ko);
            }
#pragma unroll
            for (int n2 = 0; n2 < 2; n2++) {
                ldsm4(bh[n2], BH + bOff + n2 * (16 * SSTP * 2) + ko);
                ldsm4(bl[n2], BL + bOff + n2 * (16 * SSTP * 2) + ko);
            }
#pragma unroll
            for (int mi = 0; mi < 4; mi++)
#pragma unroll
                for (int ni = 0; ni < 4; ni++) {
                    uint32_t h0 = bh[ni >> 1][(ni & 1) * 2], h1 = bh[ni >> 1][(ni & 1) * 2 + 1];
                    uint32_t l0 = bl[ni >> 1][(ni & 1) * 2], l1 = bl[ni >> 1][(ni & 1) * 2 + 1];
                    mma_bf16(acc[mi][ni], ah[mi], h0, h1);
                    mma_bf16(acc[mi][ni], ah[mi], l0, l1);
                    mma_bf16(acc[mi][ni], al[mi], h0, h1);
                }
        }
        __syncthreads();
        if (kc + 2 < 4) {
            uint32_t st2 = sb + (uint32_t)(kc & 1) * EPSTG;
#pragma unroll
            for (int j = 0; j < 4; j++) {
                int row = lrow + j * 32;
                uint32_t so = (uint32_t)((row * SSTP + lc8 * 8) * 2);
                size_t go = (size_t)row * 512 + (kc + 2) * 128 + lc8 * 16;
                cp16(st2 + so,           gAh + go);
                cp16(st2 + STG + so,     gAl + go);
                cp16(st2 + 2 * STG + so, gBh + go);
                cp16(st2 + 3 * STG + so, gBl + go);
            }
            CP_COMMIT();
        }
    }

    __syncthreads();
    float* epi = (float*)smem;
    {
        const int r0 = wr + (lane >> 2);
        const int c0 = wc + (lane & 3) * 2;
#pragma unroll
        for (int mi = 0; mi < 4; mi++)
#pragma unroll
            for (int ni = 0; ni < 4; ni++) {
                int rr = r0 + mi * 16, cc = c0 + ni * 8;
                *(float2*)(epi + rr * 132 + cc) = make_float2(acc[mi][ni][0], acc[mi][ni][1]);
                *(float2*)(epi + (rr + 8) * 132 + cc) = make_float2(acc[mi][ni][2], acc[mi][ni][3]);
            }
    }
    __syncthreads();
#pragma unroll
    for (int j = 0; j < 16; j++) {
        int idx = j * 256 + tid;
        int row = idx >> 5, c4 = idx & 31;
        uint4 v = *(uint4*)(epi + row * 132 + c4 * 4);
        *(uint4*)(g_eproj + (size_t)(bm + row) * ODIM + bn + c4 * 4) = v;
    }
}

// ---------------- gather: z_q_out[r] = g_eproj[ind_r] + b_out ----------------
__global__ void gather_kernel(const float* __restrict__ b_out, float* __restrict__ out) {
    int r = blockIdx.x, t = threadIdx.x;
    int ind = (int)out[OFF_IND + r];
    const float* src = g_eproj + (size_t)ind * ODIM;
    float* dst = out + OFF_ZQ + (size_t)r * ODIM;
#pragma unroll
    for (int c = t; c < ODIM; c += 256)
        dst[c] = src[c] + b_out[c];
}

// ---------------- row finalize: reduce partials, candidate scan, exact argmin ----------------
__global__ void __launch_bounds__(256)
row_finalize_kernel(const float* __restrict__ embed, float* __restrict__ out) {
    const int r = blockIdx.x, t = threadIdx.x;
    __shared__ float pS[64], pT[64], pM[64];
    __shared__ float sxn[256];
    __shared__ float sred[256];
    __shared__ int scnt;
    __shared__ int scand[64];
    __shared__ unsigned long long sbest;

    if (t < 64) {
        size_t o = (size_t)t * NTOK + r;
        pS[t] = g_Sp[o]; pT[t] = g_Tp[o]; pM[t] = g_Mp[o];
    }
    sxn[t] = g_xn[(size_t)r * EDIM + t];
    if (t == 0) { scnt = 0; sbest = ~0ULL; }
    __syncthreads();
    for (int s = 32; s > 0; s >>= 1) {
        if (t < s) {
            pS[t] += pS[t+s]; pT[t] += pT[t+s]; pM[t] = fminf(pM[t], pM[t+s]);
        }
        __syncthreads();
    }
    float Stot = pS[0], Ttot = pT[0], gmin = pM[0];

    int qthr = (int)floorf((gmin + 2.0e-2f) * QSCALE);
    if (qthr > 127) qthr = 127;
    uint32_t thr4 = (uint32_t)(qthr & 0xff) * 0x01010101u;

    const uint32_t* dp = (const uint32_t*)(g_d8 + (size_t)r * NE);
#pragma unroll
    for (int j = 0; j < 8; j++) {
        uint32_t u = dp[t + j * 256];
        uint32_t m = __vcmples4(u, thr4);
        if (m) {
#pragma unroll
            for (int b = 0; b < 4; b++)
                if ((m >> (8 * b)) & 1) {
                    int p = atomicAdd(&scnt, 1);
                    if (p < 64) scand[p] = (t + 256 * j) * 4 + b;
                }
        }
    }
    __syncthreads();
    int ncand = scnt < 64 ? scnt : 64;
    int ind;
    if (ncand == 1) {
        ind = scand[0];
    } else {
        for (int i = 0; i < ncand; i++) {
            const float* er = embed + (size_t)scand[i] * EDIM;
            sred[t] = sxn[t] * er[t];
            __syncthreads();
            for (int s = 128; s > 0; s >>= 1) { if (t < s) sred[t] += sred[t+s]; __syncthreads(); }
            if (t == 0) {
                unsigned u = __float_as_uint(sred[0]);
                u = (u & 0x80000000u) ? ~u : (u | 0x80000000u);
                unsigned long long k = ((unsigned long long)u << 32) | (unsigned)scand[i];
                if (k < sbest) sbest = k;
            }
            __syncthreads();
        }
        ind = (int)(sbest & 0xffffffffu);
    }

    float xnv = sxn[t];
    float ev = embed[(size_t)ind * EDIM + t];
    float df = ev - xnv;
    sred[t] = df * df;
    atomicAdd(&g_embed_sum[(size_t)ind * EDIM + t], xnv);
    __syncthreads();
    for (int s = 128; s > 0; s >>= 1) { if (t < s) sred[t] += sred[t+s]; __syncthreads(); }
    if (t == 0) {
        atomicAdd(&g_scal[0], sred[0]);
        out[OFF_IND + r] = (float)ind;
        atomicAdd(&g_bins[ind], 1.0f);
        atomicAdd(&g_scal[1], logf(Stot) - Ttot / Stot);
        g_invS[r] = 1.0f / Stot;
    }
}

// ---------------- ap column pass (replicated conflict-free LUT, 4 cols/thread) ----------------
__global__ void __launch_bounds__(256)
ap_kernel() {
    __shared__ float lut[8192];
    __shared__ float sh_inv[256];
    int t = threadIdx.x, lane = t & 31;
    for (int i = t; i < 8192; i += 256) {
        int b = i >> 5;
        int q = (b < 128) ? b : b - 256;
        lut[i] = fast_exp(10.f * (float)q * QINV);
    }
    int c0 = (blockIdx.x * 256 + t) * 4;
    int r0 = blockIdx.y * 1024;
    float a0 = 0.f, a1 = 0.f, a2 = 0.f, a3 = 0.f;
    for (int rr = 0; rr < 1024; rr += 256) {
        __syncthreads();
        sh_inv[t] = g_invS[r0 + rr + t];
        __syncthreads();
        const signed char* ep = g_d8 + (size_t)(r0 + rr) * NE + c0;
#pragma unroll 4
        for (int j = 0; j < 256; j++) {
            uint32_t w = *(const uint32_t*)(ep + (size_t)j * NE);
            float inv = sh_inv[j];
            a0 = fmaf(lut[((w & 255u) << 5) | lane], inv, a0);
            a1 = fmaf(lut[(((w >> 8) & 255u) << 5) | lane], inv, a1);
            a2 = fmaf(lut[(((w >> 16) & 255u) << 5) | lane], inv, a2);
            a3 = fmaf(lut[((w >> 24) << 5) | lane], inv, a3);
        }
    }
    atomicAdd(&g_ap[c0],     a0);
    atomicAdd(&g_ap[c0 + 1], a1);
    atomicAdd(&g_ap[c0 + 2], a2);
    atomicAdd(&g_ap[c0 + 3], a3);
}

// ---------------- code updates ----------------
__global__ void e1_kernel(const float* __restrict__ cluster_size, float* __restrict__ out) {
    int i = blockIdx.x * 256 + threadIdx.x;
    if (i >= NE) return;
    float cn = cluster_size[i] * 0.99f + g_bins[i] * 0.01f;
    g_cluster_new[i] = cn;
    int ex = (cn < 0.1f);
    g_expired[i] = ex;
    out[OFF_CS + i] = ex ? 0.12f : cn;
    atomicAdd(&g_scal[2], cn);
}

__global__ void scan_kernel() {
    int t = threadIdx.x;
    __shared__ int sh[1024];
    int vals[8]; int s = 0;
#pragma unroll
    for (int j = 0; j < 8; j++) { s += g_expired[t*8 + j]; vals[j] = s; }
    sh[t] = s;
    __syncthreads();
    for (int off = 1; off < 1024; off <<= 1) {
        int v = (t >= off) ? sh[t - off] : 0;
        __syncthreads();
        sh[t] += v;
        __syncthreads();
    }
    int excl = (t > 0) ? sh[t-1] : 0;
#pragma unroll
    for (int j = 0; j < 8; j++) {
        int cum = excl + vals[j];
        int idx = cum - 1; if (idx < 0) idx = 0;
        g_sampidx[t*8 + j] = idx;
    }
}

__global__ void e3_kernel(const float* __restrict__ embed_avg, float* __restrict__ out) {
    int c = blockIdx.x, k = threadIdx.x;
    float ea = embed_avg[(size_t)c * EDIM + k] * 0.99f + g_embed_sum[(size_t)c * EDIM + k] * 0.01f;
    float total = g_scal[2];
    float cn = g_cluster_new[c];
    float cs = (cn + 1e-5f) / (total + (float)NE * 1e-5f) * total;
    float en = ea / cs;
    float ef, eaf;
    if (g_expired[c]) {
        float sv = g_xn[(size_t)g_sampidx[c] * EDIM + k];
        ef = sv; eaf = sv * 0.12f;
    } else { ef = en; eaf = ea; }
    out[OFF_EMB  + (size_t)c * EDIM + k] = ef;
    out[OFF_EAVG + (size_t)c * EDIM + k] = eaf;
}

__global__ void scalars_kernel(float* __restrict__ out) {
    int t = threadIdx.x;
    __shared__ float sh[1024];
    float local = 0.f;
#pragma unroll
    for (int j = 0; j < 8; j++) {
        float ap = g_ap[t*8 + j] * (1.0f / (float)NTOK);
        local -= ap * logf(ap);
    }
    sh[t] = local;
    __syncthreads();
    for (int s = 512; s > 0; s >>= 1) { if (t < s) sh[t] += sh[t+s]; __syncthreads(); }
    if (t == 0) {
        float ent_max = sh[0];
        float commit  = g_scal[0] / ((float)NTOK * (float)EDIM);
        out[OFF_LOSS]   = commit - ent_max;
        out[OFF_ENTMIN] = g_scal[1] / (float)NTOK;
        out[OFF_COMMIT] = commit;
    }
}

// ---------------- launch ----------------
extern "C" void kernel_launch(void* const* d_in, const int* in_sizes, int n_in,
                              void* d_out, int out_size) {
    const float* x         = (const float*)d_in[0];
    const float* W_in      = (const float*)d_in[1];
    const float* b_in      = (const float*)d_in[2];
    const float* W_out     = (const float*)d_in[3];
    const float* b_out     = (const float*)d_in[4];
    const float* embed     = (const float*)d_in[5];
    const float* embed_avg = (const float*)d_in[6];
    const float* cluster   = (const float*)d_in[7];
    float* out = (float*)d_out;

    void *p_xn=nullptr, *p_a=nullptr, *p_eh=nullptr, *p_el=nullptr, *p_wh=nullptr, *p_wl=nullptr;
    cudaGetSymbolAddress(&p_xn, g_xn);
    cudaGetSymbolAddress(&p_a, g_a);
    cudaGetSymbolAddress(&p_eh, g_eh);
    cudaGetSymbolAddress(&p_el, g_el);
    cudaGetSymbolAddress(&p_wh, g_wh);
    cudaGetSymbolAddress(&p_wl, g_wl);

    cudaFuncSetAttribute(mma_d_kernel, cudaFuncAttributeMaxDynamicSharedMemorySize, SMEM_MMA);
    cudaFuncSetAttribute(eproj_kernel, cudaFuncAttributeMaxDynamicSharedMemorySize, SMEM_EP);

    // order: eproj at ncu-profiled slot #4 (first measurement of this kernel)
    conv_split_kernel<<<NE*EDIM/8/256, 256>>>(embed, (__nv_bfloat16*)p_eh,
                                              (__nv_bfloat16*)p_el);               // 1
    zero_kernel<<<8192, 256>>>();                                                  // 2
    conv_split_kernel<<<ODIM*EDIM/8/256, 256>>>(W_out, (__nv_bfloat16*)p_wh,
                                                (__nv_bfloat16*)p_wl);             // 3
    eproj_kernel<<<dim3(ODIM/128, NE/128), 256, SMEM_EP>>>();                      // 4 <- profile
    gemm_bias_kernel<<<dim3(EDIM/128, NTOK/128), 256>>>(x, W_in, b_in, (float*)p_xn,
                                                        NTOK, EDIM, LAT);          // 5
    l2norm_kernel<<<NTOK, 256>>>((float*)p_xn, (__nv_bfloat16*)p_a);               // 6
    mma_d_kernel<<<dim3(NE/128, NTOK/128), 256, SMEM_MMA>>>();                     // 7
    row_finalize_kernel<<<NTOK, 256>>>(embed, out);                                // 8
    ap_kernel<<<dim3(NE/1024, NTOK/1024), 256>>>();                                // 9
    e1_kernel<<<NE/256, 256>>>(cluster, out);                                      // 10
    scan_kernel<<<1, 1024>>>();                                                    // 11
    scalars_kernel<<<1, 1024>>>(out);                                              // 12
    e3_kernel<<<NE, 256>>>(embed_avg, out);                                        // 13
    gather_kernel<<<NTOK, 256>>>(b_out, out);                                      // 14
}

// round 13
// speedup vs baseline: 2.9876x; 1.0045x over previous
#include <cuda_runtime.h>
#include <cuda_bf16.h>
#include <math.h>
#include <stdint.h>

// ---------------- problem constants ----------------
#define NTOK   16384
#define EDIM   256
#define NE     8192
#define LAT    768
#define ODIM   768

// output layout (concatenated tuple, float32)
#define OFF_ZQ     ((size_t)0)
#define OFF_IND    ((size_t)12582912)
#define OFF_LOSS   ((size_t)12599296)
#define OFF_EMB    ((size_t)12599297)
#define OFF_EAVG   ((size_t)14696449)
#define OFF_CS     ((size_t)16793601)
#define OFF_ENTMIN ((size_t)16801793)
#define OFF_COMMIT ((size_t)16801794)

#define QSCALE 126.0f
#define QINV   (1.0f / 126.0f)

// ---------------- device scratch ----------------
__device__ signed char g_d8[(size_t)NTOK * NE];     // approx d, int8 (128MB)
__device__ __nv_bfloat16 g_a[(size_t)NTOK * EDIM];  // xn bf16
__device__ __nv_bfloat16 g_eh[(size_t)NE * EDIM];   // embed hi (also mma_d B)
__device__ __nv_bfloat16 g_el[(size_t)NE * EDIM];   // embed lo
__device__ __nv_bfloat16 g_wh[(size_t)ODIM * EDIM]; // W_out hi
__device__ __nv_bfloat16 g_wl[(size_t)ODIM * EDIM]; // W_out lo
__device__ float g_eproj[(size_t)NE * ODIM];        // embed @ W_out^T
__device__ float g_xn[NTOK * EDIM];
__device__ float g_Sp[(size_t)64 * NTOK];           // per-(bn,row) partials
__device__ float g_Tp[(size_t)64 * NTOK];
__device__ float g_Mp[(size_t)64 * NTOK];
__device__ float g_Sf[NTOK];                        // reduced per-row
__device__ float g_Tf[NTOK];
__device__ float g_Mf[NTOK];
__device__ float g_invS[NTOK];
__device__ float g_bins[NE];
__device__ float g_ap[NE];
__device__ float g_cluster_new[NE];
__device__ int   g_expired[NE];
__device__ int   g_sampidx[NE];
__device__ float g_embed_sum[NE * EDIM];
__device__ float g_scal[4];   // 0: commit sum, 1: entmin sum, 2: total cluster

// ---------------- fast exp (FFMA only) ----------------
__device__ __forceinline__ float fast_exp(float x) {
    float z = x * 1.4426950408889634f;
    int   i = __float2int_rn(z);
    float rf = (float)i;
    float g = fmaf(rf, -0.693359375f, x);
    g = fmaf(rf, 2.12194440e-4f, g);
    float p = 1.98412698e-4f;
    p = fmaf(p, g, 1.38888889e-3f);
    p = fmaf(p, g, 8.33333333e-3f);
    p = fmaf(p, g, 4.16666667e-2f);
    p = fmaf(p, g, 1.66666667e-1f);
    p = fmaf(p, g, 0.5f);
    p = fmaf(p, g, 1.0f);
    p = fmaf(p, g, 1.0f);
    float sc = __int_as_float((i + 127) << 23);
    return p * sc;
}

// ---------------- warp MMA / async-copy helpers ----------------
__device__ __forceinline__ uint32_t smem_u32(const void* p) {
    uint32_t a;
    asm("{ .reg .u64 t; cvta.to.shared.u64 t, %1; cvt.u32.u64 %0, t; }" : "=r"(a) : "l"(p));
    return a;
}
__device__ __forceinline__ void ldsm4(uint32_t* r, uint32_t addr) {
    asm volatile("ldmatrix.sync.aligned.m8n8.x4.shared.b16 {%0,%1,%2,%3}, [%4];"
                 : "=r"(r[0]), "=r"(r[1]), "=r"(r[2]), "=r"(r[3]) : "r"(addr));
}
__device__ __forceinline__ void mma_bf16(float* c, const uint32_t* a, uint32_t b0, uint32_t b1) {
    asm volatile("mma.sync.aligned.m16n8k16.row.col.f32.bf16.bf16.f32 "
                 "{%0,%1,%2,%3}, {%4,%5,%6,%7}, {%8,%9}, {%0,%1,%2,%3};"
                 : "+f"(c[0]), "+f"(c[1]), "+f"(c[2]), "+f"(c[3])
                 : "r"(a[0]), "r"(a[1]), "r"(a[2]), "r"(a[3]), "r"(b0), "r"(b1));
}
__device__ __forceinline__ void cp16(uint32_t dst, const void* src) {
    asm volatile("cp.async.cg.shared.global [%0], [%1], 16;" :: "r"(dst), "l"(src));
}
#define CP_COMMIT() asm volatile("cp.async.commit_group;")

__device__ __forceinline__ signed char q8(float d) {
    float v = fminf(fmaxf(d * QSCALE, -127.f), 127.f);
    return (signed char)__float2int_rn(v);
}

// ---------------- zeroing ----------------
__global__ void zero_kernel() {
    int i = blockIdx.x * 256 + threadIdx.x;
    if (i < NE * EDIM) g_embed_sum[i] = 0.f;
    if (i < NE)   { g_bins[i] = 0.f; g_ap[i] = 0.f; }
    if (i < 4)    g_scal[i] = 0.f;
}

// ---------------- fp32 SGEMM, double-buffered + vectorized LDS ----------------
__global__ void __launch_bounds__(256)
gemm_bias_kernel(const float* __restrict__ A, const float* __restrict__ W,
                 const float* __restrict__ bias, float* __restrict__ C,
                 int M, int N, int K) {
    __shared__ float As[2][8][132];
    __shared__ float Ws[2][8][132];
    const int tid = threadIdx.x;
    const int tx = tid & 15, ty = tid >> 4;
    const int bm = blockIdx.y * 128, bn = blockIdx.x * 128;
    float acc[8][8] = {};
    const int lrow = tid >> 1;
    const int lk4  = (tid & 1) * 4;
    const float* Ap = A + (size_t)(bm + lrow) * K + lk4;
    const float* Wp = W + (size_t)(bn + lrow) * K + lk4;
    const int NIT = K >> 3;

    float4 av = *(const float4*)(Ap);
    float4 wv = *(const float4*)(Wp);
    As[0][lk4+0][lrow]=av.x; As[0][lk4+1][lrow]=av.y; As[0][lk4+2][lrow]=av.z; As[0][lk4+3][lrow]=av.w;
    Ws[0][lk4+0][lrow]=wv.x; Ws[0][lk4+1][lrow]=wv.y; Ws[0][lk4+2][lrow]=wv.z; Ws[0][lk4+3][lrow]=wv.w;
    __syncthreads();

    for (int it = 0; it < NIT; it++) {
        int cur = it & 1;
        if (it + 1 < NIT) {
            av = *(const float4*)(Ap + (it + 1) * 8);
            wv = *(const float4*)(Wp + (it + 1) * 8);
        }
#pragma unroll
        for (int k = 0; k < 8; k++) {
            float4 a0 = *(const float4*)&As[cur][k][ty * 8];
            float4 a1 = *(const float4*)&As[cur][k][ty * 8 + 4];
            float2 b0 = *(const float2*)&Ws[cur][k][tx * 2];
            float2 b1 = *(const float2*)&Ws[cur][k][32 + tx * 2];
            float2 b2 = *(const float2*)&Ws[cur][k][64 + tx * 2];
            float2 b3 = *(const float2*)&Ws[cur][k][96 + tx * 2];
            float a[8] = {a0.x, a0.y, a0.z, a0.w, a1.x, a1.y, a1.z, a1.w};
            float b[8] = {b0.x, b0.y, b1.x, b1.y, b2.x, b2.y, b3.x, b3.y};
#pragma unroll
            for (int ir = 0; ir < 8; ir++)
#pragma unroll
                for (int ic = 0; ic < 8; ic++)
                    acc[ir][ic] = fmaf(a[ir], b[ic], acc[ir][ic]);
        }
        if (it + 1 < NIT) {
            int nxt = cur ^ 1;
            As[nxt][lk4+0][lrow]=av.x; As[nxt][lk4+1][lrow]=av.y; As[nxt][lk4+2][lrow]=av.z; As[nxt][lk4+3][lrow]=av.w;
            Ws[nxt][lk4+0][lrow]=wv.x; Ws[nxt][lk4+1][lrow]=wv.y; Ws[nxt][lk4+2][lrow]=wv.z; Ws[nxt][lk4+3][lrow]=wv.w;
        }
        __syncthreads();
    }
#pragma unroll
    for (int ir = 0; ir < 8; ir++) {
        int row = bm + ty * 8 + ir;
#pragma unroll
        for (int ic2 = 0; ic2 < 4; ic2++) {
            int col = bn + ic2 * 32 + tx * 2;
            float2 v = make_float2(acc[ir][ic2*2]   + bias[col],
                                   acc[ir][ic2*2+1] + bias[col + 1]);
            *(float2*)(C + (size_t)row * N + col) = v;
        }
    }
}

// ---------------- row l2-normalize, fused bf16 output ----------------
__global__ void l2norm_kernel(float* __restrict__ x, __nv_bfloat16* __restrict__ xb) {
    int r = blockIdx.x, t = threadIdx.x;
    __shared__ float sh[256];
    float v = x[(size_t)r * EDIM + t];
    sh[t] = v * v;
    __syncthreads();
    for (int s = 128; s > 0; s >>= 1) { if (t < s) sh[t] += sh[t+s]; __syncthreads(); }
    float nrm = sqrtf(sh[0]);
    float xn = v / nrm;
    x[(size_t)r * EDIM + t] = xn;
    xb[(size_t)r * EDIM + t] = __float2bfloat16(xn);
}

// ---------------- fp32 -> bf16 hi/lo split ----------------
__global__ void conv_split_kernel(const float* __restrict__ src,
                                  __nv_bfloat16* __restrict__ hi,
                                  __nv_bfloat16* __restrict__ lo) {
    int i = blockIdx.x * 256 + threadIdx.x;
    float v[8];
    float4 v0 = ((const float4*)src)[2*i];
    float4 v1 = ((const float4*)src)[2*i+1];
    v[0]=v0.x; v[1]=v0.y; v[2]=v0.z; v[3]=v0.w;
    v[4]=v1.x; v[5]=v1.y; v[6]=v1.z; v[7]=v1.w;
    __nv_bfloat16 h[8], l[8];
#pragma unroll
    for (int j = 0; j < 8; j++) {
        h[j] = __float2bfloat16(v[j]);
        l[j] = __float2bfloat16(v[j] - __bfloat162float(h[j]));
    }
    uint4 ph, pl;
    ph.x = *(uint32_t*)&h[0]; ph.y = *(uint32_t*)&h[2];
    ph.z = *(uint32_t*)&h[4]; ph.w = *(uint32_t*)&h[6];
    pl.x = *(uint32_t*)&l[0]; pl.y = *(uint32_t*)&l[2];
    pl.z = *(uint32_t*)&l[4]; pl.w = *(uint32_t*)&l[6];
    ((uint4*)hi)[i] = ph;
    ((uint4*)lo)[i] = pl;
}

// ---------------- bf16 TC d-GEMM, cp.async 3-stage pipeline, fused S/T/min epilogue ----------------
#define SSTP 72
#define STG  (128 * SSTP * 2)
#define NSTAGE 3
#define SMEM_MMA (NSTAGE * 2 * STG)    // 110592 B

__global__ void __launch_bounds__(256, 2)
mma_d_kernel() {
    extern __shared__ __align__(16) char smem[];
    const int tid = threadIdx.x;
    const int bm = blockIdx.y * 128, bn = blockIdx.x * 128;
    const int wid = tid >> 5, lane = tid & 31;
    const int wr = (wid & 1) * 64;
    const int wc = (wid >> 1) * 32;

    uint32_t sb = smem_u32(smem);
    uint32_t aOff = (uint32_t)(((wr + (lane & 15)) * SSTP + (lane >> 4) * 8) * 2);
    uint32_t bRow = (uint32_t)(wc + (lane & 7) + ((lane >> 4) << 3));
    uint32_t bOff = (uint32_t)((bRow * SSTP + ((lane >> 3) & 1) * 8) * 2);

    const char* gA = (const char*)g_a  + (size_t)bm * 512;
    const char* gB = (const char*)g_eh + (size_t)bn * 512;
    const int lrow = tid >> 3, lc8 = tid & 7;

    float acc[4][4][4] = {};

#pragma unroll
    for (int pc = 0; pc < 2; pc++) {
        uint32_t dstA = sb + (uint32_t)pc * 2 * STG;
        uint32_t dstB = dstA + STG;
#pragma unroll
        for (int j = 0; j < 4; j++) {
            int row = lrow + j * 32;
            uint32_t so = (uint32_t)((row * SSTP + lc8 * 8) * 2);
            cp16(dstA + so, gA + (size_t)row * 512 + pc * 128 + lc8 * 16);
            cp16(dstB + so, gB + (size_t)row * 512 + pc * 128 + lc8 * 16);
        }
        CP_COMMIT();
    }

#pragma unroll
    for (int kc = 0; kc < 4; kc++) {
        if (kc < 3) asm volatile("cp.async.wait_group 1;");
        else        asm volatile("cp.async.wait_group 0;");
        __syncthreads();
        if (kc + 2 < 4) {
            int st = (kc + 2) % NSTAGE;
            uint32_t dstA = sb + (uint32_t)st * 2 * STG;
            uint32_t dstB = dstA + STG;
#pragma unroll
            for (int j = 0; j < 4; j++) {
                int row = lrow + j * 32;
                uint32_t so = (uint32_t)((row * SSTP + lc8 * 8) * 2);
                cp16(dstA + so, gA + (size_t)row * 512 + (kc + 2) * 128 + lc8 * 16);
                cp16(dstB + so, gB + (size_t)row * 512 + (kc + 2) * 128 + lc8 * 16);
            }
            CP_COMMIT();
        }
        uint32_t stA = sb + (uint32_t)(kc % NSTAGE) * 2 * STG;
        uint32_t stB = stA + STG;
#pragma unroll
        for (int kk = 0; kk < 4; kk++) {
            uint32_t ko = (uint32_t)kk * 32;
            uint32_t aF[4][4], bF[2][4];
#pragma unroll
            for (int mi = 0; mi < 4; mi++) ldsm4(aF[mi], stA + aOff + mi * (16 * SSTP * 2) + ko);
#pragma unroll
            for (int n2 = 0; n2 < 2; n2++) ldsm4(bF[n2], stB + bOff + n2 * (16 * SSTP * 2) + ko);
#pragma unroll
            for (int mi = 0; mi < 4; mi++)
#pragma unroll
                for (int ni = 0; ni < 4; ni++)
                    mma_bf16(acc[mi][ni], aF[mi], bF[ni >> 1][(ni & 1) * 2], bF[ni >> 1][(ni & 1) * 2 + 1]);
        }
    }

    __syncthreads();

    // ---- fused per-row S/T/min partials ----
    float* rS = (float*)(smem + 36864);
    float* rT = rS + 512;
    float* rM = rT + 512;
    const int cg = wid >> 1;
    const int rsub = lane >> 2;
#pragma unroll
    for (int mi = 0; mi < 4; mi++) {
#pragma unroll
        for (int half = 0; half < 2; half++) {
            float S = 0.f, T = 0.f, m = 1e30f;
#pragma unroll
            for (int ni = 0; ni < 4; ni++) {
                float d0 = acc[mi][ni][half*2], d1 = acc[mi][ni][half*2+1];
                float t0 = 10.f * d0, t1 = 10.f * d1;
                float e0 = fast_exp(t0), e1 = fast_exp(t1);
                S += e0 + e1;
                T = fmaf(e0, t0, fmaf(e1, t1, T));
                m = fminf(m, fminf(d0, d1));
            }
#pragma unroll
            for (int o = 1; o < 4; o <<= 1) {
                S += __shfl_xor_sync(0xffffffffu, S, o);
                T += __shfl_xor_sync(0xffffffffu, T, o);
                m = fminf(m, __shfl_xor_sync(0xffffffffu, m, o));
            }
            if ((lane & 3) == 0) {
                int row = wr + mi * 16 + half * 8 + rsub;
                rS[cg * 128 + row] = S;
                rT[cg * 128 + row] = T;
                rM[cg * 128 + row] = m;
            }
        }
    }
    __syncthreads();
    if (tid < 128) {
        float S = rS[tid] + rS[128 + tid] + rS[256 + tid] + rS[384 + tid];
        float T = rT[tid] + rT[128 + tid] + rT[256 + tid] + rT[384 + tid];
        float m = fminf(fminf(rM[tid], rM[128 + tid]), fminf(rM[256 + tid], rM[384 + tid]));
        size_t o = (size_t)blockIdx.x * NTOK + bm + tid;
        g_Sp[o] = S; g_Tp[o] = T; g_Mp[o] = m;
    }

    // ---- quantize to int8, smem stage (144B pitch), coalesced stores ----
    signed char* epi = (signed char*)smem;
    {
        const int r0 = wr + (lane >> 2);
        const int c0 = wc + (lane & 3) * 2;
#pragma unroll
        for (int mi = 0; mi < 4; mi++)
#pragma unroll
            for (int ni = 0; ni < 4; ni++) {
                int rr = r0 + mi * 16, cc = c0 + ni * 8;
                epi[rr * 144 + cc]       = q8(acc[mi][ni][0]);
                epi[rr * 144 + cc + 1]   = q8(acc[mi][ni][1]);
                epi[(rr+8) * 144 + cc]     = q8(acc[mi][ni][2]);
                epi[(rr+8) * 144 + cc + 1] = q8(acc[mi][ni][3]);
            }
    }
    __syncthreads();
#pragma unroll
    for (int j = 0; j < 4; j++) {
        int idx = j * 256 + tid;
        int row = idx >> 3, c16 = idx & 7;
        uint4 v = *(uint4*)(epi + row * 144 + c16 * 16);
        *(uint4*)(g_d8 + (size_t)(bm + row) * NE + bn + c16 * 16) = v;
    }
}

// ---------------- reduce partials: coalesced over rows ----------------
__global__ void reduce_partials_kernel() {
    int r = blockIdx.x * 256 + threadIdx.x;
    float S = 0.f, T = 0.f, m = 1e30f;
#pragma unroll 8
    for (int b = 0; b < 64; b++) {
        size_t o = (size_t)b * NTOK + r;
        S += g_Sp[o];
        T += g_Tp[o];
        m = fminf(m, g_Mp[o]);
    }
    g_Sf[r] = S; g_Tf[r] = T; g_Mf[r] = m;
    g_invS[r] = 1.0f / S;
}

// ---------------- bf16-split TC GEMM (cp.async pipeline): g_eproj = embed @ W_out^T ----------------
#define EPSTG (4 * STG)
#define SMEM_EP (2 * EPSTG)

__global__ void __launch_bounds__(256)
eproj_kernel() {
    extern __shared__ __align__(16) char smem[];
    const int tid = threadIdx.x;
    const int bm = blockIdx.y * 128, bn = blockIdx.x * 128;
    const int wid = tid >> 5, lane = tid & 31;
    const int wr = (wid & 1) * 64;
    const int wc = (wid >> 1) * 32;

    uint32_t sb = smem_u32(smem);
    uint32_t aOff = (uint32_t)(((wr + (lane & 15)) * SSTP + (lane >> 4) * 8) * 2);
    uint32_t bRow = (uint32_t)(wc + (lane & 7) + ((lane >> 4) << 3));
    uint32_t bOff = (uint32_t)((bRow * SSTP + ((lane >> 3) & 1) * 8) * 2);

    const char* gAh = (const char*)g_eh + (size_t)bm * 512;
    const char* gAl = (const char*)g_el + (size_t)bm * 512;
    const char* gBh = (const char*)g_wh + (size_t)bn * 512;
    const char* gBl = (const char*)g_wl + (size_t)bn * 512;
    const int lrow = tid >> 3, lc8 = tid & 7;

    float acc[4][4][4] = {};

#pragma unroll
    for (int pc = 0; pc < 2; pc++) {
        uint32_t st = sb + (uint32_t)pc * EPSTG;
#pragma unroll
        for (int j = 0; j < 4; j++) {
            int row = lrow + j * 32;
            uint32_t so = (uint32_t)((row * SSTP + lc8 * 8) * 2);
            size_t go = (size_t)row * 512 + pc * 128 + lc8 * 16;
            cp16(st + so,           gAh + go);
            cp16(st + STG + so,     gAl + go);
            cp16(st + 2 * STG + so, gBh + go);
            cp16(st + 3 * STG + so, gBl + go);
        }
        CP_COMMIT();
    }

#pragma unroll
    for (int kc = 0; kc < 4; kc++) {
        if (kc < 3) asm volatile("cp.async.wait_group 1;");
        else        asm volatile("cp.async.wait_group 0;");
        __syncthreads();
        uint32_t st = sb + (uint32_t)(kc & 1) * EPSTG;
        const uint32_t AH = st, AL = st + STG, BH = st + 2 * STG, BL = st + 3 * STG;
#pragma unroll
        for (int kk = 0; kk < 4; kk++) {
            uint32_t ko = (uint32_t)kk * 32;
            uint32_t ah[4][4], al[4][4], bh[2][4], bl[2][4];
#pragma unroll
            for (int mi = 0; mi < 4; mi++) {
                ldsm4(ah[mi], AH + aOff + mi * (16 * SSTP * 2) + ko);
                ldsm4(al[mi], AL + aOff + mi * (16 * SSTP * 2) + ko);
            }
#pragma unroll
            for (int n2 = 0; n2 < 2; n2++) {
                ldsm4(bh[n2], BH + bOff + n2 * (16 * SSTP * 2) + ko);
                ldsm4(bl[n2], BL + bOff + n2 * (16 * SSTP * 2) + ko);
            }
#pragma unroll
            for (int mi = 0; mi < 4; mi++)
#pragma unroll
                for (int ni = 0; ni < 4; ni++) {
                    uint32_t h0 = bh[ni >> 1][(ni & 1) * 2], h1 = bh[ni >> 1][(ni & 1) * 2 + 1];
                    uint32_t l0 = bl[ni >> 1][(ni & 1) * 2], l1 = bl[ni >> 1][(ni & 1) * 2 + 1];
                    mma_bf16(acc[mi][ni], ah[mi], h0, h1);
                    mma_bf16(acc[mi][ni], ah[mi], l0, l1);
                    mma_bf16(acc[mi][ni], al[mi], h0, h1);
                }
        }
        __syncthreads();
        if (kc + 2 < 4) {
            uint32_t st2 = sb + (uint32_t)(kc & 1) * EPSTG;
#pragma unroll
            for (int j = 0; j < 4; j++) {
                int row = lrow + j * 32;
                uint32_t so = (uint32_t)((row * SSTP + lc8 * 8) * 2);
                size_t go = (size_t)row * 512 + (kc + 2) * 128 + lc8 * 16;
                cp16(st2 + so,           gAh + go);
                cp16(st2 + STG + so,     gAl + go);
                cp16(st2 + 2 * STG + so, gBh + go);
                cp16(st2 + 3 * STG + so, gBl + go);
            }
            CP_COMMIT();
        }
    }

    __syncthreads();
    float* epi = (float*)smem;
    {
        const int r0 = wr + (lane >> 2);
        const int c0 = wc + (lane & 3) * 2;
#pragma unroll
        for (int mi = 0; mi < 4; mi++)
#pragma unroll
            for (int ni = 0; ni < 4; ni++) {
                int rr = r0 + mi * 16, cc = c0 + ni * 8;
                *(float2*)(epi + rr * 132 + cc) = make_float2(acc[mi][ni][0], acc[mi][ni][1]);
                *(float2*)(epi + (rr + 8) * 132 + cc) = make_float2(acc[mi][ni][2], acc[mi][ni][3]);
            }
    }
    __syncthreads();
#pragma unroll
    for (int j = 0; j < 16; j++) {
        int idx = j * 256 + tid;
        int row = idx >> 5, c4 = idx & 31;
        uint4 v = *(uint4*)(epi + row * 132 + c4 * 4);
        *(uint4*)(g_eproj + (size_t)(bm + row) * ODIM + bn + c4 * 4) = v;
    }
}

// ---------------- gather: z_q_out[r] = g_eproj[ind_r] + b_out ----------------
__global__ void gather_kernel(const float* __restrict__ b_out, float* __restrict__ out) {
    int r = blockIdx.x, t = threadIdx.x;
    int ind = (int)out[OFF_IND + r];
    const float* src = g_eproj + (size_t)ind * ODIM;
    float* dst = out + OFF_ZQ + (size_t)r * ODIM;
#pragma unroll
    for (int c = t; c < ODIM; c += 256)
        dst[c] = src[c] + b_out[c];
}

// ---------------- row finalize: candidate scan, exact argmin, stats ----------------
__global__ void __launch_bounds__(256)
row_finalize_kernel(const float* __restrict__ embed, float* __restrict__ out) {
    const int r = blockIdx.x, t = threadIdx.x;
    __shared__ float sxn[256];
    __shared__ float sred[256];
    __shared__ int scnt;
    __shared__ int scand[64];
    __shared__ unsigned long long sbest;

    sxn[t] = g_xn[(size_t)r * EDIM + t];
    if (t == 0) { scnt = 0; sbest = ~0ULL; }
    float Stot = g_Sf[r], Ttot = g_Tf[r], gmin = g_Mf[r];
    __syncthreads();

    int qthr = (int)floorf((gmin + 2.0e-2f) * QSCALE);
    if (qthr > 127) qthr = 127;
    uint32_t thr4 = (uint32_t)(qthr & 0xff) * 0x01010101u;

    const uint32_t* dp = (const uint32_t*)(g_d8 + (size_t)r * NE);
#pragma unroll
    for (int j = 0; j < 8; j++) {
        uint32_t u = dp[t + j * 256];
        uint32_t m = __vcmples4(u, thr4);
        if (m) {
#pragma unroll
            for (int b = 0; b < 4; b++)
                if ((m >> (8 * b)) & 1) {
                    int p = atomicAdd(&scnt, 1);
                    if (p < 64) scand[p] = (t + 256 * j) * 4 + b;
                }
        }
    }
    __syncthreads();
    int ncand = scnt < 64 ? scnt : 64;
    int ind;
    if (ncand == 1) {
        ind = scand[0];
    } else {
        for (int i = 0; i < ncand; i++) {
            const float* er = embed + (size_t)scand[i] * EDIM;
            sred[t] = sxn[t] * er[t];
            __syncthreads();
            for (int s = 128; s > 0; s >>= 1) { if (t < s) sred[t] += sred[t+s]; __syncthreads(); }
            if (t == 0) {
                unsigned u = __float_as_uint(sred[0]);
                u = (u & 0x80000000u) ? ~u : (u | 0x80000000u);
                unsigned long long k = ((unsigned long long)u << 32) | (unsigned)scand[i];
                if (k < sbest) sbest = k;
            }
            __syncthreads();
        }
        ind = (int)(sbest & 0xffffffffu);
    }

    float xnv = sxn[t];
    float ev = embed[(size_t)ind * EDIM + t];
    float df = ev - xnv;
    sred[t] = df * df;
    atomicAdd(&g_embed_sum[(size_t)ind * EDIM + t], xnv);
    __syncthreads();
    for (int s = 128; s > 0; s >>= 1) { if (t < s) sred[t] += sred[t+s]; __syncthreads(); }
    if (t == 0) {
        atomicAdd(&g_scal[0], sred[0]);
        out[OFF_IND + r] = (float)ind;
        atomicAdd(&g_bins[ind], 1.0f);
        atomicAdd(&g_scal[1], logf(Stot) - Ttot / Stot);
    }
}

// ---------------- ap column pass (replicated conflict-free LUT, 4 cols/thread) ----------------
__global__ void __launch_bounds__(256)
ap_kernel() {
    __shared__ float lut[8192];
    __shared__ float sh_inv[256];
    int t = threadIdx.x, lane = t & 31;
    for (int i = t; i < 8192; i += 256) {
        int b = i >> 5;
        int q = (b < 128) ? b : b - 256;
        lut[i] = fast_exp(10.f * (float)q * QINV);
    }
    int c0 = (blockIdx.x * 256 + t) * 4;
    int r0 = blockIdx.y * 1024;
    float a0 = 0.f, a1 = 0.f, a2 = 0.f, a3 = 0.f;
    for (int rr = 0; rr < 1024; rr += 256) {
        __syncthreads();
        sh_inv[t] = g_invS[r0 + rr + t];
        __syncthreads();
        const signed char* ep = g_d8 + (size_t)(r0 + rr) * NE + c0;
#pragma unroll 4
        for (int j = 0; j < 256; j++) {
            uint32_t w = *(const uint32_t*)(ep + (size_t)j * NE);
            float inv = sh_inv[j];
            a0 = fmaf(lut[((w & 255u) << 5) | lane], inv, a0);
            a1 = fmaf(lut[(((w >> 8) & 255u) << 5) | lane], inv, a1);
            a2 = fmaf(lut[(((w >> 16) & 255u) << 5) | lane], inv, a2);
            a3 = fmaf(lut[((w >> 24) << 5) | lane], inv, a3);
        }
    }
    atomicAdd(&g_ap[c0],     a0);
    atomicAdd(&g_ap[c0 + 1], a1);
    atomicAdd(&g_ap[c0 + 2], a2);
    atomicAdd(&g_ap[c0 + 3], a3);
}

// ---------------- merged e1 + scan (single block) ----------------
__global__ void e1scan_kernel(const float* __restrict__ cluster_size, float* __restrict__ out) {
    int t = threadIdx.x;
    __shared__ int sh[1024];
    __shared__ float shf[1024];
    int vals[8]; int s = 0; float csum = 0.f;
#pragma unroll
    for (int j = 0; j < 8; j++) {
        int i = t * 8 + j;
        float cn = cluster_size[i] * 0.99f + g_bins[i] * 0.01f;
        g_cluster_new[i] = cn;
        int ex = (cn < 0.1f);
        g_expired[i] = ex;
        out[OFF_CS + i] = ex ? 0.12f : cn;
        csum += cn;
        s += ex; vals[j] = s;
    }
    sh[t] = s; shf[t] = csum;
    __syncthreads();
    for (int off = 1; off < 1024; off <<= 1) {
        int v = (t >= off) ? sh[t - off] : 0;
        __syncthreads();
        sh[t] += v;
        __syncthreads();
    }
    // total cluster sum
    for (int ss = 512; ss > 0; ss >>= 1) { if (t < ss) shf[t] += shf[t+ss]; __syncthreads(); }
    if (t == 0) g_scal[2] = shf[0];
    int excl = (t > 0) ? sh[t-1] : 0;
#pragma unroll
    for (int j = 0; j < 8; j++) {
        int cum = excl + vals[j];
        int idx = cum - 1; if (idx < 0) idx = 0;
        g_sampidx[t*8 + j] = idx;
    }
}

__global__ void e3_kernel(const float* __restrict__ embed_avg, float* __restrict__ out) {
    int c = blockIdx.x, k = threadIdx.x;
    float ea = embed_avg[(size_t)c * EDIM + k] * 0.99f + g_embed_sum[(size_t)c * EDIM + k] * 0.01f;
    float total = g_scal[2];
    float cn = g_cluster_new[c];
    float cs = (cn + 1e-5f) / (total + (float)NE * 1e-5f) * total;
    float en = ea / cs;
    float ef, eaf;
    if (g_expired[c]) {
        float sv = g_xn[(size_t)g_sampidx[c] * EDIM + k];
        ef = sv; eaf = sv * 0.12f;
    } else { ef = en; eaf = ea; }
    out[OFF_EMB  + (size_t)c * EDIM + k] = ef;
    out[OFF_EAVG + (size_t)c * EDIM + k] = eaf;
}

__global__ void scalars_kernel(float* __restrict__ out) {
    int t = threadIdx.x;
    __shared__ float sh[1024];
    float local = 0.f;
#pragma unroll
    for (int j = 0; j < 8; j++) {
        float ap = g_ap[t*8 + j] * (1.0f / (float)NTOK);
        local -= ap * logf(ap);
    }
    sh[t] = local;
    __syncthreads();
    for (int s = 512; s > 0; s >>= 1) { if (t < s) sh[t] += sh[t+s]; __syncthreads(); }
    if (t == 0) {
        float ent_max = sh[0];
        float commit  = g_scal[0] / ((float)NTOK * (float)EDIM);
        out[OFF_LOSS]   = commit - ent_max;
        out[OFF_ENTMIN] = g_scal[1] / (float)NTOK;
        out[OFF_COMMIT] = commit;
    }
}

// ---------------- launch ----------------
extern "C" void kernel_launch(void* const* d_in, const int* in_sizes, int n_in,
                              void* d_out, int out_size) {
    const float* x         = (const float*)d_in[0];
    const float* W_in      = (const float*)d_in[1];
    const float* b_in      = (const float*)d_in[2];
    const float* W_out     = (const float*)d_in[3];
    const float* b_out     = (const float*)d_in[4];
    const float* embed     = (const float*)d_in[5];
    const float* embed_avg = (const float*)d_in[6];
    const float* cluster   = (const float*)d_in[7];
    float* out = (float*)d_out;

    void *p_xn=nullptr, *p_a=nullptr, *p_eh=nullptr, *p_el=nullptr, *p_wh=nullptr, *p_wl=nullptr;
    cudaGetSymbolAddress(&p_xn, g_xn);
    cudaGetSymbolAddress(&p_a, g_a);
    cudaGetSymbolAddress(&p_eh, g_eh);
    cudaGetSymbolAddress(&p_el, g_el);
    cudaGetSymbolAddress(&p_wh, g_wh);
    cudaGetSymbolAddress(&p_wl, g_wl);

    cudaFuncSetAttribute(mma_d_kernel, cudaFuncAttributeMaxDynamicSharedMemorySize, SMEM_MMA);
    cudaFuncSetAttribute(eproj_kernel, cudaFuncAttributeMaxDynamicSharedMemorySize, SMEM_EP);

    // order: mma_d at ncu-profiled slot #4 (verify 3-stage pipeline)
    conv_split_kernel<<<NE*EDIM/8/256, 256>>>(embed, (__nv_bfloat16*)p_eh,
                                              (__nv_bfloat16*)p_el);               // 1
    gemm_bias_kernel<<<dim3(EDIM/128, NTOK/128), 256>>>(x, W_in, b_in, (float*)p_xn,
                                                        NTOK, EDIM, LAT);          // 2
    l2norm_kernel<<<NTOK, 256>>>((float*)p_xn, (__nv_bfloat16*)p_a);               // 3
    mma_d_kernel<<<dim3(NE/128, NTOK/128), 256, SMEM_MMA>>>();                     // 4 <- profile
    zero_kernel<<<8192, 256>>>();                                                  // 5
    conv_split_kernel<<<ODIM*EDIM/8/256, 256>>>(W_out, (__nv_bfloat16*)p_wh,
                                                (__nv_bfloat16*)p_wl);             // 6
    reduce_partials_kernel<<<NTOK/256, 256>>>();                                   // 7
    row_finalize_kernel<<<NTOK, 256>>>(embed, out);                                // 8
    eproj_kernel<<<dim3(ODIM/128, NE/128), 256, SMEM_EP>>>();                      // 9
    ap_kernel<<<dim3(NE/1024, NTOK/1024), 256>>>();                                // 10
    e1scan_kernel<<<1, 1024>>>(cluster, out);                                      // 11
    scalars_kernel<<<1, 1024>>>(out);                                              // 12
    e3_kernel<<<NE, 256>>>(embed_avg, out);                                        // 13
    gather_kernel<<<NTOK, 256>>>(b_out, out);                                      // 14
}

// round 14
// speedup vs baseline: 3.2579x; 1.0905x over previous
#include <cuda_runtime.h>
#include <cuda_bf16.h>
#include <math.h>
#include <stdint.h>

// ---------------- problem constants ----------------
#define NTOK   16384
#define EDIM   256
#define NE     8192
#define LAT    768
#define ODIM   768

#define OFF_ZQ     ((size_t)0)
#define OFF_IND    ((size_t)12582912)
#define OFF_LOSS   ((size_t)12599296)
#define OFF_EMB    ((size_t)12599297)
#define OFF_EAVG   ((size_t)14696449)
#define OFF_CS     ((size_t)16793601)
#define OFF_ENTMIN ((size_t)16801793)
#define OFF_COMMIT ((size_t)16801794)

#define QSCALE 126.0f
#define QINV   (1.0f / 126.0f)

// ---------------- device scratch ----------------
__device__ signed char g_d8[(size_t)NTOK * NE];
__device__ __nv_bfloat16 g_a[(size_t)NTOK * EDIM];
__device__ __nv_bfloat16 g_eh[(size_t)NE * EDIM];
__device__ __nv_bfloat16 g_el[(size_t)NE * EDIM];
__device__ __nv_bfloat16 g_wh[(size_t)ODIM * EDIM];
__device__ __nv_bfloat16 g_wl[(size_t)ODIM * EDIM];
__device__ float g_eproj[(size_t)NE * ODIM];
__device__ float g_xn[NTOK * EDIM];
__device__ float g_Sp[(size_t)64 * NTOK];
__device__ float g_Tp[(size_t)64 * NTOK];
__device__ int   g_Mp[(size_t)64 * NTOK];
__device__ float g_Sf[NTOK];
__device__ float g_Tf[NTOK];
__device__ int   g_Mf[NTOK];
__device__ float g_invS[NTOK];
__device__ float g_bins[NE];
__device__ float g_ap[NE];
__device__ float g_cluster_new[NE];
__device__ int   g_expired[NE];
__device__ int   g_sampidx[NE];
__device__ float g_embed_sum[NE * EDIM];
__device__ float g_scal[4];

// ---------------- fast exp (FFMA only) ----------------
__device__ __forceinline__ float fast_exp(float x) {
    float z = x * 1.4426950408889634f;
    int   i = __float2int_rn(z);
    float rf = (float)i;
    float g = fmaf(rf, -0.693359375f, x);
    g = fmaf(rf, 2.12194440e-4f, g);
    float p = 1.98412698e-4f;
    p = fmaf(p, g, 1.38888889e-3f);
    p = fmaf(p, g, 8.33333333e-3f);
    p = fmaf(p, g, 4.16666667e-2f);
    p = fmaf(p, g, 1.66666667e-1f);
    p = fmaf(p, g, 0.5f);
    p = fmaf(p, g, 1.0f);
    p = fmaf(p, g, 1.0f);
    float sc = __int_as_float((i + 127) << 23);
    return p * sc;
}

// ---------------- helpers ----------------
__device__ __forceinline__ uint32_t smem_u32(const void* p) {
    uint32_t a;
    asm("{ .reg .u64 t; cvta.to.shared.u64 t, %1; cvt.u32.u64 %0, t; }" : "=r"(a) : "l"(p));
    return a;
}
__device__ __forceinline__ void ldsm4(uint32_t* r, uint32_t addr) {
    asm volatile("ldmatrix.sync.aligned.m8n8.x4.shared.b16 {%0,%1,%2,%3}, [%4];"
                 : "=r"(r[0]), "=r"(r[1]), "=r"(r[2]), "=r"(r[3]) : "r"(addr));
}
__device__ __forceinline__ void mma_bf16(float* c, const uint32_t* a, uint32_t b0, uint32_t b1) {
    asm volatile("mma.sync.aligned.m16n8k16.row.col.f32.bf16.bf16.f32 "
                 "{%0,%1,%2,%3}, {%4,%5,%6,%7}, {%8,%9}, {%0,%1,%2,%3};"
                 : "+f"(c[0]), "+f"(c[1]), "+f"(c[2]), "+f"(c[3])
                 : "r"(a[0]), "r"(a[1]), "r"(a[2]), "r"(a[3]), "r"(b0), "r"(b1));
}
__device__ __forceinline__ void cp16(uint32_t dst, const void* src) {
    asm volatile("cp.async.cg.shared.global [%0], [%1], 16;" :: "r"(dst), "l"(src));
}
#define CP_COMMIT() asm volatile("cp.async.commit_group;")

__device__ __forceinline__ int q8i(float d) {
    return __float2int_rn(fminf(fmaxf(d * QSCALE, -127.f), 127.f));
}

// ---------------- zeroing ----------------
__global__ void zero_kernel() {
    int i = blockIdx.x * 256 + threadIdx.x;
    if (i < NE * EDIM) g_embed_sum[i] = 0.f;
    if (i < NE)   { g_bins[i] = 0.f; g_ap[i] = 0.f; }
    if (i < 4)    g_scal[i] = 0.f;
}

// ---------------- fp32 SGEMM, double-buffered + vectorized LDS ----------------
__global__ void __launch_bounds__(256)
gemm_bias_kernel(const float* __restrict__ A, const float* __restrict__ W,
                 const float* __restrict__ bias, float* __restrict__ C,
                 int M, int N, int K) {
    __shared__ float As[2][8][132];
    __shared__ float Ws[2][8][132];
    const int tid = threadIdx.x;
    const int tx = tid & 15, ty = tid >> 4;
    const int bm = blockIdx.y * 128, bn = blockIdx.x * 128;
    float acc[8][8] = {};
    const int lrow = tid >> 1;
    const int lk4  = (tid & 1) * 4;
    const float* Ap = A + (size_t)(bm + lrow) * K + lk4;
    const float* Wp = W + (size_t)(bn + lrow) * K + lk4;
    const int NIT = K >> 3;

    float4 av = *(const float4*)(Ap);
    float4 wv = *(const float4*)(Wp);
    As[0][lk4+0][lrow]=av.x; As[0][lk4+1][lrow]=av.y; As[0][lk4+2][lrow]=av.z; As[0][lk4+3][lrow]=av.w;
    Ws[0][lk4+0][lrow]=wv.x; Ws[0][lk4+1][lrow]=wv.y; Ws[0][lk4+2][lrow]=wv.z; Ws[0][lk4+3][lrow]=wv.w;
    __syncthreads();

    for (int it = 0; it < NIT; it++) {
        int cur = it & 1;
        if (it + 1 < NIT) {
            av = *(const float4*)(Ap + (it + 1) * 8);
            wv = *(const float4*)(Wp + (it + 1) * 8);
        }
#pragma unroll
        for (int k = 0; k < 8; k++) {
            float4 a0 = *(const float4*)&As[cur][k][ty * 8];
            float4 a1 = *(const float4*)&As[cur][k][ty * 8 + 4];
            float2 b0 = *(const float2*)&Ws[cur][k][tx * 2];
            float2 b1 = *(const float2*)&Ws[cur][k][32 + tx * 2];
            float2 b2 = *(const float2*)&Ws[cur][k][64 + tx * 2];
            float2 b3 = *(const float2*)&Ws[cur][k][96 + tx * 2];
            float a[8] = {a0.x, a0.y, a0.z, a0.w, a1.x, a1.y, a1.z, a1.w};
            float b[8] = {b0.x, b0.y, b1.x, b1.y, b2.x, b2.y, b3.x, b3.y};
#pragma unroll
            for (int ir = 0; ir < 8; ir++)
#pragma unroll
                for (int ic = 0; ic < 8; ic++)
                    acc[ir][ic] = fmaf(a[ir], b[ic], acc[ir][ic]);
        }
        if (it + 1 < NIT) {
            int nxt = cur ^ 1;
            As[nxt][lk4+0][lrow]=av.x; As[nxt][lk4+1][lrow]=av.y; As[nxt][lk4+2][lrow]=av.z; As[nxt][lk4+3][lrow]=av.w;
            Ws[nxt][lk4+0][lrow]=wv.x; Ws[nxt][lk4+1][lrow]=wv.y; Ws[nxt][lk4+2][lrow]=wv.z; Ws[nxt][lk4+3][lrow]=wv.w;
        }
        __syncthreads();
    }
#pragma unroll
    for (int ir = 0; ir < 8; ir++) {
        int row = bm + ty * 8 + ir;
#pragma unroll
        for (int ic2 = 0; ic2 < 4; ic2++) {
            int col = bn + ic2 * 32 + tx * 2;
            float2 v = make_float2(acc[ir][ic2*2]   + bias[col],
                                   acc[ir][ic2*2+1] + bias[col + 1]);
            *(float2*)(C + (size_t)row * N + col) = v;
        }
    }
}

// ---------------- row l2-normalize (shuffle reduce), fused bf16 output ----------------
__global__ void l2norm_kernel(float* __restrict__ x, __nv_bfloat16* __restrict__ xb) {
    int r = blockIdx.x, t = threadIdx.x;
    int w = t >> 5, lane = t & 31;
    __shared__ float sw[8];
    float v = x[(size_t)r * EDIM + t];
    float s = v * v;
#pragma unroll
    for (int o = 16; o; o >>= 1) s += __shfl_xor_sync(0xffffffffu, s, o);
    if (lane == 0) sw[w] = s;
    __syncthreads();
    if (t == 0) {
        float tot = sw[0];
#pragma unroll
        for (int j = 1; j < 8; j++) tot += sw[j];
        sw[0] = sqrtf(tot);
    }
    __syncthreads();
    float xn = v / sw[0];
    x[(size_t)r * EDIM + t] = xn;
    xb[(size_t)r * EDIM + t] = __float2bfloat16(xn);
}

// ---------------- fp32 -> bf16 hi/lo split ----------------
__global__ void conv_split_kernel(const float* __restrict__ src,
                                  __nv_bfloat16* __restrict__ hi,
                                  __nv_bfloat16* __restrict__ lo) {
    int i = blockIdx.x * 256 + threadIdx.x;
    float v[8];
    float4 v0 = ((const float4*)src)[2*i];
    float4 v1 = ((const float4*)src)[2*i+1];
    v[0]=v0.x; v[1]=v0.y; v[2]=v0.z; v[3]=v0.w;
    v[4]=v1.x; v[5]=v1.y; v[6]=v1.z; v[7]=v1.w;
    __nv_bfloat16 h[8], l[8];
#pragma unroll
    for (int j = 0; j < 8; j++) {
        h[j] = __float2bfloat16(v[j]);
        l[j] = __float2bfloat16(v[j] - __bfloat162float(h[j]));
    }
    uint4 ph, pl;
    ph.x = *(uint32_t*)&h[0]; ph.y = *(uint32_t*)&h[2];
    ph.z = *(uint32_t*)&h[4]; ph.w = *(uint32_t*)&h[6];
    pl.x = *(uint32_t*)&l[0]; pl.y = *(uint32_t*)&l[2];
    pl.z = *(uint32_t*)&l[4]; pl.w = *(uint32_t*)&l[6];
    ((uint4*)hi)[i] = ph;
    ((uint4*)lo)[i] = pl;
}

// ---------------- bf16 TC d-GEMM, 3-stage cp.async, int8-LUT epilogue ----------------
#define SSTP 72
#define STG  (128 * SSTP * 2)
#define NSTAGE 3
#define SMEM_MMA (NSTAGE * 2 * STG)    // 110592 B

__global__ void __launch_bounds__(256, 2)
mma_d_kernel() {
    extern __shared__ __align__(16) char smem[];
    const int tid = threadIdx.x;
    const int bm = blockIdx.y * 128, bn = blockIdx.x * 128;
    const int wid = tid >> 5, lane = tid & 31;
    const int wr = (wid & 1) * 64;
    const int wc = (wid >> 1) * 32;

    uint32_t sb = smem_u32(smem);
    uint32_t aOff = (uint32_t)(((wr + (lane & 15)) * SSTP + (lane >> 4) * 8) * 2);
    uint32_t bRow = (uint32_t)(wc + (lane & 7) + ((lane >> 4) << 3));
    uint32_t bOff = (uint32_t)((bRow * SSTP + ((lane >> 3) & 1) * 8) * 2);

    const char* gA = (const char*)g_a  + (size_t)bm * 512;
    const char* gB = (const char*)g_eh + (size_t)bn * 512;
    const int lrow = tid >> 3, lc8 = tid & 7;

    float acc[4][4][4] = {};

#pragma unroll
    for (int pc = 0; pc < 2; pc++) {
        uint32_t dstA = sb + (uint32_t)pc * 2 * STG;
        uint32_t dstB = dstA + STG;
#pragma unroll
        for (int j = 0; j < 4; j++) {
            int row = lrow + j * 32;
            uint32_t so = (uint32_t)((row * SSTP + lc8 * 8) * 2);
            cp16(dstA + so, gA + (size_t)row * 512 + pc * 128 + lc8 * 16);
            cp16(dstB + so, gB + (size_t)row * 512 + pc * 128 + lc8 * 16);
        }
        CP_COMMIT();
    }

#pragma unroll
    for (int kc = 0; kc < 4; kc++) {
        if (kc < 3) asm volatile("cp.async.wait_group 1;");
        else        asm volatile("cp.async.wait_group 0;");
        __syncthreads();
        if (kc + 2 < 4) {
            int st = (kc + 2) % NSTAGE;
            uint32_t dstA = sb + (uint32_t)st * 2 * STG;
            uint32_t dstB = dstA + STG;
#pragma unroll
            for (int j = 0; j < 4; j++) {
                int row = lrow + j * 32;
                uint32_t so = (uint32_t)((row * SSTP + lc8 * 8) * 2);
                cp16(dstA + so, gA + (size_t)row * 512 + (kc + 2) * 128 + lc8 * 16);
                cp16(dstB + so, gB + (size_t)row * 512 + (kc + 2) * 128 + lc8 * 16);
            }
            CP_COMMIT();
        }
        uint32_t stA = sb + (uint32_t)(kc % NSTAGE) * 2 * STG;
        uint32_t stB = stA + STG;
#pragma unroll
        for (int kk = 0; kk < 4; kk++) {
            uint32_t ko = (uint32_t)kk * 32;
            uint32_t aF[4][4], bF[2][4];
#pragma unroll
            for (int mi = 0; mi < 4; mi++) ldsm4(aF[mi], stA + aOff + mi * (16 * SSTP * 2) + ko);
#pragma unroll
            for (int n2 = 0; n2 < 2; n2++) ldsm4(bF[n2], stB + bOff + n2 * (16 * SSTP * 2) + ko);
#pragma unroll
            for (int mi = 0; mi < 4; mi++)
#pragma unroll
                for (int ni = 0; ni < 4; ni++)
                    mma_bf16(acc[mi][ni], aF[mi], bF[ni >> 1][(ni & 1) * 2], bF[ni >> 1][(ni & 1) * 2 + 1]);
        }
    }

    __syncthreads();

    // ---- int8-native epilogue: quantize, LUT S/T, int min, packed stores ----
    signed char* epi = (signed char*)smem;         // 0 .. 18432
    float* rS = (float*)(smem + 36864);            // [4][128]
    float* rT = rS + 512;
    int*   rM = (int*)(rT + 512);
    float* lutS = (float*)(smem + 43008);          // 256 floats
    float* lutT = lutS + 256;
    {
        int qv = (tid < 128) ? tid : tid - 256;
        float t10 = 10.f * (float)qv * QINV;
        float e = fast_exp(t10);
        lutS[tid] = e;
        lutT[tid] = e * t10;
    }
    __syncthreads();

    const int cg = wid >> 1;
    const int r0 = wr + (lane >> 2);
    const int c0 = wc + (lane & 3) * 2;
#pragma unroll
    for (int mi = 0; mi < 4; mi++) {
#pragma unroll
        for (int half = 0; half < 2; half++) {
            int rr = r0 + mi * 16 + half * 8;
            float S = 0.f, T = 0.f;
            int qm = 127;
#pragma unroll
            for (int ni = 0; ni < 4; ni++) {
                int q0 = q8i(acc[mi][ni][half*2]);
                int q1 = q8i(acc[mi][ni][half*2+1]);
                S += lutS[q0 & 255] + lutS[q1 & 255];
                T += lutT[q0 & 255] + lutT[q1 & 255];
                qm = min(qm, min(q0, q1));
                *(short*)(epi + rr * 144 + c0 + ni * 8) =
                    (short)((q0 & 0xff) | (q1 << 8));
            }
#pragma unroll
            for (int o = 1; o < 4; o <<= 1) {
                S += __shfl_xor_sync(0xffffffffu, S, o);
                T += __shfl_xor_sync(0xffffffffu, T, o);
                qm = min(qm, __shfl_xor_sync(0xffffffffu, qm, o));
            }
            if ((lane & 3) == 0) {
                rS[cg * 128 + rr] = S;
                rT[cg * 128 + rr] = T;
                rM[cg * 128 + rr] = qm;
            }
        }
    }
    __syncthreads();
    if (tid < 128) {
        float S = rS[tid] + rS[128 + tid] + rS[256 + tid] + rS[384 + tid];
        float T = rT[tid] + rT[128 + tid] + rT[256 + tid] + rT[384 + tid];
        int m = min(min(rM[tid], rM[128 + tid]), min(rM[256 + tid], rM[384 + tid]));
        size_t o = (size_t)blockIdx.x * NTOK + bm + tid;
        g_Sp[o] = S; g_Tp[o] = T; g_Mp[o] = m;
    }
#pragma unroll
    for (int j = 0; j < 4; j++) {
        int idx = j * 256 + tid;
        int row = idx >> 3, c16 = idx & 7;
        uint4 v = *(uint4*)(epi + row * 144 + c16 * 16);
        *(uint4*)(g_d8 + (size_t)(bm + row) * NE + bn + c16 * 16) = v;
    }
}

// ---------------- reduce partials: coalesced over rows ----------------
__global__ void reduce_partials_kernel() {
    int r = blockIdx.x * 256 + threadIdx.x;
    float S = 0.f, T = 0.f;
    int m = 127;
#pragma unroll 8
    for (int b = 0; b < 64; b++) {
        size_t o = (size_t)b * NTOK + r;
        S += g_Sp[o];
        T += g_Tp[o];
        m = min(m, g_Mp[o]);
    }
    g_Sf[r] = S; g_Tf[r] = T; g_Mf[r] = m;
    g_invS[r] = 1.0f / S;
}

// ---------------- bf16-split TC GEMM (cp.async pipeline): g_eproj = embed @ W_out^T ----------------
#define EPSTG (4 * STG)
#define SMEM_EP (2 * EPSTG)

__global__ void __launch_bounds__(256)
eproj_kernel() {
    extern __shared__ __align__(16) char smem[];
    const int tid = threadIdx.x;
    const int bm = blockIdx.y * 128, bn = blockIdx.x * 128;
    const int wid = tid >> 5, lane = tid & 31;
    const int wr = (wid & 1) * 64;
    const int wc = (wid >> 1) * 32;

    uint32_t sb = smem_u32(smem);
    uint32_t aOff = (uint32_t)(((wr + (lane & 15)) * SSTP + (lane >> 4) * 8) * 2);
    uint32_t bRow = (uint32_t)(wc + (lane & 7) + ((lane >> 4) << 3));
    uint32_t bOff = (uint32_t)((bRow * SSTP + ((lane >> 3) & 1) * 8) * 2);

    const char* gAh = (const char*)g_eh + (size_t)bm * 512;
    const char* gAl = (const char*)g_el + (size_t)bm * 512;
    const char* gBh = (const char*)g_wh + (size_t)bn * 512;
    const char* gBl = (const char*)g_wl + (size_t)bn * 512;
    const int lrow = tid >> 3, lc8 = tid & 7;

    float acc[4][4][4] = {};

#pragma unroll
    for (int pc = 0; pc < 2; pc++) {
        uint32_t st = sb + (uint32_t)pc * EPSTG;
#pragma unroll
        for (int j = 0; j < 4; j++) {
            int row = lrow + j * 32;
            uint32_t so = (uint32_t)((row * SSTP + lc8 * 8) * 2);
            size_t go = (size_t)row * 512 + pc * 128 + lc8 * 16;
            cp16(st + so,           gAh + go);
            cp16(st + STG + so,     gAl + go);
            cp16(st + 2 * STG + so, gBh + go);
            cp16(st + 3 * STG + so, gBl + go);
        }
        CP_COMMIT();
    }

#pragma unroll
    for (int kc = 0; kc < 4; kc++) {
        if (kc < 3) asm volatile("cp.async.wait_group 1;");
        else        asm volatile("cp.async.wait_group 0;");
        __syncthreads();
        uint32_t st = sb + (uint32_t)(kc & 1) * EPSTG;
        const uint32_t AH = st, AL = st + STG, BH = st + 2 * STG, BL = st + 3 * STG;
#pragma unroll
        for (int kk = 0; kk < 4; kk++) {
            uint32_t ko = (uint32_t)kk * 32;
            uint32_t ah[4][4], al[4][4], bh[2][4], bl[2][4];
#pragma unroll
            for (int mi = 0; mi < 4; mi++) {
                ldsm4(ah[mi], AH + aOff + mi * (16 * SSTP * 2) + ko);
                ldsm4(al[mi], AL + aOff + mi * (16 * SSTP * 2) + ko);
            }
#pragma unroll
            for (int n2 = 0; n2 < 2; n2++) {
                ldsm4(bh[n2], BH + bOff + n2 * (16 * SSTP * 2) + ko);
                ldsm4(bl[n2], BL + bOff + n2 * (16 * SSTP * 2) + ko);
            }
#pragma unroll
            for (int mi = 0; mi < 4; mi++)
#pragma unroll
                for (int ni = 0; ni < 4; ni++) {
                    uint32_t h0 = bh[ni >> 1][(ni & 1) * 2], h1 = bh[ni >> 1][(ni & 1) * 2 + 1];
                    uint32_t l0 = bl[ni >> 1][(ni & 1) * 2], l1 = bl[ni >> 1][(ni & 1) * 2 + 1];
                    mma_bf16(acc[mi][ni], ah[mi], h0, h1);
                    mma_bf16(acc[mi][ni], ah[mi], l0, l1);
                    mma_bf16(acc[mi][ni], al[mi], h0, h1);
                }
        }
        __syncthreads();
        if (kc + 2 < 4) {
            uint32_t st2 = sb + (uint32_t)(kc & 1) * EPSTG;
#pragma unroll
            for (int j = 0; j < 4; j++) {
                int row = lrow + j * 32;
                uint32_t so = (uint32_t)((row * SSTP + lc8 * 8) * 2);
                size_t go = (size_t)row * 512 + (kc + 2) * 128 + lc8 * 16;
                cp16(st2 + so,           gAh + go);
                cp16(st2 + STG + so,     gAl + go);
                cp16(st2 + 2 * STG + so, gBh + go);
                cp16(st2 + 3 * STG + so, gBl + go);
            }
            CP_COMMIT();
        }
    }

    __syncthreads();
    float* epi = (float*)smem;
    {
        const int r0 = wr + (lane >> 2);
        const int c0 = wc + (lane & 3) * 2;
#pragma unroll
        for (int mi = 0; mi < 4; mi++)
#pragma unroll
            for (int ni = 0; ni < 4; ni++) {
                int rr = r0 + mi * 16, cc = c0 + ni * 8;
                *(float2*)(epi + rr * 132 + cc) = make_float2(acc[mi][ni][0], acc[mi][ni][1]);
                *(float2*)(epi + (rr + 8) * 132 + cc) = make_float2(acc[mi][ni][2], acc[mi][ni][3]);
            }
    }
    __syncthreads();
#pragma unroll
    for (int j = 0; j < 16; j++) {
        int idx = j * 256 + tid;
        int row = idx >> 5, c4 = idx & 31;
        uint4 v = *(uint4*)(epi + row * 132 + c4 * 4);
        *(uint4*)(g_eproj + (size_t)(bm + row) * ODIM + bn + c4 * 4) = v;
    }
}

// ---------------- gather: z_q_out[r] = g_eproj[ind_r] + b_out ----------------
__global__ void gather_kernel(const float* __restrict__ b_out, float* __restrict__ out) {
    int r = blockIdx.x, t = threadIdx.x;
    int ind = (int)out[OFF_IND + r];
    const float* src = g_eproj + (size_t)ind * ODIM;
    float* dst = out + OFF_ZQ + (size_t)r * ODIM;
#pragma unroll
    for (int c = t; c < ODIM; c += 256)
        dst[c] = src[c] + b_out[c];
}

// ---------------- row finalize: candidate scan, warp-parallel exact argmin ----------------
__global__ void __launch_bounds__(256)
row_finalize_kernel(const float* __restrict__ embed, float* __restrict__ out) {
    const int r = blockIdx.x, t = threadIdx.x;
    const int w = t >> 5, lane = t & 31;
    __shared__ float sxn[256];
    __shared__ float swred[8];
    __shared__ unsigned long long swbest[8];
    __shared__ int scnt;
    __shared__ int scand[64];
    __shared__ int sind;

    sxn[t] = g_xn[(size_t)r * EDIM + t];
    if (t == 0) scnt = 0;
    float Stot = g_Sf[r], Ttot = g_Tf[r];
    int qthr = g_Mf[r] + 2;
    if (qthr > 127) qthr = 127;
    __syncthreads();

    uint32_t thr4 = (uint32_t)(qthr & 0xff) * 0x01010101u;
    const uint32_t* dp = (const uint32_t*)(g_d8 + (size_t)r * NE);
#pragma unroll
    for (int j = 0; j < 8; j++) {
        uint32_t u = dp[t + j * 256];
        uint32_t m = __vcmples4(u, thr4);
        if (m) {
#pragma unroll
            for (int b = 0; b < 4; b++)
                if ((m >> (8 * b)) & 1) {
                    int p = atomicAdd(&scnt, 1);
                    if (p < 64) scand[p] = (t + 256 * j) * 4 + b;
                }
        }
    }
    __syncthreads();
    int ncand = scnt < 64 ? scnt : 64;
    int ind;
    if (ncand == 1) {
        ind = scand[0];
    } else {
        // each warp evaluates candidates w, w+8, ... in exact fp32
        unsigned long long best = ~0ULL;
        for (int i = w; i < ncand; i += 8) {
            int c = scand[i];
            const float* er = embed + (size_t)c * EDIM;
            float s = 0.f;
#pragma unroll
            for (int j = 0; j < 8; j++)
                s = fmaf(sxn[lane + j * 32], er[lane + j * 32], s);
#pragma unroll
            for (int o = 16; o; o >>= 1) s += __shfl_xor_sync(0xffffffffu, s, o);
            unsigned u = __float_as_uint(s);
            u = (u & 0x80000000u) ? ~u : (u | 0x80000000u);
            unsigned long long k = ((unsigned long long)u << 32) | (unsigned)c;
            if (k < best) best = k;
        }
        if (lane == 0) swbest[w] = best;
        __syncthreads();
        if (t == 0) {
            unsigned long long b = swbest[0];
#pragma unroll
            for (int j = 1; j < 8; j++) if (swbest[j] < b) b = swbest[j];
            sind = (int)(b & 0xffffffffu);
        }
        __syncthreads();
        ind = sind;
    }

    float xnv = sxn[t];
    float ev = embed[(size_t)ind * EDIM + t];
    float df = ev - xnv;
    atomicAdd(&g_embed_sum[(size_t)ind * EDIM + t], xnv);
    float cs = df * df;
#pragma unroll
    for (int o = 16; o; o >>= 1) cs += __shfl_xor_sync(0xffffffffu, cs, o);
    if (lane == 0) swred[w] = cs;
    __syncthreads();
    if (t == 0) {
        float tot = swred[0];
#pragma unroll
        for (int j = 1; j < 8; j++) tot += swred[j];
        atomicAdd(&g_scal[0], tot);
        out[OFF_IND + r] = (float)ind;
        atomicAdd(&g_bins[ind], 1.0f);
        atomicAdd(&g_scal[1], logf(Stot) - Ttot / Stot);
    }
}

// ---------------- ap column pass (replicated conflict-free LUT, 4 cols/thread) ----------------
__global__ void __launch_bounds__(256)
ap_kernel() {
    __shared__ float lut[8192];
    __shared__ float sh_inv[256];
    int t = threadIdx.x, lane = t & 31;
    for (int i = t; i < 8192; i += 256) {
        int b = i >> 5;
        int q = (b < 128) ? b : b - 256;
        lut[i] = fast_exp(10.f * (float)q * QINV);
    }
    int c0 = (blockIdx.x * 256 + t) * 4;
    int r0 = blockIdx.y * 1024;
    float a0 = 0.f, a1 = 0.f, a2 = 0.f, a3 = 0.f;
    for (int rr = 0; rr < 1024; rr += 256) {
        __syncthreads();
        sh_inv[t] = g_invS[r0 + rr + t];
        __syncthreads();
        const signed char* ep = g_d8 + (size_t)(r0 + rr) * NE + c0;
#pragma unroll 4
        for (int j = 0; j < 256; j++) {
            uint32_t w = *(const uint32_t*)(ep + (size_t)j * NE);
            float inv = sh_inv[j];
            a0 = fmaf(lut[((w & 255u) << 5) | lane], inv, a0);
            a1 = fmaf(lut[(((w >> 8) & 255u) << 5) | lane], inv, a1);
            a2 = fmaf(lut[(((w >> 16) & 255u) << 5) | lane], inv, a2);
            a3 = fmaf(lut[((w >> 24) << 5) | lane], inv, a3);
        }
    }
    atomicAdd(&g_ap[c0],     a0);
    atomicAdd(&g_ap[c0 + 1], a1);
    atomicAdd(&g_ap[c0 + 2], a2);
    atomicAdd(&g_ap[c0 + 3], a3);
}

// ---------------- merged e1 + scan (single block) ----------------
__global__ void e1scan_kernel(const float* __restrict__ cluster_size, float* __restrict__ out) {
    int t = threadIdx.x;
    __shared__ int sh[1024];
    __shared__ float shf[1024];
    int vals[8]; int s = 0; float csum = 0.f;
#pragma unroll
    for (int j = 0; j < 8; j++) {
        int i = t * 8 + j;
        float cn = cluster_size[i] * 0.99f + g_bins[i] * 0.01f;
        g_cluster_new[i] = cn;
        int ex = (cn < 0.1f);
        g_expired[i] = ex;
        out[OFF_CS + i] = ex ? 0.12f : cn;
        csum += cn;
        s += ex; vals[j] = s;
    }
    sh[t] = s; shf[t] = csum;
    __syncthreads();
    for (int off = 1; off < 1024; off <<= 1) {
        int v = (t >= off) ? sh[t - off] : 0;
        __syncthreads();
        sh[t] += v;
        __syncthreads();
    }
    for (int ss = 512; ss > 0; ss >>= 1) { if (t < ss) shf[t] += shf[t+ss]; __syncthreads(); }
    if (t == 0) g_scal[2] = shf[0];
    int excl = (t > 0) ? sh[t-1] : 0;
#pragma unroll
    for (int j = 0; j < 8; j++) {
        int cum = excl + vals[j];
        int idx = cum - 1; if (idx < 0) idx = 0;
        g_sampidx[t*8 + j] = idx;
    }
}

__global__ void e3_kernel(const float* __restrict__ embed_avg, float* __restrict__ out) {
    int c = blockIdx.x, k = threadIdx.x;
    float ea = embed_avg[(size_t)c * EDIM + k] * 0.99f + g_embed_sum[(size_t)c * EDIM + k] * 0.01f;
    float total = g_scal[2];
    float cn = g_cluster_new[c];
    float cs = (cn + 1e-5f) / (total + (float)NE * 1e-5f) * total;
    float en = ea / cs;
    float ef, eaf;
    if (g_expired[c]) {
        float sv = g_xn[(size_t)g_sampidx[c] * EDIM + k];
        ef = sv; eaf = sv * 0.12f;
    } else { ef = en; eaf = ea; }
    out[OFF_EMB  + (size_t)c * EDIM + k] = ef;
    out[OFF_EAVG + (size_t)c * EDIM + k] = eaf;
}

__global__ void scalars_kernel(float* __restrict__ out) {
    int t = threadIdx.x;
    __shared__ float sh[1024];
    float local = 0.f;
#pragma unroll
    for (int j = 0; j < 8; j++) {
        float ap = g_ap[t*8 + j] * (1.0f / (float)NTOK);
        local -= ap * logf(ap);
    }
    sh[t] = local;
    __syncthreads();
    for (int s = 512; s > 0; s >>= 1) { if (t < s) sh[t] += sh[t+s]; __syncthreads(); }
    if (t == 0) {
        float ent_max = sh[0];
        float commit  = g_scal[0] / ((float)NTOK * (float)EDIM);
        out[OFF_LOSS]   = commit - ent_max;
        out[OFF_ENTMIN] = g_scal[1] / (float)NTOK;
        out[OFF_COMMIT] = commit;
    }
}

// ---------------- launch ----------------
extern "C" void kernel_launch(void* const* d_in, const int* in_sizes, int n_in,
                              void* d_out, int out_size) {
    const float* x         = (const float*)d_in[0];
    const float* W_in      = (const float*)d_in[1];
    const float* b_in      = (const float*)d_in[2];
    const float* W_out     = (const float*)d_in[3];
    const float* b_out     = (const float*)d_in[4];
    const float* embed     = (const float*)d_in[5];
    const float* embed_avg = (const float*)d_in[6];
    const float* cluster   = (const float*)d_in[7];
    float* out = (float*)d_out;

    void *p_xn=nullptr, *p_a=nullptr, *p_eh=nullptr, *p_el=nullptr, *p_wh=nullptr, *p_wl=nullptr;
    cudaGetSymbolAddress(&p_xn, g_xn);
    cudaGetSymbolAddress(&p_a, g_a);
    cudaGetSymbolAddress(&p_eh, g_eh);
    cudaGetSymbolAddress(&p_el, g_el);
    cudaGetSymbolAddress(&p_wh, g_wh);
    cudaGetSymbolAddress(&p_wl, g_wl);

    cudaFuncSetAttribute(mma_d_kernel, cudaFuncAttributeMaxDynamicSharedMemorySize, SMEM_MMA);
    cudaFuncSetAttribute(eproj_kernel, cudaFuncAttributeMaxDynamicSharedMemorySize, SMEM_EP);

    // order: mma_d at ncu-profiled slot #4 (verify int8-LUT epilogue)
    conv_split_kernel<<<NE*EDIM/8/256, 256>>>(embed, (__nv_bfloat16*)p_eh,
                                              (__nv_bfloat16*)p_el);               // 1
    gemm_bias_kernel<<<dim3(EDIM/128, NTOK/128), 256>>>(x, W_in, b_in, (float*)p_xn,
                                                        NTOK, EDIM, LAT);          // 2
    l2norm_kernel<<<NTOK, 256>>>((float*)p_xn, (__nv_bfloat16*)p_a);               // 3
    mma_d_kernel<<<dim3(NE/128, NTOK/128), 256, SMEM_MMA>>>();                     // 4 <- profile
    zero_kernel<<<8192, 256>>>();                                                  // 5
    conv_split_kernel<<<ODIM*EDIM/8/256, 256>>>(W_out, (__nv_bfloat16*)p_wh,
                                                (__nv_bfloat16*)p_wl);             // 6
    reduce_partials_kernel<<<NTOK/256, 256>>>();                                   // 7
    row_finalize_kernel<<<NTOK, 256>>>(embed, out);                                // 8
    eproj_kernel<<<dim3(ODIM/128, NE/128), 256, SMEM_EP>>>();                      // 9
    ap_kernel<<<dim3(NE/1024, NTOK/1024), 256>>>();                                // 10
    e1scan_kernel<<<1, 1024>>>(cluster, out);                                      // 11
    scalars_kernel<<<1, 1024>>>(out);                                              // 12
    e3_kernel<<<NE, 256>>>(embed_avg, out);                                        // 13
    gather_kernel<<<NTOK, 256>>>(b_out, out);                                      // 14
}

// round 15
// speedup vs baseline: 3.2974x; 1.0121x over previous
#include <cuda_runtime.h>
#include <cuda_bf16.h>
#include <math.h>
#include <stdint.h>

// ---------------- problem constants ----------------
#define NTOK   16384
#define EDIM   256
#define NE     8192
#define LAT    768
#define ODIM   768

#define OFF_ZQ     ((size_t)0)
#define OFF_IND    ((size_t)12582912)
#define OFF_LOSS   ((size_t)12599296)
#define OFF_EMB    ((size_t)12599297)
#define OFF_EAVG   ((size_t)14696449)
#define OFF_CS     ((size_t)16793601)
#define OFF_ENTMIN ((size_t)16801793)
#define OFF_COMMIT ((size_t)16801794)

#define QSCALE 126.0f
#define QINV   (1.0f / 126.0f)

// ---------------- device scratch ----------------
__device__ signed char g_d8[(size_t)NTOK * NE];
__device__ __nv_bfloat16 g_a[(size_t)NTOK * EDIM];
__device__ __nv_bfloat16 g_eh[(size_t)NE * EDIM];
__device__ __nv_bfloat16 g_el[(size_t)NE * EDIM];
__device__ __nv_bfloat16 g_wh[(size_t)ODIM * EDIM];
__device__ __nv_bfloat16 g_wl[(size_t)ODIM * EDIM];
__device__ float g_eproj[(size_t)NE * ODIM];
__device__ float g_xn[NTOK * EDIM];
__device__ float g_Sp[(size_t)64 * NTOK];
__device__ float g_Tp[(size_t)64 * NTOK];
__device__ int   g_Mp[(size_t)64 * NTOK];
__device__ float g_Sf[NTOK];
__device__ float g_Tf[NTOK];
__device__ int   g_Mf[NTOK];
__device__ unsigned long long g_mask[NTOK];   // bn-blocks possibly containing candidates
__device__ float g_invS[NTOK];
__device__ float g_bins[NE];
__device__ float g_ap[NE];
__device__ float g_cluster_new[NE];
__device__ int   g_expired[NE];
__device__ int   g_sampidx[NE];
__device__ float g_embed_sum[NE * EDIM];
__device__ float g_scal[4];

// ---------------- fast exp (FFMA only) ----------------
__device__ __forceinline__ float fast_exp(float x) {
    float z = x * 1.4426950408889634f;
    int   i = __float2int_rn(z);
    float rf = (float)i;
    float g = fmaf(rf, -0.693359375f, x);
    g = fmaf(rf, 2.12194440e-4f, g);
    float p = 1.98412698e-4f;
    p = fmaf(p, g, 1.38888889e-3f);
    p = fmaf(p, g, 8.33333333e-3f);
    p = fmaf(p, g, 4.16666667e-2f);
    p = fmaf(p, g, 1.66666667e-1f);
    p = fmaf(p, g, 0.5f);
    p = fmaf(p, g, 1.0f);
    p = fmaf(p, g, 1.0f);
    float sc = __int_as_float((i + 127) << 23);
    return p * sc;
}

// ---------------- helpers ----------------
__device__ __forceinline__ uint32_t smem_u32(const void* p) {
    uint32_t a;
    asm("{ .reg .u64 t; cvta.to.shared.u64 t, %1; cvt.u32.u64 %0, t; }" : "=r"(a) : "l"(p));
    return a;
}
__device__ __forceinline__ void ldsm4(uint32_t* r, uint32_t addr) {
    asm volatile("ldmatrix.sync.aligned.m8n8.x4.shared.b16 {%0,%1,%2,%3}, [%4];"
                 : "=r"(r[0]), "=r"(r[1]), "=r"(r[2]), "=r"(r[3]) : "r"(addr));
}
__device__ __forceinline__ void mma_bf16(float* c, const uint32_t* a, uint32_t b0, uint32_t b1) {
    asm volatile("mma.sync.aligned.m16n8k16.row.col.f32.bf16.bf16.f32 "
                 "{%0,%1,%2,%3}, {%4,%5,%6,%7}, {%8,%9}, {%0,%1,%2,%3};"
                 : "+f"(c[0]), "+f"(c[1]), "+f"(c[2]), "+f"(c[3])
                 : "r"(a[0]), "r"(a[1]), "r"(a[2]), "r"(a[3]), "r"(b0), "r"(b1));
}
__device__ __forceinline__ void cp16(uint32_t dst, const void* src) {
    asm volatile("cp.async.cg.shared.global [%0], [%1], 16;" :: "r"(dst), "l"(src));
}
#define CP_COMMIT() asm volatile("cp.async.commit_group;")

__device__ __forceinline__ int q8i(float d) {
    return __float2int_rn(fminf(fmaxf(d * QSCALE, -127.f), 127.f));
}

// ---------------- zeroing ----------------
__global__ void zero_kernel() {
    int i = blockIdx.x * 256 + threadIdx.x;
    if (i < NE * EDIM) g_embed_sum[i] = 0.f;
    if (i < NE)   { g_bins[i] = 0.f; g_ap[i] = 0.f; }
    if (i < 4)    g_scal[i] = 0.f;
}

// ---------------- fp32 SGEMM, double-buffered + vectorized LDS ----------------
__global__ void __launch_bounds__(256)
gemm_bias_kernel(const float* __restrict__ A, const float* __restrict__ W,
                 const float* __restrict__ bias, float* __restrict__ C,
                 int M, int N, int K) {
    __shared__ float As[2][8][132];
    __shared__ float Ws[2][8][132];
    const int tid = threadIdx.x;
    const int tx = tid & 15, ty = tid >> 4;
    const int bm = blockIdx.y * 128, bn = blockIdx.x * 128;
    float acc[8][8] = {};
    const int lrow = tid >> 1;
    const int lk4  = (tid & 1) * 4;
    const float* Ap = A + (size_t)(bm + lrow) * K + lk4;
    const float* Wp = W + (size_t)(bn + lrow) * K + lk4;
    const int NIT = K >> 3;

    float4 av = *(const float4*)(Ap);
    float4 wv = *(const float4*)(Wp);
    As[0][lk4+0][lrow]=av.x; As[0][lk4+1][lrow]=av.y; As[0][lk4+2][lrow]=av.z; As[0][lk4+3][lrow]=av.w;
    Ws[0][lk4+0][lrow]=wv.x; Ws[0][lk4+1][lrow]=wv.y; Ws[0][lk4+2][lrow]=wv.z; Ws[0][lk4+3][lrow]=wv.w;
    __syncthreads();

    for (int it = 0; it < NIT; it++) {
        int cur = it & 1;
        if (it + 1 < NIT) {
            av = *(const float4*)(Ap + (it + 1) * 8);
            wv = *(const float4*)(Wp + (it + 1) * 8);
        }
#pragma unroll
        for (int k = 0; k < 8; k++) {
            float4 a0 = *(const float4*)&As[cur][k][ty * 8];
            float4 a1 = *(const float4*)&As[cur][k][ty * 8 + 4];
            float2 b0 = *(const float2*)&Ws[cur][k][tx * 2];
            float2 b1 = *(const float2*)&Ws[cur][k][32 + tx * 2];
            float2 b2 = *(const float2*)&Ws[cur][k][64 + tx * 2];
            float2 b3 = *(const float2*)&Ws[cur][k][96 + tx * 2];
            float a[8] = {a0.x, a0.y, a0.z, a0.w, a1.x, a1.y, a1.z, a1.w};
            float b[8] = {b0.x, b0.y, b1.x, b1.y, b2.x, b2.y, b3.x, b3.y};
#pragma unroll
            for (int ir = 0; ir < 8; ir++)
#pragma unroll
                for (int ic = 0; ic < 8; ic++)
                    acc[ir][ic] = fmaf(a[ir], b[ic], acc[ir][ic]);
        }
        if (it + 1 < NIT) {
            int nxt = cur ^ 1;
            As[nxt][lk4+0][lrow]=av.x; As[nxt][lk4+1][lrow]=av.y; As[nxt][lk4+2][lrow]=av.z; As[nxt][lk4+3][lrow]=av.w;
            Ws[nxt][lk4+0][lrow]=wv.x; Ws[nxt][lk4+1][lrow]=wv.y; Ws[nxt][lk4+2][lrow]=wv.z; Ws[nxt][lk4+3][lrow]=wv.w;
        }
        __syncthreads();
    }
#pragma unroll
    for (int ir = 0; ir < 8; ir++) {
        int row = bm + ty * 8 + ir;
#pragma unroll
        for (int ic2 = 0; ic2 < 4; ic2++) {
            int col = bn + ic2 * 32 + tx * 2;
            float2 v = make_float2(acc[ir][ic2*2]   + bias[col],
                                   acc[ir][ic2*2+1] + bias[col + 1]);
            *(float2*)(C + (size_t)row * N + col) = v;
        }
    }
}

// ---------------- row l2-normalize (shuffle reduce), fused bf16 output ----------------
__global__ void l2norm_kernel(float* __restrict__ x, __nv_bfloat16* __restrict__ xb) {
    int r = blockIdx.x, t = threadIdx.x;
    int w = t >> 5, lane = t & 31;
    __shared__ float sw[8];
    float v = x[(size_t)r * EDIM + t];
    float s = v * v;
#pragma unroll
    for (int o = 16; o; o >>= 1) s += __shfl_xor_sync(0xffffffffu, s, o);
    if (lane == 0) sw[w] = s;
    __syncthreads();
    if (t == 0) {
        float tot = sw[0];
#pragma unroll
        for (int j = 1; j < 8; j++) tot += sw[j];
        sw[0] = sqrtf(tot);
    }
    __syncthreads();
    float xn = v / sw[0];
    x[(size_t)r * EDIM + t] = xn;
    xb[(size_t)r * EDIM + t] = __float2bfloat16(xn);
}

// ---------------- fp32 -> bf16 hi/lo split ----------------
__global__ void conv_split_kernel(const float* __restrict__ src,
                                  __nv_bfloat16* __restrict__ hi,
                                  __nv_bfloat16* __restrict__ lo) {
    int i = blockIdx.x * 256 + threadIdx.x;
    float v[8];
    float4 v0 = ((const float4*)src)[2*i];
    float4 v1 = ((const float4*)src)[2*i+1];
    v[0]=v0.x; v[1]=v0.y; v[2]=v0.z; v[3]=v0.w;
    v[4]=v1.x; v[5]=v1.y; v[6]=v1.z; v[7]=v1.w;
    __nv_bfloat16 h[8], l[8];
#pragma unroll
    for (int j = 0; j < 8; j++) {
        h[j] = __float2bfloat16(v[j]);
        l[j] = __float2bfloat16(v[j] - __bfloat162float(h[j]));
    }
    uint4 ph, pl;
    ph.x = *(uint32_t*)&h[0]; ph.y = *(uint32_t*)&h[2];
    ph.z = *(uint32_t*)&h[4]; ph.w = *(uint32_t*)&h[6];
    pl.x = *(uint32_t*)&l[0]; pl.y = *(uint32_t*)&l[2];
    pl.z = *(uint32_t*)&l[4]; pl.w = *(uint32_t*)&l[6];
    ((uint4*)hi)[i] = ph;
    ((uint4*)lo)[i] = pl;
}

// ---------------- bf16 TC d-GEMM, 3-stage cp.async, int8-LUT epilogue ----------------
#define SSTP 72
#define STG  (128 * SSTP * 2)
#define NSTAGE 3
#define SMEM_MMA (NSTAGE * 2 * STG)    // 110592 B

__global__ void __launch_bounds__(256, 2)
mma_d_kernel() {
    extern __shared__ __align__(16) char smem[];
    const int tid = threadIdx.x;
    const int bm = blockIdx.y * 128, bn = blockIdx.x * 128;
    const int wid = tid >> 5, lane = tid & 31;
    const int wr = (wid & 1) * 64;
    const int wc = (wid >> 1) * 32;

    uint32_t sb = smem_u32(smem);
    uint32_t aOff = (uint32_t)(((wr + (lane & 15)) * SSTP + (lane >> 4) * 8) * 2);
    uint32_t bRow = (uint32_t)(wc + (lane & 7) + ((lane >> 4) << 3));
    uint32_t bOff = (uint32_t)((bRow * SSTP + ((lane >> 3) & 1) * 8) * 2);

    const char* gA = (const char*)g_a  + (size_t)bm * 512;
    const char* gB = (const char*)g_eh + (size_t)bn * 512;
    const int lrow = tid >> 3, lc8 = tid & 7;

    float acc[4][4][4] = {};

#pragma unroll
    for (int pc = 0; pc < 2; pc++) {
        uint32_t dstA = sb + (uint32_t)pc * 2 * STG;
        uint32_t dstB = dstA + STG;
#pragma unroll
        for (int j = 0; j < 4; j++) {
            int row = lrow + j * 32;
            uint32_t so = (uint32_t)((row * SSTP + lc8 * 8) * 2);
            cp16(dstA + so, gA + (size_t)row * 512 + pc * 128 + lc8 * 16);
            cp16(dstB + so, gB + (size_t)row * 512 + pc * 128 + lc8 * 16);
        }
        CP_COMMIT();
    }

#pragma unroll
    for (int kc = 0; kc < 4; kc++) {
        if (kc < 3) asm volatile("cp.async.wait_group 1;");
        else        asm volatile("cp.async.wait_group 0;");
        __syncthreads();
        if (kc + 2 < 4) {
            int st = (kc + 2) % NSTAGE;
            uint32_t dstA = sb + (uint32_t)st * 2 * STG;
            uint32_t dstB = dstA + STG;
#pragma unroll
            for (int j = 0; j < 4; j++) {
                int row = lrow + j * 32;
                uint32_t so = (uint32_t)((row * SSTP + lc8 * 8) * 2);
                cp16(dstA + so, gA + (size_t)row * 512 + (kc + 2) * 128 + lc8 * 16);
                cp16(dstB + so, gB + (size_t)row * 512 + (kc + 2) * 128 + lc8 * 16);
            }
            CP_COMMIT();
        }
        uint32_t stA = sb + (uint32_t)(kc % NSTAGE) * 2 * STG;
        uint32_t stB = stA + STG;
#pragma unroll
        for (int kk = 0; kk < 4; kk++) {
            uint32_t ko = (uint32_t)kk * 32;
            uint32_t aF[4][4], bF[2][4];
#pragma unroll
            for (int mi = 0; mi < 4; mi++) ldsm4(aF[mi], stA + aOff + mi * (16 * SSTP * 2) + ko);
#pragma unroll
            for (int n2 = 0; n2 < 2; n2++) ldsm4(bF[n2], stB + bOff + n2 * (16 * SSTP * 2) + ko);
#pragma unroll
            for (int mi = 0; mi < 4; mi++)
#pragma unroll
                for (int ni = 0; ni < 4; ni++)
                    mma_bf16(acc[mi][ni], aF[mi], bF[ni >> 1][(ni & 1) * 2], bF[ni >> 1][(ni & 1) * 2 + 1]);
        }
    }

    __syncthreads();

    // ---- int8-native epilogue: quantize, LUT S/T, int min, packed stores ----
    signed char* epi = (signed char*)smem;
    float* rS = (float*)(smem + 36864);
    float* rT = rS + 512;
    int*   rM = (int*)(rT + 512);
    float* lutS = (float*)(smem + 43008);
    float* lutT = lutS + 256;
    {
        int qv = (tid < 128) ? tid : tid - 256;
        float t10 = 10.f * (float)qv * QINV;
        float e = fast_exp(t10);
        lutS[tid] = e;
        lutT[tid] = e * t10;
    }
    __syncthreads();

    const int cg = wid >> 1;
    const int r0 = wr + (lane >> 2);
    const int c0 = wc + (lane & 3) * 2;
#pragma unroll
    for (int mi = 0; mi < 4; mi++) {
#pragma unroll
        for (int half = 0; half < 2; half++) {
            int rr = r0 + mi * 16 + half * 8;
            float S = 0.f, T = 0.f;
            int qm = 127;
#pragma unroll
            for (int ni = 0; ni < 4; ni++) {
                int q0 = q8i(acc[mi][ni][half*2]);
                int q1 = q8i(acc[mi][ni][half*2+1]);
                S += lutS[q0 & 255] + lutS[q1 & 255];
                T += lutT[q0 & 255] + lutT[q1 & 255];
                qm = min(qm, min(q0, q1));
                *(short*)(epi + rr * 144 + c0 + ni * 8) =
                    (short)((q0 & 0xff) | (q1 << 8));
            }
#pragma unroll
            for (int o = 1; o < 4; o <<= 1) {
                S += __shfl_xor_sync(0xffffffffu, S, o);
                T += __shfl_xor_sync(0xffffffffu, T, o);
                qm = min(qm, __shfl_xor_sync(0xffffffffu, qm, o));
            }
            if ((lane & 3) == 0) {
                rS[cg * 128 + rr] = S;
                rT[cg * 128 + rr] = T;
                rM[cg * 128 + rr] = qm;
            }
        }
    }
    __syncthreads();
    if (tid < 128) {
        float S = rS[tid] + rS[128 + tid] + rS[256 + tid] + rS[384 + tid];
        float T = rT[tid] + rT[128 + tid] + rT[256 + tid] + rT[384 + tid];
        int m = min(min(rM[tid], rM[128 + tid]), min(rM[256 + tid], rM[384 + tid]));
        size_t o = (size_t)blockIdx.x * NTOK + bm + tid;
        g_Sp[o] = S; g_Tp[o] = T; g_Mp[o] = m;
    }
#pragma unroll
    for (int j = 0; j < 4; j++) {
        int idx = j * 256 + tid;
        int row = idx >> 3, c16 = idx & 7;
        uint4 v = *(uint4*)(epi + row * 144 + c16 * 16);
        *(uint4*)(g_d8 + (size_t)(bm + row) * NE + bn + c16 * 16) = v;
    }
}

// ---------------- reduce partials + candidate block mask ----------------
__global__ void reduce_partials_kernel() {
    int r = blockIdx.x * 256 + threadIdx.x;
    float S = 0.f, T = 0.f;
    int m = 127;
#pragma unroll 8
    for (int b = 0; b < 64; b++) {
        size_t o = (size_t)b * NTOK + r;
        S += g_Sp[o];
        T += g_Tp[o];
        m = min(m, g_Mp[o]);
    }
    int qthr = min(m + 2, 127);
    unsigned long long mask = 0ULL;
#pragma unroll 8
    for (int b = 0; b < 64; b++) {
        if (g_Mp[(size_t)b * NTOK + r] <= qthr)
            mask |= (1ULL << b);
    }
    g_Sf[r] = S; g_Tf[r] = T; g_Mf[r] = qthr;
    g_mask[r] = mask;
    g_invS[r] = 1.0f / S;
}

// ---------------- bf16-split TC GEMM (cp.async pipeline): g_eproj = embed @ W_out^T ----------------
#define EPSTG (4 * STG)
#define SMEM_EP (2 * EPSTG)

__global__ void __launch_bounds__(256)
eproj_kernel() {
    extern __shared__ __align__(16) char smem[];
    const int tid = threadIdx.x;
    const int bm = blockIdx.y * 128, bn = blockIdx.x * 128;
    const int wid = tid >> 5, lane = tid & 31;
    const int wr = (wid & 1) * 64;
    const int wc = (wid >> 1) * 32;

    uint32_t sb = smem_u32(smem);
    uint32_t aOff = (uint32_t)(((wr + (lane & 15)) * SSTP + (lane >> 4) * 8) * 2);
    uint32_t bRow = (uint32_t)(wc + (lane & 7) + ((lane >> 4) << 3));
    uint32_t bOff = (uint32_t)((bRow * SSTP + ((lane >> 3) & 1) * 8) * 2);

    const char* gAh = (const char*)g_eh + (size_t)bm * 512;
    const char* gAl = (const char*)g_el + (size_t)bm * 512;
    const char* gBh = (const char*)g_wh + (size_t)bn * 512;
    const char* gBl = (const char*)g_wl + (size_t)bn * 512;
    const int lrow = tid >> 3, lc8 = tid & 7;

    float acc[4][4][4] = {};

#pragma unroll
    for (int pc = 0; pc < 2; pc++) {
        uint32_t st = sb + (uint32_t)pc * EPSTG;
#pragma unroll
        for (int j = 0; j < 4; j++) {
            int row = lrow + j * 32;
            uint32_t so = (uint32_t)((row * SSTP + lc8 * 8) * 2);
            size_t go = (size_t)row * 512 + pc * 128 + lc8 * 16;
            cp16(st + so,           gAh + go);
            cp16(st + STG + so,     gAl + go);
            cp16(st + 2 * STG + so, gBh + go);
            cp16(st + 3 * STG + so, gBl + go);
        }
        CP_COMMIT();
    }

#pragma unroll
    for (int kc = 0; kc < 4; kc++) {
        if (kc < 3) asm volatile("cp.async.wait_group 1;");
        else        asm volatile("cp.async.wait_group 0;");
        __syncthreads();
        uint32_t st = sb + (uint32_t)(kc & 1) * EPSTG;
        const uint32_t AH = st, AL = st + STG, BH = st + 2 * STG, BL = st + 3 * STG;
#pragma unroll
        for (int kk = 0; kk < 4; kk++) {
            uint32_t ko = (uint32_t)kk * 32;
            uint32_t ah[4][4], al[4][4], bh[2][4], bl[2][4];
#pragma unroll
            for (int mi = 0; mi < 4; mi++) {
                ldsm4(ah[mi], AH + aOff + mi * (16 * SSTP * 2) + ko);
                ldsm4(al[mi], AL + aOff + mi * (16 * SSTP * 2) + ko);
            }
#pragma unroll
            for (int n2 = 0; n2 < 2; n2++) {
                ldsm4(bh[n2], BH + bOff + n2 * (16 * SSTP * 2) + ko);
                ldsm4(bl[n2], BL + bOff + n2 * (16 * SSTP * 2) + ko);
            }
#pragma unroll
            for (int mi = 0; mi < 4; mi++)
#pragma unroll
                for (int ni = 0; ni < 4; ni++) {
                    uint32_t h0 = bh[ni >> 1][(ni & 1) * 2], h1 = bh[ni >> 1][(ni & 1) * 2 + 1];
                    uint32_t l0 = bl[ni >> 1][(ni & 1) * 2], l1 = bl[ni >> 1][(ni & 1) * 2 + 1];
                    mma_bf16(acc[mi][ni], ah[mi], h0, h1);
                    mma_bf16(acc[mi][ni], ah[mi], l0, l1);
                    mma_bf16(acc[mi][ni], al[mi], h0, h1);
                }
        }
        __syncthreads();
        if (kc + 2 < 4) {
            uint32_t st2 = sb + (uint32_t)(kc & 1) * EPSTG;
#pragma unroll
            for (int j = 0; j < 4; j++) {
                int row = lrow + j * 32;
                uint32_t so = (uint32_t)((row * SSTP + lc8 * 8) * 2);
                size_t go = (size_t)row * 512 + (kc + 2) * 128 + lc8 * 16;
                cp16(st2 + so,           gAh + go);
                cp16(st2 + STG + so,     gAl + go);
                cp16(st2 + 2 * STG + so, gBh + go);
                cp16(st2 + 3 * STG + so, gBl + go);
            }
            CP_COMMIT();
        }
    }

    __syncthreads();
    float* epi = (float*)smem;
    {
        const int r0 = wr + (lane >> 2);
        const int c0 = wc + (lane & 3) * 2;
#pragma unroll
        for (int mi = 0; mi < 4; mi++)
#pragma unroll
            for (int ni = 0; ni < 4; ni++) {
                int rr = r0 + mi * 16, cc = c0 + ni * 8;
                *(float2*)(epi + rr * 132 + cc) = make_float2(acc[mi][ni][0], acc[mi][ni][1]);
                *(float2*)(epi + (rr + 8) * 132 + cc) = make_float2(acc[mi][ni][2], acc[mi][ni][3]);
            }
    }
    __syncthreads();
#pragma unroll
    for (int j = 0; j < 16; j++) {
        int idx = j * 256 + tid;
        int row = idx >> 5, c4 = idx & 31;
        uint4 v = *(uint4*)(epi + row * 132 + c4 * 4);
        *(uint4*)(g_eproj + (size_t)(bm + row) * ODIM + bn + c4 * 4) = v;
    }
}

// ---------------- row finalize: masked candidate scan, exact argmin, fused gather ----------------
__global__ void __launch_bounds__(256)
row_finalize_kernel(const float* __restrict__ embed, const float* __restrict__ b_out,
                    float* __restrict__ out) {
    const int r = blockIdx.x, t = threadIdx.x;
    const int w = t >> 5, lane = t & 31;
    __shared__ float sxn[256];
    __shared__ float swred[8];
    __shared__ unsigned long long swbest[8];
    __shared__ int scnt;
    __shared__ int scand[64];
    __shared__ int sind;

    sxn[t] = g_xn[(size_t)r * EDIM + t];
    if (t == 0) scnt = 0;
    float Stot = g_Sf[r], Ttot = g_Tf[r];
    int qthr = g_Mf[r];                    // already min+2, capped
    unsigned long long mask = g_mask[r];
    __syncthreads();

    // candidate scan over masked 128-col blocks only (warp 0)
    if (w == 0) {
        uint32_t thr4 = (uint32_t)(qthr & 0xff) * 0x01010101u;
        const uint32_t* dp = (const uint32_t*)(g_d8 + (size_t)r * NE);
        unsigned long long mk = mask;
        while (mk) {
            int b = __ffsll(mk) - 1;
            mk &= mk - 1;
            uint32_t u = dp[b * 32 + lane];
            uint32_t m = __vcmples4(u, thr4);
            if (m) {
#pragma unroll
                for (int by = 0; by < 4; by++)
                    if ((m >> (8 * by)) & 1) {
                        int p = atomicAdd(&scnt, 1);
                        if (p < 64) scand[p] = (b * 32 + lane) * 4 + by;
                    }
            }
        }
    }
    __syncthreads();
    int ncand = scnt < 64 ? scnt : 64;
    int ind;
    if (ncand == 1) {
        ind = scand[0];
    } else {
        unsigned long long best = ~0ULL;
        for (int i = w; i < ncand; i += 8) {
            int c = scand[i];
            const float* er = embed + (size_t)c * EDIM;
            float s = 0.f;
#pragma unroll
            for (int j = 0; j < 8; j++)
                s = fmaf(sxn[lane + j * 32], er[lane + j * 32], s);
#pragma unroll
            for (int o = 16; o; o >>= 1) s += __shfl_xor_sync(0xffffffffu, s, o);
            unsigned u = __float_as_uint(s);
            u = (u & 0x80000000u) ? ~u : (u | 0x80000000u);
            unsigned long long k = ((unsigned long long)u << 32) | (unsigned)c;
            if (k < best) best = k;
        }
        if (lane == 0) swbest[w] = best;
        __syncthreads();
        if (t == 0) {
            unsigned long long b = swbest[0];
#pragma unroll
            for (int j = 1; j < 8; j++) if (swbest[j] < b) b = swbest[j];
            sind = (int)(b & 0xffffffffu);
        }
        __syncthreads();
        ind = sind;
    }

    float xnv = sxn[t];
    float ev = embed[(size_t)ind * EDIM + t];
    float df = ev - xnv;
    atomicAdd(&g_embed_sum[(size_t)ind * EDIM + t], xnv);
    float cs = df * df;
#pragma unroll
    for (int o = 16; o; o >>= 1) cs += __shfl_xor_sync(0xffffffffu, cs, o);
    if (lane == 0) swred[w] = cs;

    // fused gather: z_q_out[r] = eproj[ind] + b_out
    {
        const float* src = g_eproj + (size_t)ind * ODIM;
        float* dst = out + OFF_ZQ + (size_t)r * ODIM;
#pragma unroll
        for (int c = t; c < ODIM; c += 256)
            dst[c] = src[c] + b_out[c];
    }
    __syncthreads();
    if (t == 0) {
        float tot = swred[0];
#pragma unroll
        for (int j = 1; j < 8; j++) tot += swred[j];
        atomicAdd(&g_scal[0], tot);
        out[OFF_IND + r] = (float)ind;
        atomicAdd(&g_bins[ind], 1.0f);
        atomicAdd(&g_scal[1], logf(Stot) - Ttot / Stot);
    }
}

// ---------------- ap column pass (replicated conflict-free LUT, 4 cols/thread) ----------------
__global__ void __launch_bounds__(256)
ap_kernel() {
    __shared__ float lut[8192];
    __shared__ float sh_inv[256];
    int t = threadIdx.x, lane = t & 31;
    for (int i = t; i < 8192; i += 256) {
        int b = i >> 5;
        int q = (b < 128) ? b : b - 256;
        lut[i] = fast_exp(10.f * (float)q * QINV);
    }
    int c0 = (blockIdx.x * 256 + t) * 4;
    int r0 = blockIdx.y * 1024;
    float a0 = 0.f, a1 = 0.f, a2 = 0.f, a3 = 0.f;
    for (int rr = 0; rr < 1024; rr += 256) {
        __syncthreads();
        sh_inv[t] = g_invS[r0 + rr + t];
        __syncthreads();
        const signed char* ep = g_d8 + (size_t)(r0 + rr) * NE + c0;
#pragma unroll 4
        for (int j = 0; j < 256; j++) {
            uint32_t w = *(const uint32_t*)(ep + (size_t)j * NE);
            float inv = sh_inv[j];
            a0 = fmaf(lut[((w & 255u) << 5) | lane], inv, a0);
            a1 = fmaf(lut[(((w >> 8) & 255u) << 5) | lane], inv, a1);
            a2 = fmaf(lut[(((w >> 16) & 255u) << 5) | lane], inv, a2);
            a3 = fmaf(lut[((w >> 24) << 5) | lane], inv, a3);
        }
    }
    atomicAdd(&g_ap[c0],     a0);
    atomicAdd(&g_ap[c0 + 1], a1);
    atomicAdd(&g_ap[c0 + 2], a2);
    atomicAdd(&g_ap[c0 + 3], a3);
}

// ---------------- merged e1 + scan (single block) ----------------
__global__ void e1scan_kernel(const float* __restrict__ cluster_size, float* __restrict__ out) {
    int t = threadIdx.x;
    __shared__ int sh[1024];
    __shared__ float shf[1024];
    int vals[8]; int s = 0; float csum = 0.f;
#pragma unroll
    for (int j = 0; j < 8; j++) {
        int i = t * 8 + j;
        float cn = cluster_size[i] * 0.99f + g_bins[i] * 0.01f;
        g_cluster_new[i] = cn;
        int ex = (cn < 0.1f);
        g_expired[i] = ex;
        out[OFF_CS + i] = ex ? 0.12f : cn;
        csum += cn;
        s += ex; vals[j] = s;
    }
    sh[t] = s; shf[t] = csum;
    __syncthreads();
    for (int off = 1; off < 1024; off <<= 1) {
        int v = (t >= off) ? sh[t - off] : 0;
        __syncthreads();
        sh[t] += v;
        __syncthreads();
    }
    for (int ss = 512; ss > 0; ss >>= 1) { if (t < ss) shf[t] += shf[t+ss]; __syncthreads(); }
    if (t == 0) g_scal[2] = shf[0];
    int excl = (t > 0) ? sh[t-1] : 0;
#pragma unroll
    for (int j = 0; j < 8; j++) {
        int cum = excl + vals[j];
        int idx = cum - 1; if (idx < 0) idx = 0;
        g_sampidx[t*8 + j] = idx;
    }
}

__global__ void e3_kernel(const float* __restrict__ embed_avg, float* __restrict__ out) {
    int c = blockIdx.x, k = threadIdx.x;
    float ea = embed_avg[(size_t)c * EDIM + k] * 0.99f + g_embed_sum[(size_t)c * EDIM + k] * 0.01f;
    float total = g_scal[2];
    float cn = g_cluster_new[c];
    float cs = (cn + 1e-5f) / (total + (float)NE * 1e-5f) * total;
    float en = ea / cs;
    float ef, eaf;
    if (g_expired[c]) {
        float sv = g_xn[(size_t)g_sampidx[c] * EDIM + k];
        ef = sv; eaf = sv * 0.12f;
    } else { ef = en; eaf = ea; }
    out[OFF_EMB  + (size_t)c * EDIM + k] = ef;
    out[OFF_EAVG + (size_t)c * EDIM + k] = eaf;
}

__global__ void scalars_kernel(float* __restrict__ out) {
    int t = threadIdx.x;
    __shared__ float sh[1024];
    float local = 0.f;
#pragma unroll
    for (int j = 0; j < 8; j++) {
        float ap = g_ap[t*8 + j] * (1.0f / (float)NTOK);
        local -= ap * logf(ap);
    }
    sh[t] = local;
    __syncthreads();
    for (int s = 512; s > 0; s >>= 1) { if (t < s) sh[t] += sh[t+s]; __syncthreads(); }
    if (t == 0) {
        float ent_max = sh[0];
        float commit  = g_scal[0] / ((float)NTOK * (float)EDIM);
        out[OFF_LOSS]   = commit - ent_max;
        out[OFF_ENTMIN] = g_scal[1] / (float)NTOK;
        out[OFF_COMMIT] = commit;
    }
}

// ---------------- launch ----------------
extern "C" void kernel_launch(void* const* d_in, const int* in_sizes, int n_in,
                              void* d_out, int out_size) {
    const float* x         = (const float*)d_in[0];
    const float* W_in      = (const float*)d_in[1];
    const float* b_in      = (const float*)d_in[2];
    const float* W_out     = (const float*)d_in[3];
    const float* b_out     = (const float*)d_in[4];
    const float* embed     = (const float*)d_in[5];
    const float* embed_avg = (const float*)d_in[6];
    const float* cluster   = (const float*)d_in[7];
    float* out = (float*)d_out;

    void *p_xn=nullptr, *p_a=nullptr, *p_eh=nullptr, *p_el=nullptr, *p_wh=nullptr, *p_wl=nullptr;
    cudaGetSymbolAddress(&p_xn, g_xn);
    cudaGetSymbolAddress(&p_a, g_a);
    cudaGetSymbolAddress(&p_eh, g_eh);
    cudaGetSymbolAddress(&p_el, g_el);
    cudaGetSymbolAddress(&p_wh, g_wh);
    cudaGetSymbolAddress(&p_wl, g_wl);

    cudaFuncSetAttribute(mma_d_kernel, cudaFuncAttributeMaxDynamicSharedMemorySize, SMEM_MMA);
    cudaFuncSetAttribute(eproj_kernel, cudaFuncAttributeMaxDynamicSharedMemorySize, SMEM_EP);

    // order: mma_d at ncu-profiled slot #4 (control)
    conv_split_kernel<<<NE*EDIM/8/256, 256>>>(embed, (__nv_bfloat16*)p_eh,
                                              (__nv_bfloat16*)p_el);               // 1
    gemm_bias_kernel<<<dim3(EDIM/128, NTOK/128), 256>>>(x, W_in, b_in, (float*)p_xn,
                                                        NTOK, EDIM, LAT);          // 2
    l2norm_kernel<<<NTOK, 256>>>((float*)p_xn, (__nv_bfloat16*)p_a);               // 3
    mma_d_kernel<<<dim3(NE/128, NTOK/128), 256, SMEM_MMA>>>();                     // 4 <- profile
    zero_kernel<<<8192, 256>>>();                                                  // 5
    conv_split_kernel<<<ODIM*EDIM/8/256, 256>>>(W_out, (__nv_bfloat16*)p_wh,
                                                (__nv_bfloat16*)p_wl);             // 6
    eproj_kernel<<<dim3(ODIM/128, NE/128), 256, SMEM_EP>>>();                      // 7
    reduce_partials_kernel<<<NTOK/256, 256>>>();                                   // 8
    row_finalize_kernel<<<NTOK, 256>>>(embed, b_out, out);                         // 9 (fused gather)
    ap_kernel<<<dim3(NE/1024, NTOK/1024), 256>>>();                                // 10
    e1scan_kernel<<<1, 1024>>>(cluster, out);                                      // 11
    scalars_kernel<<<1, 1024>>>(out);                                              // 12
    e3_kernel<<<NE, 256>>>(embed_avg, out);                                        // 13
}

// round 16
// speedup vs baseline: 4.0477x; 1.2275x over previous
#include <cuda_runtime.h>
#include <cuda_bf16.h>
#include <math.h>
#include <stdint.h>

// ---------------- problem constants ----------------
#define NTOK   16384
#define EDIM   256
#define NE     8192
#define LAT    768
#define ODIM   768

#define OFF_ZQ     ((size_t)0)
#define OFF_IND    ((size_t)12582912)
#define OFF_LOSS   ((size_t)12599296)
#define OFF_EMB    ((size_t)12599297)
#define OFF_EAVG   ((size_t)14696449)
#define OFF_CS     ((size_t)16793601)
#define OFF_ENTMIN ((size_t)16801793)
#define OFF_COMMIT ((size_t)16801794)

#define QSCALE 126.0f
#define QINV   (1.0f / 126.0f)

// ---------------- device scratch ----------------
__device__ signed char g_d8[(size_t)NTOK * NE];
__device__ __nv_bfloat16 g_a[(size_t)NTOK * EDIM];
__device__ __nv_bfloat16 g_eh[(size_t)NE * EDIM];
__device__ __nv_bfloat16 g_el[(size_t)NE * EDIM];
__device__ __nv_bfloat16 g_wh[(size_t)ODIM * EDIM];
__device__ __nv_bfloat16 g_wl[(size_t)ODIM * EDIM];
__device__ float g_eproj[(size_t)NE * ODIM];
__device__ float g_xn[NTOK * EDIM];
__device__ float g_Sp[(size_t)64 * NTOK];
__device__ float g_Tp[(size_t)64 * NTOK];
__device__ int   g_Mp[(size_t)64 * NTOK];
__device__ float g_Sf[NTOK];
__device__ float g_Tf[NTOK];
__device__ int   g_Mf[NTOK];
__device__ unsigned long long g_mask[NTOK];
__device__ float g_invS[NTOK];
__device__ float g_bins[NE];
__device__ float g_ap[NE];
__device__ float g_cluster_new[NE];
__device__ int   g_expired[NE];
__device__ int   g_sampidx[NE];
__device__ float g_embed_sum[NE * EDIM];
__device__ float g_scal[4];

// ---------------- fast exp (FFMA only) ----------------
__device__ __forceinline__ float fast_exp(float x) {
    float z = x * 1.4426950408889634f;
    int   i = __float2int_rn(z);
    float rf = (float)i;
    float g = fmaf(rf, -0.693359375f, x);
    g = fmaf(rf, 2.12194440e-4f, g);
    float p = 1.98412698e-4f;
    p = fmaf(p, g, 1.38888889e-3f);
    p = fmaf(p, g, 8.33333333e-3f);
    p = fmaf(p, g, 4.16666667e-2f);
    p = fmaf(p, g, 1.66666667e-1f);
    p = fmaf(p, g, 0.5f);
    p = fmaf(p, g, 1.0f);
    p = fmaf(p, g, 1.0f);
    float sc = __int_as_float((i + 127) << 23);
    return p * sc;
}

// ---------------- helpers ----------------
__device__ __forceinline__ uint32_t smem_u32(const void* p) {
    uint32_t a;
    asm("{ .reg .u64 t; cvta.to.shared.u64 t, %1; cvt.u32.u64 %0, t; }" : "=r"(a) : "l"(p));
    return a;
}
__device__ __forceinline__ void ldsm4(uint32_t* r, uint32_t addr) {
    asm volatile("ldmatrix.sync.aligned.m8n8.x4.shared.b16 {%0,%1,%2,%3}, [%4];"
                 : "=r"(r[0]), "=r"(r[1]), "=r"(r[2]), "=r"(r[3]) : "r"(addr));
}
__device__ __forceinline__ void mma_bf16(float* c, const uint32_t* a, uint32_t b0, uint32_t b1) {
    asm volatile("mma.sync.aligned.m16n8k16.row.col.f32.bf16.bf16.f32 "
                 "{%0,%1,%2,%3}, {%4,%5,%6,%7}, {%8,%9}, {%0,%1,%2,%3};"
                 : "+f"(c[0]), "+f"(c[1]), "+f"(c[2]), "+f"(c[3])
                 : "r"(a[0]), "r"(a[1]), "r"(a[2]), "r"(a[3]), "r"(b0), "r"(b1));
}
__device__ __forceinline__ void cp16(uint32_t dst, const void* src) {
    asm volatile("cp.async.cg.shared.global [%0], [%1], 16;" :: "r"(dst), "l"(src));
}
#define CP_COMMIT() asm volatile("cp.async.commit_group;")

__device__ __forceinline__ int q8i(float d) {
    return __float2int_rn(fminf(fmaxf(d * QSCALE, -127.f), 127.f));
}

// ---------------- zeroing ----------------
__global__ void zero_kernel() {
    int i = blockIdx.x * 256 + threadIdx.x;
    if (i < NE * EDIM) g_embed_sum[i] = 0.f;
    if (i < NE)   { g_bins[i] = 0.f; g_ap[i] = 0.f; }
    if (i < 4)    g_scal[i] = 0.f;
}

// ---------------- fp32 SGEMM, double-buffered + vectorized LDS ----------------
__global__ void __launch_bounds__(256)
gemm_bias_kernel(const float* __restrict__ A, const float* __restrict__ W,
                 const float* __restrict__ bias, float* __restrict__ C,
                 int M, int N, int K) {
    __shared__ float As[2][8][132];
    __shared__ float Ws[2][8][132];
    const int tid = threadIdx.x;
    const int tx = tid & 15, ty = tid >> 4;
    const int bm = blockIdx.y * 128, bn = blockIdx.x * 128;
    float acc[8][8] = {};
    const int lrow = tid >> 1;
    const int lk4  = (tid & 1) * 4;
    const float* Ap = A + (size_t)(bm + lrow) * K + lk4;
    const float* Wp = W + (size_t)(bn + lrow) * K + lk4;
    const int NIT = K >> 3;

    float4 av = *(const float4*)(Ap);
    float4 wv = *(const float4*)(Wp);
    As[0][lk4+0][lrow]=av.x; As[0][lk4+1][lrow]=av.y; As[0][lk4+2][lrow]=av.z; As[0][lk4+3][lrow]=av.w;
    Ws[0][lk4+0][lrow]=wv.x; Ws[0][lk4+1][lrow]=wv.y; Ws[0][lk4+2][lrow]=wv.z; Ws[0][lk4+3][lrow]=wv.w;
    __syncthreads();

    for (int it = 0; it < NIT; it++) {
        int cur = it & 1;
        if (it + 1 < NIT) {
            av = *(const float4*)(Ap + (it + 1) * 8);
            wv = *(const float4*)(Wp + (it + 1) * 8);
        }
#pragma unroll
        for (int k = 0; k < 8; k++) {
            float4 a0 = *(const float4*)&As[cur][k][ty * 8];
            float4 a1 = *(const float4*)&As[cur][k][ty * 8 + 4];
            float2 b0 = *(const float2*)&Ws[cur][k][tx * 2];
            float2 b1 = *(const float2*)&Ws[cur][k][32 + tx * 2];
            float2 b2 = *(const float2*)&Ws[cur][k][64 + tx * 2];
            float2 b3 = *(const float2*)&Ws[cur][k][96 + tx * 2];
            float a[8] = {a0.x, a0.y, a0.z, a0.w, a1.x, a1.y, a1.z, a1.w};
            float b[8] = {b0.x, b0.y, b1.x, b1.y, b2.x, b2.y, b3.x, b3.y};
#pragma unroll
            for (int ir = 0; ir < 8; ir++)
#pragma unroll
                for (int ic = 0; ic < 8; ic++)
                    acc[ir][ic] = fmaf(a[ir], b[ic], acc[ir][ic]);
        }
        if (it + 1 < NIT) {
            int nxt = cur ^ 1;
            As[nxt][lk4+0][lrow]=av.x; As[nxt][lk4+1][lrow]=av.y; As[nxt][lk4+2][lrow]=av.z; As[nxt][lk4+3][lrow]=av.w;
            Ws[nxt][lk4+0][lrow]=wv.x; Ws[nxt][lk4+1][lrow]=wv.y; Ws[nxt][lk4+2][lrow]=wv.z; Ws[nxt][lk4+3][lrow]=wv.w;
        }
        __syncthreads();
    }
#pragma unroll
    for (int ir = 0; ir < 8; ir++) {
        int row = bm + ty * 8 + ir;
#pragma unroll
        for (int ic2 = 0; ic2 < 4; ic2++) {
            int col = bn + ic2 * 32 + tx * 2;
            float2 v = make_float2(acc[ir][ic2*2]   + bias[col],
                                   acc[ir][ic2*2+1] + bias[col + 1]);
            *(float2*)(C + (size_t)row * N + col) = v;
        }
    }
}

// ---------------- row l2-normalize (shuffle reduce), fused bf16 output ----------------
__global__ void l2norm_kernel(float* __restrict__ x, __nv_bfloat16* __restrict__ xb) {
    int r = blockIdx.x, t = threadIdx.x;
    int w = t >> 5, lane = t & 31;
    __shared__ float sw[8];
    float v = x[(size_t)r * EDIM + t];
    float s = v * v;
#pragma unroll
    for (int o = 16; o; o >>= 1) s += __shfl_xor_sync(0xffffffffu, s, o);
    if (lane == 0) sw[w] = s;
    __syncthreads();
    if (t == 0) {
        float tot = sw[0];
#pragma unroll
        for (int j = 1; j < 8; j++) tot += sw[j];
        sw[0] = sqrtf(tot);
    }
    __syncthreads();
    float xn = v / sw[0];
    x[(size_t)r * EDIM + t] = xn;
    xb[(size_t)r * EDIM + t] = __float2bfloat16(xn);
}

// ---------------- fp32 -> bf16 hi/lo split ----------------
__global__ void conv_split_kernel(const float* __restrict__ src,
                                  __nv_bfloat16* __restrict__ hi,
                                  __nv_bfloat16* __restrict__ lo) {
    int i = blockIdx.x * 256 + threadIdx.x;
    float v[8];
    float4 v0 = ((const float4*)src)[2*i];
    float4 v1 = ((const float4*)src)[2*i+1];
    v[0]=v0.x; v[1]=v0.y; v[2]=v0.z; v[3]=v0.w;
    v[4]=v1.x; v[5]=v1.y; v[6]=v1.z; v[7]=v1.w;
    __nv_bfloat16 h[8], l[8];
#pragma unroll
    for (int j = 0; j < 8; j++) {
        h[j] = __float2bfloat16(v[j]);
        l[j] = __float2bfloat16(v[j] - __bfloat162float(h[j]));
    }
    uint4 ph, pl;
    ph.x = *(uint32_t*)&h[0]; ph.y = *(uint32_t*)&h[2];
    ph.z = *(uint32_t*)&h[4]; ph.w = *(uint32_t*)&h[6];
    pl.x = *(uint32_t*)&l[0]; pl.y = *(uint32_t*)&l[2];
    pl.z = *(uint32_t*)&l[4]; pl.w = *(uint32_t*)&l[6];
    ((uint4*)hi)[i] = ph;
    ((uint4*)lo)[i] = pl;
}

// ---------------- bf16 TC d-GEMM, 3-stage cp.async, int8-LUT epilogue ----------------
#define SSTP 72
#define STG  (128 * SSTP * 2)
#define NSTAGE 3
#define SMEM_MMA (NSTAGE * 2 * STG)    // 110592 B

__global__ void __launch_bounds__(256, 2)
mma_d_kernel() {
    extern __shared__ __align__(16) char smem[];
    const int tid = threadIdx.x;
    const int bm = blockIdx.y * 128, bn = blockIdx.x * 128;
    const int wid = tid >> 5, lane = tid & 31;
    const int wr = (wid & 1) * 64;
    const int wc = (wid >> 1) * 32;

    uint32_t sb = smem_u32(smem);
    uint32_t aOff = (uint32_t)(((wr + (lane & 15)) * SSTP + (lane >> 4) * 8) * 2);
    uint32_t bRow = (uint32_t)(wc + (lane & 7) + ((lane >> 4) << 3));
    uint32_t bOff = (uint32_t)((bRow * SSTP + ((lane >> 3) & 1) * 8) * 2);

    const char* gA = (const char*)g_a  + (size_t)bm * 512;
    const char* gB = (const char*)g_eh + (size_t)bn * 512;
    const int lrow = tid >> 3, lc8 = tid & 7;

    float acc[4][4][4] = {};

#pragma unroll
    for (int pc = 0; pc < 2; pc++) {
        uint32_t dstA = sb + (uint32_t)pc * 2 * STG;
        uint32_t dstB = dstA + STG;
#pragma unroll
        for (int j = 0; j < 4; j++) {
            int row = lrow + j * 32;
            uint32_t so = (uint32_t)((row * SSTP + lc8 * 8) * 2);
            cp16(dstA + so, gA + (size_t)row * 512 + pc * 128 + lc8 * 16);
            cp16(dstB + so, gB + (size_t)row * 512 + pc * 128 + lc8 * 16);
        }
        CP_COMMIT();
    }

#pragma unroll
    for (int kc = 0; kc < 4; kc++) {
        if (kc < 3) asm volatile("cp.async.wait_group 1;");
        else        asm volatile("cp.async.wait_group 0;");
        __syncthreads();
        if (kc + 2 < 4) {
            int st = (kc + 2) % NSTAGE;
            uint32_t dstA = sb + (uint32_t)st * 2 * STG;
            uint32_t dstB = dstA + STG;
#pragma unroll
            for (int j = 0; j < 4; j++) {
                int row = lrow + j * 32;
                uint32_t so = (uint32_t)((row * SSTP + lc8 * 8) * 2);
                cp16(dstA + so, gA + (size_t)row * 512 + (kc + 2) * 128 + lc8 * 16);
                cp16(dstB + so, gB + (size_t)row * 512 + (kc + 2) * 128 + lc8 * 16);
            }
            CP_COMMIT();
        }
        uint32_t stA = sb + (uint32_t)(kc % NSTAGE) * 2 * STG;
        uint32_t stB = stA + STG;
#pragma unroll
        for (int kk = 0; kk < 4; kk++) {
            uint32_t ko = (uint32_t)kk * 32;
            uint32_t aF[4][4], bF[2][4];
#pragma unroll
            for (int mi = 0; mi < 4; mi++) ldsm4(aF[mi], stA + aOff + mi * (16 * SSTP * 2) + ko);
#pragma unroll
            for (int n2 = 0; n2 < 2; n2++) ldsm4(bF[n2], stB + bOff + n2 * (16 * SSTP * 2) + ko);
#pragma unroll
            for (int mi = 0; mi < 4; mi++)
#pragma unroll
                for (int ni = 0; ni < 4; ni++)
                    mma_bf16(acc[mi][ni], aF[mi], bF[ni >> 1][(ni & 1) * 2], bF[ni >> 1][(ni & 1) * 2 + 1]);
        }
    }

    __syncthreads();

    // ---- int8-native epilogue: quantize, LUT S/T, int min, packed stores ----
    signed char* epi = (signed char*)smem;
    float* rS = (float*)(smem + 36864);
    float* rT = rS + 512;
    int*   rM = (int*)(rT + 512);
    float* lutS = (float*)(smem + 43008);
    float* lutT = lutS + 256;
    {
        int qv = (tid < 128) ? tid : tid - 256;
        float t10 = 10.f * (float)qv * QINV;
        float e = fast_exp(t10);
        lutS[tid] = e;
        lutT[tid] = e * t10;
    }
    __syncthreads();

    const int cg = wid >> 1;
    const int r0 = wr + (lane >> 2);
    const int c0 = wc + (lane & 3) * 2;
#pragma unroll
    for (int mi = 0; mi < 4; mi++) {
#pragma unroll
        for (int half = 0; half < 2; half++) {
            int rr = r0 + mi * 16 + half * 8;
            float S = 0.f, T = 0.f;
            int qm = 127;
#pragma unroll
            for (int ni = 0; ni < 4; ni++) {
                int q0 = q8i(acc[mi][ni][half*2]);
                int q1 = q8i(acc[mi][ni][half*2+1]);
                S += lutS[q0 & 255] + lutS[q1 & 255];
                T += lutT[q0 & 255] + lutT[q1 & 255];
                qm = min(qm, min(q0, q1));
                *(short*)(epi + rr * 144 + c0 + ni * 8) =
                    (short)((q0 & 0xff) | (q1 << 8));
            }
#pragma unroll
            for (int o = 1; o < 4; o <<= 1) {
                S += __shfl_xor_sync(0xffffffffu, S, o);
                T += __shfl_xor_sync(0xffffffffu, T, o);
                qm = min(qm, __shfl_xor_sync(0xffffffffu, qm, o));
            }
            if ((lane & 3) == 0) {
                rS[cg * 128 + rr] = S;
                rT[cg * 128 + rr] = T;
                rM[cg * 128 + rr] = qm;
            }
        }
    }
    __syncthreads();
    if (tid < 128) {
        float S = rS[tid] + rS[128 + tid] + rS[256 + tid] + rS[384 + tid];
        float T = rT[tid] + rT[128 + tid] + rT[256 + tid] + rT[384 + tid];
        int m = min(min(rM[tid], rM[128 + tid]), min(rM[256 + tid], rM[384 + tid]));
        size_t o = (size_t)blockIdx.x * NTOK + bm + tid;
        g_Sp[o] = S; g_Tp[o] = T; g_Mp[o] = m;
    }
#pragma unroll
    for (int j = 0; j < 4; j++) {
        int idx = j * 256 + tid;
        int row = idx >> 3, c16 = idx & 7;
        uint4 v = *(uint4*)(epi + row * 144 + c16 * 16);
        *(uint4*)(g_d8 + (size_t)(bm + row) * NE + bn + c16 * 16) = v;
    }
}

// ---------------- reduce partials + candidate block mask ----------------
__global__ void reduce_partials_kernel() {
    int r = blockIdx.x * 256 + threadIdx.x;
    float S = 0.f, T = 0.f;
    int m = 127;
#pragma unroll 8
    for (int b = 0; b < 64; b++) {
        size_t o = (size_t)b * NTOK + r;
        S += g_Sp[o];
        T += g_Tp[o];
        m = min(m, g_Mp[o]);
    }
    int qthr = min(m + 2, 127);
    unsigned long long mask = 0ULL;
#pragma unroll 8
    for (int b = 0; b < 64; b++) {
        if (g_Mp[(size_t)b * NTOK + r] <= qthr)
            mask |= (1ULL << b);
    }
    g_Sf[r] = S; g_Tf[r] = T; g_Mf[r] = qthr;
    g_mask[r] = mask;
    g_invS[r] = 1.0f / S;
}

// ---------------- bf16-split TC GEMM (cp.async pipeline): g_eproj = embed @ W_out^T ----------------
#define EPSTG (4 * STG)
#define SMEM_EP (2 * EPSTG)

__global__ void __launch_bounds__(256)
eproj_kernel() {
    extern __shared__ __align__(16) char smem[];
    const int tid = threadIdx.x;
    const int bm = blockIdx.y * 128, bn = blockIdx.x * 128;
    const int wid = tid >> 5, lane = tid & 31;
    const int wr = (wid & 1) * 64;
    const int wc = (wid >> 1) * 32;

    uint32_t sb = smem_u32(smem);
    uint32_t aOff = (uint32_t)(((wr + (lane & 15)) * SSTP + (lane >> 4) * 8) * 2);
    uint32_t bRow = (uint32_t)(wc + (lane & 7) + ((lane >> 4) << 3));
    uint32_t bOff = (uint32_t)((bRow * SSTP + ((lane >> 3) & 1) * 8) * 2);

    const char* gAh = (const char*)g_eh + (size_t)bm * 512;
    const char* gAl = (const char*)g_el + (size_t)bm * 512;
    const char* gBh = (const char*)g_wh + (size_t)bn * 512;
    const char* gBl = (const char*)g_wl + (size_t)bn * 512;
    const int lrow = tid >> 3, lc8 = tid & 7;

    float acc[4][4][4] = {};

#pragma unroll
    for (int pc = 0; pc < 2; pc++) {
        uint32_t st = sb + (uint32_t)pc * EPSTG;
#pragma unroll
        for (int j = 0; j < 4; j++) {
            int row = lrow + j * 32;
            uint32_t so = (uint32_t)((row * SSTP + lc8 * 8) * 2);
            size_t go = (size_t)row * 512 + pc * 128 + lc8 * 16;
            cp16(st + so,           gAh + go);
            cp16(st + STG + so,     gAl + go);
            cp16(st + 2 * STG + so, gBh + go);
            cp16(st + 3 * STG + so, gBl + go);
        }
        CP_COMMIT();
    }

#pragma unroll
    for (int kc = 0; kc < 4; kc++) {
        if (kc < 3) asm volatile("cp.async.wait_group 1;");
        else        asm volatile("cp.async.wait_group 0;");
        __syncthreads();
        uint32_t st = sb + (uint32_t)(kc & 1) * EPSTG;
        const uint32_t AH = st, AL = st + STG, BH = st + 2 * STG, BL = st + 3 * STG;
#pragma unroll
        for (int kk = 0; kk < 4; kk++) {
            uint32_t ko = (uint32_t)kk * 32;
            uint32_t ah[4][4], al[4][4], bh[2][4], bl[2][4];
#pragma unroll
            for (int mi = 0; mi < 4; mi++) {
                ldsm4(ah[mi], AH + aOff + mi * (16 * SSTP * 2) + ko);
                ldsm4(al[mi], AL + aOff + mi * (16 * SSTP * 2) + ko);
            }
#pragma unroll
            for (int n2 = 0; n2 < 2; n2++) {
                ldsm4(bh[n2], BH + bOff + n2 * (16 * SSTP * 2) + ko);
                ldsm4(bl[n2], BL + bOff + n2 * (16 * SSTP * 2) + ko);
            }
#pragma unroll
            for (int mi = 0; mi < 4; mi++)
#pragma unroll
                for (int ni = 0; ni < 4; ni++) {
                    uint32_t h0 = bh[ni >> 1][(ni & 1) * 2], h1 = bh[ni >> 1][(ni & 1) * 2 + 1];
                    uint32_t l0 = bl[ni >> 1][(ni & 1) * 2], l1 = bl[ni >> 1][(ni & 1) * 2 + 1];
                    mma_bf16(acc[mi][ni], ah[mi], h0, h1);
                    mma_bf16(acc[mi][ni], ah[mi], l0, l1);
                    mma_bf16(acc[mi][ni], al[mi], h0, h1);
                }
        }
        __syncthreads();
        if (kc + 2 < 4) {
            uint32_t st2 = sb + (uint32_t)(kc & 1) * EPSTG;
#pragma unroll
            for (int j = 0; j < 4; j++) {
                int row = lrow + j * 32;
                uint32_t so = (uint32_t)((row * SSTP + lc8 * 8) * 2);
                size_t go = (size_t)row * 512 + (kc + 2) * 128 + lc8 * 16;
                cp16(st2 + so,           gAh + go);
                cp16(st2 + STG + so,     gAl + go);
                cp16(st2 + 2 * STG + so, gBh + go);
                cp16(st2 + 3 * STG + so, gBl + go);
            }
            CP_COMMIT();
        }
    }

    __syncthreads();
    float* epi = (float*)smem;
    {
        const int r0 = wr + (lane >> 2);
        const int c0 = wc + (lane & 3) * 2;
#pragma unroll
        for (int mi = 0; mi < 4; mi++)
#pragma unroll
            for (int ni = 0; ni < 4; ni++) {
                int rr = r0 + mi * 16, cc = c0 + ni * 8;
                *(float2*)(epi + rr * 132 + cc) = make_float2(acc[mi][ni][0], acc[mi][ni][1]);
                *(float2*)(epi + (rr + 8) * 132 + cc) = make_float2(acc[mi][ni][2], acc[mi][ni][3]);
            }
    }
    __syncthreads();
#pragma unroll
    for (int j = 0; j < 16; j++) {
        int idx = j * 256 + tid;
        int row = idx >> 5, c4 = idx & 31;
        uint4 v = *(uint4*)(epi + row * 132 + c4 * 4);
        *(uint4*)(g_eproj + (size_t)(bm + row) * ODIM + bn + c4 * 4) = v;
    }
}

// ---------------- row finalize: masked candidate scan, exact argmin, fused gather ----------------
__global__ void __launch_bounds__(256)
row_finalize_kernel(const float* __restrict__ embed, const float* __restrict__ b_out,
                    float* __restrict__ out) {
    const int r = blockIdx.x, t = threadIdx.x;
    const int w = t >> 5, lane = t & 31;
    __shared__ float sxn[256];
    __shared__ float swred[8];
    __shared__ unsigned long long swbest[8];
    __shared__ int scnt;
    __shared__ int scand[64];
    __shared__ int sind;

    sxn[t] = g_xn[(size_t)r * EDIM + t];
    if (t == 0) scnt = 0;
    float Stot = g_Sf[r], Ttot = g_Tf[r];
    int qthr = g_Mf[r];
    unsigned long long mask = g_mask[r];
    __syncthreads();

    if (w == 0) {
        uint32_t thr4 = (uint32_t)(qthr & 0xff) * 0x01010101u;
        const uint32_t* dp = (const uint32_t*)(g_d8 + (size_t)r * NE);
        unsigned long long mk = mask;
        while (mk) {
            int b = __ffsll(mk) - 1;
            mk &= mk - 1;
            uint32_t u = dp[b * 32 + lane];
            uint32_t m = __vcmples4(u, thr4);
            if (m) {
#pragma unroll
                for (int by = 0; by < 4; by++)
                    if ((m >> (8 * by)) & 1) {
                        int p = atomicAdd(&scnt, 1);
                        if (p < 64) scand[p] = (b * 32 + lane) * 4 + by;
                    }
            }
        }
    }
    __syncthreads();
    int ncand = scnt < 64 ? scnt : 64;
    int ind;
    if (ncand == 1) {
        ind = scand[0];
    } else {
        unsigned long long best = ~0ULL;
        for (int i = w; i < ncand; i += 8) {
            int c = scand[i];
            const float* er = embed + (size_t)c * EDIM;
            float s = 0.f;
#pragma unroll
            for (int j = 0; j < 8; j++)
                s = fmaf(sxn[lane + j * 32], er[lane + j * 32], s);
#pragma unroll
            for (int o = 16; o; o >>= 1) s += __shfl_xor_sync(0xffffffffu, s, o);
            unsigned u = __float_as_uint(s);
            u = (u & 0x80000000u) ? ~u : (u | 0x80000000u);
            unsigned long long k = ((unsigned long long)u << 32) | (unsigned)c;
            if (k < best) best = k;
        }
        if (lane == 0) swbest[w] = best;
        __syncthreads();
        if (t == 0) {
            unsigned long long b = swbest[0];
#pragma unroll
            for (int j = 1; j < 8; j++) if (swbest[j] < b) b = swbest[j];
            sind = (int)(b & 0xffffffffu);
        }
        __syncthreads();
        ind = sind;
    }

    float xnv = sxn[t];
    float ev = embed[(size_t)ind * EDIM + t];
    float df = ev - xnv;
    atomicAdd(&g_embed_sum[(size_t)ind * EDIM + t], xnv);
    float cs = df * df;
#pragma unroll
    for (int o = 16; o; o >>= 1) cs += __shfl_xor_sync(0xffffffffu, cs, o);
    if (lane == 0) swred[w] = cs;

    {
        const float* src = g_eproj + (size_t)ind * ODIM;
        float* dst = out + OFF_ZQ + (size_t)r * ODIM;
#pragma unroll
        for (int c = t; c < ODIM; c += 256)
            dst[c] = src[c] + b_out[c];
    }
    __syncthreads();
    if (t == 0) {
        float tot = swred[0];
#pragma unroll
        for (int j = 1; j < 8; j++) tot += swred[j];
        atomicAdd(&g_scal[0], tot);
        out[OFF_IND + r] = (float)ind;
        atomicAdd(&g_bins[ind], 1.0f);
        atomicAdd(&g_scal[1], logf(Stot) - Ttot / Stot);
    }
}

// ---------------- ap column pass: 512 CTAs, unroll-8, conflict-free LUT ----------------
__global__ void __launch_bounds__(256)
ap_kernel() {
    __shared__ float lut[8192];
    __shared__ float sh_inv[256];
    int t = threadIdx.x, lane = t & 31;
    for (int i = t; i < 8192; i += 256) {
        int b = i >> 5;
        int q = (b < 128) ? b : b - 256;
        lut[i] = fast_exp(10.f * (float)q * QINV);
    }
    int c0 = (blockIdx.x * 256 + t) * 4;
    int r0 = blockIdx.y * 256;
    __syncthreads();
    sh_inv[t] = g_invS[r0 + t];
    __syncthreads();
    float a0 = 0.f, a1 = 0.f, a2 = 0.f, a3 = 0.f;
    const signed char* ep = g_d8 + (size_t)r0 * NE + c0;
#pragma unroll 8
    for (int j = 0; j < 256; j++) {
        uint32_t w = *(const uint32_t*)(ep + (size_t)j * NE);
        float inv = sh_inv[j];
        a0 = fmaf(lut[((w & 255u) << 5) | lane], inv, a0);
        a1 = fmaf(lut[(((w >> 8) & 255u) << 5) | lane], inv, a1);
        a2 = fmaf(lut[(((w >> 16) & 255u) << 5) | lane], inv, a2);
        a3 = fmaf(lut[((w >> 24) << 5) | lane], inv, a3);
    }
    atomicAdd(&g_ap[c0],     a0);
    atomicAdd(&g_ap[c0 + 1], a1);
    atomicAdd(&g_ap[c0 + 2], a2);
    atomicAdd(&g_ap[c0 + 3], a3);
}

// ---------------- merged e1 + scan (single block) ----------------
__global__ void e1scan_kernel(const float* __restrict__ cluster_size, float* __restrict__ out) {
    int t = threadIdx.x;
    __shared__ int sh[1024];
    __shared__ float shf[1024];
    int vals[8]; int s = 0; float csum = 0.f;
#pragma unroll
    for (int j = 0; j < 8; j++) {
        int i = t * 8 + j;
        float cn = cluster_size[i] * 0.99f + g_bins[i] * 0.01f;
        g_cluster_new[i] = cn;
        int ex = (cn < 0.1f);
        g_expired[i] = ex;
        out[OFF_CS + i] = ex ? 0.12f : cn;
        csum += cn;
        s += ex; vals[j] = s;
    }
    sh[t] = s; shf[t] = csum;
    __syncthreads();
    for (int off = 1; off < 1024; off <<= 1) {
        int v = (t >= off) ? sh[t - off] : 0;
        __syncthreads();
        sh[t] += v;
        __syncthreads();
    }
    for (int ss = 512; ss > 0; ss >>= 1) { if (t < ss) shf[t] += shf[t+ss]; __syncthreads(); }
    if (t == 0) g_scal[2] = shf[0];
    int excl = (t > 0) ? sh[t-1] : 0;
#pragma unroll
    for (int j = 0; j < 8; j++) {
        int cum = excl + vals[j];
        int idx = cum - 1; if (idx < 0) idx = 0;
        g_sampidx[t*8 + j] = idx;
    }
}

__global__ void e3_kernel(const float* __restrict__ embed_avg, float* __restrict__ out) {
    int c = blockIdx.x, k = threadIdx.x;
    float ea = embed_avg[(size_t)c * EDIM + k] * 0.99f + g_embed_sum[(size_t)c * EDIM + k] * 0.01f;
    float total = g_scal[2];
    float cn = g_cluster_new[c];
    float cs = (cn + 1e-5f) / (total + (float)NE * 1e-5f) * total;
    float en = ea / cs;
    float ef, eaf;
    if (g_expired[c]) {
        float sv = g_xn[(size_t)g_sampidx[c] * EDIM + k];
        ef = sv; eaf = sv * 0.12f;
    } else { ef = en; eaf = ea; }
    out[OFF_EMB  + (size_t)c * EDIM + k] = ef;
    out[OFF_EAVG + (size_t)c * EDIM + k] = eaf;
}

__global__ void scalars_kernel(float* __restrict__ out) {
    int t = threadIdx.x;
    __shared__ float sh[1024];
    float local = 0.f;
#pragma unroll
    for (int j = 0; j < 8; j++) {
        float ap = g_ap[t*8 + j] * (1.0f / (float)NTOK);
        local -= ap * logf(ap);
    }
    sh[t] = local;
    __syncthreads();
    for (int s = 512; s > 0; s >>= 1) { if (t < s) sh[t] += sh[t+s]; __syncthreads(); }
    if (t == 0) {
        float ent_max = sh[0];
        float commit  = g_scal[0] / ((float)NTOK * (float)EDIM);
        out[OFF_LOSS]   = commit - ent_max;
        out[OFF_ENTMIN] = g_scal[1] / (float)NTOK;
        out[OFF_COMMIT] = commit;
    }
}

// ---------------- launch ----------------
extern "C" void kernel_launch(void* const* d_in, const int* in_sizes, int n_in,
                              void* d_out, int out_size) {
    const float* x         = (const float*)d_in[0];
    const float* W_in      = (const float*)d_in[1];
    const float* b_in      = (const float*)d_in[2];
    const float* W_out     = (const float*)d_in[3];
    const float* b_out     = (const float*)d_in[4];
    const float* embed     = (const float*)d_in[5];
    const float* embed_avg = (const float*)d_in[6];
    const float* cluster   = (const float*)d_in[7];
    float* out = (float*)d_out;

    void *p_xn=nullptr, *p_a=nullptr, *p_eh=nullptr, *p_el=nullptr, *p_wh=nullptr, *p_wl=nullptr;
    cudaGetSymbolAddress(&p_xn, g_xn);
    cudaGetSymbolAddress(&p_a, g_a);
    cudaGetSymbolAddress(&p_eh, g_eh);
    cudaGetSymbolAddress(&p_el, g_el);
    cudaGetSymbolAddress(&p_wh, g_wh);
    cudaGetSymbolAddress(&p_wl, g_wl);

    cudaFuncSetAttribute(mma_d_kernel, cudaFuncAttributeMaxDynamicSharedMemorySize, SMEM_MMA);
    cudaFuncSetAttribute(eproj_kernel, cudaFuncAttributeMaxDynamicSharedMemorySize, SMEM_EP);

    conv_split_kernel<<<NE*EDIM/8/256, 256>>>(embed, (__nv_bfloat16*)p_eh,
                                              (__nv_bfloat16*)p_el);               // 1
    gemm_bias_kernel<<<dim3(EDIM/128, NTOK/128), 256>>>(x, W_in, b_in, (float*)p_xn,
                                                        NTOK, EDIM, LAT);          // 2
    l2norm_kernel<<<NTOK, 256>>>((float*)p_xn, (__nv_bfloat16*)p_a);               // 3
    mma_d_kernel<<<dim3(NE/128, NTOK/128), 256, SMEM_MMA>>>();                     // 4 <- profile
    zero_kernel<<<8192, 256>>>();                                                  // 5
    conv_split_kernel<<<ODIM*EDIM/8/256, 256>>>(W_out, (__nv_bfloat16*)p_wh,
                                                (__nv_bfloat16*)p_wl);             // 6
    eproj_kernel<<<dim3(ODIM/128, NE/128), 256, SMEM_EP>>>();                      // 7
    reduce_partials_kernel<<<NTOK/256, 256>>>();                                   // 8
    row_finalize_kernel<<<NTOK, 256>>>(embed, b_out, out);                         // 9
    ap_kernel<<<dim3(NE/1024, NTOK/256), 256>>>();                                 // 10 (512 CTAs)
    e1scan_kernel<<<1, 1024>>>(cluster, out);                                      // 11
    scalars_kernel<<<1, 1024>>>(out);                                              // 12
    e3_kernel<<<NE, 256>>>(embed_avg, out);                                        // 13
}